// round 1
// baseline (speedup 1.0000x reference)
#include <cuda_runtime.h>
#include <cuda_bf16.h>
#include <math.h>

// Problem constants
#define BB   2
#define SS   1024
#define DDIM 1024
#define HH   16
#define LLAY 4
#define FFD  2048
#define DKH  64
#define BSR  (BB*SS)   // 2048 rows

// ---------------- scratch (static device globals; no allocs allowed) ----------
__device__ float g_x [BSR*DDIM];
__device__ float g_q [BSR*DDIM];
__device__ float g_k [BSR*DDIM];
__device__ float g_v [BSR*DDIM];
__device__ float g_o [BSR*DDIM];
__device__ float g_t [BSR*DDIM];
__device__ float g_h1[BSR*FFD];
__device__ float g_sc[(size_t)BB*HH*SS*SS];   // 128 MB scores scratch

// ---------------- embedding + (buggy-faithful) positional encoding ------------
// ref bug: pe computed for n=B rows; pe[b] broadcast over the sequence dim.
__global__ void embed_pe(const int* __restrict__ tok, const float* __restrict__ emb) {
    int idx = blockIdx.x * 256 + threadIdx.x;          // 0 .. B*S*D-1
    int d  = idx & (DDIM - 1);
    int bs = idx >> 10;                                 // b*S + s
    int b  = bs >> 10;
    int t  = tok[bs];
    int i2 = (d >> 1) << 1;                             // 2*i
    float div = expf(-(float)i2 * (9.210340371976184f / (float)DDIM));
    float ang = (float)b * div;
    float pe  = (d & 1) ? cosf(ang) : sinf(ang);
    g_x[idx] = emb[(size_t)t * DDIM + d] + pe;
}

// ---------------- generic SGEMM: C[M,N] = A[M,K] @ B[K,N] + bias (opt relu) ---
// BM=128, BN=64, BK=16, 256 threads, 8x4 microtile per thread.
template<bool RELU>
__global__ __launch_bounds__(256)
void sgemm_bias(const float* __restrict__ A, const float* __restrict__ B,
                const float* __restrict__ bias, float* __restrict__ C,
                int M, int N, int K) {
    __shared__ float As[128][16];
    __shared__ float Bs[16][64];
    const int tid = threadIdx.x;
    const int tx = tid & 15, ty = tid >> 4;
    const int m0 = blockIdx.y * 128, n0 = blockIdx.x * 64;

    float acc[8][4];
#pragma unroll
    for (int r = 0; r < 8; r++)
#pragma unroll
        for (int c = 0; c < 4; c++) acc[r][c] = 0.f;

    const int arow = tid >> 2, ak4 = (tid & 3) << 2;    // A: 2 float4/thread
    const int brow = tid >> 4, bn4 = (tid & 15) << 2;   // B: 1 float4/thread

    for (int k0 = 0; k0 < K; k0 += 16) {
#pragma unroll
        for (int e = 0; e < 2; e++) {
            int row = arow + e * 64;
            *(float4*)&As[row][ak4] =
                *(const float4*)(A + (size_t)(m0 + row) * K + k0 + ak4);
        }
        *(float4*)&Bs[brow][bn4] =
            *(const float4*)(B + (size_t)(k0 + brow) * N + n0 + bn4);
        __syncthreads();
#pragma unroll
        for (int kk = 0; kk < 16; kk++) {
            float4 bf = *(const float4*)&Bs[kk][tx << 2];
#pragma unroll
            for (int r = 0; r < 8; r++) {
                float a = As[(ty << 3) + r][kk];
                acc[r][0] += a * bf.x; acc[r][1] += a * bf.y;
                acc[r][2] += a * bf.z; acc[r][3] += a * bf.w;
            }
        }
        __syncthreads();
    }
    const int n = n0 + (tx << 2);
    float b0 = bias[n], b1 = bias[n+1], b2 = bias[n+2], b3 = bias[n+3];
#pragma unroll
    for (int r = 0; r < 8; r++) {
        int m = m0 + (ty << 3) + r;
        float4 o;
        o.x = acc[r][0] + b0; o.y = acc[r][1] + b1;
        o.z = acc[r][2] + b2; o.w = acc[r][3] + b3;
        if (RELU) {
            o.x = fmaxf(o.x, 0.f); o.y = fmaxf(o.y, 0.f);
            o.z = fmaxf(o.z, 0.f); o.w = fmaxf(o.w, 0.f);
        }
        *(float4*)(C + (size_t)m * N + n) = o;
    }
}

// ---------------- attention scores: sc[z,i,j] = (q_i . k_j) / 8 --------------
// 64x64 output tile per block; K-dim = 64 loaded fully into smem.
__global__ __launch_bounds__(256)
void attn_scores(const float* __restrict__ q, const float* __restrict__ k) {
    const int z = blockIdx.z, b = z >> 4, h = z & 15;
    const float* qb = q + (size_t)b * SS * DDIM + h * DKH;
    const float* kb = k + (size_t)b * SS * DDIM + h * DKH;
    float* out = g_sc + (size_t)z * SS * SS;
    __shared__ float Qs[64][64];
    __shared__ float Ks[64][65];   // padded: 2-way max on j-strided reads
    const int tid = threadIdx.x, tx = tid & 15, ty = tid >> 4;
    const int i0 = blockIdx.y * 64, j0 = blockIdx.x * 64;

#pragma unroll
    for (int e = 0; e < 4; e++) {
        int lin = tid + e * 256;
        int row = lin >> 4, d4 = (lin & 15) << 2;
        *(float4*)&Qs[row][d4] =
            *(const float4*)(qb + (size_t)(i0 + row) * DDIM + d4);
        float4 vk = *(const float4*)(kb + (size_t)(j0 + row) * DDIM + d4);
        Ks[row][d4] = vk.x; Ks[row][d4+1] = vk.y;
        Ks[row][d4+2] = vk.z; Ks[row][d4+3] = vk.w;
    }
    __syncthreads();

    float acc[4][4];
#pragma unroll
    for (int r = 0; r < 4; r++)
#pragma unroll
        for (int c = 0; c < 4; c++) acc[r][c] = 0.f;

#pragma unroll 8
    for (int d = 0; d < 64; d++) {
        float a[4], bb[4];
#pragma unroll
        for (int r = 0; r < 4; r++) a[r] = Qs[(ty << 2) + r][d];
#pragma unroll
        for (int c = 0; c < 4; c++) bb[c] = Ks[(tx << 2) + c][d];
#pragma unroll
        for (int r = 0; r < 4; r++)
#pragma unroll
            for (int c = 0; c < 4; c++) acc[r][c] += a[r] * bb[c];
    }
#pragma unroll
    for (int r = 0; r < 4; r++) {
        float4 o;
        o.x = acc[r][0]*0.125f; o.y = acc[r][1]*0.125f;
        o.z = acc[r][2]*0.125f; o.w = acc[r][3]*0.125f;
        *(float4*)(out + (size_t)(i0 + (ty << 2) + r) * SS + j0 + (tx << 2)) = o;
    }
}

// ---------------- row softmax over S=1024 (in place on g_sc) -----------------
__global__ __launch_bounds__(256)
void softmax_rows() {
    __shared__ float sm[8];
    __shared__ float bc;
    const int tid = threadIdx.x;
    float* p = g_sc + (size_t)blockIdx.x * SS;
    float4 v = reinterpret_cast<float4*>(p)[tid];

    float m = fmaxf(fmaxf(v.x, v.y), fmaxf(v.z, v.w));
#pragma unroll
    for (int o = 16; o; o >>= 1) m = fmaxf(m, __shfl_xor_sync(~0u, m, o));
    if ((tid & 31) == 0) sm[tid >> 5] = m;
    __syncthreads();
    if (tid < 32) {
        float t = (tid < 8) ? sm[tid] : -1e30f;
#pragma unroll
        for (int o = 4; o; o >>= 1) t = fmaxf(t, __shfl_xor_sync(~0u, t, o));
        if (tid == 0) bc = t;
    }
    __syncthreads();
    m = bc;
    v.x = __expf(v.x - m); v.y = __expf(v.y - m);
    v.z = __expf(v.z - m); v.w = __expf(v.w - m);
    float s = v.x + v.y + v.z + v.w;
    __syncthreads();             // protect sm/bc reuse
#pragma unroll
    for (int o = 16; o; o >>= 1) s += __shfl_xor_sync(~0u, s, o);
    if ((tid & 31) == 0) sm[tid >> 5] = s;
    __syncthreads();
    if (tid < 32) {
        float t = (tid < 8) ? sm[tid] : 0.f;
#pragma unroll
        for (int o = 4; o; o >>= 1) t += __shfl_xor_sync(~0u, t, o);
        if (tid == 0) bc = t;
    }
    __syncthreads();
    float inv = 1.0f / bc;
    v.x *= inv; v.y *= inv; v.z *= inv; v.w *= inv;
    reinterpret_cast<float4*>(p)[tid] = v;
}

// ---------------- AV: o[b,:,h*64:] = attn[z] @ v[b,:,h*64:] ------------------
__global__ __launch_bounds__(256)
void attn_av(const float* __restrict__ v) {
    const int z = blockIdx.z, b = z >> 4, h = z & 15;
    const float* A  = g_sc + (size_t)z * SS * SS;                 // lda = SS
    const float* Bv = v   + (size_t)b * SS * DDIM + h * DKH;      // ldb = DDIM
    float*       C  = g_o + (size_t)b * SS * DDIM + h * DKH;      // ldc = DDIM
    __shared__ float As[128][16];
    __shared__ float Bs[16][64];
    const int tid = threadIdx.x, tx = tid & 15, ty = tid >> 4;
    const int m0 = blockIdx.y * 128;
    float acc[8][4];
#pragma unroll
    for (int r = 0; r < 8; r++)
#pragma unroll
        for (int c = 0; c < 4; c++) acc[r][c] = 0.f;
    const int arow = tid >> 2, ak4 = (tid & 3) << 2;
    const int brow = tid >> 4, bn4 = (tid & 15) << 2;

    for (int k0 = 0; k0 < SS; k0 += 16) {
#pragma unroll
        for (int e = 0; e < 2; e++) {
            int row = arow + e * 64;
            *(float4*)&As[row][ak4] =
                *(const float4*)(A + (size_t)(m0 + row) * SS + k0 + ak4);
        }
        *(float4*)&Bs[brow][bn4] =
            *(const float4*)(Bv + (size_t)(k0 + brow) * DDIM + bn4);
        __syncthreads();
#pragma unroll
        for (int kk = 0; kk < 16; kk++) {
            float4 bf = *(const float4*)&Bs[kk][tx << 2];
#pragma unroll
            for (int r = 0; r < 8; r++) {
                float a = As[(ty << 3) + r][kk];
                acc[r][0] += a * bf.x; acc[r][1] += a * bf.y;
                acc[r][2] += a * bf.z; acc[r][3] += a * bf.w;
            }
        }
        __syncthreads();
    }
#pragma unroll
    for (int r = 0; r < 8; r++) {
        float4 o;
        o.x = acc[r][0]; o.y = acc[r][1]; o.z = acc[r][2]; o.w = acc[r][3];
        *(float4*)(C + (size_t)(m0 + (ty << 3) + r) * DDIM + (tx << 2)) = o;
    }
}

// ---------------- add + LayerNorm (row of D=1024) ----------------------------
__global__ __launch_bounds__(256)
void add_ln(const float* __restrict__ x, const float* __restrict__ y,
            const float* __restrict__ g, const float* __restrict__ be,
            float* __restrict__ out) {
    __shared__ float sm[8];
    __shared__ float bc;
    const int tid = threadIdx.x;
    const size_t ro = (size_t)blockIdx.x * DDIM;
    float4 a = reinterpret_cast<const float4*>(x + ro)[tid];
    float4 b = reinterpret_cast<const float4*>(y + ro)[tid];
    a.x += b.x; a.y += b.y; a.z += b.z; a.w += b.w;

    float s = a.x + a.y + a.z + a.w;
#pragma unroll
    for (int o = 16; o; o >>= 1) s += __shfl_xor_sync(~0u, s, o);
    if ((tid & 31) == 0) sm[tid >> 5] = s;
    __syncthreads();
    if (tid < 32) {
        float t = (tid < 8) ? sm[tid] : 0.f;
#pragma unroll
        for (int o = 4; o; o >>= 1) t += __shfl_xor_sync(~0u, t, o);
        if (tid == 0) bc = t;
    }
    __syncthreads();
    const float mu = bc * (1.0f / DDIM);
    a.x -= mu; a.y -= mu; a.z -= mu; a.w -= mu;
    float q = a.x*a.x + a.y*a.y + a.z*a.z + a.w*a.w;
    __syncthreads();
#pragma unroll
    for (int o = 16; o; o >>= 1) q += __shfl_xor_sync(~0u, q, o);
    if ((tid & 31) == 0) sm[tid >> 5] = q;
    __syncthreads();
    if (tid < 32) {
        float t = (tid < 8) ? sm[tid] : 0.f;
#pragma unroll
        for (int o = 4; o; o >>= 1) t += __shfl_xor_sync(~0u, t, o);
        if (tid == 0) bc = t;
    }
    __syncthreads();
    const float rs = rsqrtf(bc * (1.0f / DDIM) + 1e-5f);
    float4 gv = reinterpret_cast<const float4*>(g)[tid];
    float4 bv = reinterpret_cast<const float4*>(be)[tid];
    float4 o;
    o.x = a.x * rs * gv.x + bv.x;
    o.y = a.y * rs * gv.y + bv.y;
    o.z = a.z * rs * gv.z + bv.z;
    o.w = a.w * rs * gv.w + bv.w;
    reinterpret_cast<float4*>(out + ro)[tid] = o;
}

// ---------------- launch ------------------------------------------------------
extern "C" void kernel_launch(void* const* d_in, const int* in_sizes, int n_in,
                              void* d_out, int out_size) {
    const int*   tokens = (const int*)  d_in[0];
    const float* emb    = (const float*)d_in[1];
    const float* Wq = (const float*)d_in[2],  *bq = (const float*)d_in[3];
    const float* Wk = (const float*)d_in[4],  *bk = (const float*)d_in[5];
    const float* Wv = (const float*)d_in[6],  *bv = (const float*)d_in[7];
    const float* Wo = (const float*)d_in[8],  *bo = (const float*)d_in[9];
    const float* W1 = (const float*)d_in[10], *b1 = (const float*)d_in[11];
    const float* W2 = (const float*)d_in[12], *b2 = (const float*)d_in[13];
    const float* gamma = (const float*)d_in[14], *beta = (const float*)d_in[15];
    float* out = (float*)d_out;

    float *x, *q, *k, *v, *o, *t, *h1;
    cudaGetSymbolAddress((void**)&x,  g_x);
    cudaGetSymbolAddress((void**)&q,  g_q);
    cudaGetSymbolAddress((void**)&k,  g_k);
    cudaGetSymbolAddress((void**)&v,  g_v);
    cudaGetSymbolAddress((void**)&o,  g_o);
    cudaGetSymbolAddress((void**)&t,  g_t);
    cudaGetSymbolAddress((void**)&h1, g_h1);

    embed_pe<<<BSR * DDIM / 256, 256>>>(tokens, emb);

    const dim3 gp(DDIM / 64, BSR / 128);        // proj GEMMs (N=1024)
    const dim3 gf(FFD  / 64, BSR / 128);        // FFN up (N=2048)

    for (int l = 0; l < LLAY; l++) {
        const float* lWq = Wq + (size_t)l * DDIM * DDIM;
        const float* lWk = Wk + (size_t)l * DDIM * DDIM;
        const float* lWv = Wv + (size_t)l * DDIM * DDIM;
        const float* lWo = Wo + (size_t)l * DDIM * DDIM;
        const float* lW1 = W1 + (size_t)l * DDIM * FFD;
        const float* lW2 = W2 + (size_t)l * FFD  * DDIM;
        const float* lbq = bq + (size_t)l * DDIM;
        const float* lbk = bk + (size_t)l * DDIM;
        const float* lbv = bv + (size_t)l * DDIM;
        const float* lbo = bo + (size_t)l * DDIM;
        const float* lb1 = b1 + (size_t)l * FFD;
        const float* lb2 = b2 + (size_t)l * DDIM;
        const float* lg  = gamma + (size_t)l * DDIM;
        const float* lbe = beta  + (size_t)l * DDIM;

        sgemm_bias<false><<<gp, 256>>>(x, lWq, lbq, q, BSR, DDIM, DDIM);
        sgemm_bias<false><<<gp, 256>>>(x, lWk, lbk, k, BSR, DDIM, DDIM);
        sgemm_bias<false><<<gp, 256>>>(x, lWv, lbv, v, BSR, DDIM, DDIM);

        attn_scores<<<dim3(SS / 64, SS / 64, BB * HH), 256>>>(q, k);
        softmax_rows<<<BB * HH * SS, 256>>>();
        attn_av<<<dim3(1, SS / 128, BB * HH), 256>>>(v);

        sgemm_bias<false><<<gp, 256>>>(o, lWo, lbo, t, BSR, DDIM, DDIM);
        add_ln<<<BSR, 256>>>(x, t, lg, lbe, x);

        sgemm_bias<true ><<<gf, 256>>>(x,  lW1, lb1, h1, BSR, FFD, DDIM);
        sgemm_bias<false><<<gp, 256>>>(h1, lW2, lb2, t,  BSR, DDIM, FFD);

        float* xo = (l == LLAY - 1) ? out : x;
        add_ln<<<BSR, 256>>>(x, t, lg, lbe, xo);
    }
}

// round 2
// speedup vs baseline: 1.0931x; 1.0931x over previous
#include <cuda_runtime.h>
#include <cuda_bf16.h>
#include <math.h>
#include <stdint.h>

// Problem constants
#define BB   2
#define SS   1024
#define DDIM 1024
#define HH   16
#define LLAY 4
#define FFD  2048
#define DKH  64
#define BSR  (BB*SS)   // 2048 rows

// ---------------- scratch (static device globals; no allocs allowed) ----------
__device__ float g_x [BSR*DDIM];
__device__ float g_q [BSR*DDIM];
__device__ float g_k [BSR*DDIM];
__device__ float g_v [BSR*DDIM];
__device__ float g_o [BSR*DDIM];
__device__ float g_t [BSR*DDIM];
__device__ float g_h1[BSR*FFD];
__device__ float g_sc[(size_t)BB*HH*SS*SS];   // 128 MB scores scratch

// ---------------- tf32 helpers ------------------------------------------------
__device__ __forceinline__ uint32_t f2tf32(float x) {
    uint32_t r;
    asm("cvt.rna.tf32.f32 %0, %1;" : "=r"(r) : "f"(x));
    return r;
}
__device__ __forceinline__ void mma8(float* c, const uint32_t* a, const uint32_t* b) {
    asm volatile(
        "mma.sync.aligned.m16n8k8.row.col.f32.tf32.tf32.f32 "
        "{%0,%1,%2,%3}, {%4,%5,%6,%7}, {%8,%9}, {%0,%1,%2,%3};"
        : "+f"(c[0]), "+f"(c[1]), "+f"(c[2]), "+f"(c[3])
        : "r"(a[0]), "r"(a[1]), "r"(a[2]), "r"(a[3]), "r"(b[0]), "r"(b[1]));
}

// ---------------- embedding + (buggy-faithful) positional encoding ------------
__global__ void embed_pe(const int* __restrict__ tok, const float* __restrict__ emb) {
    int idx = blockIdx.x * 256 + threadIdx.x;
    int d  = idx & (DDIM - 1);
    int bs = idx >> 10;
    int b  = bs >> 10;
    int t  = tok[bs];
    int i2 = (d >> 1) << 1;
    float div = expf(-(float)i2 * (9.210340371976184f / (float)DDIM));
    float ang = (float)b * div;
    float pe  = (d & 1) ? cosf(ang) : sinf(ang);
    g_x[idx] = emb[(size_t)t * DDIM + d] + pe;
}

// ---------------- 3xTF32 tensor-core GEMM: C = A[M,K]@B[K,N] + bias ----------
// BM=128, BN=128, BK=16; 256 threads = 8 warps (2x4); warp tile 64x32.
template<bool RELU>
__global__ __launch_bounds__(256, 1)
void sgemm_tc3(const float* __restrict__ A, const float* __restrict__ B,
               const float* __restrict__ bias, float* __restrict__ C,
               int M, int N, int K) {
    __shared__ uint32_t As_h[16][132], As_l[16][132];   // k-major
    __shared__ uint32_t Bs_h[16][132], Bs_l[16][132];   // [k][n]
    const int tid  = threadIdx.x;
    const int wid  = tid >> 5, lane = tid & 31;
    const int gid  = lane >> 2, tig = lane & 3;
    const int wm   = wid >> 2, wn = wid & 3;
    const int m0   = blockIdx.y * 128, n0 = blockIdx.x * 128;

    float acc[4][4][4];
#pragma unroll
    for (int mt = 0; mt < 4; mt++)
#pragma unroll
        for (int nt = 0; nt < 4; nt++)
#pragma unroll
            for (int i = 0; i < 4; i++) acc[mt][nt][i] = 0.f;

    float4 pa[2], pb[2];
#pragma unroll
    for (int e = 0; e < 2; e++) {
        int lin = tid + e * 256;
        pa[e] = *(const float4*)(A + (size_t)(m0 + (lin >> 2)) * K + ((lin & 3) << 2));
        pb[e] = *(const float4*)(B + (size_t)(lin >> 5) * N + n0 + ((lin & 31) << 2));
    }

    for (int k0 = 0; k0 < K; k0 += 16) {
        // convert + store current tile
#pragma unroll
        for (int e = 0; e < 2; e++) {
            int lin = tid + e * 256;
            int ar = lin >> 2, ac = (lin & 3) << 2;
            float* va = (float*)&pa[e];
#pragma unroll
            for (int j = 0; j < 4; j++) {
                uint32_t h = f2tf32(va[j]);
                As_h[ac + j][ar] = h;
                As_l[ac + j][ar] = f2tf32(va[j] - __uint_as_float(h));
            }
            int br = lin >> 5, bc = (lin & 31) << 2;
            float* vb = (float*)&pb[e];
#pragma unroll
            for (int j = 0; j < 4; j++) {
                uint32_t h = f2tf32(vb[j]);
                Bs_h[br][bc + j] = h;
                Bs_l[br][bc + j] = f2tf32(vb[j] - __uint_as_float(h));
            }
        }
        __syncthreads();
        if (k0 + 16 < K) {
#pragma unroll
            for (int e = 0; e < 2; e++) {
                int lin = tid + e * 256;
                pa[e] = *(const float4*)(A + (size_t)(m0 + (lin >> 2)) * K + k0 + 16 + ((lin & 3) << 2));
                pb[e] = *(const float4*)(B + (size_t)(k0 + 16 + (lin >> 5)) * N + n0 + ((lin & 31) << 2));
            }
        }
#pragma unroll
        for (int ks = 0; ks < 16; ks += 8) {
            uint32_t ah[4][4], al[4][4], bh[4][2], bl[4][2];
#pragma unroll
            for (int mt = 0; mt < 4; mt++) {
                int m = wm * 64 + mt * 16 + gid;
                ah[mt][0] = As_h[ks + tig][m];     ah[mt][1] = As_h[ks + tig][m + 8];
                ah[mt][2] = As_h[ks + tig + 4][m]; ah[mt][3] = As_h[ks + tig + 4][m + 8];
                al[mt][0] = As_l[ks + tig][m];     al[mt][1] = As_l[ks + tig][m + 8];
                al[mt][2] = As_l[ks + tig + 4][m]; al[mt][3] = As_l[ks + tig + 4][m + 8];
            }
#pragma unroll
            for (int nt = 0; nt < 4; nt++) {
                int n = wn * 32 + nt * 8 + gid;
                bh[nt][0] = Bs_h[ks + tig][n]; bh[nt][1] = Bs_h[ks + tig + 4][n];
                bl[nt][0] = Bs_l[ks + tig][n]; bl[nt][1] = Bs_l[ks + tig + 4][n];
            }
#pragma unroll
            for (int mt = 0; mt < 4; mt++)
#pragma unroll
                for (int nt = 0; nt < 4; nt++) {
                    mma8(acc[mt][nt], al[mt], bh[nt]);
                    mma8(acc[mt][nt], ah[mt], bl[nt]);
                    mma8(acc[mt][nt], ah[mt], bh[nt]);
                }
        }
        __syncthreads();
    }

#pragma unroll
    for (int mt = 0; mt < 4; mt++) {
        int r0 = m0 + wm * 64 + mt * 16 + gid;
#pragma unroll
        for (int nt = 0; nt < 4; nt++) {
            int c = n0 + wn * 32 + nt * 8 + (tig << 1);
            float b0 = bias[c], b1 = bias[c + 1];
            float2 o0 = make_float2(acc[mt][nt][0] + b0, acc[mt][nt][1] + b1);
            float2 o1 = make_float2(acc[mt][nt][2] + b0, acc[mt][nt][3] + b1);
            if (RELU) {
                o0.x = fmaxf(o0.x, 0.f); o0.y = fmaxf(o0.y, 0.f);
                o1.x = fmaxf(o1.x, 0.f); o1.y = fmaxf(o1.y, 0.f);
            }
            *(float2*)(C + (size_t)r0 * N + c)       = o0;
            *(float2*)(C + (size_t)(r0 + 8) * N + c) = o1;
        }
    }
}

// ---------------- attention scores (single TF32): sc = QK^T / 8 --------------
// per (b,h): M=N=1024, K=64. BM=BN=128.
__global__ __launch_bounds__(256, 1)
void attn_scores_tc(const float* __restrict__ q, const float* __restrict__ k) {
    const int z = blockIdx.z, b = z >> 4, h = z & 15;
    const float* Aq = q + (size_t)b * SS * DDIM + h * DKH;
    const float* Bk = k + (size_t)b * SS * DDIM + h * DKH;
    float* out = g_sc + (size_t)z * SS * SS;
    __shared__ uint32_t As[16][132], Bs[16][132];   // both k-major
    const int tid = threadIdx.x;
    const int wid = tid >> 5, lane = tid & 31;
    const int gid = lane >> 2, tig = lane & 3;
    const int wm  = wid >> 2, wn = wid & 3;
    const int i0  = blockIdx.y * 128, j0 = blockIdx.x * 128;

    float acc[4][4][4];
#pragma unroll
    for (int mt = 0; mt < 4; mt++)
#pragma unroll
        for (int nt = 0; nt < 4; nt++)
#pragma unroll
            for (int i = 0; i < 4; i++) acc[mt][nt][i] = 0.f;

    for (int d0 = 0; d0 < DKH; d0 += 16) {
#pragma unroll
        for (int e = 0; e < 2; e++) {
            int lin = tid + e * 256;
            int row = lin >> 2, c4 = (lin & 3) << 2;
            float4 va = *(const float4*)(Aq + (size_t)(i0 + row) * DDIM + d0 + c4);
            float4 vb = *(const float4*)(Bk + (size_t)(j0 + row) * DDIM + d0 + c4);
            float* a = (float*)&va; float* c = (float*)&vb;
#pragma unroll
            for (int j = 0; j < 4; j++) {
                As[c4 + j][row] = f2tf32(a[j]);
                Bs[c4 + j][row] = f2tf32(c[j]);
            }
        }
        __syncthreads();
#pragma unroll
        for (int ks = 0; ks < 16; ks += 8) {
            uint32_t af[4][4], bf[4][2];
#pragma unroll
            for (int mt = 0; mt < 4; mt++) {
                int m = wm * 64 + mt * 16 + gid;
                af[mt][0] = As[ks + tig][m];     af[mt][1] = As[ks + tig][m + 8];
                af[mt][2] = As[ks + tig + 4][m]; af[mt][3] = As[ks + tig + 4][m + 8];
            }
#pragma unroll
            for (int nt = 0; nt < 4; nt++) {
                int n = wn * 32 + nt * 8 + gid;
                bf[nt][0] = Bs[ks + tig][n]; bf[nt][1] = Bs[ks + tig + 4][n];
            }
#pragma unroll
            for (int mt = 0; mt < 4; mt++)
#pragma unroll
                for (int nt = 0; nt < 4; nt++)
                    mma8(acc[mt][nt], af[mt], bf[nt]);
        }
        __syncthreads();
    }
#pragma unroll
    for (int mt = 0; mt < 4; mt++) {
        int r0 = i0 + wm * 64 + mt * 16 + gid;
#pragma unroll
        for (int nt = 0; nt < 4; nt++) {
            int c = j0 + wn * 32 + nt * 8 + (tig << 1);
            float2 o0 = make_float2(acc[mt][nt][0] * 0.125f, acc[mt][nt][1] * 0.125f);
            float2 o1 = make_float2(acc[mt][nt][2] * 0.125f, acc[mt][nt][3] * 0.125f);
            *(float2*)(out + (size_t)r0 * SS + c)       = o0;
            *(float2*)(out + (size_t)(r0 + 8) * SS + c) = o1;
        }
    }
}

// ---------------- row softmax over S=1024 (in place on g_sc) -----------------
__global__ __launch_bounds__(256)
void softmax_rows() {
    __shared__ float sm[8];
    __shared__ float bc;
    const int tid = threadIdx.x;
    float* p = g_sc + (size_t)blockIdx.x * SS;
    float4 v = reinterpret_cast<float4*>(p)[tid];

    float m = fmaxf(fmaxf(v.x, v.y), fmaxf(v.z, v.w));
#pragma unroll
    for (int o = 16; o; o >>= 1) m = fmaxf(m, __shfl_xor_sync(~0u, m, o));
    if ((tid & 31) == 0) sm[tid >> 5] = m;
    __syncthreads();
    if (tid < 32) {
        float t = (tid < 8) ? sm[tid] : -1e30f;
#pragma unroll
        for (int o = 4; o; o >>= 1) t = fmaxf(t, __shfl_xor_sync(~0u, t, o));
        if (tid == 0) bc = t;
    }
    __syncthreads();
    m = bc;
    v.x = __expf(v.x - m); v.y = __expf(v.y - m);
    v.z = __expf(v.z - m); v.w = __expf(v.w - m);
    float s = v.x + v.y + v.z + v.w;
    __syncthreads();
#pragma unroll
    for (int o = 16; o; o >>= 1) s += __shfl_xor_sync(~0u, s, o);
    if ((tid & 31) == 0) sm[tid >> 5] = s;
    __syncthreads();
    if (tid < 32) {
        float t = (tid < 8) ? sm[tid] : 0.f;
#pragma unroll
        for (int o = 4; o; o >>= 1) t += __shfl_xor_sync(~0u, t, o);
        if (tid == 0) bc = t;
    }
    __syncthreads();
    float inv = 1.0f / bc;
    v.x *= inv; v.y *= inv; v.z *= inv; v.w *= inv;
    reinterpret_cast<float4*>(p)[tid] = v;
}

// ---------------- AV (single TF32): o_head = attn[z] @ v_head ----------------
// per (b,h): M=1024, N=64, K=1024. BM=128, BN=64; 8 warps (4x2), warp 32x32.
__global__ __launch_bounds__(256, 1)
void attn_av_tc(const float* __restrict__ v) {
    const int z = blockIdx.z, b = z >> 4, h = z & 15;
    const float* A  = g_sc + (size_t)z * SS * SS;
    const float* Bv = v + (size_t)b * SS * DDIM + h * DKH;
    float*       C  = g_o + (size_t)b * SS * DDIM + h * DKH;
    __shared__ uint32_t As[16][132];   // k-major
    __shared__ uint32_t Bs[16][68];    // [k][n]
    const int tid = threadIdx.x;
    const int wid = tid >> 5, lane = tid & 31;
    const int gid = lane >> 2, tig = lane & 3;
    const int wm  = wid >> 1, wn = wid & 1;
    const int m0  = blockIdx.y * 128;

    float acc[2][4][4];
#pragma unroll
    for (int mt = 0; mt < 2; mt++)
#pragma unroll
        for (int nt = 0; nt < 4; nt++)
#pragma unroll
            for (int i = 0; i < 4; i++) acc[mt][nt][i] = 0.f;

    float4 pa[2], pb;
#pragma unroll
    for (int e = 0; e < 2; e++) {
        int lin = tid + e * 256;
        pa[e] = *(const float4*)(A + (size_t)(m0 + (lin >> 2)) * SS + ((lin & 3) << 2));
    }
    pb = *(const float4*)(Bv + (size_t)(tid >> 4) * DDIM + ((tid & 15) << 2));

    for (int k0 = 0; k0 < SS; k0 += 16) {
#pragma unroll
        for (int e = 0; e < 2; e++) {
            int lin = tid + e * 256;
            int ar = lin >> 2, ac = (lin & 3) << 2;
            float* va = (float*)&pa[e];
#pragma unroll
            for (int j = 0; j < 4; j++) As[ac + j][ar] = f2tf32(va[j]);
        }
        {
            int br = tid >> 4, bc = (tid & 15) << 2;
            float* vb = (float*)&pb;
#pragma unroll
            for (int j = 0; j < 4; j++) Bs[br][bc + j] = f2tf32(vb[j]);
        }
        __syncthreads();
        if (k0 + 16 < SS) {
#pragma unroll
            for (int e = 0; e < 2; e++) {
                int lin = tid + e * 256;
                pa[e] = *(const float4*)(A + (size_t)(m0 + (lin >> 2)) * SS + k0 + 16 + ((lin & 3) << 2));
            }
            pb = *(const float4*)(Bv + (size_t)(k0 + 16 + (tid >> 4)) * DDIM + ((tid & 15) << 2));
        }
#pragma unroll
        for (int ks = 0; ks < 16; ks += 8) {
            uint32_t af[2][4], bf[4][2];
#pragma unroll
            for (int mt = 0; mt < 2; mt++) {
                int m = wm * 32 + mt * 16 + gid;
                af[mt][0] = As[ks + tig][m];     af[mt][1] = As[ks + tig][m + 8];
                af[mt][2] = As[ks + tig + 4][m]; af[mt][3] = As[ks + tig + 4][m + 8];
            }
#pragma unroll
            for (int nt = 0; nt < 4; nt++) {
                int n = wn * 32 + nt * 8 + gid;
                bf[nt][0] = Bs[ks + tig][n]; bf[nt][1] = Bs[ks + tig + 4][n];
            }
#pragma unroll
            for (int mt = 0; mt < 2; mt++)
#pragma unroll
                for (int nt = 0; nt < 4; nt++)
                    mma8(acc[mt][nt], af[mt], bf[nt]);
        }
        __syncthreads();
    }
#pragma unroll
    for (int mt = 0; mt < 2; mt++) {
        int r0 = m0 + wm * 32 + mt * 16 + gid;
#pragma unroll
        for (int nt = 0; nt < 4; nt++) {
            int c = wn * 32 + nt * 8 + (tig << 1);
            *(float2*)(C + (size_t)r0 * DDIM + c) =
                make_float2(acc[mt][nt][0], acc[mt][nt][1]);
            *(float2*)(C + (size_t)(r0 + 8) * DDIM + c) =
                make_float2(acc[mt][nt][2], acc[mt][nt][3]);
        }
    }
}

// ---------------- add + LayerNorm (row of D=1024) ----------------------------
__global__ __launch_bounds__(256)
void add_ln(const float* __restrict__ x, const float* __restrict__ y,
            const float* __restrict__ g, const float* __restrict__ be,
            float* __restrict__ out) {
    __shared__ float sm[8];
    __shared__ float bc;
    const int tid = threadIdx.x;
    const size_t ro = (size_t)blockIdx.x * DDIM;
    float4 a = reinterpret_cast<const float4*>(x + ro)[tid];
    float4 b = reinterpret_cast<const float4*>(y + ro)[tid];
    a.x += b.x; a.y += b.y; a.z += b.z; a.w += b.w;

    float s = a.x + a.y + a.z + a.w;
#pragma unroll
    for (int o = 16; o; o >>= 1) s += __shfl_xor_sync(~0u, s, o);
    if ((tid & 31) == 0) sm[tid >> 5] = s;
    __syncthreads();
    if (tid < 32) {
        float t = (tid < 8) ? sm[tid] : 0.f;
#pragma unroll
        for (int o = 4; o; o >>= 1) t += __shfl_xor_sync(~0u, t, o);
        if (tid == 0) bc = t;
    }
    __syncthreads();
    const float mu = bc * (1.0f / DDIM);
    a.x -= mu; a.y -= mu; a.z -= mu; a.w -= mu;
    float qv = a.x*a.x + a.y*a.y + a.z*a.z + a.w*a.w;
    __syncthreads();
#pragma unroll
    for (int o = 16; o; o >>= 1) qv += __shfl_xor_sync(~0u, qv, o);
    if ((tid & 31) == 0) sm[tid >> 5] = qv;
    __syncthreads();
    if (tid < 32) {
        float t = (tid < 8) ? sm[tid] : 0.f;
#pragma unroll
        for (int o = 4; o; o >>= 1) t += __shfl_xor_sync(~0u, t, o);
        if (tid == 0) bc = t;
    }
    __syncthreads();
    const float rs = rsqrtf(bc * (1.0f / DDIM) + 1e-5f);
    float4 gv = reinterpret_cast<const float4*>(g)[tid];
    float4 bv = reinterpret_cast<const float4*>(be)[tid];
    float4 o;
    o.x = a.x * rs * gv.x + bv.x;
    o.y = a.y * rs * gv.y + bv.y;
    o.z = a.z * rs * gv.z + bv.z;
    o.w = a.w * rs * gv.w + bv.w;
    reinterpret_cast<float4*>(out + ro)[tid] = o;
}

// ---------------- launch ------------------------------------------------------
extern "C" void kernel_launch(void* const* d_in, const int* in_sizes, int n_in,
                              void* d_out, int out_size) {
    const int*   tokens = (const int*)  d_in[0];
    const float* emb    = (const float*)d_in[1];
    const float* Wq = (const float*)d_in[2],  *bq = (const float*)d_in[3];
    const float* Wk = (const float*)d_in[4],  *bk = (const float*)d_in[5];
    const float* Wv = (const float*)d_in[6],  *bv = (const float*)d_in[7];
    const float* Wo = (const float*)d_in[8],  *bo = (const float*)d_in[9];
    const float* W1 = (const float*)d_in[10], *b1 = (const float*)d_in[11];
    const float* W2 = (const float*)d_in[12], *b2 = (const float*)d_in[13];
    const float* gamma = (const float*)d_in[14], *beta = (const float*)d_in[15];
    float* out = (float*)d_out;

    float *x, *q, *k, *v, *o, *t, *h1;
    cudaGetSymbolAddress((void**)&x,  g_x);
    cudaGetSymbolAddress((void**)&q,  g_q);
    cudaGetSymbolAddress((void**)&k,  g_k);
    cudaGetSymbolAddress((void**)&v,  g_v);
    cudaGetSymbolAddress((void**)&o,  g_o);
    cudaGetSymbolAddress((void**)&t,  g_t);
    cudaGetSymbolAddress((void**)&h1, g_h1);

    embed_pe<<<BSR * DDIM / 256, 256>>>(tokens, emb);

    const dim3 gp(DDIM / 128, BSR / 128);   // proj GEMMs (N=1024): 8x16
    const dim3 gf(FFD  / 128, BSR / 128);   // FFN up (N=2048): 16x16

    for (int l = 0; l < LLAY; l++) {
        const float* lWq = Wq + (size_t)l * DDIM * DDIM;
        const float* lWk = Wk + (size_t)l * DDIM * DDIM;
        const float* lWv = Wv + (size_t)l * DDIM * DDIM;
        const float* lWo = Wo + (size_t)l * DDIM * DDIM;
        const float* lW1 = W1 + (size_t)l * DDIM * FFD;
        const float* lW2 = W2 + (size_t)l * FFD  * DDIM;
        const float* lbq = bq + (size_t)l * DDIM;
        const float* lbk = bk + (size_t)l * DDIM;
        const float* lbv = bv + (size_t)l * DDIM;
        const float* lbo = bo + (size_t)l * DDIM;
        const float* lb1 = b1 + (size_t)l * FFD;
        const float* lb2 = b2 + (size_t)l * DDIM;
        const float* lg  = gamma + (size_t)l * DDIM;
        const float* lbe = beta  + (size_t)l * DDIM;

        sgemm_tc3<false><<<gp, 256>>>(x, lWq, lbq, q, BSR, DDIM, DDIM);
        sgemm_tc3<false><<<gp, 256>>>(x, lWk, lbk, k, BSR, DDIM, DDIM);
        sgemm_tc3<false><<<gp, 256>>>(x, lWv, lbv, v, BSR, DDIM, DDIM);

        attn_scores_tc<<<dim3(SS / 128, SS / 128, BB * HH), 256>>>(q, k);
        softmax_rows<<<BB * HH * SS, 256>>>();
        attn_av_tc<<<dim3(1, SS / 128, BB * HH), 256>>>(v);

        sgemm_tc3<false><<<gp, 256>>>(o, lWo, lbo, t, BSR, DDIM, DDIM);
        add_ln<<<BSR, 256>>>(x, t, lg, lbe, x);

        sgemm_tc3<true ><<<gf, 256>>>(x,  lW1, lb1, h1, BSR, FFD, DDIM);
        sgemm_tc3<false><<<gp, 256>>>(h1, lW2, lb2, t,  BSR, DDIM, FFD);

        float* xo = (l == LLAY - 1) ? out : x;
        add_ln<<<BSR, 256>>>(x, t, lg, lbe, xo);
    }
}

// round 3
// speedup vs baseline: 1.8063x; 1.6525x over previous
#include <cuda_runtime.h>
#include <cuda_bf16.h>
#include <math.h>
#include <stdint.h>

// Problem constants
#define BB   2
#define SS   1024
#define DDIM 1024
#define HH   16
#define LLAY 4
#define FFD  2048
#define DKH  64
#define BSR  (BB*SS)   // 2048 rows

typedef __nv_bfloat16 bf16;

// ---------------- scratch (static device globals; no allocs allowed) ----------
__device__ float g_x [BSR*DDIM];
__device__ float g_q [BSR*DDIM];
__device__ float g_k [BSR*DDIM];
__device__ float g_v [BSR*DDIM];
__device__ float g_o [BSR*DDIM];
__device__ float g_t [BSR*DDIM];
__device__ float g_h1[BSR*FFD];
__device__ float g_sc[(size_t)BB*HH*SS*SS];   // 128 MB scores scratch

// bf16 hi/lo planes: weights transposed to [N][K]
__device__ bf16 g_wqh[LLAY*DDIM*DDIM], g_wql[LLAY*DDIM*DDIM];
__device__ bf16 g_wkh[LLAY*DDIM*DDIM], g_wkl[LLAY*DDIM*DDIM];
__device__ bf16 g_wvh[LLAY*DDIM*DDIM], g_wvl[LLAY*DDIM*DDIM];
__device__ bf16 g_woh[LLAY*DDIM*DDIM], g_wol[LLAY*DDIM*DDIM];
__device__ bf16 g_w1h[LLAY*DDIM*FFD],  g_w1l[LLAY*DDIM*FFD];   // [FFD][DDIM] per layer
__device__ bf16 g_w2h[LLAY*FFD*DDIM],  g_w2l[LLAY*FFD*DDIM];   // [DDIM][FFD] per layer
// activation planes (max 2048x2048 for h1)
__device__ bf16 g_ah[BSR*FFD], g_al[BSR*FFD];

// ---------------- helpers -----------------------------------------------------
__device__ __forceinline__ uint32_t f2tf32(float x) {
    uint32_t r;
    asm("cvt.rna.tf32.f32 %0, %1;" : "=r"(r) : "f"(x));
    return r;
}
__device__ __forceinline__ void mma8(float* c, const uint32_t* a, const uint32_t* b) {
    asm volatile(
        "mma.sync.aligned.m16n8k8.row.col.f32.tf32.tf32.f32 "
        "{%0,%1,%2,%3}, {%4,%5,%6,%7}, {%8,%9}, {%0,%1,%2,%3};"
        : "+f"(c[0]), "+f"(c[1]), "+f"(c[2]), "+f"(c[3])
        : "r"(a[0]), "r"(a[1]), "r"(a[2]), "r"(a[3]), "r"(b[0]), "r"(b[1]));
}
__device__ __forceinline__ void mma16(float* c, const uint32_t* a, const uint32_t* b) {
    asm volatile(
        "mma.sync.aligned.m16n8k16.row.col.f32.bf16.bf16.f32 "
        "{%0,%1,%2,%3}, {%4,%5,%6,%7}, {%8,%9}, {%0,%1,%2,%3};"
        : "+f"(c[0]), "+f"(c[1]), "+f"(c[2]), "+f"(c[3])
        : "r"(a[0]), "r"(a[1]), "r"(a[2]), "r"(a[3]), "r"(b[0]), "r"(b[1]));
}

// ---------------- embedding + (buggy-faithful) positional encoding ------------
__global__ void embed_pe(const int* __restrict__ tok, const float* __restrict__ emb) {
    int idx = blockIdx.x * 256 + threadIdx.x;
    int d  = idx & (DDIM - 1);
    int bs = idx >> 10;
    int b  = bs >> 10;
    int t  = tok[bs];
    int i2 = (d >> 1) << 1;
    float div = expf(-(float)i2 * (9.210340371976184f / (float)DDIM));
    float ang = (float)b * div;
    float pe  = (d & 1) ? cosf(ang) : sinf(ang);
    g_x[idx] = emb[(size_t)t * DDIM + d] + pe;
}

// ---------------- activation hi/lo split (no transpose) ----------------------
__global__ __launch_bounds__(256)
void split_a(const float* __restrict__ s, bf16* __restrict__ hi, bf16* __restrict__ lo) {
    int i4 = (blockIdx.x * 256 + threadIdx.x) * 4;
    float4 v = *(const float4*)(s + i4);
    bf16 h0 = __float2bfloat16_rn(v.x), h1 = __float2bfloat16_rn(v.y);
    bf16 h2 = __float2bfloat16_rn(v.z), h3 = __float2bfloat16_rn(v.w);
    bf16 l0 = __float2bfloat16_rn(v.x - __bfloat162float(h0));
    bf16 l1 = __float2bfloat16_rn(v.y - __bfloat162float(h1));
    bf16 l2 = __float2bfloat16_rn(v.z - __bfloat162float(h2));
    bf16 l3 = __float2bfloat16_rn(v.w - __bfloat162float(h3));
    __nv_bfloat162 hh0; hh0.x = h0; hh0.y = h1;
    __nv_bfloat162 hh1; hh1.x = h2; hh1.y = h3;
    __nv_bfloat162 ll0; ll0.x = l0; ll0.y = l1;
    __nv_bfloat162 ll1; ll1.x = l2; ll1.y = l3;
    *(__nv_bfloat162*)(hi + i4)     = hh0;
    *(__nv_bfloat162*)(hi + i4 + 2) = hh1;
    *(__nv_bfloat162*)(lo + i4)     = ll0;
    *(__nv_bfloat162*)(lo + i4 + 2) = ll1;
}

// ---------------- weight transpose + hi/lo split: W[K][N] -> [N][K] ----------
__global__ __launch_bounds__(256)
void split_w_t(const float* __restrict__ W, bf16* __restrict__ th, bf16* __restrict__ tl,
               int K, int N) {
    __shared__ float tile[32][33];
    const int n0 = blockIdx.x * 32, k0 = blockIdx.y * 32;
    const int tx = threadIdx.x & 31, ty = threadIdx.x >> 5;
#pragma unroll
    for (int i = 0; i < 32; i += 8)
        tile[ty + i][tx] = W[(size_t)(k0 + ty + i) * N + n0 + tx];
    __syncthreads();
#pragma unroll
    for (int i = 0; i < 32; i += 8) {
        int n = n0 + ty + i, k = k0 + tx;
        float v = tile[tx][ty + i];
        bf16 h = __float2bfloat16_rn(v);
        th[(size_t)n * K + k] = h;
        tl[(size_t)n * K + k] = __float2bfloat16_rn(v - __bfloat162float(h));
    }
}

// ---------------- bf16x3 tensor-core GEMM: C = A[M,K]@B^T + bias -------------
// A planes [M][K] row-major; B planes [N][K] row-major (pre-transposed weight).
// BM=128, BN=128, BK=32; 256 threads = 8 warps (2x4); warp tile 64x32.
template<bool RELU>
__global__ __launch_bounds__(256, 1)
void gemm_bf16x3(const bf16* __restrict__ Ah, const bf16* __restrict__ Al,
                 const bf16* __restrict__ Bh, const bf16* __restrict__ Bl,
                 const float* __restrict__ bias, float* __restrict__ C,
                 int M, int N, int K) {
    // uint32 = 2 bf16 along k; 16 words per row of 32 k; pad to 20 (conflict-free)
    __shared__ uint32_t As_h[128][20], As_l[128][20];
    __shared__ uint32_t Bs_h[128][20], Bs_l[128][20];
    const int tid  = threadIdx.x;
    const int wid  = tid >> 5, lane = tid & 31;
    const int gid  = lane >> 2, tig = lane & 3;
    const int wm   = wid >> 2, wn = wid & 3;
    const int m0   = blockIdx.y * 128, n0 = blockIdx.x * 128;

    float acc[4][4][4];
#pragma unroll
    for (int mt = 0; mt < 4; mt++)
#pragma unroll
        for (int nt = 0; nt < 4; nt++)
#pragma unroll
            for (int i = 0; i < 4; i++) acc[mt][nt][i] = 0.f;

    uint4 pah[2], pal[2], pbh[2], pbl[2];
#pragma unroll
    for (int e = 0; e < 2; e++) {
        int idx = tid + e * 256;
        int row = idx >> 2, c8 = (idx & 3) << 3;
        pah[e] = *(const uint4*)(Ah + (size_t)(m0 + row) * K + c8);
        pal[e] = *(const uint4*)(Al + (size_t)(m0 + row) * K + c8);
        pbh[e] = *(const uint4*)(Bh + (size_t)(n0 + row) * K + c8);
        pbl[e] = *(const uint4*)(Bl + (size_t)(n0 + row) * K + c8);
    }

    for (int k0 = 0; k0 < K; k0 += 32) {
#pragma unroll
        for (int e = 0; e < 2; e++) {
            int idx = tid + e * 256;
            int row = idx >> 2, w4 = (idx & 3) << 2;
            *(uint4*)&As_h[row][w4] = pah[e];
            *(uint4*)&As_l[row][w4] = pal[e];
            *(uint4*)&Bs_h[row][w4] = pbh[e];
            *(uint4*)&Bs_l[row][w4] = pbl[e];
        }
        __syncthreads();
        if (k0 + 32 < K) {
#pragma unroll
            for (int e = 0; e < 2; e++) {
                int idx = tid + e * 256;
                int row = idx >> 2, c8 = (idx & 3) << 3;
                pah[e] = *(const uint4*)(Ah + (size_t)(m0 + row) * K + k0 + 32 + c8);
                pal[e] = *(const uint4*)(Al + (size_t)(m0 + row) * K + k0 + 32 + c8);
                pbh[e] = *(const uint4*)(Bh + (size_t)(n0 + row) * K + k0 + 32 + c8);
                pbl[e] = *(const uint4*)(Bl + (size_t)(n0 + row) * K + k0 + 32 + c8);
            }
        }
#pragma unroll
        for (int s = 0; s < 2; s++) {
            const int kb = s * 8;
            uint32_t ah[4][4], al[4][4], bh4[4][2], bl4[4][2];
#pragma unroll
            for (int mt = 0; mt < 4; mt++) {
                int m = wm * 64 + mt * 16 + gid;
                ah[mt][0] = As_h[m][kb + tig];     ah[mt][1] = As_h[m + 8][kb + tig];
                ah[mt][2] = As_h[m][kb + tig + 4]; ah[mt][3] = As_h[m + 8][kb + tig + 4];
                al[mt][0] = As_l[m][kb + tig];     al[mt][1] = As_l[m + 8][kb + tig];
                al[mt][2] = As_l[m][kb + tig + 4]; al[mt][3] = As_l[m + 8][kb + tig + 4];
            }
#pragma unroll
            for (int nt = 0; nt < 4; nt++) {
                int n = wn * 32 + nt * 8 + gid;
                bh4[nt][0] = Bs_h[n][kb + tig]; bh4[nt][1] = Bs_h[n][kb + tig + 4];
                bl4[nt][0] = Bs_l[n][kb + tig]; bl4[nt][1] = Bs_l[n][kb + tig + 4];
            }
#pragma unroll
            for (int mt = 0; mt < 4; mt++)
#pragma unroll
                for (int nt = 0; nt < 4; nt++) {
                    mma16(acc[mt][nt], al[mt], bh4[nt]);
                    mma16(acc[mt][nt], ah[mt], bl4[nt]);
                    mma16(acc[mt][nt], ah[mt], bh4[nt]);
                }
        }
        __syncthreads();
    }

#pragma unroll
    for (int mt = 0; mt < 4; mt++) {
        int r0 = m0 + wm * 64 + mt * 16 + gid;
#pragma unroll
        for (int nt = 0; nt < 4; nt++) {
            int c = n0 + wn * 32 + nt * 8 + (tig << 1);
            float b0 = bias[c], b1 = bias[c + 1];
            float2 o0 = make_float2(acc[mt][nt][0] + b0, acc[mt][nt][1] + b1);
            float2 o1 = make_float2(acc[mt][nt][2] + b0, acc[mt][nt][3] + b1);
            if (RELU) {
                o0.x = fmaxf(o0.x, 0.f); o0.y = fmaxf(o0.y, 0.f);
                o1.x = fmaxf(o1.x, 0.f); o1.y = fmaxf(o1.y, 0.f);
            }
            *(float2*)(C + (size_t)r0 * N + c)       = o0;
            *(float2*)(C + (size_t)(r0 + 8) * N + c) = o1;
        }
    }
}

// ---------------- attention scores (single TF32): sc = QK^T / 8 --------------
__global__ __launch_bounds__(256, 1)
void attn_scores_tc(const float* __restrict__ q, const float* __restrict__ k) {
    const int z = blockIdx.z, b = z >> 4, h = z & 15;
    const float* Aq = q + (size_t)b * SS * DDIM + h * DKH;
    const float* Bk = k + (size_t)b * SS * DDIM + h * DKH;
    float* out = g_sc + (size_t)z * SS * SS;
    __shared__ uint32_t As[16][132], Bs[16][132];
    const int tid = threadIdx.x;
    const int wid = tid >> 5, lane = tid & 31;
    const int gid = lane >> 2, tig = lane & 3;
    const int wm  = wid >> 2, wn = wid & 3;
    const int i0  = blockIdx.y * 128, j0 = blockIdx.x * 128;

    float acc[4][4][4];
#pragma unroll
    for (int mt = 0; mt < 4; mt++)
#pragma unroll
        for (int nt = 0; nt < 4; nt++)
#pragma unroll
            for (int i = 0; i < 4; i++) acc[mt][nt][i] = 0.f;

    for (int d0 = 0; d0 < DKH; d0 += 16) {
#pragma unroll
        for (int e = 0; e < 2; e++) {
            int lin = tid + e * 256;
            int row = lin >> 2, c4 = (lin & 3) << 2;
            float4 va = *(const float4*)(Aq + (size_t)(i0 + row) * DDIM + d0 + c4);
            float4 vb = *(const float4*)(Bk + (size_t)(j0 + row) * DDIM + d0 + c4);
            float* a = (float*)&va; float* c = (float*)&vb;
#pragma unroll
            for (int j = 0; j < 4; j++) {
                As[c4 + j][row] = f2tf32(a[j]);
                Bs[c4 + j][row] = f2tf32(c[j]);
            }
        }
        __syncthreads();
#pragma unroll
        for (int ks = 0; ks < 16; ks += 8) {
            uint32_t af[4][4], bf[4][2];
#pragma unroll
            for (int mt = 0; mt < 4; mt++) {
                int m = wm * 64 + mt * 16 + gid;
                af[mt][0] = As[ks + tig][m];     af[mt][1] = As[ks + tig][m + 8];
                af[mt][2] = As[ks + tig + 4][m]; af[mt][3] = As[ks + tig + 4][m + 8];
            }
#pragma unroll
            for (int nt = 0; nt < 4; nt++) {
                int n = wn * 32 + nt * 8 + gid;
                bf[nt][0] = Bs[ks + tig][n]; bf[nt][1] = Bs[ks + tig + 4][n];
            }
#pragma unroll
            for (int mt = 0; mt < 4; mt++)
#pragma unroll
                for (int nt = 0; nt < 4; nt++)
                    mma8(acc[mt][nt], af[mt], bf[nt]);
        }
        __syncthreads();
    }
#pragma unroll
    for (int mt = 0; mt < 4; mt++) {
        int r0 = i0 + wm * 64 + mt * 16 + gid;
#pragma unroll
        for (int nt = 0; nt < 4; nt++) {
            int c = j0 + wn * 32 + nt * 8 + (tig << 1);
            float2 o0 = make_float2(acc[mt][nt][0] * 0.125f, acc[mt][nt][1] * 0.125f);
            float2 o1 = make_float2(acc[mt][nt][2] * 0.125f, acc[mt][nt][3] * 0.125f);
            *(float2*)(out + (size_t)r0 * SS + c)       = o0;
            *(float2*)(out + (size_t)(r0 + 8) * SS + c) = o1;
        }
    }
}

// ---------------- row softmax over S=1024 (in place on g_sc) -----------------
__global__ __launch_bounds__(256)
void softmax_rows() {
    __shared__ float sm[8];
    __shared__ float bc;
    const int tid = threadIdx.x;
    float* p = g_sc + (size_t)blockIdx.x * SS;
    float4 v = reinterpret_cast<float4*>(p)[tid];

    float m = fmaxf(fmaxf(v.x, v.y), fmaxf(v.z, v.w));
#pragma unroll
    for (int o = 16; o; o >>= 1) m = fmaxf(m, __shfl_xor_sync(~0u, m, o));
    if ((tid & 31) == 0) sm[tid >> 5] = m;
    __syncthreads();
    if (tid < 32) {
        float t = (tid < 8) ? sm[tid] : -1e30f;
#pragma unroll
        for (int o = 4; o; o >>= 1) t = fmaxf(t, __shfl_xor_sync(~0u, t, o));
        if (tid == 0) bc = t;
    }
    __syncthreads();
    m = bc;
    v.x = __expf(v.x - m); v.y = __expf(v.y - m);
    v.z = __expf(v.z - m); v.w = __expf(v.w - m);
    float s = v.x + v.y + v.z + v.w;
    __syncthreads();
#pragma unroll
    for (int o = 16; o; o >>= 1) s += __shfl_xor_sync(~0u, s, o);
    if ((tid & 31) == 0) sm[tid >> 5] = s;
    __syncthreads();
    if (tid < 32) {
        float t = (tid < 8) ? sm[tid] : 0.f;
#pragma unroll
        for (int o = 4; o; o >>= 1) t += __shfl_xor_sync(~0u, t, o);
        if (tid == 0) bc = t;
    }
    __syncthreads();
    float inv = 1.0f / bc;
    v.x *= inv; v.y *= inv; v.z *= inv; v.w *= inv;
    reinterpret_cast<float4*>(p)[tid] = v;
}

// ---------------- AV (single TF32): o_head = attn[z] @ v_head ----------------
__global__ __launch_bounds__(256, 1)
void attn_av_tc(const float* __restrict__ v) {
    const int z = blockIdx.z, b = z >> 4, h = z & 15;
    const float* A  = g_sc + (size_t)z * SS * SS;
    const float* Bv = v + (size_t)b * SS * DDIM + h * DKH;
    float*       C  = g_o + (size_t)b * SS * DDIM + h * DKH;
    __shared__ uint32_t As[16][132];
    __shared__ uint32_t Bs[16][68];
    const int tid = threadIdx.x;
    const int wid = tid >> 5, lane = tid & 31;
    const int gid = lane >> 2, tig = lane & 3;
    const int wm  = wid >> 1, wn = wid & 1;
    const int m0  = blockIdx.y * 128;

    float acc[2][4][4];
#pragma unroll
    for (int mt = 0; mt < 2; mt++)
#pragma unroll
        for (int nt = 0; nt < 4; nt++)
#pragma unroll
            for (int i = 0; i < 4; i++) acc[mt][nt][i] = 0.f;

    float4 pa[2], pb;
#pragma unroll
    for (int e = 0; e < 2; e++) {
        int lin = tid + e * 256;
        pa[e] = *(const float4*)(A + (size_t)(m0 + (lin >> 2)) * SS + ((lin & 3) << 2));
    }
    pb = *(const float4*)(Bv + (size_t)(tid >> 4) * DDIM + ((tid & 15) << 2));

    for (int k0 = 0; k0 < SS; k0 += 16) {
#pragma unroll
        for (int e = 0; e < 2; e++) {
            int lin = tid + e * 256;
            int ar = lin >> 2, ac = (lin & 3) << 2;
            float* va = (float*)&pa[e];
#pragma unroll
            for (int j = 0; j < 4; j++) As[ac + j][ar] = f2tf32(va[j]);
        }
        {
            int br = tid >> 4, bc = (tid & 15) << 2;
            float* vb = (float*)&pb;
#pragma unroll
            for (int j = 0; j < 4; j++) Bs[br][bc + j] = f2tf32(vb[j]);
        }
        __syncthreads();
        if (k0 + 16 < SS) {
#pragma unroll
            for (int e = 0; e < 2; e++) {
                int lin = tid + e * 256;
                pa[e] = *(const float4*)(A + (size_t)(m0 + (lin >> 2)) * SS + k0 + 16 + ((lin & 3) << 2));
            }
            pb = *(const float4*)(Bv + (size_t)(k0 + 16 + (tid >> 4)) * DDIM + ((tid & 15) << 2));
        }
#pragma unroll
        for (int ks = 0; ks < 16; ks += 8) {
            uint32_t af[2][4], bf[4][2];
#pragma unroll
            for (int mt = 0; mt < 2; mt++) {
                int m = wm * 32 + mt * 16 + gid;
                af[mt][0] = As[ks + tig][m];     af[mt][1] = As[ks + tig][m + 8];
                af[mt][2] = As[ks + tig + 4][m]; af[mt][3] = As[ks + tig + 4][m + 8];
            }
#pragma unroll
            for (int nt = 0; nt < 4; nt++) {
                int n = wn * 32 + nt * 8 + gid;
                bf[nt][0] = Bs[ks + tig][n]; bf[nt][1] = Bs[ks + tig + 4][n];
            }
#pragma unroll
            for (int mt = 0; mt < 2; mt++)
#pragma unroll
                for (int nt = 0; nt < 4; nt++)
                    mma8(acc[mt][nt], af[mt], bf[nt]);
        }
        __syncthreads();
    }
#pragma unroll
    for (int mt = 0; mt < 2; mt++) {
        int r0 = m0 + wm * 32 + mt * 16 + gid;
#pragma unroll
        for (int nt = 0; nt < 4; nt++) {
            int c = wn * 32 + nt * 8 + (tig << 1);
            *(float2*)(C + (size_t)r0 * DDIM + c) =
                make_float2(acc[mt][nt][0], acc[mt][nt][1]);
            *(float2*)(C + (size_t)(r0 + 8) * DDIM + c) =
                make_float2(acc[mt][nt][2], acc[mt][nt][3]);
        }
    }
}

// ---------------- add + LayerNorm (row of D=1024) ----------------------------
__global__ __launch_bounds__(256)
void add_ln(const float* __restrict__ x, const float* __restrict__ y,
            const float* __restrict__ g, const float* __restrict__ be,
            float* __restrict__ out) {
    __shared__ float sm[8];
    __shared__ float bc;
    const int tid = threadIdx.x;
    const size_t ro = (size_t)blockIdx.x * DDIM;
    float4 a = reinterpret_cast<const float4*>(x + ro)[tid];
    float4 b = reinterpret_cast<const float4*>(y + ro)[tid];
    a.x += b.x; a.y += b.y; a.z += b.z; a.w += b.w;

    float s = a.x + a.y + a.z + a.w;
#pragma unroll
    for (int o = 16; o; o >>= 1) s += __shfl_xor_sync(~0u, s, o);
    if ((tid & 31) == 0) sm[tid >> 5] = s;
    __syncthreads();
    if (tid < 32) {
        float t = (tid < 8) ? sm[tid] : 0.f;
#pragma unroll
        for (int o = 4; o; o >>= 1) t += __shfl_xor_sync(~0u, t, o);
        if (tid == 0) bc = t;
    }
    __syncthreads();
    const float mu = bc * (1.0f / DDIM);
    a.x -= mu; a.y -= mu; a.z -= mu; a.w -= mu;
    float qv = a.x*a.x + a.y*a.y + a.z*a.z + a.w*a.w;
    __syncthreads();
#pragma unroll
    for (int o = 16; o; o >>= 1) qv += __shfl_xor_sync(~0u, qv, o);
    if ((tid & 31) == 0) sm[tid >> 5] = qv;
    __syncthreads();
    if (tid < 32) {
        float t = (tid < 8) ? sm[tid] : 0.f;
#pragma unroll
        for (int o = 4; o; o >>= 1) t += __shfl_xor_sync(~0u, t, o);
        if (tid == 0) bc = t;
    }
    __syncthreads();
    const float rs = rsqrtf(bc * (1.0f / DDIM) + 1e-5f);
    float4 gv = reinterpret_cast<const float4*>(g)[tid];
    float4 bv = reinterpret_cast<const float4*>(be)[tid];
    float4 o;
    o.x = a.x * rs * gv.x + bv.x;
    o.y = a.y * rs * gv.y + bv.y;
    o.z = a.z * rs * gv.z + bv.z;
    o.w = a.w * rs * gv.w + bv.w;
    reinterpret_cast<float4*>(out + ro)[tid] = o;
}

// ---------------- launch ------------------------------------------------------
extern "C" void kernel_launch(void* const* d_in, const int* in_sizes, int n_in,
                              void* d_out, int out_size) {
    const int*   tokens = (const int*)  d_in[0];
    const float* emb    = (const float*)d_in[1];
    const float* Wq = (const float*)d_in[2],  *bq = (const float*)d_in[3];
    const float* Wk = (const float*)d_in[4],  *bk = (const float*)d_in[5];
    const float* Wv = (const float*)d_in[6],  *bv = (const float*)d_in[7];
    const float* Wo = (const float*)d_in[8],  *bo = (const float*)d_in[9];
    const float* W1 = (const float*)d_in[10], *b1 = (const float*)d_in[11];
    const float* W2 = (const float*)d_in[12], *b2 = (const float*)d_in[13];
    const float* gamma = (const float*)d_in[14], *beta = (const float*)d_in[15];
    float* out = (float*)d_out;

    float *x, *q, *k, *v, *o, *t, *h1;
    cudaGetSymbolAddress((void**)&x,  g_x);
    cudaGetSymbolAddress((void**)&q,  g_q);
    cudaGetSymbolAddress((void**)&k,  g_k);
    cudaGetSymbolAddress((void**)&v,  g_v);
    cudaGetSymbolAddress((void**)&o,  g_o);
    cudaGetSymbolAddress((void**)&t,  g_t);
    cudaGetSymbolAddress((void**)&h1, g_h1);
    bf16 *wqh,*wql,*wkh,*wkl,*wvh,*wvl,*woh,*wol,*w1h,*w1l,*w2h,*w2l,*ah,*al;
    cudaGetSymbolAddress((void**)&wqh, g_wqh); cudaGetSymbolAddress((void**)&wql, g_wql);
    cudaGetSymbolAddress((void**)&wkh, g_wkh); cudaGetSymbolAddress((void**)&wkl, g_wkl);
    cudaGetSymbolAddress((void**)&wvh, g_wvh); cudaGetSymbolAddress((void**)&wvl, g_wvl);
    cudaGetSymbolAddress((void**)&woh, g_woh); cudaGetSymbolAddress((void**)&wol, g_wol);
    cudaGetSymbolAddress((void**)&w1h, g_w1h); cudaGetSymbolAddress((void**)&w1l, g_w1l);
    cudaGetSymbolAddress((void**)&w2h, g_w2h); cudaGetSymbolAddress((void**)&w2l, g_w2l);
    cudaGetSymbolAddress((void**)&ah,  g_ah);  cudaGetSymbolAddress((void**)&al,  g_al);

    embed_pe<<<BSR * DDIM / 256, 256>>>(tokens, emb);

    // ---- weight conversion: transpose + bf16 hi/lo split (once per launch) ----
    const dim3 gwp(DDIM / 32, DDIM / 32);            // 1024x1024
    const dim3 gw1(FFD  / 32, DDIM / 32);            // W1: K=1024,N=2048
    const dim3 gw2(DDIM / 32, FFD  / 32);            // W2: K=2048,N=1024
    for (int l = 0; l < LLAY; l++) {
        size_t od = (size_t)l * DDIM * DDIM, of = (size_t)l * DDIM * FFD;
        split_w_t<<<gwp, 256>>>(Wq + od, wqh + od, wql + od, DDIM, DDIM);
        split_w_t<<<gwp, 256>>>(Wk + od, wkh + od, wkl + od, DDIM, DDIM);
        split_w_t<<<gwp, 256>>>(Wv + od, wvh + od, wvl + od, DDIM, DDIM);
        split_w_t<<<gwp, 256>>>(Wo + od, woh + od, wol + od, DDIM, DDIM);
        split_w_t<<<gw1, 256>>>(W1 + of, w1h + of, w1l + of, DDIM, FFD);
        split_w_t<<<gw2, 256>>>(W2 + of, w2h + of, w2l + of, FFD, DDIM);
    }

    const dim3 gp(DDIM / 128, BSR / 128);   // N=1024: 8x16
    const dim3 gf(FFD  / 128, BSR / 128);   // N=2048: 16x16
    const int nA  = BSR * DDIM / 1024;      // split_a blocks for 2M elems
    const int nH  = BSR * FFD  / 1024;      // for 4M elems

    for (int l = 0; l < LLAY; l++) {
        size_t od = (size_t)l * DDIM * DDIM, of = (size_t)l * DDIM * FFD;
        const float* lbq = bq + (size_t)l * DDIM;
        const float* lbk = bk + (size_t)l * DDIM;
        const float* lbv = bv + (size_t)l * DDIM;
        const float* lbo = bo + (size_t)l * DDIM;
        const float* lb1 = b1 + (size_t)l * FFD;
        const float* lb2 = b2 + (size_t)l * DDIM;
        const float* lg  = gamma + (size_t)l * DDIM;
        const float* lbe = beta  + (size_t)l * DDIM;

        split_a<<<nA, 256>>>(x, ah, al);
        gemm_bf16x3<false><<<gp, 256>>>(ah, al, wqh + od, wql + od, lbq, q, BSR, DDIM, DDIM);
        gemm_bf16x3<false><<<gp, 256>>>(ah, al, wkh + od, wkl + od, lbk, k, BSR, DDIM, DDIM);
        gemm_bf16x3<false><<<gp, 256>>>(ah, al, wvh + od, wvl + od, lbv, v, BSR, DDIM, DDIM);

        attn_scores_tc<<<dim3(SS / 128, SS / 128, BB * HH), 256>>>(q, k);
        softmax_rows<<<BB * HH * SS, 256>>>();
        attn_av_tc<<<dim3(1, SS / 128, BB * HH), 256>>>(v);

        split_a<<<nA, 256>>>(o, ah, al);
        gemm_bf16x3<false><<<gp, 256>>>(ah, al, woh + od, wol + od, lbo, t, BSR, DDIM, DDIM);
        add_ln<<<BSR, 256>>>(x, t, lg, lbe, x);

        split_a<<<nA, 256>>>(x, ah, al);
        gemm_bf16x3<true ><<<gf, 256>>>(ah, al, w1h + of, w1l + of, lb1, h1, BSR, FFD, DDIM);
        split_a<<<nH, 256>>>(h1, ah, al);
        gemm_bf16x3<false><<<gp, 256>>>(ah, al, w2h + of, w2l + of, lb2, t, BSR, DDIM, FFD);

        float* xo = (l == LLAY - 1) ? out : x;
        add_ln<<<BSR, 256>>>(x, t, lg, lbe, xo);
    }
}

// round 4
// speedup vs baseline: 2.1760x; 1.2047x over previous
#include <cuda_runtime.h>
#include <cuda_bf16.h>
#include <math.h>
#include <stdint.h>

// Problem constants
#define BB   2
#define SS   1024
#define DDIM 1024
#define HH   16
#define LLAY 4
#define FFD  2048
#define DKH  64
#define BSR  (BB*SS)   // 2048 rows

typedef __nv_bfloat16 bf16;

// ---------------- scratch (static device globals; no allocs allowed) ----------
__device__ float g_x [BSR*DDIM];
__device__ float g_q [BSR*DDIM];
__device__ float g_k [BSR*DDIM];
__device__ float g_v [BSR*DDIM];
__device__ float g_o [BSR*DDIM];
__device__ float g_t [BSR*DDIM];
__device__ float g_h1[BSR*FFD];

// bf16 hi/lo planes: weights transposed to [N][K]
__device__ bf16 g_wqh[LLAY*DDIM*DDIM], g_wql[LLAY*DDIM*DDIM];
__device__ bf16 g_wkh[LLAY*DDIM*DDIM], g_wkl[LLAY*DDIM*DDIM];
__device__ bf16 g_wvh[LLAY*DDIM*DDIM], g_wvl[LLAY*DDIM*DDIM];
__device__ bf16 g_woh[LLAY*DDIM*DDIM], g_wol[LLAY*DDIM*DDIM];
__device__ bf16 g_w1h[LLAY*DDIM*FFD],  g_w1l[LLAY*DDIM*FFD];
__device__ bf16 g_w2h[LLAY*FFD*DDIM],  g_w2l[LLAY*FFD*DDIM];
__device__ bf16 g_ah[BSR*FFD], g_al[BSR*FFD];

// ---------------- helpers -----------------------------------------------------
__device__ __forceinline__ uint32_t f2tf32(float x) {
    uint32_t r;
    asm("cvt.rna.tf32.f32 %0, %1;" : "=r"(r) : "f"(x));
    return r;
}
__device__ __forceinline__ void mma8(float* c, const uint32_t* a, const uint32_t* b) {
    asm volatile(
        "mma.sync.aligned.m16n8k8.row.col.f32.tf32.tf32.f32 "
        "{%0,%1,%2,%3}, {%4,%5,%6,%7}, {%8,%9}, {%0,%1,%2,%3};"
        : "+f"(c[0]), "+f"(c[1]), "+f"(c[2]), "+f"(c[3])
        : "r"(a[0]), "r"(a[1]), "r"(a[2]), "r"(a[3]), "r"(b[0]), "r"(b[1]));
}
__device__ __forceinline__ void mma16(float* c, const uint32_t* a, const uint32_t* b) {
    asm volatile(
        "mma.sync.aligned.m16n8k16.row.col.f32.bf16.bf16.f32 "
        "{%0,%1,%2,%3}, {%4,%5,%6,%7}, {%8,%9}, {%0,%1,%2,%3};"
        : "+f"(c[0]), "+f"(c[1]), "+f"(c[2]), "+f"(c[3])
        : "r"(a[0]), "r"(a[1]), "r"(a[2]), "r"(a[3]), "r"(b[0]), "r"(b[1]));
}

// ---------------- embedding + (buggy-faithful) positional encoding ------------
__global__ void embed_pe(const int* __restrict__ tok, const float* __restrict__ emb) {
    int idx = blockIdx.x * 256 + threadIdx.x;
    int d  = idx & (DDIM - 1);
    int bs = idx >> 10;
    int b  = bs >> 10;
    int t  = tok[bs];
    int i2 = (d >> 1) << 1;
    float div = expf(-(float)i2 * (9.210340371976184f / (float)DDIM));
    float ang = (float)b * div;
    float pe  = (d & 1) ? cosf(ang) : sinf(ang);
    g_x[idx] = emb[(size_t)t * DDIM + d] + pe;
}

// ---------------- activation hi/lo split --------------------------------------
__global__ __launch_bounds__(256)
void split_a(const float* __restrict__ s, bf16* __restrict__ hi, bf16* __restrict__ lo) {
    int i4 = (blockIdx.x * 256 + threadIdx.x) * 4;
    float4 v = *(const float4*)(s + i4);
    bf16 h0 = __float2bfloat16_rn(v.x), h1 = __float2bfloat16_rn(v.y);
    bf16 h2 = __float2bfloat16_rn(v.z), h3 = __float2bfloat16_rn(v.w);
    bf16 l0 = __float2bfloat16_rn(v.x - __bfloat162float(h0));
    bf16 l1 = __float2bfloat16_rn(v.y - __bfloat162float(h1));
    bf16 l2 = __float2bfloat16_rn(v.z - __bfloat162float(h2));
    bf16 l3 = __float2bfloat16_rn(v.w - __bfloat162float(h3));
    __nv_bfloat162 hh0; hh0.x = h0; hh0.y = h1;
    __nv_bfloat162 hh1; hh1.x = h2; hh1.y = h3;
    __nv_bfloat162 ll0; ll0.x = l0; ll0.y = l1;
    __nv_bfloat162 ll1; ll1.x = l2; ll1.y = l3;
    *(__nv_bfloat162*)(hi + i4)     = hh0;
    *(__nv_bfloat162*)(hi + i4 + 2) = hh1;
    *(__nv_bfloat162*)(lo + i4)     = ll0;
    *(__nv_bfloat162*)(lo + i4 + 2) = ll1;
}

// ---------------- weight transpose + hi/lo split: W[K][N] -> [N][K] ----------
__global__ __launch_bounds__(256)
void split_w_t(const float* __restrict__ W, bf16* __restrict__ th, bf16* __restrict__ tl,
               int K, int N) {
    __shared__ float tile[32][33];
    const int n0 = blockIdx.x * 32, k0 = blockIdx.y * 32;
    const int tx = threadIdx.x & 31, ty = threadIdx.x >> 5;
#pragma unroll
    for (int i = 0; i < 32; i += 8)
        tile[ty + i][tx] = W[(size_t)(k0 + ty + i) * N + n0 + tx];
    __syncthreads();
#pragma unroll
    for (int i = 0; i < 32; i += 8) {
        int n = n0 + ty + i, k = k0 + tx;
        float v = tile[tx][ty + i];
        bf16 h = __float2bfloat16_rn(v);
        th[(size_t)n * K + k] = h;
        tl[(size_t)n * K + k] = __float2bfloat16_rn(v - __bfloat162float(h));
    }
}

// ---------------- bf16x3 tensor-core GEMM: C = A[M,K]@B^T + bias -------------
template<bool RELU>
__global__ __launch_bounds__(256, 1)
void gemm_bf16x3(const bf16* __restrict__ Ah, const bf16* __restrict__ Al,
                 const bf16* __restrict__ Bh, const bf16* __restrict__ Bl,
                 const float* __restrict__ bias, float* __restrict__ C,
                 int M, int N, int K) {
    __shared__ uint32_t As_h[128][20], As_l[128][20];
    __shared__ uint32_t Bs_h[128][20], Bs_l[128][20];
    const int tid  = threadIdx.x;
    const int wid  = tid >> 5, lane = tid & 31;
    const int gid  = lane >> 2, tig = lane & 3;
    const int wm   = wid >> 2, wn = wid & 3;
    const int m0   = blockIdx.y * 128, n0 = blockIdx.x * 128;

    float acc[4][4][4];
#pragma unroll
    for (int mt = 0; mt < 4; mt++)
#pragma unroll
        for (int nt = 0; nt < 4; nt++)
#pragma unroll
            for (int i = 0; i < 4; i++) acc[mt][nt][i] = 0.f;

    uint4 pah[2], pal[2], pbh[2], pbl[2];
#pragma unroll
    for (int e = 0; e < 2; e++) {
        int idx = tid + e * 256;
        int row = idx >> 2, c8 = (idx & 3) << 3;
        pah[e] = *(const uint4*)(Ah + (size_t)(m0 + row) * K + c8);
        pal[e] = *(const uint4*)(Al + (size_t)(m0 + row) * K + c8);
        pbh[e] = *(const uint4*)(Bh + (size_t)(n0 + row) * K + c8);
        pbl[e] = *(const uint4*)(Bl + (size_t)(n0 + row) * K + c8);
    }

    for (int k0 = 0; k0 < K; k0 += 32) {
#pragma unroll
        for (int e = 0; e < 2; e++) {
            int idx = tid + e * 256;
            int row = idx >> 2, w4 = (idx & 3) << 2;
            *(uint4*)&As_h[row][w4] = pah[e];
            *(uint4*)&As_l[row][w4] = pal[e];
            *(uint4*)&Bs_h[row][w4] = pbh[e];
            *(uint4*)&Bs_l[row][w4] = pbl[e];
        }
        __syncthreads();
        if (k0 + 32 < K) {
#pragma unroll
            for (int e = 0; e < 2; e++) {
                int idx = tid + e * 256;
                int row = idx >> 2, c8 = (idx & 3) << 3;
                pah[e] = *(const uint4*)(Ah + (size_t)(m0 + row) * K + k0 + 32 + c8);
                pal[e] = *(const uint4*)(Al + (size_t)(m0 + row) * K + k0 + 32 + c8);
                pbh[e] = *(const uint4*)(Bh + (size_t)(n0 + row) * K + k0 + 32 + c8);
                pbl[e] = *(const uint4*)(Bl + (size_t)(n0 + row) * K + k0 + 32 + c8);
            }
        }
#pragma unroll
        for (int s = 0; s < 2; s++) {
            const int kb = s * 8;
            uint32_t ah[4][4], al[4][4], bh4[4][2], bl4[4][2];
#pragma unroll
            for (int mt = 0; mt < 4; mt++) {
                int m = wm * 64 + mt * 16 + gid;
                ah[mt][0] = As_h[m][kb + tig];     ah[mt][1] = As_h[m + 8][kb + tig];
                ah[mt][2] = As_h[m][kb + tig + 4]; ah[mt][3] = As_h[m + 8][kb + tig + 4];
                al[mt][0] = As_l[m][kb + tig];     al[mt][1] = As_l[m + 8][kb + tig];
                al[mt][2] = As_l[m][kb + tig + 4]; al[mt][3] = As_l[m + 8][kb + tig + 4];
            }
#pragma unroll
            for (int nt = 0; nt < 4; nt++) {
                int n = wn * 32 + nt * 8 + gid;
                bh4[nt][0] = Bs_h[n][kb + tig]; bh4[nt][1] = Bs_h[n][kb + tig + 4];
                bl4[nt][0] = Bs_l[n][kb + tig]; bl4[nt][1] = Bs_l[n][kb + tig + 4];
            }
#pragma unroll
            for (int mt = 0; mt < 4; mt++)
#pragma unroll
                for (int nt = 0; nt < 4; nt++) {
                    mma16(acc[mt][nt], al[mt], bh4[nt]);
                    mma16(acc[mt][nt], ah[mt], bl4[nt]);
                    mma16(acc[mt][nt], ah[mt], bh4[nt]);
                }
        }
        __syncthreads();
    }

#pragma unroll
    for (int mt = 0; mt < 4; mt++) {
        int r0 = m0 + wm * 64 + mt * 16 + gid;
#pragma unroll
        for (int nt = 0; nt < 4; nt++) {
            int c = n0 + wn * 32 + nt * 8 + (tig << 1);
            float b0 = bias[c], b1 = bias[c + 1];
            float2 o0 = make_float2(acc[mt][nt][0] + b0, acc[mt][nt][1] + b1);
            float2 o1 = make_float2(acc[mt][nt][2] + b0, acc[mt][nt][3] + b1);
            if (RELU) {
                o0.x = fmaxf(o0.x, 0.f); o0.y = fmaxf(o0.y, 0.f);
                o1.x = fmaxf(o1.x, 0.f); o1.y = fmaxf(o1.y, 0.f);
            }
            *(float2*)(C + (size_t)r0 * N + c)       = o0;
            *(float2*)(C + (size_t)(r0 + 8) * N + c) = o1;
        }
    }
}

// ---------------- fused flash attention --------------------------------------
// grid (SS/128, B*H); 256 thr = 8 warps, warp w owns query rows w*16..w*16+15.
// smem word layout:
//   Qs [128][68] tf32 (q rows x dims, pre-scaled by 1/8)   @ 0      (8704 w)
//   Ks [64][68]  tf32 (key rows x dims)                    @ 8704   (4352 w)
//   Vs [64][72]  tf32 (key rows x dims)                    @ 13056  (4608 w)
//   Ps [128][68] tf32 (q rows x key-col)                   @ 17664  (8704 w)
#define FA_SMEM_WORDS (8704 + 4352 + 4608 + 8704)
#define FA_SMEM_BYTES (FA_SMEM_WORDS * 4)

__global__ __launch_bounds__(256, 1)
void flash_attn(const float* __restrict__ q, const float* __restrict__ k,
                const float* __restrict__ v) {
    extern __shared__ uint32_t sm[];
    uint32_t (*Qs)[68] = (uint32_t(*)[68])(sm);
    uint32_t (*Ks)[68] = (uint32_t(*)[68])(sm + 8704);
    uint32_t (*Vs)[72] = (uint32_t(*)[72])(sm + 13056);
    uint32_t (*Ps)[68] = (uint32_t(*)[68])(sm + 17664);

    const int z = blockIdx.y, b = z >> 4, h = z & 15;
    const int i0 = blockIdx.x * 128;
    const float* Qg = q + (size_t)b * SS * DDIM + h * DKH;
    const float* Kg = k + (size_t)b * SS * DDIM + h * DKH;
    const float* Vg = v + (size_t)b * SS * DDIM + h * DKH;
    float*       Og = g_o + (size_t)b * SS * DDIM + h * DKH;

    const int tid = threadIdx.x;
    const int wid = tid >> 5, lane = tid & 31;
    const int gid = lane >> 2, tig = lane & 3;
    const int mb  = wid * 16;

    // load Q tile (scale by 1/8 here; folds the 1/sqrt(dk))
#pragma unroll
    for (int e = 0; e < 8; e++) {
        int idx = tid + e * 256;               // 2048 float4
        int row = idx >> 4, c4 = (idx & 15) << 2;
        float4 vq = *(const float4*)(Qg + (size_t)(i0 + row) * DDIM + c4);
        uint4 w;
        w.x = f2tf32(vq.x * 0.125f); w.y = f2tf32(vq.y * 0.125f);
        w.z = f2tf32(vq.z * 0.125f); w.w = f2tf32(vq.w * 0.125f);
        *(uint4*)&Qs[row][c4] = w;
    }

    float acco[8][4];
#pragma unroll
    for (int nt = 0; nt < 8; nt++)
#pragma unroll
        for (int i = 0; i < 4; i++) acco[nt][i] = 0.f;
    float m_lo = -1e30f, m_hi = -1e30f, l_lo = 0.f, l_hi = 0.f;

    for (int j0 = 0; j0 < SS; j0 += 64) {
        __syncthreads();   // previous tile's Ks/Vs reads done (also covers Q store, iter 0)
#pragma unroll
        for (int e = 0; e < 4; e++) {
            int idx = tid + e * 256;           // 1024 float4
            int row = idx >> 4, c4 = (idx & 15) << 2;
            float4 kk = *(const float4*)(Kg + (size_t)(j0 + row) * DDIM + c4);
            float4 vv = *(const float4*)(Vg + (size_t)(j0 + row) * DDIM + c4);
            uint4 wk, wv;
            wk.x = f2tf32(kk.x); wk.y = f2tf32(kk.y); wk.z = f2tf32(kk.z); wk.w = f2tf32(kk.w);
            wv.x = f2tf32(vv.x); wv.y = f2tf32(vv.y); wv.z = f2tf32(vv.z); wv.w = f2tf32(vv.w);
            *(uint4*)&Ks[row][c4] = wk;
            *(uint4*)&Vs[row][c4] = wv;
        }
        __syncthreads();

        // S = Q_tile @ K_tile^T   (warp: 16 x 64)
        float accs[8][4];
#pragma unroll
        for (int nt = 0; nt < 8; nt++)
#pragma unroll
            for (int i = 0; i < 4; i++) accs[nt][i] = 0.f;
#pragma unroll
        for (int ks = 0; ks < 64; ks += 8) {
            uint32_t a[4];
            a[0] = Qs[mb + gid][ks + tig];     a[1] = Qs[mb + gid + 8][ks + tig];
            a[2] = Qs[mb + gid][ks + tig + 4]; a[3] = Qs[mb + gid + 8][ks + tig + 4];
#pragma unroll
            for (int nt = 0; nt < 8; nt++) {
                uint32_t bb[2];
                bb[0] = Ks[nt * 8 + gid][ks + tig];
                bb[1] = Ks[nt * 8 + gid][ks + tig + 4];
                mma8(accs[nt], a, bb);
            }
        }

        // online softmax update
        float mx_lo = -1e30f, mx_hi = -1e30f;
#pragma unroll
        for (int nt = 0; nt < 8; nt++) {
            mx_lo = fmaxf(mx_lo, fmaxf(accs[nt][0], accs[nt][1]));
            mx_hi = fmaxf(mx_hi, fmaxf(accs[nt][2], accs[nt][3]));
        }
        mx_lo = fmaxf(mx_lo, __shfl_xor_sync(~0u, mx_lo, 1));
        mx_lo = fmaxf(mx_lo, __shfl_xor_sync(~0u, mx_lo, 2));
        mx_hi = fmaxf(mx_hi, __shfl_xor_sync(~0u, mx_hi, 1));
        mx_hi = fmaxf(mx_hi, __shfl_xor_sync(~0u, mx_hi, 2));
        float mn_lo = fmaxf(m_lo, mx_lo), mn_hi = fmaxf(m_hi, mx_hi);
        float al_lo = __expf(m_lo - mn_lo), al_hi = __expf(m_hi - mn_hi);
        m_lo = mn_lo; m_hi = mn_hi;

        float sum_lo = 0.f, sum_hi = 0.f;
#pragma unroll
        for (int nt = 0; nt < 8; nt++) {
            accs[nt][0] = __expf(accs[nt][0] - m_lo);
            accs[nt][1] = __expf(accs[nt][1] - m_lo);
            accs[nt][2] = __expf(accs[nt][2] - m_hi);
            accs[nt][3] = __expf(accs[nt][3] - m_hi);
            sum_lo += accs[nt][0] + accs[nt][1];
            sum_hi += accs[nt][2] + accs[nt][3];
        }
        sum_lo += __shfl_xor_sync(~0u, sum_lo, 1);
        sum_lo += __shfl_xor_sync(~0u, sum_lo, 2);
        sum_hi += __shfl_xor_sync(~0u, sum_hi, 1);
        sum_hi += __shfl_xor_sync(~0u, sum_hi, 2);
        l_lo = l_lo * al_lo + sum_lo;
        l_hi = l_hi * al_hi + sum_hi;

        // rescale O accumulator
#pragma unroll
        for (int nt = 0; nt < 8; nt++) {
            acco[nt][0] *= al_lo; acco[nt][1] *= al_lo;
            acco[nt][2] *= al_hi; acco[nt][3] *= al_hi;
        }

        // write P to smem (own rows only — no cross-warp sharing)
#pragma unroll
        for (int nt = 0; nt < 8; nt++) {
            int c = nt * 8 + (tig << 1);
            uint2 w0; w0.x = f2tf32(accs[nt][0]); w0.y = f2tf32(accs[nt][1]);
            uint2 w1; w1.x = f2tf32(accs[nt][2]); w1.y = f2tf32(accs[nt][3]);
            *(uint2*)&Ps[mb + gid][c]     = w0;
            *(uint2*)&Ps[mb + gid + 8][c] = w1;
        }
        __syncwarp();

        // O += P @ V_tile
#pragma unroll
        for (int ks = 0; ks < 64; ks += 8) {
            uint32_t a[4];
            a[0] = Ps[mb + gid][ks + tig];     a[1] = Ps[mb + gid + 8][ks + tig];
            a[2] = Ps[mb + gid][ks + tig + 4]; a[3] = Ps[mb + gid + 8][ks + tig + 4];
#pragma unroll
            for (int nt = 0; nt < 8; nt++) {
                uint32_t bb[2];
                bb[0] = Vs[ks + tig][nt * 8 + gid];
                bb[1] = Vs[ks + tig + 4][nt * 8 + gid];
                mma8(acco[nt], a, bb);
            }
        }
    }

    // normalize + write out
    const float inv_lo = 1.0f / l_lo, inv_hi = 1.0f / l_hi;
#pragma unroll
    for (int nt = 0; nt < 8; nt++) {
        int c = nt * 8 + (tig << 1);
        *(float2*)(Og + (size_t)(i0 + mb + gid) * DDIM + c) =
            make_float2(acco[nt][0] * inv_lo, acco[nt][1] * inv_lo);
        *(float2*)(Og + (size_t)(i0 + mb + gid + 8) * DDIM + c) =
            make_float2(acco[nt][2] * inv_hi, acco[nt][3] * inv_hi);
    }
}

// ---------------- add + LayerNorm (row of D=1024) ----------------------------
__global__ __launch_bounds__(256)
void add_ln(const float* __restrict__ x, const float* __restrict__ y,
            const float* __restrict__ g, const float* __restrict__ be,
            float* __restrict__ out) {
    __shared__ float sm[8];
    __shared__ float bc;
    const int tid = threadIdx.x;
    const size_t ro = (size_t)blockIdx.x * DDIM;
    float4 a = reinterpret_cast<const float4*>(x + ro)[tid];
    float4 b = reinterpret_cast<const float4*>(y + ro)[tid];
    a.x += b.x; a.y += b.y; a.z += b.z; a.w += b.w;

    float s = a.x + a.y + a.z + a.w;
#pragma unroll
    for (int o = 16; o; o >>= 1) s += __shfl_xor_sync(~0u, s, o);
    if ((tid & 31) == 0) sm[tid >> 5] = s;
    __syncthreads();
    if (tid < 32) {
        float t = (tid < 8) ? sm[tid] : 0.f;
#pragma unroll
        for (int o = 4; o; o >>= 1) t += __shfl_xor_sync(~0u, t, o);
        if (tid == 0) bc = t;
    }
    __syncthreads();
    const float mu = bc * (1.0f / DDIM);
    a.x -= mu; a.y -= mu; a.z -= mu; a.w -= mu;
    float qv = a.x*a.x + a.y*a.y + a.z*a.z + a.w*a.w;
    __syncthreads();
#pragma unroll
    for (int o = 16; o; o >>= 1) qv += __shfl_xor_sync(~0u, qv, o);
    if ((tid & 31) == 0) sm[tid >> 5] = qv;
    __syncthreads();
    if (tid < 32) {
        float t = (tid < 8) ? sm[tid] : 0.f;
#pragma unroll
        for (int o = 4; o; o >>= 1) t += __shfl_xor_sync(~0u, t, o);
        if (tid == 0) bc = t;
    }
    __syncthreads();
    const float rs = rsqrtf(bc * (1.0f / DDIM) + 1e-5f);
    float4 gv = reinterpret_cast<const float4*>(g)[tid];
    float4 bv = reinterpret_cast<const float4*>(be)[tid];
    float4 o;
    o.x = a.x * rs * gv.x + bv.x;
    o.y = a.y * rs * gv.y + bv.y;
    o.z = a.z * rs * gv.z + bv.z;
    o.w = a.w * rs * gv.w + bv.w;
    reinterpret_cast<float4*>(out + ro)[tid] = o;
}

// ---------------- launch ------------------------------------------------------
extern "C" void kernel_launch(void* const* d_in, const int* in_sizes, int n_in,
                              void* d_out, int out_size) {
    const int*   tokens = (const int*)  d_in[0];
    const float* emb    = (const float*)d_in[1];
    const float* Wq = (const float*)d_in[2],  *bq = (const float*)d_in[3];
    const float* Wk = (const float*)d_in[4],  *bk = (const float*)d_in[5];
    const float* Wv = (const float*)d_in[6],  *bv = (const float*)d_in[7];
    const float* Wo = (const float*)d_in[8],  *bo = (const float*)d_in[9];
    const float* W1 = (const float*)d_in[10], *b1 = (const float*)d_in[11];
    const float* W2 = (const float*)d_in[12], *b2 = (const float*)d_in[13];
    const float* gamma = (const float*)d_in[14], *beta = (const float*)d_in[15];
    float* out = (float*)d_out;

    float *x, *q, *k, *v, *o, *t, *h1;
    cudaGetSymbolAddress((void**)&x,  g_x);
    cudaGetSymbolAddress((void**)&q,  g_q);
    cudaGetSymbolAddress((void**)&k,  g_k);
    cudaGetSymbolAddress((void**)&v,  g_v);
    cudaGetSymbolAddress((void**)&o,  g_o);
    cudaGetSymbolAddress((void**)&t,  g_t);
    cudaGetSymbolAddress((void**)&h1, g_h1);
    bf16 *wqh,*wql,*wkh,*wkl,*wvh,*wvl,*woh,*wol,*w1h,*w1l,*w2h,*w2l,*ah,*al;
    cudaGetSymbolAddress((void**)&wqh, g_wqh); cudaGetSymbolAddress((void**)&wql, g_wql);
    cudaGetSymbolAddress((void**)&wkh, g_wkh); cudaGetSymbolAddress((void**)&wkl, g_wkl);
    cudaGetSymbolAddress((void**)&wvh, g_wvh); cudaGetSymbolAddress((void**)&wvl, g_wvl);
    cudaGetSymbolAddress((void**)&woh, g_woh); cudaGetSymbolAddress((void**)&wol, g_wol);
    cudaGetSymbolAddress((void**)&w1h, g_w1h); cudaGetSymbolAddress((void**)&w1l, g_w1l);
    cudaGetSymbolAddress((void**)&w2h, g_w2h); cudaGetSymbolAddress((void**)&w2l, g_w2l);
    cudaGetSymbolAddress((void**)&ah,  g_ah);  cudaGetSymbolAddress((void**)&al,  g_al);

    cudaFuncSetAttribute(flash_attn, cudaFuncAttributeMaxDynamicSharedMemorySize,
                         FA_SMEM_BYTES);

    embed_pe<<<BSR * DDIM / 256, 256>>>(tokens, emb);

    // ---- weight conversion: transpose + bf16 hi/lo split (once per launch) ----
    const dim3 gwp(DDIM / 32, DDIM / 32);
    const dim3 gw1(FFD  / 32, DDIM / 32);
    const dim3 gw2(DDIM / 32, FFD  / 32);
    for (int l = 0; l < LLAY; l++) {
        size_t od = (size_t)l * DDIM * DDIM, of = (size_t)l * DDIM * FFD;
        split_w_t<<<gwp, 256>>>(Wq + od, wqh + od, wql + od, DDIM, DDIM);
        split_w_t<<<gwp, 256>>>(Wk + od, wkh + od, wkl + od, DDIM, DDIM);
        split_w_t<<<gwp, 256>>>(Wv + od, wvh + od, wvl + od, DDIM, DDIM);
        split_w_t<<<gwp, 256>>>(Wo + od, woh + od, wol + od, DDIM, DDIM);
        split_w_t<<<gw1, 256>>>(W1 + of, w1h + of, w1l + of, DDIM, FFD);
        split_w_t<<<gw2, 256>>>(W2 + of, w2h + of, w2l + of, FFD, DDIM);
    }

    const dim3 gp(DDIM / 128, BSR / 128);
    const dim3 gf(FFD  / 128, BSR / 128);
    const int nA  = BSR * DDIM / 1024;
    const int nH  = BSR * FFD  / 1024;

    for (int l = 0; l < LLAY; l++) {
        size_t od = (size_t)l * DDIM * DDIM, of = (size_t)l * DDIM * FFD;
        const float* lbq = bq + (size_t)l * DDIM;
        const float* lbk = bk + (size_t)l * DDIM;
        const float* lbv = bv + (size_t)l * DDIM;
        const float* lbo = bo + (size_t)l * DDIM;
        const float* lb1 = b1 + (size_t)l * FFD;
        const float* lb2 = b2 + (size_t)l * DDIM;
        const float* lg  = gamma + (size_t)l * DDIM;
        const float* lbe = beta  + (size_t)l * DDIM;

        split_a<<<nA, 256>>>(x, ah, al);
        gemm_bf16x3<false><<<gp, 256>>>(ah, al, wqh + od, wql + od, lbq, q, BSR, DDIM, DDIM);
        gemm_bf16x3<false><<<gp, 256>>>(ah, al, wkh + od, wkl + od, lbk, k, BSR, DDIM, DDIM);
        gemm_bf16x3<false><<<gp, 256>>>(ah, al, wvh + od, wvl + od, lbv, v, BSR, DDIM, DDIM);

        flash_attn<<<dim3(SS / 128, BB * HH), 256, FA_SMEM_BYTES>>>(q, k, v);

        split_a<<<nA, 256>>>(o, ah, al);
        gemm_bf16x3<false><<<gp, 256>>>(ah, al, woh + od, wol + od, lbo, t, BSR, DDIM, DDIM);
        add_ln<<<BSR, 256>>>(x, t, lg, lbe, x);

        split_a<<<nA, 256>>>(x, ah, al);
        gemm_bf16x3<true ><<<gf, 256>>>(ah, al, w1h + of, w1l + of, lb1, h1, BSR, FFD, DDIM);
        split_a<<<nH, 256>>>(h1, ah, al);
        gemm_bf16x3<false><<<gp, 256>>>(ah, al, w2h + of, w2l + of, lb2, t, BSR, DDIM, FFD);

        float* xo = (l == LLAY - 1) ? out : x;
        add_ln<<<BSR, 256>>>(x, t, lg, lbe, xo);
    }
}

// round 5
// speedup vs baseline: 2.4594x; 1.1302x over previous
#include <cuda_runtime.h>
#include <cuda_bf16.h>
#include <math.h>
#include <stdint.h>

// Problem constants
#define BB   2
#define SS   1024
#define DDIM 1024
#define HH   16
#define LLAY 4
#define FFD  2048
#define DKH  64
#define BSR  (BB*SS)   // 2048 rows

typedef __nv_bfloat16 bf16;

// ---------------- scratch (static device globals; no allocs allowed) ----------
__device__ float g_x [BSR*DDIM];
__device__ float g_q [BSR*DDIM];
__device__ float g_k [BSR*DDIM];
__device__ float g_v [BSR*DDIM];
__device__ float g_t [BSR*DDIM];

// bf16 hi/lo planes: weights transposed to [N][K]
__device__ __align__(256) bf16 g_wqh[LLAY*DDIM*DDIM], g_wql[LLAY*DDIM*DDIM];
__device__ __align__(256) bf16 g_wkh[LLAY*DDIM*DDIM], g_wkl[LLAY*DDIM*DDIM];
__device__ __align__(256) bf16 g_wvh[LLAY*DDIM*DDIM], g_wvl[LLAY*DDIM*DDIM];
__device__ __align__(256) bf16 g_woh[LLAY*DDIM*DDIM], g_wol[LLAY*DDIM*DDIM];
__device__ __align__(256) bf16 g_w1h[LLAY*DDIM*FFD],  g_w1l[LLAY*DDIM*FFD];
__device__ __align__(256) bf16 g_w2h[LLAY*FFD*DDIM],  g_w2l[LLAY*FFD*DDIM];
// activation planes: x/o share one pair; h1 gets its own (W1 reads x while writing h1)
__device__ __align__(256) bf16 g_ah[BSR*DDIM], g_al[BSR*DDIM];
__device__ __align__(256) bf16 g_hh[BSR*FFD],  g_hl[BSR*FFD];

// ---------------- helpers -----------------------------------------------------
__device__ __forceinline__ uint32_t f2tf32(float x) {
    uint32_t r;
    asm("cvt.rna.tf32.f32 %0, %1;" : "=r"(r) : "f"(x));
    return r;
}
__device__ __forceinline__ void mma8(float* c, const uint32_t* a, const uint32_t* b) {
    asm volatile(
        "mma.sync.aligned.m16n8k8.row.col.f32.tf32.tf32.f32 "
        "{%0,%1,%2,%3}, {%4,%5,%6,%7}, {%8,%9}, {%0,%1,%2,%3};"
        : "+f"(c[0]), "+f"(c[1]), "+f"(c[2]), "+f"(c[3])
        : "r"(a[0]), "r"(a[1]), "r"(a[2]), "r"(a[3]), "r"(b[0]), "r"(b[1]));
}
__device__ __forceinline__ void mma16(float* c, const uint32_t* a, const uint32_t* b) {
    asm volatile(
        "mma.sync.aligned.m16n8k16.row.col.f32.bf16.bf16.f32 "
        "{%0,%1,%2,%3}, {%4,%5,%6,%7}, {%8,%9}, {%0,%1,%2,%3};"
        : "+f"(c[0]), "+f"(c[1]), "+f"(c[2]), "+f"(c[3])
        : "r"(a[0]), "r"(a[1]), "r"(a[2]), "r"(a[3]), "r"(b[0]), "r"(b[1]));
}
__device__ __forceinline__ void cp16(uint32_t* s, const void* g) {
    uint32_t sa = (uint32_t)__cvta_generic_to_shared(s);
    asm volatile("cp.async.cg.shared.global [%0], [%1], 16;" :: "r"(sa), "l"(g));
}
#define CP_COMMIT() asm volatile("cp.async.commit_group;")
#define CP_WAIT1()  asm volatile("cp.async.wait_group 1;")

__device__ __forceinline__ void split2(float v0, float v1, __nv_bfloat162* hi,
                                       __nv_bfloat162* lo) {
    bf16 h0 = __float2bfloat16_rn(v0), h1 = __float2bfloat16_rn(v1);
    __nv_bfloat162 hh; hh.x = h0; hh.y = h1;
    __nv_bfloat162 ll;
    ll.x = __float2bfloat16_rn(v0 - __bfloat162float(h0));
    ll.y = __float2bfloat16_rn(v1 - __bfloat162float(h1));
    *hi = hh; *lo = ll;
}

// ---------------- embedding + (buggy-faithful) positional encoding ------------
__global__ void embed_pe(const int* __restrict__ tok, const float* __restrict__ emb) {
    int idx = blockIdx.x * 256 + threadIdx.x;
    int d  = idx & (DDIM - 1);
    int bs = idx >> 10;
    int b  = bs >> 10;
    int t  = tok[bs];
    int i2 = (d >> 1) << 1;
    float div = expf(-(float)i2 * (9.210340371976184f / (float)DDIM));
    float ang = (float)b * div;
    float pe  = (d & 1) ? cosf(ang) : sinf(ang);
    g_x[idx] = emb[(size_t)t * DDIM + d] + pe;
}

// ---------------- activation hi/lo split (used once, after embed) -------------
__global__ __launch_bounds__(256)
void split_a(const float* __restrict__ s, bf16* __restrict__ hi, bf16* __restrict__ lo) {
    int i4 = (blockIdx.x * 256 + threadIdx.x) * 4;
    float4 v = *(const float4*)(s + i4);
    split2(v.x, v.y, (__nv_bfloat162*)(hi + i4),     (__nv_bfloat162*)(lo + i4));
    split2(v.z, v.w, (__nv_bfloat162*)(hi + i4 + 2), (__nv_bfloat162*)(lo + i4 + 2));
}

// ---------------- weight transpose + hi/lo split: W[K][N] -> [N][K] ----------
__global__ __launch_bounds__(256)
void split_w_t(const float* __restrict__ W, bf16* __restrict__ th, bf16* __restrict__ tl,
               int K, int N) {
    __shared__ float tile[32][33];
    const int n0 = blockIdx.x * 32, k0 = blockIdx.y * 32;
    const int tx = threadIdx.x & 31, ty = threadIdx.x >> 5;
#pragma unroll
    for (int i = 0; i < 32; i += 8)
        tile[ty + i][tx] = W[(size_t)(k0 + ty + i) * N + n0 + tx];
    __syncthreads();
#pragma unroll
    for (int i = 0; i < 32; i += 8) {
        int n = n0 + ty + i, k = k0 + tx;
        float v = tile[tx][ty + i];
        bf16 h = __float2bfloat16_rn(v);
        th[(size_t)n * K + k] = h;
        tl[(size_t)n * K + k] = __float2bfloat16_rn(v - __bfloat162float(h));
    }
}

// ---------------- bf16x3 tensor-core GEMM, cp.async 3-stage pipeline ---------
// C = A[M,K] @ B[N,K]^T + bias.  BM=BN=128, BK=32, 256 thr (8 warps, 2x4).
// dyn smem: 4 planes x 3 stages x 128 rows x 20 words = 30720 words = 120KB.
#define GS_PLANE 7680      // words per plane (3 stages x 2560)
#define GS_STAGE 2560      // words per stage
#define GEMM_SMEM_BYTES (4 * GS_PLANE * 4)

__device__ __forceinline__ void gemm_copy_stage(
    uint32_t* sm, const bf16* __restrict__ Ah, const bf16* __restrict__ Al,
    const bf16* __restrict__ Bh, const bf16* __restrict__ Bl,
    int m0, int n0, int K, int k0, int s, int tid) {
#pragma unroll
    for (int e = 0; e < 2; e++) {
        int c = tid + e * 256;                  // 0..511
        int row = c >> 2, cw = (c & 3) << 2;    // word offset within row
        int kk  = k0 + ((c & 3) << 3);          // bf16 offset
        size_t ga = (size_t)(m0 + row) * K + kk;
        size_t gb = (size_t)(n0 + row) * K + kk;
        int so = s * GS_STAGE + row * 20 + cw;
        cp16(sm + 0 * GS_PLANE + so, Ah + ga);
        cp16(sm + 1 * GS_PLANE + so, Al + ga);
        cp16(sm + 2 * GS_PLANE + so, Bh + gb);
        cp16(sm + 3 * GS_PLANE + so, Bl + gb);
    }
}

template<bool RELU, bool PLANES>
__global__ __launch_bounds__(256, 1)
void gemm_bf16x3(const bf16* __restrict__ Ah, const bf16* __restrict__ Al,
                 const bf16* __restrict__ Bh, const bf16* __restrict__ Bl,
                 const float* __restrict__ bias, float* __restrict__ C,
                 bf16* __restrict__ Chi, bf16* __restrict__ Clo,
                 int M, int N, int K) {
    extern __shared__ uint32_t sm[];
    const int tid  = threadIdx.x;
    const int wid  = tid >> 5, lane = tid & 31;
    const int gid  = lane >> 2, tig = lane & 3;
    const int wm   = wid >> 2, wn = wid & 3;
    const int m0   = blockIdx.y * 128, n0 = blockIdx.x * 128;

    float acc[4][4][4];
#pragma unroll
    for (int mt = 0; mt < 4; mt++)
#pragma unroll
        for (int nt = 0; nt < 4; nt++)
#pragma unroll
            for (int i = 0; i < 4; i++) acc[mt][nt][i] = 0.f;

    // prologue: stages 0 and 1
    gemm_copy_stage(sm, Ah, Al, Bh, Bl, m0, n0, K, 0, 0, tid);
    CP_COMMIT();
    gemm_copy_stage(sm, Ah, Al, Bh, Bl, m0, n0, K, 32, 1, tid);
    CP_COMMIT();

    int s = 0;
    for (int k0 = 0; k0 < K; k0 += 32) {
        CP_WAIT1();
        __syncthreads();
        // issue copies for stage +2 (overlaps this stage's MMAs)
        if (k0 + 64 < K) {
            int s2 = s + 2; if (s2 >= 3) s2 -= 3;
            gemm_copy_stage(sm, Ah, Al, Bh, Bl, m0, n0, K, k0 + 64, s2, tid);
        }
        CP_COMMIT();

        const uint32_t* pAH = sm + 0 * GS_PLANE + s * GS_STAGE;
        const uint32_t* pAL = sm + 1 * GS_PLANE + s * GS_STAGE;
        const uint32_t* pBH = sm + 2 * GS_PLANE + s * GS_STAGE;
        const uint32_t* pBL = sm + 3 * GS_PLANE + s * GS_STAGE;
#pragma unroll
        for (int sb = 0; sb < 2; sb++) {
            const int kb = sb * 8;
            uint32_t ah[4][4], al[4][4], bh4[4][2], bl4[4][2];
#pragma unroll
            for (int mt = 0; mt < 4; mt++) {
                int m = wm * 64 + mt * 16 + gid;
                ah[mt][0] = pAH[m * 20 + kb + tig];       ah[mt][1] = pAH[(m + 8) * 20 + kb + tig];
                ah[mt][2] = pAH[m * 20 + kb + tig + 4];   ah[mt][3] = pAH[(m + 8) * 20 + kb + tig + 4];
                al[mt][0] = pAL[m * 20 + kb + tig];       al[mt][1] = pAL[(m + 8) * 20 + kb + tig];
                al[mt][2] = pAL[m * 20 + kb + tig + 4];   al[mt][3] = pAL[(m + 8) * 20 + kb + tig + 4];
            }
#pragma unroll
            for (int nt = 0; nt < 4; nt++) {
                int n = wn * 32 + nt * 8 + gid;
                bh4[nt][0] = pBH[n * 20 + kb + tig]; bh4[nt][1] = pBH[n * 20 + kb + tig + 4];
                bl4[nt][0] = pBL[n * 20 + kb + tig]; bl4[nt][1] = pBL[n * 20 + kb + tig + 4];
            }
#pragma unroll
            for (int mt = 0; mt < 4; mt++)
#pragma unroll
                for (int nt = 0; nt < 4; nt++) {
                    mma16(acc[mt][nt], al[mt], bh4[nt]);
                    mma16(acc[mt][nt], ah[mt], bl4[nt]);
                    mma16(acc[mt][nt], ah[mt], bh4[nt]);
                }
        }
        __syncthreads();
        if (++s == 3) s = 0;
    }

#pragma unroll
    for (int mt = 0; mt < 4; mt++) {
        int r0 = m0 + wm * 64 + mt * 16 + gid;
#pragma unroll
        for (int nt = 0; nt < 4; nt++) {
            int c = n0 + wn * 32 + nt * 8 + (tig << 1);
            float b0 = bias[c], b1 = bias[c + 1];
            float2 o0 = make_float2(acc[mt][nt][0] + b0, acc[mt][nt][1] + b1);
            float2 o1 = make_float2(acc[mt][nt][2] + b0, acc[mt][nt][3] + b1);
            if (RELU) {
                o0.x = fmaxf(o0.x, 0.f); o0.y = fmaxf(o0.y, 0.f);
                o1.x = fmaxf(o1.x, 0.f); o1.y = fmaxf(o1.y, 0.f);
            }
            if (PLANES) {
                split2(o0.x, o0.y, (__nv_bfloat162*)(Chi + (size_t)r0 * N + c),
                                   (__nv_bfloat162*)(Clo + (size_t)r0 * N + c));
                split2(o1.x, o1.y, (__nv_bfloat162*)(Chi + (size_t)(r0 + 8) * N + c),
                                   (__nv_bfloat162*)(Clo + (size_t)(r0 + 8) * N + c));
            } else {
                *(float2*)(C + (size_t)r0 * N + c)       = o0;
                *(float2*)(C + (size_t)(r0 + 8) * N + c) = o1;
            }
        }
    }
}

// ---------------- fused flash attention (writes o's bf16 planes) -------------
#define FA_SMEM_WORDS (8704 + 4352 + 4608 + 8704)
#define FA_SMEM_BYTES (FA_SMEM_WORDS * 4)

__global__ __launch_bounds__(256, 1)
void flash_attn(const float* __restrict__ q, const float* __restrict__ k,
                const float* __restrict__ v) {
    extern __shared__ uint32_t sm[];
    uint32_t (*Qs)[68] = (uint32_t(*)[68])(sm);
    uint32_t (*Ks)[68] = (uint32_t(*)[68])(sm + 8704);
    uint32_t (*Vs)[72] = (uint32_t(*)[72])(sm + 13056);
    uint32_t (*Ps)[68] = (uint32_t(*)[68])(sm + 17664);

    const int z = blockIdx.y, b = z >> 4, h = z & 15;
    const int i0 = blockIdx.x * 128;
    const float* Qg = q + (size_t)b * SS * DDIM + h * DKH;
    const float* Kg = k + (size_t)b * SS * DDIM + h * DKH;
    const float* Vg = v + (size_t)b * SS * DDIM + h * DKH;
    bf16* Oh = g_ah + (size_t)b * SS * DDIM + h * DKH;
    bf16* Ol = g_al + (size_t)b * SS * DDIM + h * DKH;

    const int tid = threadIdx.x;
    const int wid = tid >> 5, lane = tid & 31;
    const int gid = lane >> 2, tig = lane & 3;
    const int mb  = wid * 16;

#pragma unroll
    for (int e = 0; e < 8; e++) {
        int idx = tid + e * 256;
        int row = idx >> 4, c4 = (idx & 15) << 2;
        float4 vq = *(const float4*)(Qg + (size_t)(i0 + row) * DDIM + c4);
        uint4 w;
        w.x = f2tf32(vq.x * 0.125f); w.y = f2tf32(vq.y * 0.125f);
        w.z = f2tf32(vq.z * 0.125f); w.w = f2tf32(vq.w * 0.125f);
        *(uint4*)&Qs[row][c4] = w;
    }

    float acco[8][4];
#pragma unroll
    for (int nt = 0; nt < 8; nt++)
#pragma unroll
        for (int i = 0; i < 4; i++) acco[nt][i] = 0.f;
    float m_lo = -1e30f, m_hi = -1e30f, l_lo = 0.f, l_hi = 0.f;

    for (int j0 = 0; j0 < SS; j0 += 64) {
        __syncthreads();
#pragma unroll
        for (int e = 0; e < 4; e++) {
            int idx = tid + e * 256;
            int row = idx >> 4, c4 = (idx & 15) << 2;
            float4 kk = *(const float4*)(Kg + (size_t)(j0 + row) * DDIM + c4);
            float4 vv = *(const float4*)(Vg + (size_t)(j0 + row) * DDIM + c4);
            uint4 wk, wv;
            wk.x = f2tf32(kk.x); wk.y = f2tf32(kk.y); wk.z = f2tf32(kk.z); wk.w = f2tf32(kk.w);
            wv.x = f2tf32(vv.x); wv.y = f2tf32(vv.y); wv.z = f2tf32(vv.z); wv.w = f2tf32(vv.w);
            *(uint4*)&Ks[row][c4] = wk;
            *(uint4*)&Vs[row][c4] = wv;
        }
        __syncthreads();

        float accs[8][4];
#pragma unroll
        for (int nt = 0; nt < 8; nt++)
#pragma unroll
            for (int i = 0; i < 4; i++) accs[nt][i] = 0.f;
#pragma unroll
        for (int ks = 0; ks < 64; ks += 8) {
            uint32_t a[4];
            a[0] = Qs[mb + gid][ks + tig];     a[1] = Qs[mb + gid + 8][ks + tig];
            a[2] = Qs[mb + gid][ks + tig + 4]; a[3] = Qs[mb + gid + 8][ks + tig + 4];
#pragma unroll
            for (int nt = 0; nt < 8; nt++) {
                uint32_t bb[2];
                bb[0] = Ks[nt * 8 + gid][ks + tig];
                bb[1] = Ks[nt * 8 + gid][ks + tig + 4];
                mma8(accs[nt], a, bb);
            }
        }

        float mx_lo = -1e30f, mx_hi = -1e30f;
#pragma unroll
        for (int nt = 0; nt < 8; nt++) {
            mx_lo = fmaxf(mx_lo, fmaxf(accs[nt][0], accs[nt][1]));
            mx_hi = fmaxf(mx_hi, fmaxf(accs[nt][2], accs[nt][3]));
        }
        mx_lo = fmaxf(mx_lo, __shfl_xor_sync(~0u, mx_lo, 1));
        mx_lo = fmaxf(mx_lo, __shfl_xor_sync(~0u, mx_lo, 2));
        mx_hi = fmaxf(mx_hi, __shfl_xor_sync(~0u, mx_hi, 1));
        mx_hi = fmaxf(mx_hi, __shfl_xor_sync(~0u, mx_hi, 2));
        float mn_lo = fmaxf(m_lo, mx_lo), mn_hi = fmaxf(m_hi, mx_hi);
        float al_lo = __expf(m_lo - mn_lo), al_hi = __expf(m_hi - mn_hi);
        m_lo = mn_lo; m_hi = mn_hi;

        float sum_lo = 0.f, sum_hi = 0.f;
#pragma unroll
        for (int nt = 0; nt < 8; nt++) {
            accs[nt][0] = __expf(accs[nt][0] - m_lo);
            accs[nt][1] = __expf(accs[nt][1] - m_lo);
            accs[nt][2] = __expf(accs[nt][2] - m_hi);
            accs[nt][3] = __expf(accs[nt][3] - m_hi);
            sum_lo += accs[nt][0] + accs[nt][1];
            sum_hi += accs[nt][2] + accs[nt][3];
        }
        sum_lo += __shfl_xor_sync(~0u, sum_lo, 1);
        sum_lo += __shfl_xor_sync(~0u, sum_lo, 2);
        sum_hi += __shfl_xor_sync(~0u, sum_hi, 1);
        sum_hi += __shfl_xor_sync(~0u, sum_hi, 2);
        l_lo = l_lo * al_lo + sum_lo;
        l_hi = l_hi * al_hi + sum_hi;

#pragma unroll
        for (int nt = 0; nt < 8; nt++) {
            acco[nt][0] *= al_lo; acco[nt][1] *= al_lo;
            acco[nt][2] *= al_hi; acco[nt][3] *= al_hi;
        }

#pragma unroll
        for (int nt = 0; nt < 8; nt++) {
            int c = nt * 8 + (tig << 1);
            uint2 w0; w0.x = f2tf32(accs[nt][0]); w0.y = f2tf32(accs[nt][1]);
            uint2 w1; w1.x = f2tf32(accs[nt][2]); w1.y = f2tf32(accs[nt][3]);
            *(uint2*)&Ps[mb + gid][c]     = w0;
            *(uint2*)&Ps[mb + gid + 8][c] = w1;
        }
        __syncwarp();

#pragma unroll
        for (int ks = 0; ks < 64; ks += 8) {
            uint32_t a[4];
            a[0] = Ps[mb + gid][ks + tig];     a[1] = Ps[mb + gid + 8][ks + tig];
            a[2] = Ps[mb + gid][ks + tig + 4]; a[3] = Ps[mb + gid + 8][ks + tig + 4];
#pragma unroll
            for (int nt = 0; nt < 8; nt++) {
                uint32_t bb[2];
                bb[0] = Vs[ks + tig][nt * 8 + gid];
                bb[1] = Vs[ks + tig + 4][nt * 8 + gid];
                mma8(acco[nt], a, bb);
            }
        }
    }

    const float inv_lo = 1.0f / l_lo, inv_hi = 1.0f / l_hi;
#pragma unroll
    for (int nt = 0; nt < 8; nt++) {
        int c = nt * 8 + (tig << 1);
        size_t r0 = (size_t)(i0 + mb + gid) * DDIM + c;
        size_t r1 = (size_t)(i0 + mb + gid + 8) * DDIM + c;
        split2(acco[nt][0] * inv_lo, acco[nt][1] * inv_lo,
               (__nv_bfloat162*)(Oh + r0), (__nv_bfloat162*)(Ol + r0));
        split2(acco[nt][2] * inv_hi, acco[nt][3] * inv_hi,
               (__nv_bfloat162*)(Oh + r1), (__nv_bfloat162*)(Ol + r1));
    }
}

// ---------------- add + LayerNorm (+ optional bf16 plane output) -------------
__global__ __launch_bounds__(256)
void add_ln(const float* __restrict__ x, const float* __restrict__ y,
            const float* __restrict__ g, const float* __restrict__ be,
            float* __restrict__ out, bf16* __restrict__ hi, bf16* __restrict__ lo) {
    __shared__ float sm[8];
    __shared__ float bc;
    const int tid = threadIdx.x;
    const size_t ro = (size_t)blockIdx.x * DDIM;
    float4 a = reinterpret_cast<const float4*>(x + ro)[tid];
    float4 b = reinterpret_cast<const float4*>(y + ro)[tid];
    a.x += b.x; a.y += b.y; a.z += b.z; a.w += b.w;

    float s = a.x + a.y + a.z + a.w;
#pragma unroll
    for (int o = 16; o; o >>= 1) s += __shfl_xor_sync(~0u, s, o);
    if ((tid & 31) == 0) sm[tid >> 5] = s;
    __syncthreads();
    if (tid < 32) {
        float t = (tid < 8) ? sm[tid] : 0.f;
#pragma unroll
        for (int o = 4; o; o >>= 1) t += __shfl_xor_sync(~0u, t, o);
        if (tid == 0) bc = t;
    }
    __syncthreads();
    const float mu = bc * (1.0f / DDIM);
    a.x -= mu; a.y -= mu; a.z -= mu; a.w -= mu;
    float qv = a.x*a.x + a.y*a.y + a.z*a.z + a.w*a.w;
    __syncthreads();
#pragma unroll
    for (int o = 16; o; o >>= 1) qv += __shfl_xor_sync(~0u, qv, o);
    if ((tid & 31) == 0) sm[tid >> 5] = qv;
    __syncthreads();
    if (tid < 32) {
        float t = (tid < 8) ? sm[tid] : 0.f;
#pragma unroll
        for (int o = 4; o; o >>= 1) t += __shfl_xor_sync(~0u, t, o);
        if (tid == 0) bc = t;
    }
    __syncthreads();
    const float rs = rsqrtf(bc * (1.0f / DDIM) + 1e-5f);
    float4 gv = reinterpret_cast<const float4*>(g)[tid];
    float4 bv = reinterpret_cast<const float4*>(be)[tid];
    float4 o;
    o.x = a.x * rs * gv.x + bv.x;
    o.y = a.y * rs * gv.y + bv.y;
    o.z = a.z * rs * gv.z + bv.z;
    o.w = a.w * rs * gv.w + bv.w;
    reinterpret_cast<float4*>(out + ro)[tid] = o;
    if (hi) {
        size_t i4 = ro + tid * 4;
        split2(o.x, o.y, (__nv_bfloat162*)(hi + i4),     (__nv_bfloat162*)(lo + i4));
        split2(o.z, o.w, (__nv_bfloat162*)(hi + i4 + 2), (__nv_bfloat162*)(lo + i4 + 2));
    }
}

// ---------------- launch ------------------------------------------------------
extern "C" void kernel_launch(void* const* d_in, const int* in_sizes, int n_in,
                              void* d_out, int out_size) {
    const int*   tokens = (const int*)  d_in[0];
    const float* emb    = (const float*)d_in[1];
    const float* Wq = (const float*)d_in[2],  *bq = (const float*)d_in[3];
    const float* Wk = (const float*)d_in[4],  *bk = (const float*)d_in[5];
    const float* Wv = (const float*)d_in[6],  *bv = (const float*)d_in[7];
    const float* Wo = (const float*)d_in[8],  *bo = (const float*)d_in[9];
    const float* W1 = (const float*)d_in[10], *b1 = (const float*)d_in[11];
    const float* W2 = (const float*)d_in[12], *b2 = (const float*)d_in[13];
    const float* gamma = (const float*)d_in[14], *beta = (const float*)d_in[15];
    float* out = (float*)d_out;

    float *x, *q, *k, *v, *t;
    cudaGetSymbolAddress((void**)&x,  g_x);
    cudaGetSymbolAddress((void**)&q,  g_q);
    cudaGetSymbolAddress((void**)&k,  g_k);
    cudaGetSymbolAddress((void**)&v,  g_v);
    cudaGetSymbolAddress((void**)&t,  g_t);
    bf16 *wqh,*wql,*wkh,*wkl,*wvh,*wvl,*woh,*wol,*w1h,*w1l,*w2h,*w2l,*ah,*al,*hh,*hl;
    cudaGetSymbolAddress((void**)&wqh, g_wqh); cudaGetSymbolAddress((void**)&wql, g_wql);
    cudaGetSymbolAddress((void**)&wkh, g_wkh); cudaGetSymbolAddress((void**)&wkl, g_wkl);
    cudaGetSymbolAddress((void**)&wvh, g_wvh); cudaGetSymbolAddress((void**)&wvl, g_wvl);
    cudaGetSymbolAddress((void**)&woh, g_woh); cudaGetSymbolAddress((void**)&wol, g_wol);
    cudaGetSymbolAddress((void**)&w1h, g_w1h); cudaGetSymbolAddress((void**)&w1l, g_w1l);
    cudaGetSymbolAddress((void**)&w2h, g_w2h); cudaGetSymbolAddress((void**)&w2l, g_w2l);
    cudaGetSymbolAddress((void**)&ah,  g_ah);  cudaGetSymbolAddress((void**)&al,  g_al);
    cudaGetSymbolAddress((void**)&hh,  g_hh);  cudaGetSymbolAddress((void**)&hl,  g_hl);

    cudaFuncSetAttribute(flash_attn, cudaFuncAttributeMaxDynamicSharedMemorySize,
                         FA_SMEM_BYTES);
    cudaFuncSetAttribute(gemm_bf16x3<false, false>,
                         cudaFuncAttributeMaxDynamicSharedMemorySize, GEMM_SMEM_BYTES);
    cudaFuncSetAttribute(gemm_bf16x3<true, true>,
                         cudaFuncAttributeMaxDynamicSharedMemorySize, GEMM_SMEM_BYTES);

    embed_pe<<<BSR * DDIM / 256, 256>>>(tokens, emb);
    split_a<<<BSR * DDIM / 1024, 256>>>(x, ah, al);

    // ---- weight conversion: transpose + bf16 hi/lo split -----------------------
    const dim3 gwp(DDIM / 32, DDIM / 32);
    const dim3 gw1(FFD  / 32, DDIM / 32);
    const dim3 gw2(DDIM / 32, FFD  / 32);
    for (int l = 0; l < LLAY; l++) {
        size_t od = (size_t)l * DDIM * DDIM, of = (size_t)l * DDIM * FFD;
        split_w_t<<<gwp, 256>>>(Wq + od, wqh + od, wql + od, DDIM, DDIM);
        split_w_t<<<gwp, 256>>>(Wk + od, wkh + od, wkl + od, DDIM, DDIM);
        split_w_t<<<gwp, 256>>>(Wv + od, wvh + od, wvl + od, DDIM, DDIM);
        split_w_t<<<gwp, 256>>>(Wo + od, woh + od, wol + od, DDIM, DDIM);
        split_w_t<<<gw1, 256>>>(W1 + of, w1h + of, w1l + of, DDIM, FFD);
        split_w_t<<<gw2, 256>>>(W2 + of, w2h + of, w2l + of, FFD, DDIM);
    }

    const dim3 gp(DDIM / 128, BSR / 128);
    const dim3 gf(FFD  / 128, BSR / 128);

    for (int l = 0; l < LLAY; l++) {
        size_t od = (size_t)l * DDIM * DDIM, of = (size_t)l * DDIM * FFD;
        const float* lbq = bq + (size_t)l * DDIM;
        const float* lbk = bk + (size_t)l * DDIM;
        const float* lbv = bv + (size_t)l * DDIM;
        const float* lbo = bo + (size_t)l * DDIM;
        const float* lb1 = b1 + (size_t)l * FFD;
        const float* lb2 = b2 + (size_t)l * DDIM;
        const float* lg  = gamma + (size_t)l * DDIM;
        const float* lbe = beta  + (size_t)l * DDIM;

        gemm_bf16x3<false, false><<<gp, 256, GEMM_SMEM_BYTES>>>(
            ah, al, wqh + od, wql + od, lbq, q, nullptr, nullptr, BSR, DDIM, DDIM);
        gemm_bf16x3<false, false><<<gp, 256, GEMM_SMEM_BYTES>>>(
            ah, al, wkh + od, wkl + od, lbk, k, nullptr, nullptr, BSR, DDIM, DDIM);
        gemm_bf16x3<false, false><<<gp, 256, GEMM_SMEM_BYTES>>>(
            ah, al, wvh + od, wvl + od, lbv, v, nullptr, nullptr, BSR, DDIM, DDIM);

        flash_attn<<<dim3(SS / 128, BB * HH), 256, FA_SMEM_BYTES>>>(q, k, v);

        gemm_bf16x3<false, false><<<gp, 256, GEMM_SMEM_BYTES>>>(
            ah, al, woh + od, wol + od, lbo, t, nullptr, nullptr, BSR, DDIM, DDIM);
        add_ln<<<BSR, 256>>>(x, t, lg, lbe, x, ah, al);

        gemm_bf16x3<true, true><<<gf, 256, GEMM_SMEM_BYTES>>>(
            ah, al, w1h + of, w1l + of, lb1, nullptr, hh, hl, BSR, FFD, DDIM);
        gemm_bf16x3<false, false><<<gp, 256, GEMM_SMEM_BYTES>>>(
            hh, hl, w2h + of, w2l + of, lb2, t, nullptr, nullptr, BSR, DDIM, FFD);

        float* xo = (l == LLAY - 1) ? out : x;
        bf16* nh = (l == LLAY - 1) ? nullptr : ah;
        bf16* nl = (l == LLAY - 1) ? nullptr : al;
        add_ln<<<BSR, 256>>>(x, t, lg, lbe, xo, nh, nl);
    }
}

// round 7
// speedup vs baseline: 2.6488x; 1.0770x over previous
#include <cuda_runtime.h>
#include <cuda_bf16.h>
#include <math.h>
#include <stdint.h>

// Problem constants
#define BB   2
#define SS   1024
#define DDIM 1024
#define HH   16
#define LLAY 4
#define FFD  2048
#define DKH  64
#define BSR  (BB*SS)   // 2048 rows

typedef __nv_bfloat16 bf16;

// ---------------- scratch (static device globals; no allocs allowed) ----------
__device__ float g_x [BSR*DDIM];
__device__ float g_q [BSR*DDIM];
__device__ float g_k [BSR*DDIM];
__device__ float g_v [BSR*DDIM];
__device__ float g_t [BSR*DDIM];

// bf16 hi/lo planes: weights transposed to [N][K]
__device__ __align__(256) bf16 g_wqh[LLAY*DDIM*DDIM], g_wql[LLAY*DDIM*DDIM];
__device__ __align__(256) bf16 g_wkh[LLAY*DDIM*DDIM], g_wkl[LLAY*DDIM*DDIM];
__device__ __align__(256) bf16 g_wvh[LLAY*DDIM*DDIM], g_wvl[LLAY*DDIM*DDIM];
__device__ __align__(256) bf16 g_woh[LLAY*DDIM*DDIM], g_wol[LLAY*DDIM*DDIM];
__device__ __align__(256) bf16 g_w1h[LLAY*DDIM*FFD],  g_w1l[LLAY*DDIM*FFD];
__device__ __align__(256) bf16 g_w2h[LLAY*FFD*DDIM],  g_w2l[LLAY*FFD*DDIM];
// activation planes
__device__ __align__(256) bf16 g_ah[BSR*DDIM], g_al[BSR*DDIM];
__device__ __align__(256) bf16 g_hh[BSR*FFD],  g_hl[BSR*FFD];

// ---------------- helpers -----------------------------------------------------
__device__ __forceinline__ void mma16(float* c, const uint32_t* a, const uint32_t* b) {
    asm volatile(
        "mma.sync.aligned.m16n8k16.row.col.f32.bf16.bf16.f32 "
        "{%0,%1,%2,%3}, {%4,%5,%6,%7}, {%8,%9}, {%0,%1,%2,%3};"
        : "+f"(c[0]), "+f"(c[1]), "+f"(c[2]), "+f"(c[3])
        : "r"(a[0]), "r"(a[1]), "r"(a[2]), "r"(a[3]), "r"(b[0]), "r"(b[1]));
}
__device__ __forceinline__ void cp16(uint32_t* s, const void* g) {
    uint32_t sa = (uint32_t)__cvta_generic_to_shared(s);
    asm volatile("cp.async.cg.shared.global [%0], [%1], 16;" :: "r"(sa), "l"(g));
}
#define CP_COMMIT() asm volatile("cp.async.commit_group;")
#define CP_WAIT1()  asm volatile("cp.async.wait_group 1;" ::: "memory")

__device__ __forceinline__ void split2(float v0, float v1, __nv_bfloat162* hi,
                                       __nv_bfloat162* lo) {
    bf16 h0 = __float2bfloat16_rn(v0), h1 = __float2bfloat16_rn(v1);
    __nv_bfloat162 hh; hh.x = h0; hh.y = h1;
    __nv_bfloat162 ll;
    ll.x = __float2bfloat16_rn(v0 - __bfloat162float(h0));
    ll.y = __float2bfloat16_rn(v1 - __bfloat162float(h1));
    *hi = hh; *lo = ll;
}
__device__ __forceinline__ uint32_t packbf(float a, float b) {
    __nv_bfloat162 p = __floats2bfloat162_rn(a, b);
    return *(uint32_t*)&p;
}

// ---------------- embedding + (buggy-faithful) positional encoding ------------
__global__ void embed_pe(const int* __restrict__ tok, const float* __restrict__ emb) {
    int idx = blockIdx.x * 256 + threadIdx.x;
    int d  = idx & (DDIM - 1);
    int bs = idx >> 10;
    int b  = bs >> 10;
    int t  = tok[bs];
    int i2 = (d >> 1) << 1;
    float div = expf(-(float)i2 * (9.210340371976184f / (float)DDIM));
    float ang = (float)b * div;
    float pe  = (d & 1) ? cosf(ang) : sinf(ang);
    g_x[idx] = emb[(size_t)t * DDIM + d] + pe;
}

// ---------------- activation hi/lo split (after embed only) -------------------
__global__ __launch_bounds__(256)
void split_a(const float* __restrict__ s, bf16* __restrict__ hi, bf16* __restrict__ lo) {
    int i4 = (blockIdx.x * 256 + threadIdx.x) * 4;
    float4 v = *(const float4*)(s + i4);
    split2(v.x, v.y, (__nv_bfloat162*)(hi + i4),     (__nv_bfloat162*)(lo + i4));
    split2(v.z, v.w, (__nv_bfloat162*)(hi + i4 + 2), (__nv_bfloat162*)(lo + i4 + 2));
}

// ---------------- weight transpose + hi/lo split, all layers (z) -------------
__global__ __launch_bounds__(256)
void split_w_t(const float* __restrict__ W0, bf16* __restrict__ th0,
               bf16* __restrict__ tl0, int K, int N) {
    const size_t lo = (size_t)blockIdx.z * K * N;
    const float* W = W0 + lo;
    bf16* th = th0 + lo;
    bf16* tl = tl0 + lo;
    __shared__ float tile[32][33];
    const int n0 = blockIdx.x * 32, k0 = blockIdx.y * 32;
    const int tx = threadIdx.x & 31, ty = threadIdx.x >> 5;
#pragma unroll
    for (int i = 0; i < 32; i += 8)
        tile[ty + i][tx] = W[(size_t)(k0 + ty + i) * N + n0 + tx];
    __syncthreads();
#pragma unroll
    for (int i = 0; i < 32; i += 8) {
        int n = n0 + ty + i, k = k0 + tx;
        float v = tile[tx][ty + i];
        bf16 h = __float2bfloat16_rn(v);
        th[(size_t)n * K + k] = h;
        tl[(size_t)n * K + k] = __float2bfloat16_rn(v - __bfloat162float(h));
    }
}

// ---------------- bf16x3 tensor-core GEMM, cp.async 2-stage pipeline ---------
// C = A[M,K] @ B[N,K]^T + bias.  BM=BN=128, BK=32, 256 thr (8 warps, 2x4).
// dyn smem: 4 planes x 2 stages x 128 rows x 20 words = 20480 words = 80KB.
#define GS_PLANE 5120      // words per plane (2 stages x 2560)
#define GS_STAGE 2560      // words per stage
#define GEMM_SMEM_BYTES (4 * GS_PLANE * 4)

__device__ __forceinline__ void gemm_copy_stage(
    uint32_t* sm, const bf16* __restrict__ Ah, const bf16* __restrict__ Al,
    const bf16* __restrict__ Bh, const bf16* __restrict__ Bl,
    int m0, int n0, int K, int k0, int s, int tid) {
#pragma unroll
    for (int e = 0; e < 2; e++) {
        int c = tid + e * 256;                  // 0..511
        int row = c >> 2, cw = (c & 3) << 2;    // word offset within row
        int kk  = k0 + ((c & 3) << 3);          // bf16 offset
        size_t ga = (size_t)(m0 + row) * K + kk;
        size_t gb = (size_t)(n0 + row) * K + kk;
        int so = s * GS_STAGE + row * 20 + cw;
        cp16(sm + 0 * GS_PLANE + so, Ah + ga);
        cp16(sm + 1 * GS_PLANE + so, Al + ga);
        cp16(sm + 2 * GS_PLANE + so, Bh + gb);
        cp16(sm + 3 * GS_PLANE + so, Bl + gb);
    }
}

template<bool RELU, bool PLANES>
__global__ __launch_bounds__(256, 2)
void gemm_bf16x3(const bf16* __restrict__ Ah, const bf16* __restrict__ Al,
                 const bf16* __restrict__ Bh, const bf16* __restrict__ Bl,
                 const float* __restrict__ bias, float* __restrict__ C,
                 bf16* __restrict__ Chi, bf16* __restrict__ Clo,
                 int M, int N, int K) {
    extern __shared__ uint32_t sm[];
    const int tid  = threadIdx.x;
    const int wid  = tid >> 5, lane = tid & 31;
    const int gid  = lane >> 2, tig = lane & 3;
    const int wm   = wid >> 2, wn = wid & 3;
    const int m0   = blockIdx.y * 128, n0 = blockIdx.x * 128;

    float acc[4][4][4];
#pragma unroll
    for (int mt = 0; mt < 4; mt++)
#pragma unroll
        for (int nt = 0; nt < 4; nt++)
#pragma unroll
            for (int i = 0; i < 4; i++) acc[mt][nt][i] = 0.f;

    // prologue: stages 0 and 1
    gemm_copy_stage(sm, Ah, Al, Bh, Bl, m0, n0, K, 0, 0, tid);
    CP_COMMIT();
    gemm_copy_stage(sm, Ah, Al, Bh, Bl, m0, n0, K, 32, 1, tid);
    CP_COMMIT();

    for (int k0 = 0; k0 < K; k0 += 32) {
        const int s = (k0 >> 5) & 1;
        CP_WAIT1();
        __syncthreads();

        const uint32_t* pAH = sm + 0 * GS_PLANE + s * GS_STAGE;
        const uint32_t* pAL = sm + 1 * GS_PLANE + s * GS_STAGE;
        const uint32_t* pBH = sm + 2 * GS_PLANE + s * GS_STAGE;
        const uint32_t* pBL = sm + 3 * GS_PLANE + s * GS_STAGE;
#pragma unroll
        for (int sb = 0; sb < 2; sb++) {
            const int kb = sb * 8;
            uint32_t ah[4][4], al[4][4], bh4[4][2], bl4[4][2];
#pragma unroll
            for (int mt = 0; mt < 4; mt++) {
                int m = wm * 64 + mt * 16 + gid;
                ah[mt][0] = pAH[m * 20 + kb + tig];       ah[mt][1] = pAH[(m + 8) * 20 + kb + tig];
                ah[mt][2] = pAH[m * 20 + kb + tig + 4];   ah[mt][3] = pAH[(m + 8) * 20 + kb + tig + 4];
                al[mt][0] = pAL[m * 20 + kb + tig];       al[mt][1] = pAL[(m + 8) * 20 + kb + tig];
                al[mt][2] = pAL[m * 20 + kb + tig + 4];   al[mt][3] = pAL[(m + 8) * 20 + kb + tig + 4];
            }
#pragma unroll
            for (int nt = 0; nt < 4; nt++) {
                int n = wn * 32 + nt * 8 + gid;
                bh4[nt][0] = pBH[n * 20 + kb + tig]; bh4[nt][1] = pBH[n * 20 + kb + tig + 4];
                bl4[nt][0] = pBL[n * 20 + kb + tig]; bl4[nt][1] = pBL[n * 20 + kb + tig + 4];
            }
#pragma unroll
            for (int mt = 0; mt < 4; mt++)
#pragma unroll
                for (int nt = 0; nt < 4; nt++) {
                    mma16(acc[mt][nt], al[mt], bh4[nt]);
                    mma16(acc[mt][nt], ah[mt], bl4[nt]);
                    mma16(acc[mt][nt], ah[mt], bh4[nt]);
                }
        }
        __syncthreads();
        if (k0 + 64 < K)
            gemm_copy_stage(sm, Ah, Al, Bh, Bl, m0, n0, K, k0 + 64, s, tid);
        CP_COMMIT();
    }

#pragma unroll
    for (int mt = 0; mt < 4; mt++) {
        int r0 = m0 + wm * 64 + mt * 16 + gid;
#pragma unroll
        for (int nt = 0; nt < 4; nt++) {
            int c = n0 + wn * 32 + nt * 8 + (tig << 1);
            float b0 = bias[c], b1 = bias[c + 1];
            float2 o0 = make_float2(acc[mt][nt][0] + b0, acc[mt][nt][1] + b1);
            float2 o1 = make_float2(acc[mt][nt][2] + b0, acc[mt][nt][3] + b1);
            if (RELU) {
                o0.x = fmaxf(o0.x, 0.f); o0.y = fmaxf(o0.y, 0.f);
                o1.x = fmaxf(o1.x, 0.f); o1.y = fmaxf(o1.y, 0.f);
            }
            if (PLANES) {
                split2(o0.x, o0.y, (__nv_bfloat162*)(Chi + (size_t)r0 * N + c),
                                   (__nv_bfloat162*)(Clo + (size_t)r0 * N + c));
                split2(o1.x, o1.y, (__nv_bfloat162*)(Chi + (size_t)(r0 + 8) * N + c),
                                   (__nv_bfloat162*)(Clo + (size_t)(r0 + 8) * N + c));
            } else {
                *(float2*)(C + (size_t)r0 * N + c)       = o0;
                *(float2*)(C + (size_t)(r0 + 8) * N + c) = o1;
            }
        }
    }
}

// ---------------- fused flash attention, bf16 mma16, P in registers ----------
// smem: Qs[128][36] @0, Ks[64][36] @4608, Vs(dim-major)[64][36] @6912
__global__ __launch_bounds__(256, 1)
void flash_attn(const float* __restrict__ q, const float* __restrict__ k,
                const float* __restrict__ v) {
    __shared__ uint32_t Qs[128][36];
    __shared__ uint32_t Ks[64][36];
    __shared__ uint32_t Vs[64][36];   // [dim][key-pair]

    const int z = blockIdx.y, b = z >> 4, h = z & 15;
    const int i0 = blockIdx.x * 128;
    const float* Qg = q + (size_t)b * SS * DDIM + h * DKH;
    const float* Kg = k + (size_t)b * SS * DDIM + h * DKH;
    const float* Vg = v + (size_t)b * SS * DDIM + h * DKH;
    bf16* Oh = g_ah + (size_t)b * SS * DDIM + h * DKH;
    bf16* Ol = g_al + (size_t)b * SS * DDIM + h * DKH;

    const int tid = threadIdx.x;
    const int wid = tid >> 5, lane = tid & 31;
    const int gid = lane >> 2, tig = lane & 3;
    const int mb  = wid * 16;

    // load Q tile -> bf16 (scaled by 1/8)
#pragma unroll
    for (int e = 0; e < 8; e++) {
        int idx = tid + e * 256;               // 2048 float4
        int row = idx >> 4, c4 = (idx & 15) << 2;
        float4 vq = *(const float4*)(Qg + (size_t)(i0 + row) * DDIM + c4);
        Qs[row][c4 >> 1]       = packbf(vq.x * 0.125f, vq.y * 0.125f);
        Qs[row][(c4 >> 1) + 1] = packbf(vq.z * 0.125f, vq.w * 0.125f);
    }

    float acco[8][4];
#pragma unroll
    for (int nt = 0; nt < 8; nt++)
#pragma unroll
        for (int i = 0; i < 4; i++) acco[nt][i] = 0.f;
    float m_lo = -1e30f, m_hi = -1e30f, l_lo = 0.f, l_hi = 0.f;

    for (int j0 = 0; j0 < SS; j0 += 64) {
        __syncthreads();   // previous tile's Ks/Vs reads done (and Q store, iter 0)
#pragma unroll
        for (int e = 0; e < 4; e++) {
            int idx = tid + e * 256;           // 1024 float4
            int row = idx >> 4, c4 = (idx & 15) << 2;
            float4 kk = *(const float4*)(Kg + (size_t)(j0 + row) * DDIM + c4);
            float4 vv = *(const float4*)(Vg + (size_t)(j0 + row) * DDIM + c4);
            Ks[row][c4 >> 1]       = packbf(kk.x, kk.y);
            Ks[row][(c4 >> 1) + 1] = packbf(kk.z, kk.w);
            // V transposed: Vs[dim][key]  (halfword stores)
            ((bf16*)&Vs[c4 + 0][0])[row] = __float2bfloat16_rn(vv.x);
            ((bf16*)&Vs[c4 + 1][0])[row] = __float2bfloat16_rn(vv.y);
            ((bf16*)&Vs[c4 + 2][0])[row] = __float2bfloat16_rn(vv.z);
            ((bf16*)&Vs[c4 + 3][0])[row] = __float2bfloat16_rn(vv.w);
        }
        __syncthreads();

        // S = Q_tile @ K_tile^T  (warp: 16 x 64, bf16 k16)
        float accs[8][4];
#pragma unroll
        for (int nt = 0; nt < 8; nt++)
#pragma unroll
            for (int i = 0; i < 4; i++) accs[nt][i] = 0.f;
#pragma unroll
        for (int ks = 0; ks < 64; ks += 16) {
            const int w = ks >> 1;
            uint32_t a[4];
            a[0] = Qs[mb + gid][w + tig];     a[1] = Qs[mb + gid + 8][w + tig];
            a[2] = Qs[mb + gid][w + tig + 4]; a[3] = Qs[mb + gid + 8][w + tig + 4];
#pragma unroll
            for (int nt = 0; nt < 8; nt++) {
                uint32_t bb[2];
                bb[0] = Ks[nt * 8 + gid][w + tig];
                bb[1] = Ks[nt * 8 + gid][w + tig + 4];
                mma16(accs[nt], a, bb);
            }
        }

        // online softmax update (accs cols: nt*8 + 2*tig, +1; rows gid / gid+8)
        float mx_lo = -1e30f, mx_hi = -1e30f;
#pragma unroll
        for (int nt = 0; nt < 8; nt++) {
            mx_lo = fmaxf(mx_lo, fmaxf(accs[nt][0], accs[nt][1]));
            mx_hi = fmaxf(mx_hi, fmaxf(accs[nt][2], accs[nt][3]));
        }
        mx_lo = fmaxf(mx_lo, __shfl_xor_sync(~0u, mx_lo, 1));
        mx_lo = fmaxf(mx_lo, __shfl_xor_sync(~0u, mx_lo, 2));
        mx_hi = fmaxf(mx_hi, __shfl_xor_sync(~0u, mx_hi, 1));
        mx_hi = fmaxf(mx_hi, __shfl_xor_sync(~0u, mx_hi, 2));
        float mn_lo = fmaxf(m_lo, mx_lo), mn_hi = fmaxf(m_hi, mx_hi);
        float al_lo = __expf(m_lo - mn_lo), al_hi = __expf(m_hi - mn_hi);
        m_lo = mn_lo; m_hi = mn_hi;

        float sum_lo = 0.f, sum_hi = 0.f;
#pragma unroll
        for (int nt = 0; nt < 8; nt++) {
            accs[nt][0] = __expf(accs[nt][0] - m_lo);
            accs[nt][1] = __expf(accs[nt][1] - m_lo);
            accs[nt][2] = __expf(accs[nt][2] - m_hi);
            accs[nt][3] = __expf(accs[nt][3] - m_hi);
            sum_lo += accs[nt][0] + accs[nt][1];
            sum_hi += accs[nt][2] + accs[nt][3];
        }
        sum_lo += __shfl_xor_sync(~0u, sum_lo, 1);
        sum_lo += __shfl_xor_sync(~0u, sum_lo, 2);
        sum_hi += __shfl_xor_sync(~0u, sum_hi, 1);
        sum_hi += __shfl_xor_sync(~0u, sum_hi, 2);
        l_lo = l_lo * al_lo + sum_lo;
        l_hi = l_hi * al_hi + sum_hi;

#pragma unroll
        for (int nt = 0; nt < 8; nt++) {
            acco[nt][0] *= al_lo; acco[nt][1] *= al_lo;
            acco[nt][2] *= al_hi; acco[nt][3] *= al_hi;
        }

        // O += P @ V_tile : P packed from registers (A-frag == C-frag layout)
#pragma unroll
        for (int s = 0; s < 4; s++) {
            uint32_t a[4];
            a[0] = packbf(accs[2*s][0],     accs[2*s][1]);
            a[1] = packbf(accs[2*s][2],     accs[2*s][3]);
            a[2] = packbf(accs[2*s + 1][0], accs[2*s + 1][1]);
            a[3] = packbf(accs[2*s + 1][2], accs[2*s + 1][3]);
#pragma unroll
            for (int nt = 0; nt < 8; nt++) {
                uint32_t bb[2];
                bb[0] = Vs[nt * 8 + gid][s * 8 + tig];
                bb[1] = Vs[nt * 8 + gid][s * 8 + tig + 4];
                mma16(acco[nt], a, bb);
            }
        }
    }

    const float inv_lo = 1.0f / l_lo, inv_hi = 1.0f / l_hi;
#pragma unroll
    for (int nt = 0; nt < 8; nt++) {
        int c = nt * 8 + (tig << 1);
        size_t r0 = (size_t)(i0 + mb + gid) * DDIM + c;
        size_t r1 = (size_t)(i0 + mb + gid + 8) * DDIM + c;
        split2(acco[nt][0] * inv_lo, acco[nt][1] * inv_lo,
               (__nv_bfloat162*)(Oh + r0), (__nv_bfloat162*)(Ol + r0));
        split2(acco[nt][2] * inv_hi, acco[nt][3] * inv_hi,
               (__nv_bfloat162*)(Oh + r1), (__nv_bfloat162*)(Ol + r1));
    }
}

// ---------------- add + LayerNorm (+ optional bf16 plane output) -------------
__global__ __launch_bounds__(256)
void add_ln(const float* __restrict__ x, const float* __restrict__ y,
            const float* __restrict__ g, const float* __restrict__ be,
            float* __restrict__ out, bf16* __restrict__ hi, bf16* __restrict__ lo) {
    __shared__ float sm[8];
    __shared__ float bc;
    const int tid = threadIdx.x;
    const size_t ro = (size_t)blockIdx.x * DDIM;
    float4 a = reinterpret_cast<const float4*>(x + ro)[tid];
    float4 b = reinterpret_cast<const float4*>(y + ro)[tid];
    a.x += b.x; a.y += b.y; a.z += b.z; a.w += b.w;

    float s = a.x + a.y + a.z + a.w;
#pragma unroll
    for (int o = 16; o; o >>= 1) s += __shfl_xor_sync(~0u, s, o);
    if ((tid & 31) == 0) sm[tid >> 5] = s;
    __syncthreads();
    if (tid < 32) {
        float t = (tid < 8) ? sm[tid] : 0.f;
#pragma unroll
        for (int o = 4; o; o >>= 1) t += __shfl_xor_sync(~0u, t, o);
        if (tid == 0) bc = t;
    }
    __syncthreads();
    const float mu = bc * (1.0f / DDIM);
    a.x -= mu; a.y -= mu; a.z -= mu; a.w -= mu;
    float qv = a.x*a.x + a.y*a.y + a.z*a.z + a.w*a.w;
    __syncthreads();
#pragma unroll
    for (int o = 16; o; o >>= 1) qv += __shfl_xor_sync(~0u, qv, o);
    if ((tid & 31) == 0) sm[tid >> 5] = qv;
    __syncthreads();
    if (tid < 32) {
        float t = (tid < 8) ? sm[tid] : 0.f;
#pragma unroll
        for (int o = 4; o; o >>= 1) t += __shfl_xor_sync(~0u, t, o);
        if (tid == 0) bc = t;
    }
    __syncthreads();
    const float rs = rsqrtf(bc * (1.0f / DDIM) + 1e-5f);
    float4 gv = reinterpret_cast<const float4*>(g)[tid];
    float4 bv = reinterpret_cast<const float4*>(be)[tid];
    float4 o;
    o.x = a.x * rs * gv.x + bv.x;
    o.y = a.y * rs * gv.y + bv.y;
    o.z = a.z * rs * gv.z + bv.z;
    o.w = a.w * rs * gv.w + bv.w;
    reinterpret_cast<float4*>(out + ro)[tid] = o;
    if (hi) {
        size_t i4 = ro + tid * 4;
        split2(o.x, o.y, (__nv_bfloat162*)(hi + i4),     (__nv_bfloat162*)(lo + i4));
        split2(o.z, o.w, (__nv_bfloat162*)(hi + i4 + 2), (__nv_bfloat162*)(lo + i4 + 2));
    }
}

// ---------------- launch ------------------------------------------------------
extern "C" void kernel_launch(void* const* d_in, const int* in_sizes, int n_in,
                              void* d_out, int out_size) {
    const int*   tokens = (const int*)  d_in[0];
    const float* emb    = (const float*)d_in[1];
    const float* Wq = (const float*)d_in[2],  *bq = (const float*)d_in[3];
    const float* Wk = (const float*)d_in[4],  *bk = (const float*)d_in[5];
    const float* Wv = (const float*)d_in[6],  *bv = (const float*)d_in[7];
    const float* Wo = (const float*)d_in[8],  *bo = (const float*)d_in[9];
    const float* W1 = (const float*)d_in[10], *b1 = (const float*)d_in[11];
    const float* W2 = (const float*)d_in[12], *b2 = (const float*)d_in[13];
    const float* gamma = (const float*)d_in[14], *beta = (const float*)d_in[15];
    float* out = (float*)d_out;

    float *x, *q, *k, *v, *t;
    cudaGetSymbolAddress((void**)&x,  g_x);
    cudaGetSymbolAddress((void**)&q,  g_q);
    cudaGetSymbolAddress((void**)&k,  g_k);
    cudaGetSymbolAddress((void**)&v,  g_v);
    cudaGetSymbolAddress((void**)&t,  g_t);
    bf16 *wqh,*wql,*wkh,*wkl,*wvh,*wvl,*woh,*wol,*w1h,*w1l,*w2h,*w2l,*ah,*al,*hh,*hl;
    cudaGetSymbolAddress((void**)&wqh, g_wqh); cudaGetSymbolAddress((void**)&wql, g_wql);
    cudaGetSymbolAddress((void**)&wkh, g_wkh); cudaGetSymbolAddress((void**)&wkl, g_wkl);
    cudaGetSymbolAddress((void**)&wvh, g_wvh); cudaGetSymbolAddress((void**)&wvl, g_wvl);
    cudaGetSymbolAddress((void**)&woh, g_woh); cudaGetSymbolAddress((void**)&wol, g_wol);
    cudaGetSymbolAddress((void**)&w1h, g_w1h); cudaGetSymbolAddress((void**)&w1l, g_w1l);
    cudaGetSymbolAddress((void**)&w2h, g_w2h); cudaGetSymbolAddress((void**)&w2l, g_w2l);
    cudaGetSymbolAddress((void**)&ah,  g_ah);  cudaGetSymbolAddress((void**)&al,  g_al);
    cudaGetSymbolAddress((void**)&hh,  g_hh);  cudaGetSymbolAddress((void**)&hl,  g_hl);

    cudaFuncSetAttribute(gemm_bf16x3<false, false>,
                         cudaFuncAttributeMaxDynamicSharedMemorySize, GEMM_SMEM_BYTES);
    cudaFuncSetAttribute(gemm_bf16x3<true, true>,
                         cudaFuncAttributeMaxDynamicSharedMemorySize, GEMM_SMEM_BYTES);

    embed_pe<<<BSR * DDIM / 256, 256>>>(tokens, emb);
    split_a<<<BSR * DDIM / 1024, 256>>>(x, ah, al);

    // weight conversion: transpose + hi/lo split, all layers per launch
    split_w_t<<<dim3(DDIM / 32, DDIM / 32, LLAY), 256>>>(Wq, wqh, wql, DDIM, DDIM);
    split_w_t<<<dim3(DDIM / 32, DDIM / 32, LLAY), 256>>>(Wk, wkh, wkl, DDIM, DDIM);
    split_w_t<<<dim3(DDIM / 32, DDIM / 32, LLAY), 256>>>(Wv, wvh, wvl, DDIM, DDIM);
    split_w_t<<<dim3(DDIM / 32, DDIM / 32, LLAY), 256>>>(Wo, woh, wol, DDIM, DDIM);
    split_w_t<<<dim3(FFD  / 32, DDIM / 32, LLAY), 256>>>(W1, w1h, w1l, DDIM, FFD);
    split_w_t<<<dim3(DDIM / 32, FFD  / 32, LLAY), 256>>>(W2, w2h, w2l, FFD, DDIM);

    const dim3 gp(DDIM / 128, BSR / 128);
    const dim3 gf(FFD  / 128, BSR / 128);

    for (int l = 0; l < LLAY; l++) {
        size_t od = (size_t)l * DDIM * DDIM, of = (size_t)l * DDIM * FFD;
        const float* lbq = bq + (size_t)l * DDIM;
        const float* lbk = bk + (size_t)l * DDIM;
        const float* lbv = bv + (size_t)l * DDIM;
        const float* lbo = bo + (size_t)l * DDIM;
        const float* lb1 = b1 + (size_t)l * FFD;
        const float* lb2 = b2 + (size_t)l * DDIM;
        const float* lg  = gamma + (size_t)l * DDIM;
        const float* lbe = beta  + (size_t)l * DDIM;

        gemm_bf16x3<false, false><<<gp, 256, GEMM_SMEM_BYTES>>>(
            ah, al, wqh + od, wql + od, lbq, q, nullptr, nullptr, BSR, DDIM, DDIM);
        gemm_bf16x3<false, false><<<gp, 256, GEMM_SMEM_BYTES>>>(
            ah, al, wkh + od, wkl + od, lbk, k, nullptr, nullptr, BSR, DDIM, DDIM);
        gemm_bf16x3<false, false><<<gp, 256, GEMM_SMEM_BYTES>>>(
            ah, al, wvh + od, wvl + od, lbv, v, nullptr, nullptr, BSR, DDIM, DDIM);

        flash_attn<<<dim3(SS / 128, BB * HH), 256>>>(q, k, v);

        gemm_bf16x3<false, false><<<gp, 256, GEMM_SMEM_BYTES>>>(
            ah, al, woh + od, wol + od, lbo, t, nullptr, nullptr, BSR, DDIM, DDIM);
        add_ln<<<BSR, 256>>>(x, t, lg, lbe, x, ah, al);

        gemm_bf16x3<true, true><<<gf, 256, GEMM_SMEM_BYTES>>>(
            ah, al, w1h + of, w1l + of, lb1, nullptr, hh, hl, BSR, FFD, DDIM);
        gemm_bf16x3<false, false><<<gp, 256, GEMM_SMEM_BYTES>>>(
            hh, hl, w2h + of, w2l + of, lb2, t, nullptr, nullptr, BSR, DDIM, FFD);

        float* xo = (l == LLAY - 1) ? out : x;
        bf16* nh = (l == LLAY - 1) ? nullptr : ah;
        bf16* nl = (l == LLAY - 1) ? nullptr : al;
        add_ln<<<BSR, 256>>>(x, t, lg, lbe, xo, nh, nl);
    }
}

// round 9
// speedup vs baseline: 2.9965x; 1.1313x over previous
#include <cuda_runtime.h>
#include <cuda_bf16.h>
#include <math.h>
#include <stdint.h>

// Problem constants
#define BB   2
#define SS   1024
#define DDIM 1024
#define HH   16
#define LLAY 4
#define FFD  2048
#define DKH  64
#define BSR  (BB*SS)   // 2048 rows
#define QD   (3*DDIM)  // fused QKV width

typedef __nv_bfloat16 bf16;

// ---------------- scratch (static device globals; no allocs allowed) ----------
__device__ float g_x  [BSR*DDIM];
__device__ float g_t  [BSR*DDIM];
__device__ float g_qkv[BSR*QD];

// bf16 weight planes, transposed to [N][K]
__device__ __align__(256) bf16 g_wqkvh[LLAY*3*DDIM*DDIM], g_wqkvl[LLAY*3*DDIM*DDIM];
__device__ __align__(256) bf16 g_woh[LLAY*DDIM*DDIM], g_wol[LLAY*DDIM*DDIM];
__device__ __align__(256) bf16 g_w1h[LLAY*DDIM*FFD],  g_w1l[LLAY*DDIM*FFD];
__device__ __align__(256) bf16 g_w2h[LLAY*FFD*DDIM],  g_w2l[LLAY*FFD*DDIM];
__device__ float g_bqkv[LLAY*QD];
// activation planes
__device__ __align__(256) bf16 g_ah[BSR*DDIM], g_al[BSR*DDIM];
__device__ __align__(256) bf16 g_hh[BSR*FFD],  g_hl[BSR*FFD];

// ---------------- helpers -----------------------------------------------------
__device__ __forceinline__ void mma16(float* c, const uint32_t* a, const uint32_t* b) {
    asm volatile(
        "mma.sync.aligned.m16n8k16.row.col.f32.bf16.bf16.f32 "
        "{%0,%1,%2,%3}, {%4,%5,%6,%7}, {%8,%9}, {%0,%1,%2,%3};"
        : "+f"(c[0]), "+f"(c[1]), "+f"(c[2]), "+f"(c[3])
        : "r"(a[0]), "r"(a[1]), "r"(a[2]), "r"(a[3]), "r"(b[0]), "r"(b[1]));
}
__device__ __forceinline__ void cp16(uint32_t* s, const void* g) {
    uint32_t sa = (uint32_t)__cvta_generic_to_shared(s);
    asm volatile("cp.async.cg.shared.global [%0], [%1], 16;" :: "r"(sa), "l"(g));
}
#define CP_COMMIT() asm volatile("cp.async.commit_group;")
#define CP_WAIT1()  asm volatile("cp.async.wait_group 1;" ::: "memory")

__device__ __forceinline__ void split2(float v0, float v1, __nv_bfloat162* hi,
                                       __nv_bfloat162* lo) {
    bf16 h0 = __float2bfloat16_rn(v0), h1 = __float2bfloat16_rn(v1);
    __nv_bfloat162 hh; hh.x = h0; hh.y = h1;
    __nv_bfloat162 ll;
    ll.x = __float2bfloat16_rn(v0 - __bfloat162float(h0));
    ll.y = __float2bfloat16_rn(v1 - __bfloat162float(h1));
    *hi = hh; *lo = ll;
}
__device__ __forceinline__ uint32_t packbf(float a, float b) {
    __nv_bfloat162 p = __floats2bfloat162_rn(a, b);
    return *(uint32_t*)&p;
}

// ---------------- embedding + (buggy-faithful) positional encoding ------------
__global__ void embed_pe(const int* __restrict__ tok, const float* __restrict__ emb) {
    int idx = blockIdx.x * 256 + threadIdx.x;
    int d  = idx & (DDIM - 1);
    int bs = idx >> 10;
    int b  = bs >> 10;
    int t  = tok[bs];
    int i2 = (d >> 1) << 1;
    float div = expf(-(float)i2 * (9.210340371976184f / (float)DDIM));
    float ang = (float)b * div;
    float pe  = (d & 1) ? cosf(ang) : sinf(ang);
    g_x[idx] = emb[(size_t)t * DDIM + d] + pe;
}

// ---------------- activation hi/lo split (after embed only) -------------------
__global__ __launch_bounds__(256)
void split_a(const float* __restrict__ s, bf16* __restrict__ hi, bf16* __restrict__ lo) {
    int i4 = (blockIdx.x * 256 + threadIdx.x) * 4;
    float4 v = *(const float4*)(s + i4);
    split2(v.x, v.y, (__nv_bfloat162*)(hi + i4),     (__nv_bfloat162*)(lo + i4));
    split2(v.z, v.w, (__nv_bfloat162*)(hi + i4 + 2), (__nv_bfloat162*)(lo + i4 + 2));
}

// ---------------- weight transpose + hi/lo split, all layers (z) -------------
__global__ __launch_bounds__(256)
void split_w_t(const float* __restrict__ W0, bf16* __restrict__ th0,
               bf16* __restrict__ tl0, int K, int N, size_t ostride) {
    const size_t li = (size_t)blockIdx.z * K * N;
    const size_t lo = (size_t)blockIdx.z * ostride;
    const float* W = W0 + li;
    bf16* th = th0 + lo;
    bf16* tl = tl0 + lo;
    __shared__ float tile[32][33];
    const int n0 = blockIdx.x * 32, k0 = blockIdx.y * 32;
    const int tx = threadIdx.x & 31, ty = threadIdx.x >> 5;
#pragma unroll
    for (int i = 0; i < 32; i += 8)
        tile[ty + i][tx] = W[(size_t)(k0 + ty + i) * N + n0 + tx];
    __syncthreads();
#pragma unroll
    for (int i = 0; i < 32; i += 8) {
        int n = n0 + ty + i, k = k0 + tx;
        float v = tile[tx][ty + i];
        bf16 h = __float2bfloat16_rn(v);
        th[(size_t)n * K + k] = h;
        tl[(size_t)n * K + k] = __float2bfloat16_rn(v - __bfloat162float(h));
    }
}

// ---------------- pack QKV biases ---------------------------------------------
__global__ void pack_bias(const float* __restrict__ bq, const float* __restrict__ bk,
                          const float* __restrict__ bv) {
    int l = blockIdx.y;
    int i = blockIdx.x * 256 + threadIdx.x;
    float v = (i < DDIM) ? bq[l * DDIM + i]
            : (i < 2 * DDIM) ? bk[l * DDIM + i - DDIM]
            : bv[l * DDIM + i - 2 * DDIM];
    g_bqkv[l * QD + i] = v;
}

// ---------------- bf16x3 tensor-core GEMM, cp.async 2-stage pipeline ---------
#define GS_PLANE 5120
#define GS_STAGE 2560
#define GEMM_SMEM_BYTES (4 * GS_PLANE * 4)

__device__ __forceinline__ void gemm_copy_stage(
    uint32_t* sm, const bf16* __restrict__ Ah, const bf16* __restrict__ Al,
    const bf16* __restrict__ Bh, const bf16* __restrict__ Bl,
    int m0, int n0, int K, int k0, int s, int tid) {
#pragma unroll
    for (int e = 0; e < 2; e++) {
        int c = tid + e * 256;
        int row = c >> 2, cw = (c & 3) << 2;
        int kk  = k0 + ((c & 3) << 3);
        size_t ga = (size_t)(m0 + row) * K + kk;
        size_t gb = (size_t)(n0 + row) * K + kk;
        int so = s * GS_STAGE + row * 20 + cw;
        cp16(sm + 0 * GS_PLANE + so, Ah + ga);
        cp16(sm + 1 * GS_PLANE + so, Al + ga);
        cp16(sm + 2 * GS_PLANE + so, Bh + gb);
        cp16(sm + 3 * GS_PLANE + so, Bl + gb);
    }
}

template<bool RELU, bool PLANES>
__global__ __launch_bounds__(256, 2)
void gemm_bf16x3(const bf16* __restrict__ Ah, const bf16* __restrict__ Al,
                 const bf16* __restrict__ Bh, const bf16* __restrict__ Bl,
                 const float* __restrict__ bias, float* __restrict__ C,
                 bf16* __restrict__ Chi, bf16* __restrict__ Clo,
                 int M, int N, int K) {
    extern __shared__ uint32_t sm[];
    const int tid  = threadIdx.x;
    const int wid  = tid >> 5, lane = tid & 31;
    const int gid  = lane >> 2, tig = lane & 3;
    const int wm   = wid >> 2, wn = wid & 3;
    const int m0   = blockIdx.y * 128, n0 = blockIdx.x * 128;

    float acc[4][4][4];
#pragma unroll
    for (int mt = 0; mt < 4; mt++)
#pragma unroll
        for (int nt = 0; nt < 4; nt++)
#pragma unroll
            for (int i = 0; i < 4; i++) acc[mt][nt][i] = 0.f;

    gemm_copy_stage(sm, Ah, Al, Bh, Bl, m0, n0, K, 0, 0, tid);
    CP_COMMIT();
    gemm_copy_stage(sm, Ah, Al, Bh, Bl, m0, n0, K, 32, 1, tid);
    CP_COMMIT();

    for (int k0 = 0; k0 < K; k0 += 32) {
        const int s = (k0 >> 5) & 1;
        CP_WAIT1();
        __syncthreads();

        const uint32_t* pAH = sm + 0 * GS_PLANE + s * GS_STAGE;
        const uint32_t* pAL = sm + 1 * GS_PLANE + s * GS_STAGE;
        const uint32_t* pBH = sm + 2 * GS_PLANE + s * GS_STAGE;
        const uint32_t* pBL = sm + 3 * GS_PLANE + s * GS_STAGE;
#pragma unroll
        for (int sb = 0; sb < 2; sb++) {
            const int kb = sb * 8;
            uint32_t ah[4][4], al[4][4], bh4[4][2], bl4[4][2];
#pragma unroll
            for (int mt = 0; mt < 4; mt++) {
                int m = wm * 64 + mt * 16 + gid;
                ah[mt][0] = pAH[m * 20 + kb + tig];       ah[mt][1] = pAH[(m + 8) * 20 + kb + tig];
                ah[mt][2] = pAH[m * 20 + kb + tig + 4];   ah[mt][3] = pAH[(m + 8) * 20 + kb + tig + 4];
                al[mt][0] = pAL[m * 20 + kb + tig];       al[mt][1] = pAL[(m + 8) * 20 + kb + tig];
                al[mt][2] = pAL[m * 20 + kb + tig + 4];   al[mt][3] = pAL[(m + 8) * 20 + kb + tig + 4];
            }
#pragma unroll
            for (int nt = 0; nt < 4; nt++) {
                int n = wn * 32 + nt * 8 + gid;
                bh4[nt][0] = pBH[n * 20 + kb + tig]; bh4[nt][1] = pBH[n * 20 + kb + tig + 4];
                bl4[nt][0] = pBL[n * 20 + kb + tig]; bl4[nt][1] = pBL[n * 20 + kb + tig + 4];
            }
#pragma unroll
            for (int mt = 0; mt < 4; mt++)
#pragma unroll
                for (int nt = 0; nt < 4; nt++) {
                    mma16(acc[mt][nt], al[mt], bh4[nt]);
                    mma16(acc[mt][nt], ah[mt], bl4[nt]);
                    mma16(acc[mt][nt], ah[mt], bh4[nt]);
                }
        }
        __syncthreads();
        if (k0 + 64 < K)
            gemm_copy_stage(sm, Ah, Al, Bh, Bl, m0, n0, K, k0 + 64, s, tid);
        CP_COMMIT();
    }

#pragma unroll
    for (int mt = 0; mt < 4; mt++) {
        int r0 = m0 + wm * 64 + mt * 16 + gid;
#pragma unroll
        for (int nt = 0; nt < 4; nt++) {
            int c = n0 + wn * 32 + nt * 8 + (tig << 1);
            float b0 = bias[c], b1 = bias[c + 1];
            float2 o0 = make_float2(acc[mt][nt][0] + b0, acc[mt][nt][1] + b1);
            float2 o1 = make_float2(acc[mt][nt][2] + b0, acc[mt][nt][3] + b1);
            if (RELU) {
                o0.x = fmaxf(o0.x, 0.f); o0.y = fmaxf(o0.y, 0.f);
                o1.x = fmaxf(o1.x, 0.f); o1.y = fmaxf(o1.y, 0.f);
            }
            if (PLANES) {
                split2(o0.x, o0.y, (__nv_bfloat162*)(Chi + (size_t)r0 * N + c),
                                   (__nv_bfloat162*)(Clo + (size_t)r0 * N + c));
                split2(o1.x, o1.y, (__nv_bfloat162*)(Chi + (size_t)(r0 + 8) * N + c),
                                   (__nv_bfloat162*)(Clo + (size_t)(r0 + 8) * N + c));
            } else {
                *(float2*)(C + (size_t)r0 * N + c)       = o0;
                *(float2*)(C + (size_t)(r0 + 8) * N + c) = o1;
            }
        }
    }
}

// ---------------- bf16 2-pass GEMM (QKV): C = Ah @ (Bh+Bl)^T + bias ----------
// weight quantization corrected (coherent error); activation lo dropped
// (per-token-independent error, attenuated by softmax averaging).
#define G2_PLANE 5120
#define G2_STAGE 2560
#define G2_SMEM  (3 * G2_PLANE * 4)   // 60 KB

__device__ __forceinline__ void g2_copy_stage(
    uint32_t* sm, const bf16* __restrict__ Ah, const bf16* __restrict__ Bh,
    const bf16* __restrict__ Bl, int m0, int n0, int K, int k0, int s, int tid) {
#pragma unroll
    for (int e = 0; e < 2; e++) {
        int c = tid + e * 256;
        int row = c >> 2, cw = (c & 3) << 2;
        int kk  = k0 + ((c & 3) << 3);
        size_t gb = (size_t)(n0 + row) * K + kk;
        int so = s * G2_STAGE + row * 20 + cw;
        cp16(sm + 0 * G2_PLANE + so, Ah + (size_t)(m0 + row) * K + kk);
        cp16(sm + 1 * G2_PLANE + so, Bh + gb);
        cp16(sm + 2 * G2_PLANE + so, Bl + gb);
    }
}

__global__ __launch_bounds__(256, 2)
void gemm_bf16x2(const bf16* __restrict__ Ah, const bf16* __restrict__ Bh,
                 const bf16* __restrict__ Bl, const float* __restrict__ bias,
                 float* __restrict__ C, int M, int N, int K) {
    extern __shared__ uint32_t sm[];
    const int tid  = threadIdx.x;
    const int wid  = tid >> 5, lane = tid & 31;
    const int gid  = lane >> 2, tig = lane & 3;
    const int wm   = wid >> 2, wn = wid & 3;
    const int m0   = blockIdx.y * 128, n0 = blockIdx.x * 128;

    float acc[4][4][4];
#pragma unroll
    for (int mt = 0; mt < 4; mt++)
#pragma unroll
        for (int nt = 0; nt < 4; nt++)
#pragma unroll
            for (int i = 0; i < 4; i++) acc[mt][nt][i] = 0.f;

    g2_copy_stage(sm, Ah, Bh, Bl, m0, n0, K, 0, 0, tid);
    CP_COMMIT();
    g2_copy_stage(sm, Ah, Bh, Bl, m0, n0, K, 32, 1, tid);
    CP_COMMIT();

    for (int k0 = 0; k0 < K; k0 += 32) {
        const int s = (k0 >> 5) & 1;
        CP_WAIT1();
        __syncthreads();

        const uint32_t* pA  = sm + 0 * G2_PLANE + s * G2_STAGE;
        const uint32_t* pBH = sm + 1 * G2_PLANE + s * G2_STAGE;
        const uint32_t* pBL = sm + 2 * G2_PLANE + s * G2_STAGE;
#pragma unroll
        for (int sb = 0; sb < 2; sb++) {
            const int kb = sb * 8;
            uint32_t a4[4][4], bh4[4][2], bl4[4][2];
#pragma unroll
            for (int mt = 0; mt < 4; mt++) {
                int m = wm * 64 + mt * 16 + gid;
                a4[mt][0] = pA[m * 20 + kb + tig];       a4[mt][1] = pA[(m + 8) * 20 + kb + tig];
                a4[mt][2] = pA[m * 20 + kb + tig + 4];   a4[mt][3] = pA[(m + 8) * 20 + kb + tig + 4];
            }
#pragma unroll
            for (int nt = 0; nt < 4; nt++) {
                int n = wn * 32 + nt * 8 + gid;
                bh4[nt][0] = pBH[n * 20 + kb + tig]; bh4[nt][1] = pBH[n * 20 + kb + tig + 4];
                bl4[nt][0] = pBL[n * 20 + kb + tig]; bl4[nt][1] = pBL[n * 20 + kb + tig + 4];
            }
#pragma unroll
            for (int mt = 0; mt < 4; mt++)
#pragma unroll
                for (int nt = 0; nt < 4; nt++) {
                    mma16(acc[mt][nt], a4[mt], bl4[nt]);
                    mma16(acc[mt][nt], a4[mt], bh4[nt]);
                }
        }
        __syncthreads();
        if (k0 + 64 < K)
            g2_copy_stage(sm, Ah, Bh, Bl, m0, n0, K, k0 + 64, s, tid);
        CP_COMMIT();
    }

#pragma unroll
    for (int mt = 0; mt < 4; mt++) {
        int r0 = m0 + wm * 64 + mt * 16 + gid;
#pragma unroll
        for (int nt = 0; nt < 4; nt++) {
            int c = n0 + wn * 32 + nt * 8 + (tig << 1);
            float b0 = bias[c], b1 = bias[c + 1];
            *(float2*)(C + (size_t)r0 * N + c) =
                make_float2(acc[mt][nt][0] + b0, acc[mt][nt][1] + b1);
            *(float2*)(C + (size_t)(r0 + 8) * N + c) =
                make_float2(acc[mt][nt][2] + b0, acc[mt][nt][3] + b1);
        }
    }
}

// ---------------- fused flash attention (reads fused qkv, stride QD) ----------
__global__ __launch_bounds__(256, 2)
void flash_attn(const float* __restrict__ qkv) {
    __shared__ uint32_t Qs[128][36];
    __shared__ uint32_t Ks[64][36];
    __shared__ uint32_t Vs[64][36];   // [dim][key-pair]

    const int z = blockIdx.y, b = z >> 4, h = z & 15;
    const int i0 = blockIdx.x * 128;
    const float* Qg = qkv + (size_t)b * SS * QD + h * DKH;
    const float* Kg = Qg + DDIM;
    const float* Vg = Qg + 2 * DDIM;
    bf16* Oh = g_ah + (size_t)b * SS * DDIM + h * DKH;
    bf16* Ol = g_al + (size_t)b * SS * DDIM + h * DKH;

    const int tid = threadIdx.x;
    const int wid = tid >> 5, lane = tid & 31;
    const int gid = lane >> 2, tig = lane & 3;
    const int mb  = wid * 16;

#pragma unroll
    for (int e = 0; e < 8; e++) {
        int idx = tid + e * 256;
        int row = idx >> 4, c4 = (idx & 15) << 2;
        float4 vq = *(const float4*)(Qg + (size_t)(i0 + row) * QD + c4);
        Qs[row][c4 >> 1]       = packbf(vq.x * 0.125f, vq.y * 0.125f);
        Qs[row][(c4 >> 1) + 1] = packbf(vq.z * 0.125f, vq.w * 0.125f);
    }

    float acco[8][4];
#pragma unroll
    for (int nt = 0; nt < 8; nt++)
#pragma unroll
        for (int i = 0; i < 4; i++) acco[nt][i] = 0.f;
    float m_lo = -1e30f, m_hi = -1e30f, l_lo = 0.f, l_hi = 0.f;

    for (int j0 = 0; j0 < SS; j0 += 64) {
        __syncthreads();
#pragma unroll
        for (int e = 0; e < 4; e++) {
            int idx = tid + e * 256;
            int row = idx >> 4, c4 = (idx & 15) << 2;
            float4 kk = *(const float4*)(Kg + (size_t)(j0 + row) * QD + c4);
            float4 vv = *(const float4*)(Vg + (size_t)(j0 + row) * QD + c4);
            Ks[row][c4 >> 1]       = packbf(kk.x, kk.y);
            Ks[row][(c4 >> 1) + 1] = packbf(kk.z, kk.w);
            ((bf16*)&Vs[c4 + 0][0])[row] = __float2bfloat16_rn(vv.x);
            ((bf16*)&Vs[c4 + 1][0])[row] = __float2bfloat16_rn(vv.y);
            ((bf16*)&Vs[c4 + 2][0])[row] = __float2bfloat16_rn(vv.z);
            ((bf16*)&Vs[c4 + 3][0])[row] = __float2bfloat16_rn(vv.w);
        }
        __syncthreads();

        float accs[8][4];
#pragma unroll
        for (int nt = 0; nt < 8; nt++)
#pragma unroll
            for (int i = 0; i < 4; i++) accs[nt][i] = 0.f;
#pragma unroll
        for (int ks = 0; ks < 64; ks += 16) {
            const int w = ks >> 1;
            uint32_t a[4];
            a[0] = Qs[mb + gid][w + tig];     a[1] = Qs[mb + gid + 8][w + tig];
            a[2] = Qs[mb + gid][w + tig + 4]; a[3] = Qs[mb + gid + 8][w + tig + 4];
#pragma unroll
            for (int nt = 0; nt < 8; nt++) {
                uint32_t bb[2];
                bb[0] = Ks[nt * 8 + gid][w + tig];
                bb[1] = Ks[nt * 8 + gid][w + tig + 4];
                mma16(accs[nt], a, bb);
            }
        }

        float mx_lo = -1e30f, mx_hi = -1e30f;
#pragma unroll
        for (int nt = 0; nt < 8; nt++) {
            mx_lo = fmaxf(mx_lo, fmaxf(accs[nt][0], accs[nt][1]));
            mx_hi = fmaxf(mx_hi, fmaxf(accs[nt][2], accs[nt][3]));
        }
        mx_lo = fmaxf(mx_lo, __shfl_xor_sync(~0u, mx_lo, 1));
        mx_lo = fmaxf(mx_lo, __shfl_xor_sync(~0u, mx_lo, 2));
        mx_hi = fmaxf(mx_hi, __shfl_xor_sync(~0u, mx_hi, 1));
        mx_hi = fmaxf(mx_hi, __shfl_xor_sync(~0u, mx_hi, 2));
        float mn_lo = fmaxf(m_lo, mx_lo), mn_hi = fmaxf(m_hi, mx_hi);
        float al_lo = __expf(m_lo - mn_lo), al_hi = __expf(m_hi - mn_hi);
        m_lo = mn_lo; m_hi = mn_hi;

        float sum_lo = 0.f, sum_hi = 0.f;
#pragma unroll
        for (int nt = 0; nt < 8; nt++) {
            accs[nt][0] = __expf(accs[nt][0] - m_lo);
            accs[nt][1] = __expf(accs[nt][1] - m_lo);
            accs[nt][2] = __expf(accs[nt][2] - m_hi);
            accs[nt][3] = __expf(accs[nt][3] - m_hi);
            sum_lo += accs[nt][0] + accs[nt][1];
            sum_hi += accs[nt][2] + accs[nt][3];
        }
        sum_lo += __shfl_xor_sync(~0u, sum_lo, 1);
        sum_lo += __shfl_xor_sync(~0u, sum_lo, 2);
        sum_hi += __shfl_xor_sync(~0u, sum_hi, 1);
        sum_hi += __shfl_xor_sync(~0u, sum_hi, 2);
        l_lo = l_lo * al_lo + sum_lo;
        l_hi = l_hi * al_hi + sum_hi;

#pragma unroll
        for (int nt = 0; nt < 8; nt++) {
            acco[nt][0] *= al_lo; acco[nt][1] *= al_lo;
            acco[nt][2] *= al_hi; acco[nt][3] *= al_hi;
        }

#pragma unroll
        for (int s = 0; s < 4; s++) {
            uint32_t a[4];
            a[0] = packbf(accs[2*s][0],     accs[2*s][1]);
            a[1] = packbf(accs[2*s][2],     accs[2*s][3]);
            a[2] = packbf(accs[2*s + 1][0], accs[2*s + 1][1]);
            a[3] = packbf(accs[2*s + 1][2], accs[2*s + 1][3]);
#pragma unroll
            for (int nt = 0; nt < 8; nt++) {
                uint32_t bb[2];
                bb[0] = Vs[nt * 8 + gid][s * 8 + tig];
                bb[1] = Vs[nt * 8 + gid][s * 8 + tig + 4];
                mma16(acco[nt], a, bb);
            }
        }
    }

    const float inv_lo = 1.0f / l_lo, inv_hi = 1.0f / l_hi;
#pragma unroll
    for (int nt = 0; nt < 8; nt++) {
        int c = nt * 8 + (tig << 1);
        size_t r0 = (size_t)(i0 + mb + gid) * DDIM + c;
        size_t r1 = (size_t)(i0 + mb + gid + 8) * DDIM + c;
        split2(acco[nt][0] * inv_lo, acco[nt][1] * inv_lo,
               (__nv_bfloat162*)(Oh + r0), (__nv_bfloat162*)(Ol + r0));
        split2(acco[nt][2] * inv_hi, acco[nt][3] * inv_hi,
               (__nv_bfloat162*)(Oh + r1), (__nv_bfloat162*)(Ol + r1));
    }
}

// ---------------- add + LayerNorm (+ optional bf16 plane output) -------------
__global__ __launch_bounds__(256)
void add_ln(const float* __restrict__ x, const float* __restrict__ y,
            const float* __restrict__ g, const float* __restrict__ be,
            float* __restrict__ out, bf16* __restrict__ hi, bf16* __restrict__ lo) {
    __shared__ float sm[8];
    __shared__ float bc;
    const int tid = threadIdx.x;
    const size_t ro = (size_t)blockIdx.x * DDIM;
    float4 a = reinterpret_cast<const float4*>(x + ro)[tid];
    float4 b = reinterpret_cast<const float4*>(y + ro)[tid];
    a.x += b.x; a.y += b.y; a.z += b.z; a.w += b.w;

    float s = a.x + a.y + a.z + a.w;
#pragma unroll
    for (int o = 16; o; o >>= 1) s += __shfl_xor_sync(~0u, s, o);
    if ((tid & 31) == 0) sm[tid >> 5] = s;
    __syncthreads();
    if (tid < 32) {
        float t = (tid < 8) ? sm[tid] : 0.f;
#pragma unroll
        for (int o = 4; o; o >>= 1) t += __shfl_xor_sync(~0u, t, o);
        if (tid == 0) bc = t;
    }
    __syncthreads();
    const float mu = bc * (1.0f / DDIM);
    a.x -= mu; a.y -= mu; a.z -= mu; a.w -= mu;
    float qv = a.x*a.x + a.y*a.y + a.z*a.z + a.w*a.w;
    __syncthreads();
#pragma unroll
    for (int o = 16; o; o >>= 1) qv += __shfl_xor_sync(~0u, qv, o);
    if ((tid & 31) == 0) sm[tid >> 5] = qv;
    __syncthreads();
    if (tid < 32) {
        float t = (tid < 8) ? sm[tid] : 0.f;
#pragma unroll
        for (int o = 4; o; o >>= 1) t += __shfl_xor_sync(~0u, t, o);
        if (tid == 0) bc = t;
    }
    __syncthreads();
    const float rs = rsqrtf(bc * (1.0f / DDIM) + 1e-5f);
    float4 gv = reinterpret_cast<const float4*>(g)[tid];
    float4 bv = reinterpret_cast<const float4*>(be)[tid];
    float4 o;
    o.x = a.x * rs * gv.x + bv.x;
    o.y = a.y * rs * gv.y + bv.y;
    o.z = a.z * rs * gv.z + bv.z;
    o.w = a.w * rs * gv.w + bv.w;
    reinterpret_cast<float4*>(out + ro)[tid] = o;
    if (hi) {
        size_t i4 = ro + tid * 4;
        split2(o.x, o.y, (__nv_bfloat162*)(hi + i4),     (__nv_bfloat162*)(lo + i4));
        split2(o.z, o.w, (__nv_bfloat162*)(hi + i4 + 2), (__nv_bfloat162*)(lo + i4 + 2));
    }
}

// ---------------- launch ------------------------------------------------------
extern "C" void kernel_launch(void* const* d_in, const int* in_sizes, int n_in,
                              void* d_out, int out_size) {
    const int*   tokens = (const int*)  d_in[0];
    const float* emb    = (const float*)d_in[1];
    const float* Wq = (const float*)d_in[2],  *bq = (const float*)d_in[3];
    const float* Wk = (const float*)d_in[4],  *bk = (const float*)d_in[5];
    const float* Wv = (const float*)d_in[6],  *bv = (const float*)d_in[7];
    const float* Wo = (const float*)d_in[8],  *bo = (const float*)d_in[9];
    const float* W1 = (const float*)d_in[10], *b1 = (const float*)d_in[11];
    const float* W2 = (const float*)d_in[12], *b2 = (const float*)d_in[13];
    const float* gamma = (const float*)d_in[14], *beta = (const float*)d_in[15];
    float* out = (float*)d_out;

    float *x, *t, *qkv, *bqkv;
    cudaGetSymbolAddress((void**)&x,    g_x);
    cudaGetSymbolAddress((void**)&t,    g_t);
    cudaGetSymbolAddress((void**)&qkv,  g_qkv);
    cudaGetSymbolAddress((void**)&bqkv, g_bqkv);
    bf16 *wqkvh,*wqkvl,*woh,*wol,*w1h,*w1l,*w2h,*w2l,*ah,*al,*hh,*hl;
    cudaGetSymbolAddress((void**)&wqkvh, g_wqkvh);
    cudaGetSymbolAddress((void**)&wqkvl, g_wqkvl);
    cudaGetSymbolAddress((void**)&woh, g_woh); cudaGetSymbolAddress((void**)&wol, g_wol);
    cudaGetSymbolAddress((void**)&w1h, g_w1h); cudaGetSymbolAddress((void**)&w1l, g_w1l);
    cudaGetSymbolAddress((void**)&w2h, g_w2h); cudaGetSymbolAddress((void**)&w2l, g_w2l);
    cudaGetSymbolAddress((void**)&ah,  g_ah);  cudaGetSymbolAddress((void**)&al,  g_al);
    cudaGetSymbolAddress((void**)&hh,  g_hh);  cudaGetSymbolAddress((void**)&hl,  g_hl);

    cudaFuncSetAttribute(gemm_bf16x3<false, false>,
                         cudaFuncAttributeMaxDynamicSharedMemorySize, GEMM_SMEM_BYTES);
    cudaFuncSetAttribute(gemm_bf16x3<true, true>,
                         cudaFuncAttributeMaxDynamicSharedMemorySize, GEMM_SMEM_BYTES);
    cudaFuncSetAttribute(gemm_bf16x2,
                         cudaFuncAttributeMaxDynamicSharedMemorySize, G2_SMEM);

    embed_pe<<<BSR * DDIM / 256, 256>>>(tokens, emb);
    split_a<<<BSR * DDIM / 1024, 256>>>(x, ah, al);

    // weight conversion
    const size_t DD = (size_t)DDIM * DDIM, DF = (size_t)DDIM * FFD;
    split_w_t<<<dim3(DDIM / 32, DDIM / 32, LLAY), 256>>>(Wq, wqkvh,          wqkvl,          DDIM, DDIM, 3 * DD);
    split_w_t<<<dim3(DDIM / 32, DDIM / 32, LLAY), 256>>>(Wk, wqkvh + DD,     wqkvl + DD,     DDIM, DDIM, 3 * DD);
    split_w_t<<<dim3(DDIM / 32, DDIM / 32, LLAY), 256>>>(Wv, wqkvh + 2 * DD, wqkvl + 2 * DD, DDIM, DDIM, 3 * DD);
    split_w_t<<<dim3(DDIM / 32, DDIM / 32, LLAY), 256>>>(Wo, woh, wol, DDIM, DDIM, DD);
    split_w_t<<<dim3(FFD  / 32, DDIM / 32, LLAY), 256>>>(W1, w1h, w1l, DDIM, FFD, DF);
    split_w_t<<<dim3(DDIM / 32, FFD  / 32, LLAY), 256>>>(W2, w2h, w2l, FFD, DDIM, DF);
    pack_bias<<<dim3(QD / 256, LLAY), 256>>>(bq, bk, bv);

    const dim3 gqkv(QD  / 128, BSR / 128);  // 24 x 16
    const dim3 gp(DDIM / 128, BSR / 128);
    const dim3 gf(FFD  / 128, BSR / 128);

    for (int l = 0; l < LLAY; l++) {
        size_t od = (size_t)l * DD, of = (size_t)l * DF;
        const float* lbo = bo + (size_t)l * DDIM;
        const float* lb1 = b1 + (size_t)l * FFD;
        const float* lb2 = b2 + (size_t)l * DDIM;
        const float* lg  = gamma + (size_t)l * DDIM;
        const float* lbe = beta  + (size_t)l * DDIM;

        gemm_bf16x2<<<gqkv, 256, G2_SMEM>>>(
            ah, wqkvh + (size_t)l * 3 * DD, wqkvl + (size_t)l * 3 * DD,
            bqkv + (size_t)l * QD, qkv, BSR, QD, DDIM);

        flash_attn<<<dim3(SS / 128, BB * HH), 256>>>(qkv);

        gemm_bf16x3<false, false><<<gp, 256, GEMM_SMEM_BYTES>>>(
            ah, al, woh + od, wol + od, lbo, t, nullptr, nullptr, BSR, DDIM, DDIM);
        add_ln<<<BSR, 256>>>(x, t, lg, lbe, x, ah, al);

        gemm_bf16x3<true, true><<<gf, 256, GEMM_SMEM_BYTES>>>(
            ah, al, w1h + of, w1l + of, lb1, nullptr, hh, hl, BSR, FFD, DDIM);
        gemm_bf16x3<false, false><<<gp, 256, GEMM_SMEM_BYTES>>>(
            hh, hl, w2h + of, w2l + of, lb2, t, nullptr, nullptr, BSR, DDIM, FFD);

        float* xo = (l == LLAY - 1) ? out : x;
        bf16* nh = (l == LLAY - 1) ? nullptr : ah;
        bf16* nl = (l == LLAY - 1) ? nullptr : al;
        add_ln<<<BSR, 256>>>(x, t, lg, lbe, xo, nh, nl);
    }
}

// round 10
// speedup vs baseline: 3.1086x; 1.0374x over previous
#include <cuda_runtime.h>
#include <cuda_bf16.h>
#include <math.h>
#include <stdint.h>

// Problem constants
#define BB   2
#define SS   1024
#define DDIM 1024
#define HH   16
#define LLAY 4
#define FFD  2048
#define DKH  64
#define BSR  (BB*SS)   // 2048 rows
#define QD   (3*DDIM)  // fused QKV width

typedef __nv_bfloat16 bf16;

// ---------------- scratch (static device globals; no allocs allowed) ----------
__device__ float g_x  [BSR*DDIM];
__device__ float g_t  [BSR*DDIM];
__device__ float g_qkv[BSR*QD];

// bf16 weight planes, transposed to [N][K]
__device__ __align__(256) bf16 g_wqkvh[LLAY*3*DDIM*DDIM], g_wqkvl[LLAY*3*DDIM*DDIM];
__device__ __align__(256) bf16 g_woh[LLAY*DDIM*DDIM], g_wol[LLAY*DDIM*DDIM];
__device__ __align__(256) bf16 g_w1h[LLAY*DDIM*FFD],  g_w1l[LLAY*DDIM*FFD];
__device__ __align__(256) bf16 g_w2h[LLAY*FFD*DDIM],  g_w2l[LLAY*FFD*DDIM];
__device__ float g_bqkv[LLAY*QD];
// activation planes
__device__ __align__(256) bf16 g_ah[BSR*DDIM], g_al[BSR*DDIM];
__device__ __align__(256) bf16 g_hh[BSR*FFD],  g_hl[BSR*FFD];

// ---------------- helpers -----------------------------------------------------
__device__ __forceinline__ void mma16(float* c, const uint32_t* a, const uint32_t* b) {
    asm volatile(
        "mma.sync.aligned.m16n8k16.row.col.f32.bf16.bf16.f32 "
        "{%0,%1,%2,%3}, {%4,%5,%6,%7}, {%8,%9}, {%0,%1,%2,%3};"
        : "+f"(c[0]), "+f"(c[1]), "+f"(c[2]), "+f"(c[3])
        : "r"(a[0]), "r"(a[1]), "r"(a[2]), "r"(a[3]), "r"(b[0]), "r"(b[1]));
}
__device__ __forceinline__ void ldsm4(uint32_t& r0, uint32_t& r1, uint32_t& r2,
                                      uint32_t& r3, uint32_t addr) {
    asm volatile("ldmatrix.sync.aligned.m8n8.x4.shared.b16 {%0,%1,%2,%3}, [%4];"
                 : "=r"(r0), "=r"(r1), "=r"(r2), "=r"(r3) : "r"(addr));
}
__device__ __forceinline__ void cp16(uint32_t* s, const void* g) {
    uint32_t sa = (uint32_t)__cvta_generic_to_shared(s);
    asm volatile("cp.async.cg.shared.global [%0], [%1], 16;" :: "r"(sa), "l"(g));
}
#define CP_COMMIT() asm volatile("cp.async.commit_group;")
#define CP_WAIT1()  asm volatile("cp.async.wait_group 1;" ::: "memory")

__device__ __forceinline__ void split2(float v0, float v1, __nv_bfloat162* hi,
                                       __nv_bfloat162* lo) {
    bf16 h0 = __float2bfloat16_rn(v0), h1 = __float2bfloat16_rn(v1);
    __nv_bfloat162 hh; hh.x = h0; hh.y = h1;
    __nv_bfloat162 ll;
    ll.x = __float2bfloat16_rn(v0 - __bfloat162float(h0));
    ll.y = __float2bfloat16_rn(v1 - __bfloat162float(h1));
    *hi = hh; *lo = ll;
}
__device__ __forceinline__ uint32_t packbf(float a, float b) {
    __nv_bfloat162 p = __floats2bfloat162_rn(a, b);
    return *(uint32_t*)&p;
}

// ---------------- embedding + (buggy-faithful) positional encoding ------------
__global__ void embed_pe(const int* __restrict__ tok, const float* __restrict__ emb) {
    int idx = blockIdx.x * 256 + threadIdx.x;
    int d  = idx & (DDIM - 1);
    int bs = idx >> 10;
    int b  = bs >> 10;
    int t  = tok[bs];
    int i2 = (d >> 1) << 1;
    float div = expf(-(float)i2 * (9.210340371976184f / (float)DDIM));
    float ang = (float)b * div;
    float pe  = (d & 1) ? cosf(ang) : sinf(ang);
    g_x[idx] = emb[(size_t)t * DDIM + d] + pe;
}

// ---------------- activation hi/lo split (after embed only) -------------------
__global__ __launch_bounds__(256)
void split_a(const float* __restrict__ s, bf16* __restrict__ hi, bf16* __restrict__ lo) {
    int i4 = (blockIdx.x * 256 + threadIdx.x) * 4;
    float4 v = *(const float4*)(s + i4);
    split2(v.x, v.y, (__nv_bfloat162*)(hi + i4),     (__nv_bfloat162*)(lo + i4));
    split2(v.z, v.w, (__nv_bfloat162*)(hi + i4 + 2), (__nv_bfloat162*)(lo + i4 + 2));
}

// ---------------- weight transpose + hi/lo split, all layers (z) -------------
__global__ __launch_bounds__(256)
void split_w_t(const float* __restrict__ W0, bf16* __restrict__ th0,
               bf16* __restrict__ tl0, int K, int N, size_t ostride) {
    const size_t li = (size_t)blockIdx.z * K * N;
    const size_t lo = (size_t)blockIdx.z * ostride;
    const float* W = W0 + li;
    bf16* th = th0 + lo;
    bf16* tl = tl0 + lo;
    __shared__ float tile[32][33];
    const int n0 = blockIdx.x * 32, k0 = blockIdx.y * 32;
    const int tx = threadIdx.x & 31, ty = threadIdx.x >> 5;
#pragma unroll
    for (int i = 0; i < 32; i += 8)
        tile[ty + i][tx] = W[(size_t)(k0 + ty + i) * N + n0 + tx];
    __syncthreads();
#pragma unroll
    for (int i = 0; i < 32; i += 8) {
        int n = n0 + ty + i, k = k0 + tx;
        float v = tile[tx][ty + i];
        bf16 h = __float2bfloat16_rn(v);
        th[(size_t)n * K + k] = h;
        tl[(size_t)n * K + k] = __float2bfloat16_rn(v - __bfloat162float(h));
    }
}

// ---------------- pack QKV biases ---------------------------------------------
__global__ void pack_bias(const float* __restrict__ bq, const float* __restrict__ bk,
                          const float* __restrict__ bv) {
    int l = blockIdx.y;
    int i = blockIdx.x * 256 + threadIdx.x;
    float v = (i < DDIM) ? bq[l * DDIM + i]
            : (i < 2 * DDIM) ? bk[l * DDIM + i - DDIM]
            : bv[l * DDIM + i - 2 * DDIM];
    g_bqkv[l * QD + i] = v;
}

// ---------------- bf16x3 tensor-core GEMM, cp.async + ldmatrix ---------------
#define GS_PLANE 5120
#define GS_STAGE 2560
#define GEMM_SMEM_BYTES (4 * GS_PLANE * 4)

__device__ __forceinline__ void gemm_copy_stage(
    uint32_t* sm, const bf16* __restrict__ Ah, const bf16* __restrict__ Al,
    const bf16* __restrict__ Bh, const bf16* __restrict__ Bl,
    int m0, int n0, int K, int k0, int s, int tid) {
#pragma unroll
    for (int e = 0; e < 2; e++) {
        int c = tid + e * 256;
        int row = c >> 2, cw = (c & 3) << 2;
        int kk  = k0 + ((c & 3) << 3);
        size_t ga = (size_t)(m0 + row) * K + kk;
        size_t gb = (size_t)(n0 + row) * K + kk;
        int so = s * GS_STAGE + row * 20 + cw;
        cp16(sm + 0 * GS_PLANE + so, Ah + ga);
        cp16(sm + 1 * GS_PLANE + so, Al + ga);
        cp16(sm + 2 * GS_PLANE + so, Bh + gb);
        cp16(sm + 3 * GS_PLANE + so, Bl + gb);
    }
}

template<bool RELU, bool PLANES>
__global__ __launch_bounds__(256, 2)
void gemm_bf16x3(const bf16* __restrict__ Ah, const bf16* __restrict__ Al,
                 const bf16* __restrict__ Bh, const bf16* __restrict__ Bl,
                 const float* __restrict__ bias, float* __restrict__ C,
                 bf16* __restrict__ Chi, bf16* __restrict__ Clo,
                 int M, int N, int K) {
    extern __shared__ uint32_t sm[];
    const int tid  = threadIdx.x;
    const int wid  = tid >> 5, lane = tid & 31;
    const int gid  = lane >> 2, tig = lane & 3;
    const int wm   = wid >> 2, wn = wid & 3;
    const int m0   = blockIdx.y * 128, n0 = blockIdx.x * 128;
    const uint32_t sbase = (uint32_t)__cvta_generic_to_shared(sm);

    // ldmatrix per-thread address components
    const int lr  = lane & 7;
    const int lg1 = (lane >> 3) & 1;   // A: +8 rows | B: k-high half
    const int lg2 = (lane >> 4) & 1;   // A: k-high  | B: +8 rows
    int rowA[4], rowB[2];
#pragma unroll
    for (int mt = 0; mt < 4; mt++) rowA[mt] = wm * 64 + mt * 16 + lg1 * 8 + lr;
#pragma unroll
    for (int np = 0; np < 2; np++) rowB[np] = wn * 32 + np * 16 + lg2 * 8 + lr;
    const int kA = lg2 * 4, kB = lg1 * 4;   // word offsets

    float acc[4][4][4];
#pragma unroll
    for (int mt = 0; mt < 4; mt++)
#pragma unroll
        for (int nt = 0; nt < 4; nt++)
#pragma unroll
            for (int i = 0; i < 4; i++) acc[mt][nt][i] = 0.f;

    gemm_copy_stage(sm, Ah, Al, Bh, Bl, m0, n0, K, 0, 0, tid);
    CP_COMMIT();
    gemm_copy_stage(sm, Ah, Al, Bh, Bl, m0, n0, K, 32, 1, tid);
    CP_COMMIT();

    for (int k0 = 0; k0 < K; k0 += 32) {
        const int s = (k0 >> 5) & 1;
        CP_WAIT1();
        __syncthreads();

        const uint32_t aAH = sbase + (0 * GS_PLANE + s * GS_STAGE) * 4;
        const uint32_t aAL = sbase + (1 * GS_PLANE + s * GS_STAGE) * 4;
        const uint32_t aBH = sbase + (2 * GS_PLANE + s * GS_STAGE) * 4;
        const uint32_t aBL = sbase + (3 * GS_PLANE + s * GS_STAGE) * 4;
#pragma unroll
        for (int sb = 0; sb < 2; sb++) {
            const int kb = sb * 8;
            uint32_t ah[4][4], al[4][4], bh4[4][2], bl4[4][2];
#pragma unroll
            for (int mt = 0; mt < 4; mt++) {
                uint32_t off = (uint32_t)(rowA[mt] * 20 + kb + kA) * 4;
                ldsm4(ah[mt][0], ah[mt][1], ah[mt][2], ah[mt][3], aAH + off);
                ldsm4(al[mt][0], al[mt][1], al[mt][2], al[mt][3], aAL + off);
            }
#pragma unroll
            for (int np = 0; np < 2; np++) {
                uint32_t off = (uint32_t)(rowB[np] * 20 + kb + kB) * 4;
                ldsm4(bh4[2*np][0], bh4[2*np][1], bh4[2*np+1][0], bh4[2*np+1][1],
                      aBH + off);
                ldsm4(bl4[2*np][0], bl4[2*np][1], bl4[2*np+1][0], bl4[2*np+1][1],
                      aBL + off);
            }
#pragma unroll
            for (int mt = 0; mt < 4; mt++)
#pragma unroll
                for (int nt = 0; nt < 4; nt++) {
                    mma16(acc[mt][nt], al[mt], bh4[nt]);
                    mma16(acc[mt][nt], ah[mt], bl4[nt]);
                    mma16(acc[mt][nt], ah[mt], bh4[nt]);
                }
        }
        __syncthreads();
        if (k0 + 64 < K)
            gemm_copy_stage(sm, Ah, Al, Bh, Bl, m0, n0, K, k0 + 64, s, tid);
        CP_COMMIT();
    }

#pragma unroll
    for (int mt = 0; mt < 4; mt++) {
        int r0 = m0 + wm * 64 + mt * 16 + gid;
#pragma unroll
        for (int nt = 0; nt < 4; nt++) {
            int c = n0 + wn * 32 + nt * 8 + (tig << 1);
            float b0 = bias[c], b1 = bias[c + 1];
            float2 o0 = make_float2(acc[mt][nt][0] + b0, acc[mt][nt][1] + b1);
            float2 o1 = make_float2(acc[mt][nt][2] + b0, acc[mt][nt][3] + b1);
            if (RELU) {
                o0.x = fmaxf(o0.x, 0.f); o0.y = fmaxf(o0.y, 0.f);
                o1.x = fmaxf(o1.x, 0.f); o1.y = fmaxf(o1.y, 0.f);
            }
            if (PLANES) {
                split2(o0.x, o0.y, (__nv_bfloat162*)(Chi + (size_t)r0 * N + c),
                                   (__nv_bfloat162*)(Clo + (size_t)r0 * N + c));
                split2(o1.x, o1.y, (__nv_bfloat162*)(Chi + (size_t)(r0 + 8) * N + c),
                                   (__nv_bfloat162*)(Clo + (size_t)(r0 + 8) * N + c));
            } else {
                *(float2*)(C + (size_t)r0 * N + c)       = o0;
                *(float2*)(C + (size_t)(r0 + 8) * N + c) = o1;
            }
        }
    }
}

// ---------------- bf16 2-pass GEMM (QKV): C = Ah @ (Bh+Bl)^T + bias ----------
#define G2_PLANE 5120
#define G2_STAGE 2560
#define G2_SMEM  (3 * G2_PLANE * 4)   // 60 KB

__device__ __forceinline__ void g2_copy_stage(
    uint32_t* sm, const bf16* __restrict__ Ah, const bf16* __restrict__ Bh,
    const bf16* __restrict__ Bl, int m0, int n0, int K, int k0, int s, int tid) {
#pragma unroll
    for (int e = 0; e < 2; e++) {
        int c = tid + e * 256;
        int row = c >> 2, cw = (c & 3) << 2;
        int kk  = k0 + ((c & 3) << 3);
        size_t gb = (size_t)(n0 + row) * K + kk;
        int so = s * G2_STAGE + row * 20 + cw;
        cp16(sm + 0 * G2_PLANE + so, Ah + (size_t)(m0 + row) * K + kk);
        cp16(sm + 1 * G2_PLANE + so, Bh + gb);
        cp16(sm + 2 * G2_PLANE + so, Bl + gb);
    }
}

__global__ __launch_bounds__(256, 2)
void gemm_bf16x2(const bf16* __restrict__ Ah, const bf16* __restrict__ Bh,
                 const bf16* __restrict__ Bl, const float* __restrict__ bias,
                 float* __restrict__ C, int M, int N, int K) {
    extern __shared__ uint32_t sm[];
    const int tid  = threadIdx.x;
    const int wid  = tid >> 5, lane = tid & 31;
    const int gid  = lane >> 2, tig = lane & 3;
    const int wm   = wid >> 2, wn = wid & 3;
    const int m0   = blockIdx.y * 128, n0 = blockIdx.x * 128;
    const uint32_t sbase = (uint32_t)__cvta_generic_to_shared(sm);

    const int lr  = lane & 7;
    const int lg1 = (lane >> 3) & 1;
    const int lg2 = (lane >> 4) & 1;
    int rowA[4], rowB[2];
#pragma unroll
    for (int mt = 0; mt < 4; mt++) rowA[mt] = wm * 64 + mt * 16 + lg1 * 8 + lr;
#pragma unroll
    for (int np = 0; np < 2; np++) rowB[np] = wn * 32 + np * 16 + lg2 * 8 + lr;
    const int kA = lg2 * 4, kB = lg1 * 4;

    float acc[4][4][4];
#pragma unroll
    for (int mt = 0; mt < 4; mt++)
#pragma unroll
        for (int nt = 0; nt < 4; nt++)
#pragma unroll
            for (int i = 0; i < 4; i++) acc[mt][nt][i] = 0.f;

    g2_copy_stage(sm, Ah, Bh, Bl, m0, n0, K, 0, 0, tid);
    CP_COMMIT();
    g2_copy_stage(sm, Ah, Bh, Bl, m0, n0, K, 32, 1, tid);
    CP_COMMIT();

    for (int k0 = 0; k0 < K; k0 += 32) {
        const int s = (k0 >> 5) & 1;
        CP_WAIT1();
        __syncthreads();

        const uint32_t aA  = sbase + (0 * G2_PLANE + s * G2_STAGE) * 4;
        const uint32_t aBH = sbase + (1 * G2_PLANE + s * G2_STAGE) * 4;
        const uint32_t aBL = sbase + (2 * G2_PLANE + s * G2_STAGE) * 4;
#pragma unroll
        for (int sb = 0; sb < 2; sb++) {
            const int kb = sb * 8;
            uint32_t a4[4][4], bh4[4][2], bl4[4][2];
#pragma unroll
            for (int mt = 0; mt < 4; mt++) {
                uint32_t off = (uint32_t)(rowA[mt] * 20 + kb + kA) * 4;
                ldsm4(a4[mt][0], a4[mt][1], a4[mt][2], a4[mt][3], aA + off);
            }
#pragma unroll
            for (int np = 0; np < 2; np++) {
                uint32_t off = (uint32_t)(rowB[np] * 20 + kb + kB) * 4;
                ldsm4(bh4[2*np][0], bh4[2*np][1], bh4[2*np+1][0], bh4[2*np+1][1],
                      aBH + off);
                ldsm4(bl4[2*np][0], bl4[2*np][1], bl4[2*np+1][0], bl4[2*np+1][1],
                      aBL + off);
            }
#pragma unroll
            for (int mt = 0; mt < 4; mt++)
#pragma unroll
                for (int nt = 0; nt < 4; nt++) {
                    mma16(acc[mt][nt], a4[mt], bl4[nt]);
                    mma16(acc[mt][nt], a4[mt], bh4[nt]);
                }
        }
        __syncthreads();
        if (k0 + 64 < K)
            g2_copy_stage(sm, Ah, Bh, Bl, m0, n0, K, k0 + 64, s, tid);
        CP_COMMIT();
    }

#pragma unroll
    for (int mt = 0; mt < 4; mt++) {
        int r0 = m0 + wm * 64 + mt * 16 + gid;
#pragma unroll
        for (int nt = 0; nt < 4; nt++) {
            int c = n0 + wn * 32 + nt * 8 + (tig << 1);
            float b0 = bias[c], b1 = bias[c + 1];
            *(float2*)(C + (size_t)r0 * N + c) =
                make_float2(acc[mt][nt][0] + b0, acc[mt][nt][1] + b1);
            *(float2*)(C + (size_t)(r0 + 8) * N + c) =
                make_float2(acc[mt][nt][2] + b0, acc[mt][nt][3] + b1);
        }
    }
}

// ---------------- fused flash attention (reads fused qkv, stride QD) ----------
__global__ __launch_bounds__(256, 2)
void flash_attn(const float* __restrict__ qkv) {
    __shared__ uint32_t Qs[128][36];
    __shared__ uint32_t Ks[64][36];
    __shared__ uint32_t Vs[64][36];   // [dim][key-pair]

    const int z = blockIdx.y, b = z >> 4, h = z & 15;
    const int i0 = blockIdx.x * 128;
    const float* Qg = qkv + (size_t)b * SS * QD + h * DKH;
    const float* Kg = Qg + DDIM;
    const float* Vg = Qg + 2 * DDIM;
    bf16* Oh = g_ah + (size_t)b * SS * DDIM + h * DKH;
    bf16* Ol = g_al + (size_t)b * SS * DDIM + h * DKH;

    const int tid = threadIdx.x;
    const int wid = tid >> 5, lane = tid & 31;
    const int gid = lane >> 2, tig = lane & 3;
    const int mb  = wid * 16;

#pragma unroll
    for (int e = 0; e < 8; e++) {
        int idx = tid + e * 256;
        int row = idx >> 4, c4 = (idx & 15) << 2;
        float4 vq = *(const float4*)(Qg + (size_t)(i0 + row) * QD + c4);
        Qs[row][c4 >> 1]       = packbf(vq.x * 0.125f, vq.y * 0.125f);
        Qs[row][(c4 >> 1) + 1] = packbf(vq.z * 0.125f, vq.w * 0.125f);
    }

    float acco[8][4];
#pragma unroll
    for (int nt = 0; nt < 8; nt++)
#pragma unroll
        for (int i = 0; i < 4; i++) acco[nt][i] = 0.f;
    float m_lo = -1e30f, m_hi = -1e30f, l_lo = 0.f, l_hi = 0.f;

    for (int j0 = 0; j0 < SS; j0 += 64) {
        __syncthreads();
#pragma unroll
        for (int e = 0; e < 4; e++) {
            int idx = tid + e * 256;
            int row = idx >> 4, c4 = (idx & 15) << 2;
            float4 kk = *(const float4*)(Kg + (size_t)(j0 + row) * QD + c4);
            float4 vv = *(const float4*)(Vg + (size_t)(j0 + row) * QD + c4);
            Ks[row][c4 >> 1]       = packbf(kk.x, kk.y);
            Ks[row][(c4 >> 1) + 1] = packbf(kk.z, kk.w);
            ((bf16*)&Vs[c4 + 0][0])[row] = __float2bfloat16_rn(vv.x);
            ((bf16*)&Vs[c4 + 1][0])[row] = __float2bfloat16_rn(vv.y);
            ((bf16*)&Vs[c4 + 2][0])[row] = __float2bfloat16_rn(vv.z);
            ((bf16*)&Vs[c4 + 3][0])[row] = __float2bfloat16_rn(vv.w);
        }
        __syncthreads();

        float accs[8][4];
#pragma unroll
        for (int nt = 0; nt < 8; nt++)
#pragma unroll
            for (int i = 0; i < 4; i++) accs[nt][i] = 0.f;
#pragma unroll
        for (int ks = 0; ks < 64; ks += 16) {
            const int w = ks >> 1;
            uint32_t a[4];
            a[0] = Qs[mb + gid][w + tig];     a[1] = Qs[mb + gid + 8][w + tig];
            a[2] = Qs[mb + gid][w + tig + 4]; a[3] = Qs[mb + gid + 8][w + tig + 4];
#pragma unroll
            for (int nt = 0; nt < 8; nt++) {
                uint32_t bb[2];
                bb[0] = Ks[nt * 8 + gid][w + tig];
                bb[1] = Ks[nt * 8 + gid][w + tig + 4];
                mma16(accs[nt], a, bb);
            }
        }

        float mx_lo = -1e30f, mx_hi = -1e30f;
#pragma unroll
        for (int nt = 0; nt < 8; nt++) {
            mx_lo = fmaxf(mx_lo, fmaxf(accs[nt][0], accs[nt][1]));
            mx_hi = fmaxf(mx_hi, fmaxf(accs[nt][2], accs[nt][3]));
        }
        mx_lo = fmaxf(mx_lo, __shfl_xor_sync(~0u, mx_lo, 1));
        mx_lo = fmaxf(mx_lo, __shfl_xor_sync(~0u, mx_lo, 2));
        mx_hi = fmaxf(mx_hi, __shfl_xor_sync(~0u, mx_hi, 1));
        mx_hi = fmaxf(mx_hi, __shfl_xor_sync(~0u, mx_hi, 2));
        float mn_lo = fmaxf(m_lo, mx_lo), mn_hi = fmaxf(m_hi, mx_hi);
        float al_lo = __expf(m_lo - mn_lo), al_hi = __expf(m_hi - mn_hi);
        m_lo = mn_lo; m_hi = mn_hi;

        float sum_lo = 0.f, sum_hi = 0.f;
#pragma unroll
        for (int nt = 0; nt < 8; nt++) {
            accs[nt][0] = __expf(accs[nt][0] - m_lo);
            accs[nt][1] = __expf(accs[nt][1] - m_lo);
            accs[nt][2] = __expf(accs[nt][2] - m_hi);
            accs[nt][3] = __expf(accs[nt][3] - m_hi);
            sum_lo += accs[nt][0] + accs[nt][1];
            sum_hi += accs[nt][2] + accs[nt][3];
        }
        sum_lo += __shfl_xor_sync(~0u, sum_lo, 1);
        sum_lo += __shfl_xor_sync(~0u, sum_lo, 2);
        sum_hi += __shfl_xor_sync(~0u, sum_hi, 1);
        sum_hi += __shfl_xor_sync(~0u, sum_hi, 2);
        l_lo = l_lo * al_lo + sum_lo;
        l_hi = l_hi * al_hi + sum_hi;

#pragma unroll
        for (int nt = 0; nt < 8; nt++) {
            acco[nt][0] *= al_lo; acco[nt][1] *= al_lo;
            acco[nt][2] *= al_hi; acco[nt][3] *= al_hi;
        }

#pragma unroll
        for (int s = 0; s < 4; s++) {
            uint32_t a[4];
            a[0] = packbf(accs[2*s][0],     accs[2*s][1]);
            a[1] = packbf(accs[2*s][2],     accs[2*s][3]);
            a[2] = packbf(accs[2*s + 1][0], accs[2*s + 1][1]);
            a[3] = packbf(accs[2*s + 1][2], accs[2*s + 1][3]);
#pragma unroll
            for (int nt = 0; nt < 8; nt++) {
                uint32_t bb[2];
                bb[0] = Vs[nt * 8 + gid][s * 8 + tig];
                bb[1] = Vs[nt * 8 + gid][s * 8 + tig + 4];
                mma16(acco[nt], a, bb);
            }
        }
    }

    const float inv_lo = 1.0f / l_lo, inv_hi = 1.0f / l_hi;
#pragma unroll
    for (int nt = 0; nt < 8; nt++) {
        int c = nt * 8 + (tig << 1);
        size_t r0 = (size_t)(i0 + mb + gid) * DDIM + c;
        size_t r1 = (size_t)(i0 + mb + gid + 8) * DDIM + c;
        split2(acco[nt][0] * inv_lo, acco[nt][1] * inv_lo,
               (__nv_bfloat162*)(Oh + r0), (__nv_bfloat162*)(Ol + r0));
        split2(acco[nt][2] * inv_hi, acco[nt][3] * inv_hi,
               (__nv_bfloat162*)(Oh + r1), (__nv_bfloat162*)(Ol + r1));
    }
}

// ---------------- add + LayerNorm (+ optional bf16 plane output) -------------
__global__ __launch_bounds__(256)
void add_ln(const float* __restrict__ x, const float* __restrict__ y,
            const float* __restrict__ g, const float* __restrict__ be,
            float* __restrict__ out, bf16* __restrict__ hi, bf16* __restrict__ lo) {
    __shared__ float sm[8];
    __shared__ float bc;
    const int tid = threadIdx.x;
    const size_t ro = (size_t)blockIdx.x * DDIM;
    float4 a = reinterpret_cast<const float4*>(x + ro)[tid];
    float4 b = reinterpret_cast<const float4*>(y + ro)[tid];
    a.x += b.x; a.y += b.y; a.z += b.z; a.w += b.w;

    float s = a.x + a.y + a.z + a.w;
#pragma unroll
    for (int o = 16; o; o >>= 1) s += __shfl_xor_sync(~0u, s, o);
    if ((tid & 31) == 0) sm[tid >> 5] = s;
    __syncthreads();
    if (tid < 32) {
        float t = (tid < 8) ? sm[tid] : 0.f;
#pragma unroll
        for (int o = 4; o; o >>= 1) t += __shfl_xor_sync(~0u, t, o);
        if (tid == 0) bc = t;
    }
    __syncthreads();
    const float mu = bc * (1.0f / DDIM);
    a.x -= mu; a.y -= mu; a.z -= mu; a.w -= mu;
    float qv = a.x*a.x + a.y*a.y + a.z*a.z + a.w*a.w;
    __syncthreads();
#pragma unroll
    for (int o = 16; o; o >>= 1) qv += __shfl_xor_sync(~0u, qv, o);
    if ((tid & 31) == 0) sm[tid >> 5] = qv;
    __syncthreads();
    if (tid < 32) {
        float t = (tid < 8) ? sm[tid] : 0.f;
#pragma unroll
        for (int o = 4; o; o >>= 1) t += __shfl_xor_sync(~0u, t, o);
        if (tid == 0) bc = t;
    }
    __syncthreads();
    const float rs = rsqrtf(bc * (1.0f / DDIM) + 1e-5f);
    float4 gv = reinterpret_cast<const float4*>(g)[tid];
    float4 bv = reinterpret_cast<const float4*>(be)[tid];
    float4 o;
    o.x = a.x * rs * gv.x + bv.x;
    o.y = a.y * rs * gv.y + bv.y;
    o.z = a.z * rs * gv.z + bv.z;
    o.w = a.w * rs * gv.w + bv.w;
    reinterpret_cast<float4*>(out + ro)[tid] = o;
    if (hi) {
        size_t i4 = ro + tid * 4;
        split2(o.x, o.y, (__nv_bfloat162*)(hi + i4),     (__nv_bfloat162*)(lo + i4));
        split2(o.z, o.w, (__nv_bfloat162*)(hi + i4 + 2), (__nv_bfloat162*)(lo + i4 + 2));
    }
}

// ---------------- launch ------------------------------------------------------
extern "C" void kernel_launch(void* const* d_in, const int* in_sizes, int n_in,
                              void* d_out, int out_size) {
    const int*   tokens = (const int*)  d_in[0];
    const float* emb    = (const float*)d_in[1];
    const float* Wq = (const float*)d_in[2],  *bq = (const float*)d_in[3];
    const float* Wk = (const float*)d_in[4],  *bk = (const float*)d_in[5];
    const float* Wv = (const float*)d_in[6],  *bv = (const float*)d_in[7];
    const float* Wo = (const float*)d_in[8],  *bo = (const float*)d_in[9];
    const float* W1 = (const float*)d_in[10], *b1 = (const float*)d_in[11];
    const float* W2 = (const float*)d_in[12], *b2 = (const float*)d_in[13];
    const float* gamma = (const float*)d_in[14], *beta = (const float*)d_in[15];
    float* out = (float*)d_out;

    float *x, *t, *qkv, *bqkv;
    cudaGetSymbolAddress((void**)&x,    g_x);
    cudaGetSymbolAddress((void**)&t,    g_t);
    cudaGetSymbolAddress((void**)&qkv,  g_qkv);
    cudaGetSymbolAddress((void**)&bqkv, g_bqkv);
    bf16 *wqkvh,*wqkvl,*woh,*wol,*w1h,*w1l,*w2h,*w2l,*ah,*al,*hh,*hl;
    cudaGetSymbolAddress((void**)&wqkvh, g_wqkvh);
    cudaGetSymbolAddress((void**)&wqkvl, g_wqkvl);
    cudaGetSymbolAddress((void**)&woh, g_woh); cudaGetSymbolAddress((void**)&wol, g_wol);
    cudaGetSymbolAddress((void**)&w1h, g_w1h); cudaGetSymbolAddress((void**)&w1l, g_w1l);
    cudaGetSymbolAddress((void**)&w2h, g_w2h); cudaGetSymbolAddress((void**)&w2l, g_w2l);
    cudaGetSymbolAddress((void**)&ah,  g_ah);  cudaGetSymbolAddress((void**)&al,  g_al);
    cudaGetSymbolAddress((void**)&hh,  g_hh);  cudaGetSymbolAddress((void**)&hl,  g_hl);

    cudaFuncSetAttribute(gemm_bf16x3<false, false>,
                         cudaFuncAttributeMaxDynamicSharedMemorySize, GEMM_SMEM_BYTES);
    cudaFuncSetAttribute(gemm_bf16x3<true, true>,
                         cudaFuncAttributeMaxDynamicSharedMemorySize, GEMM_SMEM_BYTES);
    cudaFuncSetAttribute(gemm_bf16x2,
                         cudaFuncAttributeMaxDynamicSharedMemorySize, G2_SMEM);

    embed_pe<<<BSR * DDIM / 256, 256>>>(tokens, emb);
    split_a<<<BSR * DDIM / 1024, 256>>>(x, ah, al);

    // weight conversion
    const size_t DD = (size_t)DDIM * DDIM, DF = (size_t)DDIM * FFD;
    split_w_t<<<dim3(DDIM / 32, DDIM / 32, LLAY), 256>>>(Wq, wqkvh,          wqkvl,          DDIM, DDIM, 3 * DD);
    split_w_t<<<dim3(DDIM / 32, DDIM / 32, LLAY), 256>>>(Wk, wqkvh + DD,     wqkvl + DD,     DDIM, DDIM, 3 * DD);
    split_w_t<<<dim3(DDIM / 32, DDIM / 32, LLAY), 256>>>(Wv, wqkvh + 2 * DD, wqkvl + 2 * DD, DDIM, DDIM, 3 * DD);
    split_w_t<<<dim3(DDIM / 32, DDIM / 32, LLAY), 256>>>(Wo, woh, wol, DDIM, DDIM, DD);
    split_w_t<<<dim3(FFD  / 32, DDIM / 32, LLAY), 256>>>(W1, w1h, w1l, DDIM, FFD, DF);
    split_w_t<<<dim3(DDIM / 32, FFD  / 32, LLAY), 256>>>(W2, w2h, w2l, FFD, DDIM, DF);
    pack_bias<<<dim3(QD / 256, LLAY), 256>>>(bq, bk, bv);

    const dim3 gqkv(QD  / 128, BSR / 128);  // 24 x 16
    const dim3 gp(DDIM / 128, BSR / 128);
    const dim3 gf(FFD  / 128, BSR / 128);

    for (int l = 0; l < LLAY; l++) {
        size_t od = (size_t)l * DD, of = (size_t)l * DF;
        const float* lbo = bo + (size_t)l * DDIM;
        const float* lb1 = b1 + (size_t)l * FFD;
        const float* lb2 = b2 + (size_t)l * DDIM;
        const float* lg  = gamma + (size_t)l * DDIM;
        const float* lbe = beta  + (size_t)l * DDIM;

        gemm_bf16x2<<<gqkv, 256, G2_SMEM>>>(
            ah, wqkvh + (size_t)l * 3 * DD, wqkvl + (size_t)l * 3 * DD,
            bqkv + (size_t)l * QD, qkv, BSR, QD, DDIM);

        flash_attn<<<dim3(SS / 128, BB * HH), 256>>>(qkv);

        gemm_bf16x3<false, false><<<gp, 256, GEMM_SMEM_BYTES>>>(
            ah, al, woh + od, wol + od, lbo, t, nullptr, nullptr, BSR, DDIM, DDIM);
        add_ln<<<BSR, 256>>>(x, t, lg, lbe, x, ah, al);

        gemm_bf16x3<true, true><<<gf, 256, GEMM_SMEM_BYTES>>>(
            ah, al, w1h + of, w1l + of, lb1, nullptr, hh, hl, BSR, FFD, DDIM);
        gemm_bf16x3<false, false><<<gp, 256, GEMM_SMEM_BYTES>>>(
            hh, hl, w2h + of, w2l + of, lb2, t, nullptr, nullptr, BSR, DDIM, FFD);

        float* xo = (l == LLAY - 1) ? out : x;
        bf16* nh = (l == LLAY - 1) ? nullptr : ah;
        bf16* nl = (l == LLAY - 1) ? nullptr : al;
        add_ln<<<BSR, 256>>>(x, t, lg, lbe, xo, nh, nl);
    }
}

// round 11
// speedup vs baseline: 3.7731x; 1.2138x over previous
#include <cuda_runtime.h>
#include <cuda_bf16.h>
#include <cuda_fp16.h>
#include <math.h>
#include <stdint.h>

// Problem constants
#define BB   2
#define SS   1024
#define DDIM 1024
#define HH   16
#define LLAY 4
#define FFD  2048
#define DKH  64
#define BSR  (BB*SS)   // 2048 rows
#define QD   (3*DDIM)  // fused QKV width

typedef __half hf16;

// ---------------- scratch (static device globals; no allocs allowed) ----------
__device__ float g_x  [BSR*DDIM];
__device__ float g_t  [BSR*DDIM];
__device__ float g_qkv[BSR*QD];

// fp16 weight planes, transposed to [N][K]
__device__ __align__(256) hf16 g_wqkvh[LLAY*3*DDIM*DDIM], g_wqkvl[LLAY*3*DDIM*DDIM];
__device__ __align__(256) hf16 g_woh[LLAY*DDIM*DDIM], g_wol[LLAY*DDIM*DDIM];
__device__ __align__(256) hf16 g_w1h[LLAY*DDIM*FFD],  g_w1l[LLAY*DDIM*FFD];
__device__ __align__(256) hf16 g_w2h[LLAY*FFD*DDIM],  g_w2l[LLAY*FFD*DDIM];
__device__ float g_bqkv[LLAY*QD];
// single fp16 activation planes (no lo — 2-pass scheme)
__device__ __align__(256) hf16 g_ah[BSR*DDIM];
__device__ __align__(256) hf16 g_hh[BSR*FFD];

// ---------------- helpers -----------------------------------------------------
__device__ __forceinline__ void mma16h(float* c, const uint32_t* a, const uint32_t* b) {
    asm volatile(
        "mma.sync.aligned.m16n8k16.row.col.f32.f16.f16.f32 "
        "{%0,%1,%2,%3}, {%4,%5,%6,%7}, {%8,%9}, {%0,%1,%2,%3};"
        : "+f"(c[0]), "+f"(c[1]), "+f"(c[2]), "+f"(c[3])
        : "r"(a[0]), "r"(a[1]), "r"(a[2]), "r"(a[3]), "r"(b[0]), "r"(b[1]));
}
__device__ __forceinline__ void ldsm4(uint32_t& r0, uint32_t& r1, uint32_t& r2,
                                      uint32_t& r3, uint32_t addr) {
    asm volatile("ldmatrix.sync.aligned.m8n8.x4.shared.b16 {%0,%1,%2,%3}, [%4];"
                 : "=r"(r0), "=r"(r1), "=r"(r2), "=r"(r3) : "r"(addr));
}
__device__ __forceinline__ void cp16(uint32_t* s, const void* g) {
    uint32_t sa = (uint32_t)__cvta_generic_to_shared(s);
    asm volatile("cp.async.cg.shared.global [%0], [%1], 16;" :: "r"(sa), "l"(g));
}
#define CP_COMMIT() asm volatile("cp.async.commit_group;")
#define CP_WAIT1()  asm volatile("cp.async.wait_group 1;" ::: "memory")

__device__ __forceinline__ uint32_t packhf(float a, float b) {
    __half2 p = __floats2half2_rn(a, b);
    return *(uint32_t*)&p;
}

// ---------------- embedding + (buggy-faithful) positional encoding ------------
__global__ void embed_pe(const int* __restrict__ tok, const float* __restrict__ emb) {
    int idx = blockIdx.x * 256 + threadIdx.x;
    int d  = idx & (DDIM - 1);
    int bs = idx >> 10;
    int b  = bs >> 10;
    int t  = tok[bs];
    int i2 = (d >> 1) << 1;
    float div = expf(-(float)i2 * (9.210340371976184f / (float)DDIM));
    float ang = (float)b * div;
    float pe  = (d & 1) ? cosf(ang) : sinf(ang);
    g_x[idx] = emb[(size_t)t * DDIM + d] + pe;
}

// ---------------- activation fp16 convert (after embed only) ------------------
__global__ __launch_bounds__(256)
void conv_a(const float* __restrict__ s, hf16* __restrict__ hi) {
    int i4 = (blockIdx.x * 256 + threadIdx.x) * 4;
    float4 v = *(const float4*)(s + i4);
    *(__half2*)(hi + i4)     = __floats2half2_rn(v.x, v.y);
    *(__half2*)(hi + i4 + 2) = __floats2half2_rn(v.z, v.w);
}

// ---------------- weight transpose + fp16 hi/lo split, all layers (z) --------
__global__ __launch_bounds__(256)
void split_w_t(const float* __restrict__ W0, hf16* __restrict__ th0,
               hf16* __restrict__ tl0, int K, int N, size_t ostride) {
    const size_t li = (size_t)blockIdx.z * K * N;
    const size_t lo = (size_t)blockIdx.z * ostride;
    const float* W = W0 + li;
    hf16* th = th0 + lo;
    hf16* tl = tl0 + lo;
    __shared__ float tile[32][33];
    const int n0 = blockIdx.x * 32, k0 = blockIdx.y * 32;
    const int tx = threadIdx.x & 31, ty = threadIdx.x >> 5;
#pragma unroll
    for (int i = 0; i < 32; i += 8)
        tile[ty + i][tx] = W[(size_t)(k0 + ty + i) * N + n0 + tx];
    __syncthreads();
#pragma unroll
    for (int i = 0; i < 32; i += 8) {
        int n = n0 + ty + i, k = k0 + tx;
        float v = tile[tx][ty + i];
        hf16 h = __float2half_rn(v);
        th[(size_t)n * K + k] = h;
        tl[(size_t)n * K + k] = __float2half_rn(v - __half2float(h));
    }
}

// ---------------- pack QKV biases ---------------------------------------------
__global__ void pack_bias(const float* __restrict__ bq, const float* __restrict__ bk,
                          const float* __restrict__ bv) {
    int l = blockIdx.y;
    int i = blockIdx.x * 256 + threadIdx.x;
    float v = (i < DDIM) ? bq[l * DDIM + i]
            : (i < 2 * DDIM) ? bk[l * DDIM + i - DDIM]
            : bv[l * DDIM + i - 2 * DDIM];
    g_bqkv[l * QD + i] = v;
}

// ---------------- fp16 2-pass GEMM: C = A @ (Bh+Bl)^T + bias ------------------
// A single fp16 plane [M][K]; B fp16 hi/lo [N][K]. BM=BN=128, BK=32, 256 thr.
// dyn smem: 3 planes x 2 stages x 128 rows x 20 words = 60 KB.
#define G2_PLANE 5120
#define G2_STAGE 2560
#define G2_SMEM  (3 * G2_PLANE * 4)

__device__ __forceinline__ void g2_copy_stage(
    uint32_t* sm, const hf16* __restrict__ Ah, const hf16* __restrict__ Bh,
    const hf16* __restrict__ Bl, int m0, int n0, int K, int k0, int s, int tid) {
#pragma unroll
    for (int e = 0; e < 2; e++) {
        int c = tid + e * 256;
        int row = c >> 2, cw = (c & 3) << 2;
        int kk  = k0 + ((c & 3) << 3);
        size_t gb = (size_t)(n0 + row) * K + kk;
        int so = s * G2_STAGE + row * 20 + cw;
        cp16(sm + 0 * G2_PLANE + so, Ah + (size_t)(m0 + row) * K + kk);
        cp16(sm + 1 * G2_PLANE + so, Bh + gb);
        cp16(sm + 2 * G2_PLANE + so, Bl + gb);
    }
}

template<bool RELU, bool PLANES>
__global__ __launch_bounds__(256, 2)
void gemm_hf2(const hf16* __restrict__ Ah, const hf16* __restrict__ Bh,
              const hf16* __restrict__ Bl, const float* __restrict__ bias,
              float* __restrict__ C, hf16* __restrict__ Chf,
              int M, int N, int K) {
    extern __shared__ uint32_t sm[];
    const int tid  = threadIdx.x;
    const int wid  = tid >> 5, lane = tid & 31;
    const int gid  = lane >> 2, tig = lane & 3;
    const int wm   = wid >> 2, wn = wid & 3;
    const int m0   = blockIdx.y * 128, n0 = blockIdx.x * 128;
    const uint32_t sbase = (uint32_t)__cvta_generic_to_shared(sm);

    const int lr  = lane & 7;
    const int lg1 = (lane >> 3) & 1;
    const int lg2 = (lane >> 4) & 1;
    int rowA[4], rowB[2];
#pragma unroll
    for (int mt = 0; mt < 4; mt++) rowA[mt] = wm * 64 + mt * 16 + lg1 * 8 + lr;
#pragma unroll
    for (int np = 0; np < 2; np++) rowB[np] = wn * 32 + np * 16 + lg2 * 8 + lr;
    const int kA = lg2 * 4, kB = lg1 * 4;

    float acc[4][4][4];
#pragma unroll
    for (int mt = 0; mt < 4; mt++)
#pragma unroll
        for (int nt = 0; nt < 4; nt++)
#pragma unroll
            for (int i = 0; i < 4; i++) acc[mt][nt][i] = 0.f;

    g2_copy_stage(sm, Ah, Bh, Bl, m0, n0, K, 0, 0, tid);
    CP_COMMIT();
    g2_copy_stage(sm, Ah, Bh, Bl, m0, n0, K, 32, 1, tid);
    CP_COMMIT();

    for (int k0 = 0; k0 < K; k0 += 32) {
        const int s = (k0 >> 5) & 1;
        CP_WAIT1();
        __syncthreads();

        const uint32_t aA  = sbase + (0 * G2_PLANE + s * G2_STAGE) * 4;
        const uint32_t aBH = sbase + (1 * G2_PLANE + s * G2_STAGE) * 4;
        const uint32_t aBL = sbase + (2 * G2_PLANE + s * G2_STAGE) * 4;
#pragma unroll
        for (int sb = 0; sb < 2; sb++) {
            const int kb = sb * 8;
            uint32_t a4[4][4], bh4[4][2], bl4[4][2];
#pragma unroll
            for (int mt = 0; mt < 4; mt++) {
                uint32_t off = (uint32_t)(rowA[mt] * 20 + kb + kA) * 4;
                ldsm4(a4[mt][0], a4[mt][1], a4[mt][2], a4[mt][3], aA + off);
            }
#pragma unroll
            for (int np = 0; np < 2; np++) {
                uint32_t off = (uint32_t)(rowB[np] * 20 + kb + kB) * 4;
                ldsm4(bh4[2*np][0], bh4[2*np][1], bh4[2*np+1][0], bh4[2*np+1][1],
                      aBH + off);
                ldsm4(bl4[2*np][0], bl4[2*np][1], bl4[2*np+1][0], bl4[2*np+1][1],
                      aBL + off);
            }
#pragma unroll
            for (int mt = 0; mt < 4; mt++)
#pragma unroll
                for (int nt = 0; nt < 4; nt++) {
                    mma16h(acc[mt][nt], a4[mt], bl4[nt]);
                    mma16h(acc[mt][nt], a4[mt], bh4[nt]);
                }
        }
        __syncthreads();
        if (k0 + 64 < K)
            g2_copy_stage(sm, Ah, Bh, Bl, m0, n0, K, k0 + 64, s, tid);
        CP_COMMIT();
    }

#pragma unroll
    for (int mt = 0; mt < 4; mt++) {
        int r0 = m0 + wm * 64 + mt * 16 + gid;
#pragma unroll
        for (int nt = 0; nt < 4; nt++) {
            int c = n0 + wn * 32 + nt * 8 + (tig << 1);
            float b0 = bias[c], b1 = bias[c + 1];
            float2 o0 = make_float2(acc[mt][nt][0] + b0, acc[mt][nt][1] + b1);
            float2 o1 = make_float2(acc[mt][nt][2] + b0, acc[mt][nt][3] + b1);
            if (RELU) {
                o0.x = fmaxf(o0.x, 0.f); o0.y = fmaxf(o0.y, 0.f);
                o1.x = fmaxf(o1.x, 0.f); o1.y = fmaxf(o1.y, 0.f);
            }
            if (PLANES) {
                *(__half2*)(Chf + (size_t)r0 * N + c) =
                    __floats2half2_rn(o0.x, o0.y);
                *(__half2*)(Chf + (size_t)(r0 + 8) * N + c) =
                    __floats2half2_rn(o1.x, o1.y);
            } else {
                *(float2*)(C + (size_t)r0 * N + c)       = o0;
                *(float2*)(C + (size_t)(r0 + 8) * N + c) = o1;
            }
        }
    }
}

// ---------------- fused flash attention (fp16 mma, P in registers) ------------
__global__ __launch_bounds__(256, 2)
void flash_attn(const float* __restrict__ qkv) {
    __shared__ uint32_t Qs[128][36];
    __shared__ uint32_t Ks[64][36];
    __shared__ uint32_t Vs[64][36];   // [dim][key-pair]

    const int z = blockIdx.y, b = z >> 4, h = z & 15;
    const int i0 = blockIdx.x * 128;
    const float* Qg = qkv + (size_t)b * SS * QD + h * DKH;
    const float* Kg = Qg + DDIM;
    const float* Vg = Qg + 2 * DDIM;
    hf16* Oh = g_ah + (size_t)b * SS * DDIM + h * DKH;

    const int tid = threadIdx.x;
    const int wid = tid >> 5, lane = tid & 31;
    const int gid = lane >> 2, tig = lane & 3;
    const int mb  = wid * 16;

#pragma unroll
    for (int e = 0; e < 8; e++) {
        int idx = tid + e * 256;
        int row = idx >> 4, c4 = (idx & 15) << 2;
        float4 vq = *(const float4*)(Qg + (size_t)(i0 + row) * QD + c4);
        Qs[row][c4 >> 1]       = packhf(vq.x * 0.125f, vq.y * 0.125f);
        Qs[row][(c4 >> 1) + 1] = packhf(vq.z * 0.125f, vq.w * 0.125f);
    }

    float acco[8][4];
#pragma unroll
    for (int nt = 0; nt < 8; nt++)
#pragma unroll
        for (int i = 0; i < 4; i++) acco[nt][i] = 0.f;
    float m_lo = -1e30f, m_hi = -1e30f, l_lo = 0.f, l_hi = 0.f;

    for (int j0 = 0; j0 < SS; j0 += 64) {
        __syncthreads();
#pragma unroll
        for (int e = 0; e < 4; e++) {
            int idx = tid + e * 256;
            int row = idx >> 4, c4 = (idx & 15) << 2;
            float4 kk = *(const float4*)(Kg + (size_t)(j0 + row) * QD + c4);
            float4 vv = *(const float4*)(Vg + (size_t)(j0 + row) * QD + c4);
            Ks[row][c4 >> 1]       = packhf(kk.x, kk.y);
            Ks[row][(c4 >> 1) + 1] = packhf(kk.z, kk.w);
            ((hf16*)&Vs[c4 + 0][0])[row] = __float2half_rn(vv.x);
            ((hf16*)&Vs[c4 + 1][0])[row] = __float2half_rn(vv.y);
            ((hf16*)&Vs[c4 + 2][0])[row] = __float2half_rn(vv.z);
            ((hf16*)&Vs[c4 + 3][0])[row] = __float2half_rn(vv.w);
        }
        __syncthreads();

        float accs[8][4];
#pragma unroll
        for (int nt = 0; nt < 8; nt++)
#pragma unroll
            for (int i = 0; i < 4; i++) accs[nt][i] = 0.f;
#pragma unroll
        for (int ks = 0; ks < 64; ks += 16) {
            const int w = ks >> 1;
            uint32_t a[4];
            a[0] = Qs[mb + gid][w + tig];     a[1] = Qs[mb + gid + 8][w + tig];
            a[2] = Qs[mb + gid][w + tig + 4]; a[3] = Qs[mb + gid + 8][w + tig + 4];
#pragma unroll
            for (int nt = 0; nt < 8; nt++) {
                uint32_t bb[2];
                bb[0] = Ks[nt * 8 + gid][w + tig];
                bb[1] = Ks[nt * 8 + gid][w + tig + 4];
                mma16h(accs[nt], a, bb);
            }
        }

        float mx_lo = -1e30f, mx_hi = -1e30f;
#pragma unroll
        for (int nt = 0; nt < 8; nt++) {
            mx_lo = fmaxf(mx_lo, fmaxf(accs[nt][0], accs[nt][1]));
            mx_hi = fmaxf(mx_hi, fmaxf(accs[nt][2], accs[nt][3]));
        }
        mx_lo = fmaxf(mx_lo, __shfl_xor_sync(~0u, mx_lo, 1));
        mx_lo = fmaxf(mx_lo, __shfl_xor_sync(~0u, mx_lo, 2));
        mx_hi = fmaxf(mx_hi, __shfl_xor_sync(~0u, mx_hi, 1));
        mx_hi = fmaxf(mx_hi, __shfl_xor_sync(~0u, mx_hi, 2));
        float mn_lo = fmaxf(m_lo, mx_lo), mn_hi = fmaxf(m_hi, mx_hi);
        float al_lo = __expf(m_lo - mn_lo), al_hi = __expf(m_hi - mn_hi);
        m_lo = mn_lo; m_hi = mn_hi;

        float sum_lo = 0.f, sum_hi = 0.f;
#pragma unroll
        for (int nt = 0; nt < 8; nt++) {
            accs[nt][0] = __expf(accs[nt][0] - m_lo);
            accs[nt][1] = __expf(accs[nt][1] - m_lo);
            accs[nt][2] = __expf(accs[nt][2] - m_hi);
            accs[nt][3] = __expf(accs[nt][3] - m_hi);
            sum_lo += accs[nt][0] + accs[nt][1];
            sum_hi += accs[nt][2] + accs[nt][3];
        }
        sum_lo += __shfl_xor_sync(~0u, sum_lo, 1);
        sum_lo += __shfl_xor_sync(~0u, sum_lo, 2);
        sum_hi += __shfl_xor_sync(~0u, sum_hi, 1);
        sum_hi += __shfl_xor_sync(~0u, sum_hi, 2);
        l_lo = l_lo * al_lo + sum_lo;
        l_hi = l_hi * al_hi + sum_hi;

#pragma unroll
        for (int nt = 0; nt < 8; nt++) {
            acco[nt][0] *= al_lo; acco[nt][1] *= al_lo;
            acco[nt][2] *= al_hi; acco[nt][3] *= al_hi;
        }

#pragma unroll
        for (int s = 0; s < 4; s++) {
            uint32_t a[4];
            a[0] = packhf(accs[2*s][0],     accs[2*s][1]);
            a[1] = packhf(accs[2*s][2],     accs[2*s][3]);
            a[2] = packhf(accs[2*s + 1][0], accs[2*s + 1][1]);
            a[3] = packhf(accs[2*s + 1][2], accs[2*s + 1][3]);
#pragma unroll
            for (int nt = 0; nt < 8; nt++) {
                uint32_t bb[2];
                bb[0] = Vs[nt * 8 + gid][s * 8 + tig];
                bb[1] = Vs[nt * 8 + gid][s * 8 + tig + 4];
                mma16h(acco[nt], a, bb);
            }
        }
    }

    const float inv_lo = 1.0f / l_lo, inv_hi = 1.0f / l_hi;
#pragma unroll
    for (int nt = 0; nt < 8; nt++) {
        int c = nt * 8 + (tig << 1);
        size_t r0 = (size_t)(i0 + mb + gid) * DDIM + c;
        size_t r1 = (size_t)(i0 + mb + gid + 8) * DDIM + c;
        *(__half2*)(Oh + r0) = __floats2half2_rn(acco[nt][0] * inv_lo,
                                                 acco[nt][1] * inv_lo);
        *(__half2*)(Oh + r1) = __floats2half2_rn(acco[nt][2] * inv_hi,
                                                 acco[nt][3] * inv_hi);
    }
}

// ---------------- add + LayerNorm (+ optional fp16 plane output) -------------
__global__ __launch_bounds__(256)
void add_ln(const float* __restrict__ x, const float* __restrict__ y,
            const float* __restrict__ g, const float* __restrict__ be,
            float* __restrict__ out, hf16* __restrict__ hi) {
    __shared__ float sm[8];
    __shared__ float bc;
    const int tid = threadIdx.x;
    const size_t ro = (size_t)blockIdx.x * DDIM;
    float4 a = reinterpret_cast<const float4*>(x + ro)[tid];
    float4 b = reinterpret_cast<const float4*>(y + ro)[tid];
    a.x += b.x; a.y += b.y; a.z += b.z; a.w += b.w;

    float s = a.x + a.y + a.z + a.w;
#pragma unroll
    for (int o = 16; o; o >>= 1) s += __shfl_xor_sync(~0u, s, o);
    if ((tid & 31) == 0) sm[tid >> 5] = s;
    __syncthreads();
    if (tid < 32) {
        float t = (tid < 8) ? sm[tid] : 0.f;
#pragma unroll
        for (int o = 4; o; o >>= 1) t += __shfl_xor_sync(~0u, t, o);
        if (tid == 0) bc = t;
    }
    __syncthreads();
    const float mu = bc * (1.0f / DDIM);
    a.x -= mu; a.y -= mu; a.z -= mu; a.w -= mu;
    float qv = a.x*a.x + a.y*a.y + a.z*a.z + a.w*a.w;
    __syncthreads();
#pragma unroll
    for (int o = 16; o; o >>= 1) qv += __shfl_xor_sync(~0u, qv, o);
    if ((tid & 31) == 0) sm[tid >> 5] = qv;
    __syncthreads();
    if (tid < 32) {
        float t = (tid < 8) ? sm[tid] : 0.f;
#pragma unroll
        for (int o = 4; o; o >>= 1) t += __shfl_xor_sync(~0u, t, o);
        if (tid == 0) bc = t;
    }
    __syncthreads();
    const float rs = rsqrtf(bc * (1.0f / DDIM) + 1e-5f);
    float4 gv = reinterpret_cast<const float4*>(g)[tid];
    float4 bv = reinterpret_cast<const float4*>(be)[tid];
    float4 o;
    o.x = a.x * rs * gv.x + bv.x;
    o.y = a.y * rs * gv.y + bv.y;
    o.z = a.z * rs * gv.z + bv.z;
    o.w = a.w * rs * gv.w + bv.w;
    reinterpret_cast<float4*>(out + ro)[tid] = o;
    if (hi) {
        size_t i4 = ro + tid * 4;
        *(__half2*)(hi + i4)     = __floats2half2_rn(o.x, o.y);
        *(__half2*)(hi + i4 + 2) = __floats2half2_rn(o.z, o.w);
    }
}

// ---------------- launch ------------------------------------------------------
extern "C" void kernel_launch(void* const* d_in, const int* in_sizes, int n_in,
                              void* d_out, int out_size) {
    const int*   tokens = (const int*)  d_in[0];
    const float* emb    = (const float*)d_in[1];
    const float* Wq = (const float*)d_in[2],  *bq = (const float*)d_in[3];
    const float* Wk = (const float*)d_in[4],  *bk = (const float*)d_in[5];
    const float* Wv = (const float*)d_in[6],  *bv = (const float*)d_in[7];
    const float* Wo = (const float*)d_in[8],  *bo = (const float*)d_in[9];
    const float* W1 = (const float*)d_in[10], *b1 = (const float*)d_in[11];
    const float* W2 = (const float*)d_in[12], *b2 = (const float*)d_in[13];
    const float* gamma = (const float*)d_in[14], *beta = (const float*)d_in[15];
    float* out = (float*)d_out;

    float *x, *t, *qkv, *bqkv;
    cudaGetSymbolAddress((void**)&x,    g_x);
    cudaGetSymbolAddress((void**)&t,    g_t);
    cudaGetSymbolAddress((void**)&qkv,  g_qkv);
    cudaGetSymbolAddress((void**)&bqkv, g_bqkv);
    hf16 *wqkvh,*wqkvl,*woh,*wol,*w1h,*w1l,*w2h,*w2l,*ah,*hh;
    cudaGetSymbolAddress((void**)&wqkvh, g_wqkvh);
    cudaGetSymbolAddress((void**)&wqkvl, g_wqkvl);
    cudaGetSymbolAddress((void**)&woh, g_woh); cudaGetSymbolAddress((void**)&wol, g_wol);
    cudaGetSymbolAddress((void**)&w1h, g_w1h); cudaGetSymbolAddress((void**)&w1l, g_w1l);
    cudaGetSymbolAddress((void**)&w2h, g_w2h); cudaGetSymbolAddress((void**)&w2l, g_w2l);
    cudaGetSymbolAddress((void**)&ah,  g_ah);  cudaGetSymbolAddress((void**)&hh,  g_hh);

    cudaFuncSetAttribute(gemm_hf2<false, false>,
                         cudaFuncAttributeMaxDynamicSharedMemorySize, G2_SMEM);
    cudaFuncSetAttribute(gemm_hf2<true, true>,
                         cudaFuncAttributeMaxDynamicSharedMemorySize, G2_SMEM);

    embed_pe<<<BSR * DDIM / 256, 256>>>(tokens, emb);
    conv_a<<<BSR * DDIM / 1024, 256>>>(x, ah);

    // weight conversion
    const size_t DD = (size_t)DDIM * DDIM, DF = (size_t)DDIM * FFD;
    split_w_t<<<dim3(DDIM / 32, DDIM / 32, LLAY), 256>>>(Wq, wqkvh,          wqkvl,          DDIM, DDIM, 3 * DD);
    split_w_t<<<dim3(DDIM / 32, DDIM / 32, LLAY), 256>>>(Wk, wqkvh + DD,     wqkvl + DD,     DDIM, DDIM, 3 * DD);
    split_w_t<<<dim3(DDIM / 32, DDIM / 32, LLAY), 256>>>(Wv, wqkvh + 2 * DD, wqkvl + 2 * DD, DDIM, DDIM, 3 * DD);
    split_w_t<<<dim3(DDIM / 32, DDIM / 32, LLAY), 256>>>(Wo, woh, wol, DDIM, DDIM, DD);
    split_w_t<<<dim3(FFD  / 32, DDIM / 32, LLAY), 256>>>(W1, w1h, w1l, DDIM, FFD, DF);
    split_w_t<<<dim3(DDIM / 32, FFD  / 32, LLAY), 256>>>(W2, w2h, w2l, FFD, DDIM, DF);
    pack_bias<<<dim3(QD / 256, LLAY), 256>>>(bq, bk, bv);

    const dim3 gqkv(QD  / 128, BSR / 128);  // 24 x 16
    const dim3 gp(DDIM / 128, BSR / 128);
    const dim3 gf(FFD  / 128, BSR / 128);

    for (int l = 0; l < LLAY; l++) {
        size_t od = (size_t)l * DD, of = (size_t)l * DF;
        const float* lbo = bo + (size_t)l * DDIM;
        const float* lb1 = b1 + (size_t)l * FFD;
        const float* lb2 = b2 + (size_t)l * DDIM;
        const float* lg  = gamma + (size_t)l * DDIM;
        const float* lbe = beta  + (size_t)l * DDIM;

        gemm_hf2<false, false><<<gqkv, 256, G2_SMEM>>>(
            ah, wqkvh + (size_t)l * 3 * DD, wqkvl + (size_t)l * 3 * DD,
            bqkv + (size_t)l * QD, qkv, nullptr, BSR, QD, DDIM);

        flash_attn<<<dim3(SS / 128, BB * HH), 256>>>(qkv);

        gemm_hf2<false, false><<<gp, 256, G2_SMEM>>>(
            ah, woh + od, wol + od, lbo, t, nullptr, BSR, DDIM, DDIM);
        add_ln<<<BSR, 256>>>(x, t, lg, lbe, x, ah);

        gemm_hf2<true, true><<<gf, 256, G2_SMEM>>>(
            ah, w1h + of, w1l + of, lb1, nullptr, hh, BSR, FFD, DDIM);
        gemm_hf2<false, false><<<gp, 256, G2_SMEM>>>(
            hh, w2h + of, w2l + of, lb2, t, nullptr, BSR, DDIM, FFD);

        float* xo = (l == LLAY - 1) ? out : x;
        hf16* nh = (l == LLAY - 1) ? nullptr : ah;
        add_ln<<<BSR, 256>>>(x, t, lg, lbe, xo, nh);
    }
}

// round 12
// speedup vs baseline: 4.0767x; 1.0805x over previous
#include <cuda_runtime.h>
#include <cuda_bf16.h>
#include <cuda_fp16.h>
#include <math.h>
#include <stdint.h>

// Problem constants
#define BB   2
#define SS   1024
#define DDIM 1024
#define HH   16
#define LLAY 4
#define FFD  2048
#define DKH  64
#define BSR  (BB*SS)   // 2048 rows
#define QD   (3*DDIM)  // fused QKV width

typedef __half hf16;

// ---------------- scratch (static device globals; no allocs allowed) ----------
__device__ float g_x  [BSR*DDIM];
__device__ float g_t  [BSR*DDIM];
__device__ __align__(256) hf16 g_qkv[BSR*QD];   // fp16, Q pre-scaled by 1/8

// fp16 weight planes, transposed to [N][K]
__device__ __align__(256) hf16 g_wqkvh[LLAY*3*DDIM*DDIM];     // hi only (1-pass)
__device__ __align__(256) hf16 g_woh[LLAY*DDIM*DDIM], g_wol[LLAY*DDIM*DDIM];
__device__ __align__(256) hf16 g_w1h[LLAY*DDIM*FFD],  g_w1l[LLAY*DDIM*FFD];
__device__ __align__(256) hf16 g_w2h[LLAY*FFD*DDIM],  g_w2l[LLAY*FFD*DDIM];
__device__ float g_bqkv[LLAY*QD];
// single fp16 activation planes
__device__ __align__(256) hf16 g_ah[BSR*DDIM];
__device__ __align__(256) hf16 g_hh[BSR*FFD];

// ---------------- helpers -----------------------------------------------------
__device__ __forceinline__ void mma16h(float* c, const uint32_t* a, const uint32_t* b) {
    asm volatile(
        "mma.sync.aligned.m16n8k16.row.col.f32.f16.f16.f32 "
        "{%0,%1,%2,%3}, {%4,%5,%6,%7}, {%8,%9}, {%0,%1,%2,%3};"
        : "+f"(c[0]), "+f"(c[1]), "+f"(c[2]), "+f"(c[3])
        : "r"(a[0]), "r"(a[1]), "r"(a[2]), "r"(a[3]), "r"(b[0]), "r"(b[1]));
}
__device__ __forceinline__ void ldsm4(uint32_t& r0, uint32_t& r1, uint32_t& r2,
                                      uint32_t& r3, uint32_t addr) {
    asm volatile("ldmatrix.sync.aligned.m8n8.x4.shared.b16 {%0,%1,%2,%3}, [%4];"
                 : "=r"(r0), "=r"(r1), "=r"(r2), "=r"(r3) : "r"(addr));
}
__device__ __forceinline__ void cp16(uint32_t* s, const void* g) {
    uint32_t sa = (uint32_t)__cvta_generic_to_shared(s);
    asm volatile("cp.async.cg.shared.global [%0], [%1], 16;" :: "r"(sa), "l"(g));
}
#define CP_COMMIT() asm volatile("cp.async.commit_group;")
#define CP_WAIT1()  asm volatile("cp.async.wait_group 1;" ::: "memory")

__device__ __forceinline__ uint32_t packhf(float a, float b) {
    __half2 p = __floats2half2_rn(a, b);
    return *(uint32_t*)&p;
}

// ---------------- embedding + (buggy-faithful) positional encoding ------------
__global__ void embed_pe(const int* __restrict__ tok, const float* __restrict__ emb) {
    int idx = blockIdx.x * 256 + threadIdx.x;
    int d  = idx & (DDIM - 1);
    int bs = idx >> 10;
    int b  = bs >> 10;
    int t  = tok[bs];
    int i2 = (d >> 1) << 1;
    float div = expf(-(float)i2 * (9.210340371976184f / (float)DDIM));
    float ang = (float)b * div;
    float pe  = (d & 1) ? cosf(ang) : sinf(ang);
    g_x[idx] = emb[(size_t)t * DDIM + d] + pe;
}

// ---------------- activation fp16 convert (after embed only) ------------------
__global__ __launch_bounds__(256)
void conv_a(const float* __restrict__ s, hf16* __restrict__ hi) {
    int i4 = (blockIdx.x * 256 + threadIdx.x) * 4;
    float4 v = *(const float4*)(s + i4);
    *(__half2*)(hi + i4)     = __floats2half2_rn(v.x, v.y);
    *(__half2*)(hi + i4 + 2) = __floats2half2_rn(v.z, v.w);
}

// ---------------- weight transpose + fp16 hi/lo split, all layers (z) --------
__global__ __launch_bounds__(256)
void split_w_t(const float* __restrict__ W0, hf16* __restrict__ th0,
               hf16* __restrict__ tl0, int K, int N, size_t ostride) {
    const size_t li = (size_t)blockIdx.z * K * N;
    const size_t lo = (size_t)blockIdx.z * ostride;
    const float* W = W0 + li;
    hf16* th = th0 + lo;
    hf16* tl = tl0 ? tl0 + lo : nullptr;
    __shared__ float tile[32][33];
    const int n0 = blockIdx.x * 32, k0 = blockIdx.y * 32;
    const int tx = threadIdx.x & 31, ty = threadIdx.x >> 5;
#pragma unroll
    for (int i = 0; i < 32; i += 8)
        tile[ty + i][tx] = W[(size_t)(k0 + ty + i) * N + n0 + tx];
    __syncthreads();
#pragma unroll
    for (int i = 0; i < 32; i += 8) {
        int n = n0 + ty + i, k = k0 + tx;
        float v = tile[tx][ty + i];
        hf16 h = __float2half_rn(v);
        th[(size_t)n * K + k] = h;
        if (tl) tl[(size_t)n * K + k] = __float2half_rn(v - __half2float(h));
    }
}

// ---------------- pack QKV biases ---------------------------------------------
__global__ void pack_bias(const float* __restrict__ bq, const float* __restrict__ bk,
                          const float* __restrict__ bv) {
    int l = blockIdx.y;
    int i = blockIdx.x * 256 + threadIdx.x;
    float v = (i < DDIM) ? bq[l * DDIM + i]
            : (i < 2 * DDIM) ? bk[l * DDIM + i - DDIM]
            : bv[l * DDIM + i - 2 * DDIM];
    g_bqkv[l * QD + i] = v;
}

// ---------------- fp16 1-pass GEMM (QKV): fp16 out, Q cols pre-scaled --------
#define G1_PLANE 5120
#define G1_STAGE 2560
#define G1_SMEM  (2 * G1_PLANE * 4)   // 40 KB

__device__ __forceinline__ void g1_copy_stage(
    uint32_t* sm, const hf16* __restrict__ Ah, const hf16* __restrict__ Bh,
    int m0, int n0, int K, int k0, int s, int tid) {
#pragma unroll
    for (int e = 0; e < 2; e++) {
        int c = tid + e * 256;
        int row = c >> 2, cw = (c & 3) << 2;
        int kk  = k0 + ((c & 3) << 3);
        int so = s * G1_STAGE + row * 20 + cw;
        cp16(sm + 0 * G1_PLANE + so, Ah + (size_t)(m0 + row) * K + kk);
        cp16(sm + 1 * G1_PLANE + so, Bh + (size_t)(n0 + row) * K + kk);
    }
}

__global__ __launch_bounds__(256, 3)
void gemm_hf1_qkv(const hf16* __restrict__ Ah, const hf16* __restrict__ Bh,
                  const float* __restrict__ bias, hf16* __restrict__ Chf,
                  int M, int N, int K) {
    extern __shared__ uint32_t sm[];
    const int tid  = threadIdx.x;
    const int wid  = tid >> 5, lane = tid & 31;
    const int gid  = lane >> 2, tig = lane & 3;
    const int wm   = wid >> 2, wn = wid & 3;
    const int m0   = blockIdx.y * 128, n0 = blockIdx.x * 128;
    const uint32_t sbase = (uint32_t)__cvta_generic_to_shared(sm);

    const int lr  = lane & 7;
    const int lg1 = (lane >> 3) & 1;
    const int lg2 = (lane >> 4) & 1;
    int rowA[4], rowB[2];
#pragma unroll
    for (int mt = 0; mt < 4; mt++) rowA[mt] = wm * 64 + mt * 16 + lg1 * 8 + lr;
#pragma unroll
    for (int np = 0; np < 2; np++) rowB[np] = wn * 32 + np * 16 + lg2 * 8 + lr;
    const int kA = lg2 * 4, kB = lg1 * 4;

    float acc[4][4][4];
#pragma unroll
    for (int mt = 0; mt < 4; mt++)
#pragma unroll
        for (int nt = 0; nt < 4; nt++)
#pragma unroll
            for (int i = 0; i < 4; i++) acc[mt][nt][i] = 0.f;

    g1_copy_stage(sm, Ah, Bh, m0, n0, K, 0, 0, tid);
    CP_COMMIT();
    g1_copy_stage(sm, Ah, Bh, m0, n0, K, 32, 1, tid);
    CP_COMMIT();

    for (int k0 = 0; k0 < K; k0 += 32) {
        const int s = (k0 >> 5) & 1;
        CP_WAIT1();
        __syncthreads();

        const uint32_t aA = sbase + (0 * G1_PLANE + s * G1_STAGE) * 4;
        const uint32_t aB = sbase + (1 * G1_PLANE + s * G1_STAGE) * 4;
#pragma unroll
        for (int sb = 0; sb < 2; sb++) {
            const int kb = sb * 8;
            uint32_t a4[4][4], b4[4][2];
#pragma unroll
            for (int mt = 0; mt < 4; mt++) {
                uint32_t off = (uint32_t)(rowA[mt] * 20 + kb + kA) * 4;
                ldsm4(a4[mt][0], a4[mt][1], a4[mt][2], a4[mt][3], aA + off);
            }
#pragma unroll
            for (int np = 0; np < 2; np++) {
                uint32_t off = (uint32_t)(rowB[np] * 20 + kb + kB) * 4;
                ldsm4(b4[2*np][0], b4[2*np][1], b4[2*np+1][0], b4[2*np+1][1],
                      aB + off);
            }
#pragma unroll
            for (int mt = 0; mt < 4; mt++)
#pragma unroll
                for (int nt = 0; nt < 4; nt++)
                    mma16h(acc[mt][nt], a4[mt], b4[nt]);
        }
        __syncthreads();
        if (k0 + 64 < K)
            g1_copy_stage(sm, Ah, Bh, m0, n0, K, k0 + 64, s, tid);
        CP_COMMIT();
    }

#pragma unroll
    for (int mt = 0; mt < 4; mt++) {
        int r0 = m0 + wm * 64 + mt * 16 + gid;
#pragma unroll
        for (int nt = 0; nt < 4; nt++) {
            int c = n0 + wn * 32 + nt * 8 + (tig << 1);
            float sc = (c < DDIM) ? 0.125f : 1.0f;   // pre-scale Q by 1/sqrt(dk)/... = 1/8
            float b0 = bias[c], b1 = bias[c + 1];
            *(__half2*)(Chf + (size_t)r0 * N + c) =
                __floats2half2_rn((acc[mt][nt][0] + b0) * sc,
                                  (acc[mt][nt][1] + b1) * sc);
            *(__half2*)(Chf + (size_t)(r0 + 8) * N + c) =
                __floats2half2_rn((acc[mt][nt][2] + b0) * sc,
                                  (acc[mt][nt][3] + b1) * sc);
        }
    }
}

// ---------------- fp16 2-pass GEMM: C = A @ (Bh+Bl)^T + bias ------------------
#define G2_PLANE 5120
#define G2_STAGE 2560
#define G2_SMEM  (3 * G2_PLANE * 4)

__device__ __forceinline__ void g2_copy_stage(
    uint32_t* sm, const hf16* __restrict__ Ah, const hf16* __restrict__ Bh,
    const hf16* __restrict__ Bl, int m0, int n0, int K, int k0, int s, int tid) {
#pragma unroll
    for (int e = 0; e < 2; e++) {
        int c = tid + e * 256;
        int row = c >> 2, cw = (c & 3) << 2;
        int kk  = k0 + ((c & 3) << 3);
        size_t gb = (size_t)(n0 + row) * K + kk;
        int so = s * G2_STAGE + row * 20 + cw;
        cp16(sm + 0 * G2_PLANE + so, Ah + (size_t)(m0 + row) * K + kk);
        cp16(sm + 1 * G2_PLANE + so, Bh + gb);
        cp16(sm + 2 * G2_PLANE + so, Bl + gb);
    }
}

template<bool RELU, bool PLANES>
__global__ __launch_bounds__(256, 2)
void gemm_hf2(const hf16* __restrict__ Ah, const hf16* __restrict__ Bh,
              const hf16* __restrict__ Bl, const float* __restrict__ bias,
              float* __restrict__ C, hf16* __restrict__ Chf,
              int M, int N, int K) {
    extern __shared__ uint32_t sm[];
    const int tid  = threadIdx.x;
    const int wid  = tid >> 5, lane = tid & 31;
    const int gid  = lane >> 2, tig = lane & 3;
    const int wm   = wid >> 2, wn = wid & 3;
    const int m0   = blockIdx.y * 128, n0 = blockIdx.x * 128;
    const uint32_t sbase = (uint32_t)__cvta_generic_to_shared(sm);

    const int lr  = lane & 7;
    const int lg1 = (lane >> 3) & 1;
    const int lg2 = (lane >> 4) & 1;
    int rowA[4], rowB[2];
#pragma unroll
    for (int mt = 0; mt < 4; mt++) rowA[mt] = wm * 64 + mt * 16 + lg1 * 8 + lr;
#pragma unroll
    for (int np = 0; np < 2; np++) rowB[np] = wn * 32 + np * 16 + lg2 * 8 + lr;
    const int kA = lg2 * 4, kB = lg1 * 4;

    float acc[4][4][4];
#pragma unroll
    for (int mt = 0; mt < 4; mt++)
#pragma unroll
        for (int nt = 0; nt < 4; nt++)
#pragma unroll
            for (int i = 0; i < 4; i++) acc[mt][nt][i] = 0.f;

    g2_copy_stage(sm, Ah, Bh, Bl, m0, n0, K, 0, 0, tid);
    CP_COMMIT();
    g2_copy_stage(sm, Ah, Bh, Bl, m0, n0, K, 32, 1, tid);
    CP_COMMIT();

    for (int k0 = 0; k0 < K; k0 += 32) {
        const int s = (k0 >> 5) & 1;
        CP_WAIT1();
        __syncthreads();

        const uint32_t aA  = sbase + (0 * G2_PLANE + s * G2_STAGE) * 4;
        const uint32_t aBH = sbase + (1 * G2_PLANE + s * G2_STAGE) * 4;
        const uint32_t aBL = sbase + (2 * G2_PLANE + s * G2_STAGE) * 4;
#pragma unroll
        for (int sb = 0; sb < 2; sb++) {
            const int kb = sb * 8;
            uint32_t a4[4][4], bh4[4][2], bl4[4][2];
#pragma unroll
            for (int mt = 0; mt < 4; mt++) {
                uint32_t off = (uint32_t)(rowA[mt] * 20 + kb + kA) * 4;
                ldsm4(a4[mt][0], a4[mt][1], a4[mt][2], a4[mt][3], aA + off);
            }
#pragma unroll
            for (int np = 0; np < 2; np++) {
                uint32_t off = (uint32_t)(rowB[np] * 20 + kb + kB) * 4;
                ldsm4(bh4[2*np][0], bh4[2*np][1], bh4[2*np+1][0], bh4[2*np+1][1],
                      aBH + off);
                ldsm4(bl4[2*np][0], bl4[2*np][1], bl4[2*np+1][0], bl4[2*np+1][1],
                      aBL + off);
            }
#pragma unroll
            for (int mt = 0; mt < 4; mt++)
#pragma unroll
                for (int nt = 0; nt < 4; nt++) {
                    mma16h(acc[mt][nt], a4[mt], bl4[nt]);
                    mma16h(acc[mt][nt], a4[mt], bh4[nt]);
                }
        }
        __syncthreads();
        if (k0 + 64 < K)
            g2_copy_stage(sm, Ah, Bh, Bl, m0, n0, K, k0 + 64, s, tid);
        CP_COMMIT();
    }

#pragma unroll
    for (int mt = 0; mt < 4; mt++) {
        int r0 = m0 + wm * 64 + mt * 16 + gid;
#pragma unroll
        for (int nt = 0; nt < 4; nt++) {
            int c = n0 + wn * 32 + nt * 8 + (tig << 1);
            float b0 = bias[c], b1 = bias[c + 1];
            float2 o0 = make_float2(acc[mt][nt][0] + b0, acc[mt][nt][1] + b1);
            float2 o1 = make_float2(acc[mt][nt][2] + b0, acc[mt][nt][3] + b1);
            if (RELU) {
                o0.x = fmaxf(o0.x, 0.f); o0.y = fmaxf(o0.y, 0.f);
                o1.x = fmaxf(o1.x, 0.f); o1.y = fmaxf(o1.y, 0.f);
            }
            if (PLANES) {
                *(__half2*)(Chf + (size_t)r0 * N + c) =
                    __floats2half2_rn(o0.x, o0.y);
                *(__half2*)(Chf + (size_t)(r0 + 8) * N + c) =
                    __floats2half2_rn(o1.x, o1.y);
            } else {
                *(float2*)(C + (size_t)r0 * N + c)       = o0;
                *(float2*)(C + (size_t)(r0 + 8) * N + c) = o1;
            }
        }
    }
}

// ---------------- fused flash attention (fp16 qkv input) ----------------------
// Q fragments loaded directly global->registers (once); K/V staged in smem.
__global__ __launch_bounds__(256, 2)
void flash_attn(const hf16* __restrict__ qkv) {
    __shared__ uint32_t Ks[64][36];
    __shared__ uint32_t Vs[64][36];   // [dim][key-pair]

    const int z = blockIdx.y, b = z >> 4, h = z & 15;
    const int i0 = blockIdx.x * 128;
    const hf16* Qg = qkv + (size_t)b * SS * QD + h * DKH;
    const hf16* Kg = Qg + DDIM;
    const hf16* Vg = Qg + 2 * DDIM;
    hf16* Oh = g_ah + (size_t)b * SS * DDIM + h * DKH;

    const int tid = threadIdx.x;
    const int wid = tid >> 5, lane = tid & 31;
    const int gid = lane >> 2, tig = lane & 3;
    const int mb  = wid * 16;

    // Q fragments: 4 k-chunks x 4 regs, straight from global (Q pre-scaled)
    uint32_t qf[4][4];
    {
        const size_t rA = (size_t)(i0 + mb + gid) * QD;
        const size_t rB = (size_t)(i0 + mb + gid + 8) * QD;
#pragma unroll
        for (int c = 0; c < 4; c++) {
            int col = c * 16 + (tig << 1);
            qf[c][0] = *(const uint32_t*)(Qg + rA + col);
            qf[c][1] = *(const uint32_t*)(Qg + rB + col);
            qf[c][2] = *(const uint32_t*)(Qg + rA + col + 8);
            qf[c][3] = *(const uint32_t*)(Qg + rB + col + 8);
        }
    }

    float acco[8][4];
#pragma unroll
    for (int nt = 0; nt < 8; nt++)
#pragma unroll
        for (int i = 0; i < 4; i++) acco[nt][i] = 0.f;
    float m_lo = -1e30f, m_hi = -1e30f, l_lo = 0.f, l_hi = 0.f;

    for (int j0 = 0; j0 < SS; j0 += 64) {
        __syncthreads();
#pragma unroll
        for (int e = 0; e < 2; e++) {
            int idx = tid + e * 256;          // 512 = 64 rows x 8 chunks
            int row = idx >> 3, c8 = (idx & 7) << 3;
            uint4 kk = *(const uint4*)(Kg + (size_t)(j0 + row) * QD + c8);
            *(uint4*)&Ks[row][c8 >> 1] = kk;
            uint4 vv = *(const uint4*)(Vg + (size_t)(j0 + row) * QD + c8);
            const hf16* vp = (const hf16*)&vv;
#pragma unroll
            for (int j = 0; j < 8; j++)
                ((hf16*)&Vs[c8 + j][0])[row] = vp[j];
        }
        __syncthreads();

        float accs[8][4];
#pragma unroll
        for (int nt = 0; nt < 8; nt++)
#pragma unroll
            for (int i = 0; i < 4; i++) accs[nt][i] = 0.f;
#pragma unroll
        for (int kc = 0; kc < 4; kc++) {
            const int w = kc * 8;
#pragma unroll
            for (int nt = 0; nt < 8; nt++) {
                uint32_t bb[2];
                bb[0] = Ks[nt * 8 + gid][w + tig];
                bb[1] = Ks[nt * 8 + gid][w + tig + 4];
                mma16h(accs[nt], qf[kc], bb);
            }
        }

        float mx_lo = -1e30f, mx_hi = -1e30f;
#pragma unroll
        for (int nt = 0; nt < 8; nt++) {
            mx_lo = fmaxf(mx_lo, fmaxf(accs[nt][0], accs[nt][1]));
            mx_hi = fmaxf(mx_hi, fmaxf(accs[nt][2], accs[nt][3]));
        }
        mx_lo = fmaxf(mx_lo, __shfl_xor_sync(~0u, mx_lo, 1));
        mx_lo = fmaxf(mx_lo, __shfl_xor_sync(~0u, mx_lo, 2));
        mx_hi = fmaxf(mx_hi, __shfl_xor_sync(~0u, mx_hi, 1));
        mx_hi = fmaxf(mx_hi, __shfl_xor_sync(~0u, mx_hi, 2));
        float mn_lo = fmaxf(m_lo, mx_lo), mn_hi = fmaxf(m_hi, mx_hi);
        float al_lo = __expf(m_lo - mn_lo), al_hi = __expf(m_hi - mn_hi);
        m_lo = mn_lo; m_hi = mn_hi;

        float sum_lo = 0.f, sum_hi = 0.f;
#pragma unroll
        for (int nt = 0; nt < 8; nt++) {
            accs[nt][0] = __expf(accs[nt][0] - m_lo);
            accs[nt][1] = __expf(accs[nt][1] - m_lo);
            accs[nt][2] = __expf(accs[nt][2] - m_hi);
            accs[nt][3] = __expf(accs[nt][3] - m_hi);
            sum_lo += accs[nt][0] + accs[nt][1];
            sum_hi += accs[nt][2] + accs[nt][3];
        }
        sum_lo += __shfl_xor_sync(~0u, sum_lo, 1);
        sum_lo += __shfl_xor_sync(~0u, sum_lo, 2);
        sum_hi += __shfl_xor_sync(~0u, sum_hi, 1);
        sum_hi += __shfl_xor_sync(~0u, sum_hi, 2);
        l_lo = l_lo * al_lo + sum_lo;
        l_hi = l_hi * al_hi + sum_hi;

#pragma unroll
        for (int nt = 0; nt < 8; nt++) {
            acco[nt][0] *= al_lo; acco[nt][1] *= al_lo;
            acco[nt][2] *= al_hi; acco[nt][3] *= al_hi;
        }

#pragma unroll
        for (int s = 0; s < 4; s++) {
            uint32_t a[4];
            a[0] = packhf(accs[2*s][0],     accs[2*s][1]);
            a[1] = packhf(accs[2*s][2],     accs[2*s][3]);
            a[2] = packhf(accs[2*s + 1][0], accs[2*s + 1][1]);
            a[3] = packhf(accs[2*s + 1][2], accs[2*s + 1][3]);
#pragma unroll
            for (int nt = 0; nt < 8; nt++) {
                uint32_t bb[2];
                bb[0] = Vs[nt * 8 + gid][s * 8 + tig];
                bb[1] = Vs[nt * 8 + gid][s * 8 + tig + 4];
                mma16h(acco[nt], a, bb);
            }
        }
    }

    const float inv_lo = 1.0f / l_lo, inv_hi = 1.0f / l_hi;
#pragma unroll
    for (int nt = 0; nt < 8; nt++) {
        int c = nt * 8 + (tig << 1);
        size_t r0 = (size_t)(i0 + mb + gid) * DDIM + c;
        size_t r1 = (size_t)(i0 + mb + gid + 8) * DDIM + c;
        *(__half2*)(Oh + r0) = __floats2half2_rn(acco[nt][0] * inv_lo,
                                                 acco[nt][1] * inv_lo);
        *(__half2*)(Oh + r1) = __floats2half2_rn(acco[nt][2] * inv_hi,
                                                 acco[nt][3] * inv_hi);
    }
}

// ---------------- add + LayerNorm (+ optional fp16 plane output) -------------
__global__ __launch_bounds__(256)
void add_ln(const float* __restrict__ x, const float* __restrict__ y,
            const float* __restrict__ g, const float* __restrict__ be,
            float* __restrict__ out, hf16* __restrict__ hi) {
    __shared__ float sm[8];
    __shared__ float bc;
    const int tid = threadIdx.x;
    const size_t ro = (size_t)blockIdx.x * DDIM;
    float4 a = reinterpret_cast<const float4*>(x + ro)[tid];
    float4 b = reinterpret_cast<const float4*>(y + ro)[tid];
    a.x += b.x; a.y += b.y; a.z += b.z; a.w += b.w;

    float s = a.x + a.y + a.z + a.w;
#pragma unroll
    for (int o = 16; o; o >>= 1) s += __shfl_xor_sync(~0u, s, o);
    if ((tid & 31) == 0) sm[tid >> 5] = s;
    __syncthreads();
    if (tid < 32) {
        float t = (tid < 8) ? sm[tid] : 0.f;
#pragma unroll
        for (int o = 4; o; o >>= 1) t += __shfl_xor_sync(~0u, t, o);
        if (tid == 0) bc = t;
    }
    __syncthreads();
    const float mu = bc * (1.0f / DDIM);
    a.x -= mu; a.y -= mu; a.z -= mu; a.w -= mu;
    float qv = a.x*a.x + a.y*a.y + a.z*a.z + a.w*a.w;
    __syncthreads();
#pragma unroll
    for (int o = 16; o; o >>= 1) qv += __shfl_xor_sync(~0u, qv, o);
    if ((tid & 31) == 0) sm[tid >> 5] = qv;
    __syncthreads();
    if (tid < 32) {
        float t = (tid < 8) ? sm[tid] : 0.f;
#pragma unroll
        for (int o = 4; o; o >>= 1) t += __shfl_xor_sync(~0u, t, o);
        if (tid == 0) bc = t;
    }
    __syncthreads();
    const float rs = rsqrtf(bc * (1.0f / DDIM) + 1e-5f);
    float4 gv = reinterpret_cast<const float4*>(g)[tid];
    float4 bv = reinterpret_cast<const float4*>(be)[tid];
    float4 o;
    o.x = a.x * rs * gv.x + bv.x;
    o.y = a.y * rs * gv.y + bv.y;
    o.z = a.z * rs * gv.z + bv.z;
    o.w = a.w * rs * gv.w + bv.w;
    reinterpret_cast<float4*>(out + ro)[tid] = o;
    if (hi) {
        size_t i4 = ro + tid * 4;
        *(__half2*)(hi + i4)     = __floats2half2_rn(o.x, o.y);
        *(__half2*)(hi + i4 + 2) = __floats2half2_rn(o.z, o.w);
    }
}

// ---------------- launch ------------------------------------------------------
extern "C" void kernel_launch(void* const* d_in, const int* in_sizes, int n_in,
                              void* d_out, int out_size) {
    const int*   tokens = (const int*)  d_in[0];
    const float* emb    = (const float*)d_in[1];
    const float* Wq = (const float*)d_in[2],  *bq = (const float*)d_in[3];
    const float* Wk = (const float*)d_in[4],  *bk = (const float*)d_in[5];
    const float* Wv = (const float*)d_in[6],  *bv = (const float*)d_in[7];
    const float* Wo = (const float*)d_in[8],  *bo = (const float*)d_in[9];
    const float* W1 = (const float*)d_in[10], *b1 = (const float*)d_in[11];
    const float* W2 = (const float*)d_in[12], *b2 = (const float*)d_in[13];
    const float* gamma = (const float*)d_in[14], *beta = (const float*)d_in[15];
    float* out = (float*)d_out;

    float *x, *t, *bqkv;
    cudaGetSymbolAddress((void**)&x,    g_x);
    cudaGetSymbolAddress((void**)&t,    g_t);
    cudaGetSymbolAddress((void**)&bqkv, g_bqkv);
    hf16 *qkv, *wqkvh, *woh, *wol, *w1h, *w1l, *w2h, *w2l, *ah, *hh;
    cudaGetSymbolAddress((void**)&qkv,   g_qkv);
    cudaGetSymbolAddress((void**)&wqkvh, g_wqkvh);
    cudaGetSymbolAddress((void**)&woh, g_woh); cudaGetSymbolAddress((void**)&wol, g_wol);
    cudaGetSymbolAddress((void**)&w1h, g_w1h); cudaGetSymbolAddress((void**)&w1l, g_w1l);
    cudaGetSymbolAddress((void**)&w2h, g_w2h); cudaGetSymbolAddress((void**)&w2l, g_w2l);
    cudaGetSymbolAddress((void**)&ah,  g_ah);  cudaGetSymbolAddress((void**)&hh,  g_hh);

    cudaFuncSetAttribute(gemm_hf1_qkv,
                         cudaFuncAttributeMaxDynamicSharedMemorySize, G1_SMEM);
    cudaFuncSetAttribute(gemm_hf2<false, false>,
                         cudaFuncAttributeMaxDynamicSharedMemorySize, G2_SMEM);
    cudaFuncSetAttribute(gemm_hf2<true, true>,
                         cudaFuncAttributeMaxDynamicSharedMemorySize, G2_SMEM);

    embed_pe<<<BSR * DDIM / 256, 256>>>(tokens, emb);
    conv_a<<<BSR * DDIM / 1024, 256>>>(x, ah);

    // weight conversion
    const size_t DD = (size_t)DDIM * DDIM, DF = (size_t)DDIM * FFD;
    split_w_t<<<dim3(DDIM / 32, DDIM / 32, LLAY), 256>>>(Wq, wqkvh,          nullptr, DDIM, DDIM, 3 * DD);
    split_w_t<<<dim3(DDIM / 32, DDIM / 32, LLAY), 256>>>(Wk, wqkvh + DD,     nullptr, DDIM, DDIM, 3 * DD);
    split_w_t<<<dim3(DDIM / 32, DDIM / 32, LLAY), 256>>>(Wv, wqkvh + 2 * DD, nullptr, DDIM, DDIM, 3 * DD);
    split_w_t<<<dim3(DDIM / 32, DDIM / 32, LLAY), 256>>>(Wo, woh, wol, DDIM, DDIM, DD);
    split_w_t<<<dim3(FFD  / 32, DDIM / 32, LLAY), 256>>>(W1, w1h, w1l, DDIM, FFD, DF);
    split_w_t<<<dim3(DDIM / 32, FFD  / 32, LLAY), 256>>>(W2, w2h, w2l, FFD, DDIM, DF);
    pack_bias<<<dim3(QD / 256, LLAY), 256>>>(bq, bk, bv);

    const dim3 gqkv(QD  / 128, BSR / 128);  // 24 x 16
    const dim3 gp(DDIM / 128, BSR / 128);
    const dim3 gf(FFD  / 128, BSR / 128);

    for (int l = 0; l < LLAY; l++) {
        size_t od = (size_t)l * DD, of = (size_t)l * DF;
        const float* lbo = bo + (size_t)l * DDIM;
        const float* lb1 = b1 + (size_t)l * FFD;
        const float* lb2 = b2 + (size_t)l * DDIM;
        const float* lg  = gamma + (size_t)l * DDIM;
        const float* lbe = beta  + (size_t)l * DDIM;

        gemm_hf1_qkv<<<gqkv, 256, G1_SMEM>>>(
            ah, wqkvh + (size_t)l * 3 * DD, bqkv + (size_t)l * QD, qkv,
            BSR, QD, DDIM);

        flash_attn<<<dim3(SS / 128, BB * HH), 256>>>(qkv);

        gemm_hf2<false, false><<<gp, 256, G2_SMEM>>>(
            ah, woh + od, wol + od, lbo, t, nullptr, BSR, DDIM, DDIM);
        add_ln<<<BSR, 256>>>(x, t, lg, lbe, x, ah);

        gemm_hf2<true, true><<<gf, 256, G2_SMEM>>>(
            ah, w1h + of, w1l + of, lb1, nullptr, hh, BSR, FFD, DDIM);
        gemm_hf2<false, false><<<gp, 256, G2_SMEM>>>(
            hh, w2h + of, w2l + of, lb2, t, nullptr, BSR, DDIM, FFD);

        float* xo = (l == LLAY - 1) ? out : x;
        hf16* nh = (l == LLAY - 1) ? nullptr : ah;
        add_ln<<<BSR, 256>>>(x, t, lg, lbe, xo, nh);
    }
}

// round 13
// speedup vs baseline: 4.6197x; 1.1332x over previous
#include <cuda_runtime.h>
#include <cuda_bf16.h>
#include <cuda_fp16.h>
#include <math.h>
#include <stdint.h>

// Problem constants
#define BB   2
#define SS   1024
#define DDIM 1024
#define HH   16
#define LLAY 4
#define FFD  2048
#define DKH  64
#define BSR  (BB*SS)   // 2048 rows
#define QD   (3*DDIM)  // fused QKV width

typedef __half hf16;

// ---------------- scratch (static device globals; no allocs allowed) ----------
__device__ float g_x  [BSR*DDIM];
__device__ float g_t  [BSR*DDIM];
__device__ __align__(256) hf16 g_qkv[BSR*QD];   // fp16, Q pre-scaled by 1/8

// fp16 weights (hi only, 1-pass), transposed to [N][K]
__device__ __align__(256) hf16 g_wqkvh[LLAY*3*DDIM*DDIM];
__device__ __align__(256) hf16 g_woh[LLAY*DDIM*DDIM];
__device__ __align__(256) hf16 g_w1h[LLAY*DDIM*FFD];
__device__ __align__(256) hf16 g_w2h[LLAY*FFD*DDIM];
__device__ float g_bqkv[LLAY*QD];
// single fp16 activation planes
__device__ __align__(256) hf16 g_ah[BSR*DDIM];
__device__ __align__(256) hf16 g_hh[BSR*FFD];

// ---------------- helpers -----------------------------------------------------
__device__ __forceinline__ void mma16h(float* c, const uint32_t* a, const uint32_t* b) {
    asm volatile(
        "mma.sync.aligned.m16n8k16.row.col.f32.f16.f16.f32 "
        "{%0,%1,%2,%3}, {%4,%5,%6,%7}, {%8,%9}, {%0,%1,%2,%3};"
        : "+f"(c[0]), "+f"(c[1]), "+f"(c[2]), "+f"(c[3])
        : "r"(a[0]), "r"(a[1]), "r"(a[2]), "r"(a[3]), "r"(b[0]), "r"(b[1]));
}
__device__ __forceinline__ void ldsm4(uint32_t& r0, uint32_t& r1, uint32_t& r2,
                                      uint32_t& r3, uint32_t addr) {
    asm volatile("ldmatrix.sync.aligned.m8n8.x4.shared.b16 {%0,%1,%2,%3}, [%4];"
                 : "=r"(r0), "=r"(r1), "=r"(r2), "=r"(r3) : "r"(addr));
}
__device__ __forceinline__ void cp16(uint32_t* s, const void* g) {
    uint32_t sa = (uint32_t)__cvta_generic_to_shared(s);
    asm volatile("cp.async.cg.shared.global [%0], [%1], 16;" :: "r"(sa), "l"(g));
}
#define CP_COMMIT() asm volatile("cp.async.commit_group;")
#define CP_WAIT1()  asm volatile("cp.async.wait_group 1;" ::: "memory")

__device__ __forceinline__ uint32_t packhf(float a, float b) {
    __half2 p = __floats2half2_rn(a, b);
    return *(uint32_t*)&p;
}

// ---------------- embedding + (buggy-faithful) positional encoding ------------
__global__ void embed_pe(const int* __restrict__ tok, const float* __restrict__ emb) {
    int idx = blockIdx.x * 256 + threadIdx.x;
    int d  = idx & (DDIM - 1);
    int bs = idx >> 10;
    int b  = bs >> 10;
    int t  = tok[bs];
    int i2 = (d >> 1) << 1;
    float div = expf(-(float)i2 * (9.210340371976184f / (float)DDIM));
    float ang = (float)b * div;
    float pe  = (d & 1) ? cosf(ang) : sinf(ang);
    g_x[idx] = emb[(size_t)t * DDIM + d] + pe;
}

// ---------------- activation fp16 convert (after embed only) ------------------
__global__ __launch_bounds__(256)
void conv_a(const float* __restrict__ s, hf16* __restrict__ hi) {
    int i4 = (blockIdx.x * 256 + threadIdx.x) * 4;
    float4 v = *(const float4*)(s + i4);
    *(__half2*)(hi + i4)     = __floats2half2_rn(v.x, v.y);
    *(__half2*)(hi + i4 + 2) = __floats2half2_rn(v.z, v.w);
}

// ---------------- weight transpose + fp16 convert, all layers (z) -------------
__global__ __launch_bounds__(256)
void conv_w_t(const float* __restrict__ W0, hf16* __restrict__ th0,
              int K, int N, size_t ostride) {
    const size_t li = (size_t)blockIdx.z * K * N;
    const float* W = W0 + li;
    hf16* th = th0 + (size_t)blockIdx.z * ostride;
    __shared__ float tile[32][33];
    const int n0 = blockIdx.x * 32, k0 = blockIdx.y * 32;
    const int tx = threadIdx.x & 31, ty = threadIdx.x >> 5;
#pragma unroll
    for (int i = 0; i < 32; i += 8)
        tile[ty + i][tx] = W[(size_t)(k0 + ty + i) * N + n0 + tx];
    __syncthreads();
#pragma unroll
    for (int i = 0; i < 32; i += 8) {
        int n = n0 + ty + i, k = k0 + tx;
        th[(size_t)n * K + k] = __float2half_rn(tile[tx][ty + i]);
    }
}

// ---------------- pack QKV biases ---------------------------------------------
__global__ void pack_bias(const float* __restrict__ bq, const float* __restrict__ bk,
                          const float* __restrict__ bv) {
    int l = blockIdx.y;
    int i = blockIdx.x * 256 + threadIdx.x;
    float v = (i < DDIM) ? bq[l * DDIM + i]
            : (i < 2 * DDIM) ? bk[l * DDIM + i - DDIM]
            : bv[l * DDIM + i - 2 * DDIM];
    g_bqkv[l * QD + i] = v;
}

// ---------------- fp16 1-pass GEMM: C = A @ B^T + bias ------------------------
// A fp16 [M][K]; B fp16 [N][K]. BM=BN=128, BK=32, 256 thr, 2 stages, 40 KB.
#define G1_PLANE 5120
#define G1_STAGE 2560
#define G1_SMEM  (2 * G1_PLANE * 4)

__device__ __forceinline__ void g1_copy_stage(
    uint32_t* sm, const hf16* __restrict__ Ah, const hf16* __restrict__ Bh,
    int m0, int n0, int K, int k0, int s, int tid) {
#pragma unroll
    for (int e = 0; e < 2; e++) {
        int c = tid + e * 256;
        int row = c >> 2, cw = (c & 3) << 2;
        int kk  = k0 + ((c & 3) << 3);
        int so = s * G1_STAGE + row * 20 + cw;
        cp16(sm + 0 * G1_PLANE + so, Ah + (size_t)(m0 + row) * K + kk);
        cp16(sm + 1 * G1_PLANE + so, Bh + (size_t)(n0 + row) * K + kk);
    }
}

template<bool RELU, bool PLANES, bool QSCALE>
__global__ __launch_bounds__(256, 3)
void gemm_hf1(const hf16* __restrict__ Ah, const hf16* __restrict__ Bh,
              const float* __restrict__ bias, float* __restrict__ C,
              hf16* __restrict__ Chf, int M, int N, int K) {
    extern __shared__ uint32_t sm[];
    const int tid  = threadIdx.x;
    const int wid  = tid >> 5, lane = tid & 31;
    const int gid  = lane >> 2, tig = lane & 3;
    const int wm   = wid >> 2, wn = wid & 3;
    const int m0   = blockIdx.y * 128, n0 = blockIdx.x * 128;
    const uint32_t sbase = (uint32_t)__cvta_generic_to_shared(sm);

    const int lr  = lane & 7;
    const int lg1 = (lane >> 3) & 1;
    const int lg2 = (lane >> 4) & 1;
    int rowA[4], rowB[2];
#pragma unroll
    for (int mt = 0; mt < 4; mt++) rowA[mt] = wm * 64 + mt * 16 + lg1 * 8 + lr;
#pragma unroll
    for (int np = 0; np < 2; np++) rowB[np] = wn * 32 + np * 16 + lg2 * 8 + lr;
    const int kA = lg2 * 4, kB = lg1 * 4;

    float acc[4][4][4];
#pragma unroll
    for (int mt = 0; mt < 4; mt++)
#pragma unroll
        for (int nt = 0; nt < 4; nt++)
#pragma unroll
            for (int i = 0; i < 4; i++) acc[mt][nt][i] = 0.f;

    g1_copy_stage(sm, Ah, Bh, m0, n0, K, 0, 0, tid);
    CP_COMMIT();
    g1_copy_stage(sm, Ah, Bh, m0, n0, K, 32, 1, tid);
    CP_COMMIT();

    for (int k0 = 0; k0 < K; k0 += 32) {
        const int s = (k0 >> 5) & 1;
        CP_WAIT1();
        __syncthreads();

        const uint32_t aA = sbase + (0 * G1_PLANE + s * G1_STAGE) * 4;
        const uint32_t aB = sbase + (1 * G1_PLANE + s * G1_STAGE) * 4;
#pragma unroll
        for (int sb = 0; sb < 2; sb++) {
            const int kb = sb * 8;
            uint32_t a4[4][4], b4[4][2];
#pragma unroll
            for (int mt = 0; mt < 4; mt++) {
                uint32_t off = (uint32_t)(rowA[mt] * 20 + kb + kA) * 4;
                ldsm4(a4[mt][0], a4[mt][1], a4[mt][2], a4[mt][3], aA + off);
            }
#pragma unroll
            for (int np = 0; np < 2; np++) {
                uint32_t off = (uint32_t)(rowB[np] * 20 + kb + kB) * 4;
                ldsm4(b4[2*np][0], b4[2*np][1], b4[2*np+1][0], b4[2*np+1][1],
                      aB + off);
            }
#pragma unroll
            for (int mt = 0; mt < 4; mt++)
#pragma unroll
                for (int nt = 0; nt < 4; nt++)
                    mma16h(acc[mt][nt], a4[mt], b4[nt]);
        }
        __syncthreads();
        if (k0 + 64 < K)
            g1_copy_stage(sm, Ah, Bh, m0, n0, K, k0 + 64, s, tid);
        CP_COMMIT();
    }

#pragma unroll
    for (int mt = 0; mt < 4; mt++) {
        int r0 = m0 + wm * 64 + mt * 16 + gid;
#pragma unroll
        for (int nt = 0; nt < 4; nt++) {
            int c = n0 + wn * 32 + nt * 8 + (tig << 1);
            float b0 = bias[c], b1 = bias[c + 1];
            float2 o0 = make_float2(acc[mt][nt][0] + b0, acc[mt][nt][1] + b1);
            float2 o1 = make_float2(acc[mt][nt][2] + b0, acc[mt][nt][3] + b1);
            if (RELU) {
                o0.x = fmaxf(o0.x, 0.f); o0.y = fmaxf(o0.y, 0.f);
                o1.x = fmaxf(o1.x, 0.f); o1.y = fmaxf(o1.y, 0.f);
            }
            if (QSCALE) {
                float sc = (c < DDIM) ? 0.125f : 1.0f;
                o0.x *= sc; o0.y *= sc; o1.x *= sc; o1.y *= sc;
            }
            if (PLANES) {
                *(__half2*)(Chf + (size_t)r0 * N + c) =
                    __floats2half2_rn(o0.x, o0.y);
                *(__half2*)(Chf + (size_t)(r0 + 8) * N + c) =
                    __floats2half2_rn(o1.x, o1.y);
            } else {
                *(float2*)(C + (size_t)r0 * N + c)       = o0;
                *(float2*)(C + (size_t)(r0 + 8) * N + c) = o1;
            }
        }
    }
}

// ---------------- fused flash attention (fp16 qkv input) ----------------------
__global__ __launch_bounds__(256, 2)
void flash_attn(const hf16* __restrict__ qkv) {
    __shared__ uint32_t Ks[64][36];
    __shared__ uint32_t Vs[64][36];   // [dim][key-pair]

    const int z = blockIdx.y, b = z >> 4, h = z & 15;
    const int i0 = blockIdx.x * 128;
    const hf16* Qg = qkv + (size_t)b * SS * QD + h * DKH;
    const hf16* Kg = Qg + DDIM;
    const hf16* Vg = Qg + 2 * DDIM;
    hf16* Oh = g_ah + (size_t)b * SS * DDIM + h * DKH;

    const int tid = threadIdx.x;
    const int wid = tid >> 5, lane = tid & 31;
    const int gid = lane >> 2, tig = lane & 3;
    const int mb  = wid * 16;

    uint32_t qf[4][4];
    {
        const size_t rA = (size_t)(i0 + mb + gid) * QD;
        const size_t rB = (size_t)(i0 + mb + gid + 8) * QD;
#pragma unroll
        for (int c = 0; c < 4; c++) {
            int col = c * 16 + (tig << 1);
            qf[c][0] = *(const uint32_t*)(Qg + rA + col);
            qf[c][1] = *(const uint32_t*)(Qg + rB + col);
            qf[c][2] = *(const uint32_t*)(Qg + rA + col + 8);
            qf[c][3] = *(const uint32_t*)(Qg + rB + col + 8);
        }
    }

    float acco[8][4];
#pragma unroll
    for (int nt = 0; nt < 8; nt++)
#pragma unroll
        for (int i = 0; i < 4; i++) acco[nt][i] = 0.f;
    float m_lo = -1e30f, m_hi = -1e30f, l_lo = 0.f, l_hi = 0.f;

    for (int j0 = 0; j0 < SS; j0 += 64) {
        __syncthreads();
#pragma unroll
        for (int e = 0; e < 2; e++) {
            int idx = tid + e * 256;
            int row = idx >> 3, c8 = (idx & 7) << 3;
            uint4 kk = *(const uint4*)(Kg + (size_t)(j0 + row) * QD + c8);
            *(uint4*)&Ks[row][c8 >> 1] = kk;
            uint4 vv = *(const uint4*)(Vg + (size_t)(j0 + row) * QD + c8);
            const hf16* vp = (const hf16*)&vv;
#pragma unroll
            for (int j = 0; j < 8; j++)
                ((hf16*)&Vs[c8 + j][0])[row] = vp[j];
        }
        __syncthreads();

        float accs[8][4];
#pragma unroll
        for (int nt = 0; nt < 8; nt++)
#pragma unroll
            for (int i = 0; i < 4; i++) accs[nt][i] = 0.f;
#pragma unroll
        for (int kc = 0; kc < 4; kc++) {
            const int w = kc * 8;
#pragma unroll
            for (int nt = 0; nt < 8; nt++) {
                uint32_t bb[2];
                bb[0] = Ks[nt * 8 + gid][w + tig];
                bb[1] = Ks[nt * 8 + gid][w + tig + 4];
                mma16h(accs[nt], qf[kc], bb);
            }
        }

        float mx_lo = -1e30f, mx_hi = -1e30f;
#pragma unroll
        for (int nt = 0; nt < 8; nt++) {
            mx_lo = fmaxf(mx_lo, fmaxf(accs[nt][0], accs[nt][1]));
            mx_hi = fmaxf(mx_hi, fmaxf(accs[nt][2], accs[nt][3]));
        }
        mx_lo = fmaxf(mx_lo, __shfl_xor_sync(~0u, mx_lo, 1));
        mx_lo = fmaxf(mx_lo, __shfl_xor_sync(~0u, mx_lo, 2));
        mx_hi = fmaxf(mx_hi, __shfl_xor_sync(~0u, mx_hi, 1));
        mx_hi = fmaxf(mx_hi, __shfl_xor_sync(~0u, mx_hi, 2));
        float mn_lo = fmaxf(m_lo, mx_lo), mn_hi = fmaxf(m_hi, mx_hi);
        float al_lo = __expf(m_lo - mn_lo), al_hi = __expf(m_hi - mn_hi);
        m_lo = mn_lo; m_hi = mn_hi;

        float sum_lo = 0.f, sum_hi = 0.f;
#pragma unroll
        for (int nt = 0; nt < 8; nt++) {
            accs[nt][0] = __expf(accs[nt][0] - m_lo);
            accs[nt][1] = __expf(accs[nt][1] - m_lo);
            accs[nt][2] = __expf(accs[nt][2] - m_hi);
            accs[nt][3] = __expf(accs[nt][3] - m_hi);
            sum_lo += accs[nt][0] + accs[nt][1];
            sum_hi += accs[nt][2] + accs[nt][3];
        }
        sum_lo += __shfl_xor_sync(~0u, sum_lo, 1);
        sum_lo += __shfl_xor_sync(~0u, sum_lo, 2);
        sum_hi += __shfl_xor_sync(~0u, sum_hi, 1);
        sum_hi += __shfl_xor_sync(~0u, sum_hi, 2);
        l_lo = l_lo * al_lo + sum_lo;
        l_hi = l_hi * al_hi + sum_hi;

#pragma unroll
        for (int nt = 0; nt < 8; nt++) {
            acco[nt][0] *= al_lo; acco[nt][1] *= al_lo;
            acco[nt][2] *= al_hi; acco[nt][3] *= al_hi;
        }

#pragma unroll
        for (int s = 0; s < 4; s++) {
            uint32_t a[4];
            a[0] = packhf(accs[2*s][0],     accs[2*s][1]);
            a[1] = packhf(accs[2*s][2],     accs[2*s][3]);
            a[2] = packhf(accs[2*s + 1][0], accs[2*s + 1][1]);
            a[3] = packhf(accs[2*s + 1][2], accs[2*s + 1][3]);
#pragma unroll
            for (int nt = 0; nt < 8; nt++) {
                uint32_t bb[2];
                bb[0] = Vs[nt * 8 + gid][s * 8 + tig];
                bb[1] = Vs[nt * 8 + gid][s * 8 + tig + 4];
                mma16h(acco[nt], a, bb);
            }
        }
    }

    const float inv_lo = 1.0f / l_lo, inv_hi = 1.0f / l_hi;
#pragma unroll
    for (int nt = 0; nt < 8; nt++) {
        int c = nt * 8 + (tig << 1);
        size_t r0 = (size_t)(i0 + mb + gid) * DDIM + c;
        size_t r1 = (size_t)(i0 + mb + gid + 8) * DDIM + c;
        *(__half2*)(Oh + r0) = __floats2half2_rn(acco[nt][0] * inv_lo,
                                                 acco[nt][1] * inv_lo);
        *(__half2*)(Oh + r1) = __floats2half2_rn(acco[nt][2] * inv_hi,
                                                 acco[nt][3] * inv_hi);
    }
}

// ---------------- add + LayerNorm (+ optional fp16 plane output) -------------
__global__ __launch_bounds__(256)
void add_ln(const float* __restrict__ x, const float* __restrict__ y,
            const float* __restrict__ g, const float* __restrict__ be,
            float* __restrict__ out, hf16* __restrict__ hi) {
    __shared__ float sm[8];
    __shared__ float bc;
    const int tid = threadIdx.x;
    const size_t ro = (size_t)blockIdx.x * DDIM;
    float4 a = reinterpret_cast<const float4*>(x + ro)[tid];
    float4 b = reinterpret_cast<const float4*>(y + ro)[tid];
    a.x += b.x; a.y += b.y; a.z += b.z; a.w += b.w;

    float s = a.x + a.y + a.z + a.w;
#pragma unroll
    for (int o = 16; o; o >>= 1) s += __shfl_xor_sync(~0u, s, o);
    if ((tid & 31) == 0) sm[tid >> 5] = s;
    __syncthreads();
    if (tid < 32) {
        float t = (tid < 8) ? sm[tid] : 0.f;
#pragma unroll
        for (int o = 4; o; o >>= 1) t += __shfl_xor_sync(~0u, t, o);
        if (tid == 0) bc = t;
    }
    __syncthreads();
    const float mu = bc * (1.0f / DDIM);
    a.x -= mu; a.y -= mu; a.z -= mu; a.w -= mu;
    float qv = a.x*a.x + a.y*a.y + a.z*a.z + a.w*a.w;
    __syncthreads();
#pragma unroll
    for (int o = 16; o; o >>= 1) qv += __shfl_xor_sync(~0u, qv, o);
    if ((tid & 31) == 0) sm[tid >> 5] = qv;
    __syncthreads();
    if (tid < 32) {
        float t = (tid < 8) ? sm[tid] : 0.f;
#pragma unroll
        for (int o = 4; o; o >>= 1) t += __shfl_xor_sync(~0u, t, o);
        if (tid == 0) bc = t;
    }
    __syncthreads();
    const float rs = rsqrtf(bc * (1.0f / DDIM) + 1e-5f);
    float4 gv = reinterpret_cast<const float4*>(g)[tid];
    float4 bv = reinterpret_cast<const float4*>(be)[tid];
    float4 o;
    o.x = a.x * rs * gv.x + bv.x;
    o.y = a.y * rs * gv.y + bv.y;
    o.z = a.z * rs * gv.z + bv.z;
    o.w = a.w * rs * gv.w + bv.w;
    reinterpret_cast<float4*>(out + ro)[tid] = o;
    if (hi) {
        size_t i4 = ro + tid * 4;
        *(__half2*)(hi + i4)     = __floats2half2_rn(o.x, o.y);
        *(__half2*)(hi + i4 + 2) = __floats2half2_rn(o.z, o.w);
    }
}

// ---------------- launch ------------------------------------------------------
extern "C" void kernel_launch(void* const* d_in, const int* in_sizes, int n_in,
                              void* d_out, int out_size) {
    const int*   tokens = (const int*)  d_in[0];
    const float* emb    = (const float*)d_in[1];
    const float* Wq = (const float*)d_in[2],  *bq = (const float*)d_in[3];
    const float* Wk = (const float*)d_in[4],  *bk = (const float*)d_in[5];
    const float* Wv = (const float*)d_in[6],  *bv = (const float*)d_in[7];
    const float* Wo = (const float*)d_in[8],  *bo = (const float*)d_in[9];
    const float* W1 = (const float*)d_in[10], *b1 = (const float*)d_in[11];
    const float* W2 = (const float*)d_in[12], *b2 = (const float*)d_in[13];
    const float* gamma = (const float*)d_in[14], *beta = (const float*)d_in[15];
    float* out = (float*)d_out;

    float *x, *t, *bqkv;
    cudaGetSymbolAddress((void**)&x,    g_x);
    cudaGetSymbolAddress((void**)&t,    g_t);
    cudaGetSymbolAddress((void**)&bqkv, g_bqkv);
    hf16 *qkv, *wqkvh, *woh, *w1h, *w2h, *ah, *hh;
    cudaGetSymbolAddress((void**)&qkv,   g_qkv);
    cudaGetSymbolAddress((void**)&wqkvh, g_wqkvh);
    cudaGetSymbolAddress((void**)&woh, g_woh);
    cudaGetSymbolAddress((void**)&w1h, g_w1h);
    cudaGetSymbolAddress((void**)&w2h, g_w2h);
    cudaGetSymbolAddress((void**)&ah,  g_ah);
    cudaGetSymbolAddress((void**)&hh,  g_hh);

    cudaFuncSetAttribute(gemm_hf1<false, true, true>,
                         cudaFuncAttributeMaxDynamicSharedMemorySize, G1_SMEM);
    cudaFuncSetAttribute(gemm_hf1<false, false, false>,
                         cudaFuncAttributeMaxDynamicSharedMemorySize, G1_SMEM);
    cudaFuncSetAttribute(gemm_hf1<true, true, false>,
                         cudaFuncAttributeMaxDynamicSharedMemorySize, G1_SMEM);

    embed_pe<<<BSR * DDIM / 256, 256>>>(tokens, emb);
    conv_a<<<BSR * DDIM / 1024, 256>>>(x, ah);

    // weight conversion (hi only)
    const size_t DD = (size_t)DDIM * DDIM, DF = (size_t)DDIM * FFD;
    conv_w_t<<<dim3(DDIM / 32, DDIM / 32, LLAY), 256>>>(Wq, wqkvh,          DDIM, DDIM, 3 * DD);
    conv_w_t<<<dim3(DDIM / 32, DDIM / 32, LLAY), 256>>>(Wk, wqkvh + DD,     DDIM, DDIM, 3 * DD);
    conv_w_t<<<dim3(DDIM / 32, DDIM / 32, LLAY), 256>>>(Wv, wqkvh + 2 * DD, DDIM, DDIM, 3 * DD);
    conv_w_t<<<dim3(DDIM / 32, DDIM / 32, LLAY), 256>>>(Wo, woh, DDIM, DDIM, DD);
    conv_w_t<<<dim3(FFD  / 32, DDIM / 32, LLAY), 256>>>(W1, w1h, DDIM, FFD, DF);
    conv_w_t<<<dim3(DDIM / 32, FFD  / 32, LLAY), 256>>>(W2, w2h, FFD, DDIM, DF);
    pack_bias<<<dim3(QD / 256, LLAY), 256>>>(bq, bk, bv);

    const dim3 gqkv(QD  / 128, BSR / 128);  // 24 x 16
    const dim3 gp(DDIM / 128, BSR / 128);
    const dim3 gf(FFD  / 128, BSR / 128);

    for (int l = 0; l < LLAY; l++) {
        size_t od = (size_t)l * DD, of = (size_t)l * DF;
        const float* lbo = bo + (size_t)l * DDIM;
        const float* lb1 = b1 + (size_t)l * FFD;
        const float* lb2 = b2 + (size_t)l * DDIM;
        const float* lg  = gamma + (size_t)l * DDIM;
        const float* lbe = beta  + (size_t)l * DDIM;

        gemm_hf1<false, true, true><<<gqkv, 256, G1_SMEM>>>(
            ah, wqkvh + (size_t)l * 3 * DD, bqkv + (size_t)l * QD,
            nullptr, qkv, BSR, QD, DDIM);

        flash_attn<<<dim3(SS / 128, BB * HH), 256>>>(qkv);

        gemm_hf1<false, false, false><<<gp, 256, G1_SMEM>>>(
            ah, woh + od, lbo, t, nullptr, BSR, DDIM, DDIM);
        add_ln<<<BSR, 256>>>(x, t, lg, lbe, x, ah);

        gemm_hf1<true, true, false><<<gf, 256, G1_SMEM>>>(
            ah, w1h + of, lb1, nullptr, hh, BSR, FFD, DDIM);
        gemm_hf1<false, false, false><<<gp, 256, G1_SMEM>>>(
            hh, w2h + of, lb2, t, nullptr, BSR, DDIM, FFD);

        float* xo = (l == LLAY - 1) ? out : x;
        hf16* nh = (l == LLAY - 1) ? nullptr : ah;
        add_ln<<<BSR, 256>>>(x, t, lg, lbe, xo, nh);
    }
}

// round 14
// speedup vs baseline: 4.7056x; 1.0186x over previous
#include <cuda_runtime.h>
#include <cuda_bf16.h>
#include <cuda_fp16.h>
#include <math.h>
#include <stdint.h>

// Problem constants
#define BB   2
#define SS   1024
#define DDIM 1024
#define HH   16
#define LLAY 4
#define FFD  2048
#define DKH  64
#define BSR  (BB*SS)   // 2048 rows
#define QD   (3*DDIM)  // fused QKV width

typedef __half hf16;

// ---------------- scratch (static device globals; no allocs allowed) ----------
__device__ float g_x  [BSR*DDIM];
__device__ float g_t  [BSR*DDIM];
__device__ __align__(256) hf16 g_qkv[BSR*QD];   // fp16, Q pre-scaled by 1/8

// fp16 weights (hi only, 1-pass), transposed to [N][K]
__device__ __align__(256) hf16 g_wqkvh[LLAY*3*DDIM*DDIM];
__device__ __align__(256) hf16 g_woh[LLAY*DDIM*DDIM];
__device__ __align__(256) hf16 g_w1h[LLAY*DDIM*FFD];
__device__ __align__(256) hf16 g_w2h[LLAY*FFD*DDIM];
__device__ float g_bqkv[LLAY*QD];
// single fp16 activation planes
__device__ __align__(256) hf16 g_ah[BSR*DDIM];
__device__ __align__(256) hf16 g_hh[BSR*FFD];

// ---------------- helpers -----------------------------------------------------
__device__ __forceinline__ void mma16h(float* c, const uint32_t* a, const uint32_t* b) {
    asm volatile(
        "mma.sync.aligned.m16n8k16.row.col.f32.f16.f16.f32 "
        "{%0,%1,%2,%3}, {%4,%5,%6,%7}, {%8,%9}, {%0,%1,%2,%3};"
        : "+f"(c[0]), "+f"(c[1]), "+f"(c[2]), "+f"(c[3])
        : "r"(a[0]), "r"(a[1]), "r"(a[2]), "r"(a[3]), "r"(b[0]), "r"(b[1]));
}
__device__ __forceinline__ void ldsm4(uint32_t& r0, uint32_t& r1, uint32_t& r2,
                                      uint32_t& r3, uint32_t addr) {
    asm volatile("ldmatrix.sync.aligned.m8n8.x4.shared.b16 {%0,%1,%2,%3}, [%4];"
                 : "=r"(r0), "=r"(r1), "=r"(r2), "=r"(r3) : "r"(addr));
}
__device__ __forceinline__ void cp16(uint32_t* s, const void* g) {
    uint32_t sa = (uint32_t)__cvta_generic_to_shared(s);
    asm volatile("cp.async.cg.shared.global [%0], [%1], 16;" :: "r"(sa), "l"(g));
}
#define CP_COMMIT() asm volatile("cp.async.commit_group;")
#define CP_WAIT1()  asm volatile("cp.async.wait_group 1;" ::: "memory")

__device__ __forceinline__ uint32_t packhf(float a, float b) {
    __half2 p = __floats2half2_rn(a, b);
    return *(uint32_t*)&p;
}

// ---------------- embedding + pe (buggy-faithful) + fp16 plane ---------------
__global__ void embed_pe(const int* __restrict__ tok, const float* __restrict__ emb) {
    int idx = blockIdx.x * 256 + threadIdx.x;
    int d  = idx & (DDIM - 1);
    int bs = idx >> 10;
    int b  = bs >> 10;
    int t  = tok[bs];
    int i2 = (d >> 1) << 1;
    float div = expf(-(float)i2 * (9.210340371976184f / (float)DDIM));
    float ang = (float)b * div;
    float pe  = (d & 1) ? cosf(ang) : sinf(ang);
    float v = emb[(size_t)t * DDIM + d] + pe;
    g_x[idx]  = v;
    g_ah[idx] = __float2half_rn(v);
}

// ---------------- weight transpose + fp16 convert, all layers (z) -------------
__global__ __launch_bounds__(256)
void conv_w_t(const float* __restrict__ W0, hf16* __restrict__ th0,
              int K, int N, size_t ostride) {
    const size_t li = (size_t)blockIdx.z * K * N;
    const float* W = W0 + li;
    hf16* th = th0 + (size_t)blockIdx.z * ostride;
    __shared__ float tile[32][33];
    const int n0 = blockIdx.x * 32, k0 = blockIdx.y * 32;
    const int tx = threadIdx.x & 31, ty = threadIdx.x >> 5;
#pragma unroll
    for (int i = 0; i < 32; i += 8)
        tile[ty + i][tx] = W[(size_t)(k0 + ty + i) * N + n0 + tx];
    __syncthreads();
#pragma unroll
    for (int i = 0; i < 32; i += 8) {
        int n = n0 + ty + i, k = k0 + tx;
        th[(size_t)n * K + k] = __float2half_rn(tile[tx][ty + i]);
    }
}

// ---------------- pack QKV biases ---------------------------------------------
__global__ void pack_bias(const float* __restrict__ bq, const float* __restrict__ bk,
                          const float* __restrict__ bv) {
    int l = blockIdx.y;
    int i = blockIdx.x * 256 + threadIdx.x;
    float v = (i < DDIM) ? bq[l * DDIM + i]
            : (i < 2 * DDIM) ? bk[l * DDIM + i - DDIM]
            : bv[l * DDIM + i - 2 * DDIM];
    g_bqkv[l * QD + i] = v;
}

// ---------------- fp16 1-pass GEMM, 3-stage cp.async ring --------------------
// C = A[M,K] @ B[N,K]^T + bias.  BM=BN=128, BK=32, 256 thr.
// smem: 2 planes x 3 stages x 128 rows x 20 words = 15360 words = 60 KB.
#define G1_STAGE 2560
#define G1_PLANE (3 * G1_STAGE)
#define G1_SMEM  (2 * G1_PLANE * 4)

__device__ __forceinline__ void g1_copy_stage(
    uint32_t* sm, const hf16* __restrict__ Ah, const hf16* __restrict__ Bh,
    int m0, int n0, int K, int k0, int s, int tid) {
#pragma unroll
    for (int e = 0; e < 2; e++) {
        int c = tid + e * 256;
        int row = c >> 2, cw = (c & 3) << 2;
        int kk  = k0 + ((c & 3) << 3);
        int so = s * G1_STAGE + row * 20 + cw;
        cp16(sm + 0 * G1_PLANE + so, Ah + (size_t)(m0 + row) * K + kk);
        cp16(sm + 1 * G1_PLANE + so, Bh + (size_t)(n0 + row) * K + kk);
    }
}

template<bool RELU, bool PLANES, bool QSCALE>
__global__ __launch_bounds__(256, 3)
void gemm_hf1(const hf16* __restrict__ Ah, const hf16* __restrict__ Bh,
              const float* __restrict__ bias, float* __restrict__ C,
              hf16* __restrict__ Chf, int M, int N, int K) {
    extern __shared__ uint32_t sm[];
    const int tid  = threadIdx.x;
    const int wid  = tid >> 5, lane = tid & 31;
    const int gid  = lane >> 2, tig = lane & 3;
    const int wm   = wid >> 2, wn = wid & 3;
    const int m0   = blockIdx.y * 128, n0 = blockIdx.x * 128;
    const uint32_t sbase = (uint32_t)__cvta_generic_to_shared(sm);

    const int lr  = lane & 7;
    const int lg1 = (lane >> 3) & 1;
    const int lg2 = (lane >> 4) & 1;
    int rowA[4], rowB[2];
#pragma unroll
    for (int mt = 0; mt < 4; mt++) rowA[mt] = wm * 64 + mt * 16 + lg1 * 8 + lr;
#pragma unroll
    for (int np = 0; np < 2; np++) rowB[np] = wn * 32 + np * 16 + lg2 * 8 + lr;
    const int kA = lg2 * 4, kB = lg1 * 4;

    float acc[4][4][4];
#pragma unroll
    for (int mt = 0; mt < 4; mt++)
#pragma unroll
        for (int nt = 0; nt < 4; nt++)
#pragma unroll
            for (int i = 0; i < 4; i++) acc[mt][nt][i] = 0.f;

    g1_copy_stage(sm, Ah, Bh, m0, n0, K, 0, 0, tid);
    CP_COMMIT();
    g1_copy_stage(sm, Ah, Bh, m0, n0, K, 32, 1, tid);
    CP_COMMIT();

    int s = 0;
    for (int k0 = 0; k0 < K; k0 += 32) {
        CP_WAIT1();
        __syncthreads();
        // issue copy for stage s+2 BEFORE the MMA phase (2 phases to land)
        if (k0 + 64 < K) {
            int s2 = s + 2; if (s2 >= 3) s2 -= 3;
            g1_copy_stage(sm, Ah, Bh, m0, n0, K, k0 + 64, s2, tid);
        }
        CP_COMMIT();

        const uint32_t aA = sbase + (0 * G1_PLANE + s * G1_STAGE) * 4;
        const uint32_t aB = sbase + (1 * G1_PLANE + s * G1_STAGE) * 4;
#pragma unroll
        for (int sb = 0; sb < 2; sb++) {
            const int kb = sb * 8;
            uint32_t a4[4][4], b4[4][2];
#pragma unroll
            for (int mt = 0; mt < 4; mt++) {
                uint32_t off = (uint32_t)(rowA[mt] * 20 + kb + kA) * 4;
                ldsm4(a4[mt][0], a4[mt][1], a4[mt][2], a4[mt][3], aA + off);
            }
#pragma unroll
            for (int np = 0; np < 2; np++) {
                uint32_t off = (uint32_t)(rowB[np] * 20 + kb + kB) * 4;
                ldsm4(b4[2*np][0], b4[2*np][1], b4[2*np+1][0], b4[2*np+1][1],
                      aB + off);
            }
#pragma unroll
            for (int mt = 0; mt < 4; mt++)
#pragma unroll
                for (int nt = 0; nt < 4; nt++)
                    mma16h(acc[mt][nt], a4[mt], b4[nt]);
        }
        __syncthreads();
        if (++s == 3) s = 0;
    }

#pragma unroll
    for (int mt = 0; mt < 4; mt++) {
        int r0 = m0 + wm * 64 + mt * 16 + gid;
#pragma unroll
        for (int nt = 0; nt < 4; nt++) {
            int c = n0 + wn * 32 + nt * 8 + (tig << 1);
            float b0 = bias[c], b1 = bias[c + 1];
            float2 o0 = make_float2(acc[mt][nt][0] + b0, acc[mt][nt][1] + b1);
            float2 o1 = make_float2(acc[mt][nt][2] + b0, acc[mt][nt][3] + b1);
            if (RELU) {
                o0.x = fmaxf(o0.x, 0.f); o0.y = fmaxf(o0.y, 0.f);
                o1.x = fmaxf(o1.x, 0.f); o1.y = fmaxf(o1.y, 0.f);
            }
            if (QSCALE) {
                float sc = (c < DDIM) ? 0.125f : 1.0f;
                o0.x *= sc; o0.y *= sc; o1.x *= sc; o1.y *= sc;
            }
            if (PLANES) {
                *(__half2*)(Chf + (size_t)r0 * N + c) =
                    __floats2half2_rn(o0.x, o0.y);
                *(__half2*)(Chf + (size_t)(r0 + 8) * N + c) =
                    __floats2half2_rn(o1.x, o1.y);
            } else {
                *(float2*)(C + (size_t)r0 * N + c)       = o0;
                *(float2*)(C + (size_t)(r0 + 8) * N + c) = o1;
            }
        }
    }
}

// ---------------- fused flash attention (fp16 qkv input) ----------------------
__global__ __launch_bounds__(256, 2)
void flash_attn(const hf16* __restrict__ qkv) {
    __shared__ uint32_t Ks[64][36];
    __shared__ uint32_t Vs[64][36];   // [dim][key-pair]

    const int z = blockIdx.y, b = z >> 4, h = z & 15;
    const int i0 = blockIdx.x * 128;
    const hf16* Qg = qkv + (size_t)b * SS * QD + h * DKH;
    const hf16* Kg = Qg + DDIM;
    const hf16* Vg = Qg + 2 * DDIM;
    hf16* Oh = g_ah + (size_t)b * SS * DDIM + h * DKH;

    const int tid = threadIdx.x;
    const int wid = tid >> 5, lane = tid & 31;
    const int gid = lane >> 2, tig = lane & 3;
    const int mb  = wid * 16;

    uint32_t qf[4][4];
    {
        const size_t rA = (size_t)(i0 + mb + gid) * QD;
        const size_t rB = (size_t)(i0 + mb + gid + 8) * QD;
#pragma unroll
        for (int c = 0; c < 4; c++) {
            int col = c * 16 + (tig << 1);
            qf[c][0] = *(const uint32_t*)(Qg + rA + col);
            qf[c][1] = *(const uint32_t*)(Qg + rB + col);
            qf[c][2] = *(const uint32_t*)(Qg + rA + col + 8);
            qf[c][3] = *(const uint32_t*)(Qg + rB + col + 8);
        }
    }

    float acco[8][4];
#pragma unroll
    for (int nt = 0; nt < 8; nt++)
#pragma unroll
        for (int i = 0; i < 4; i++) acco[nt][i] = 0.f;
    float m_lo = -1e30f, m_hi = -1e30f, l_lo = 0.f, l_hi = 0.f;

    for (int j0 = 0; j0 < SS; j0 += 64) {
        __syncthreads();
#pragma unroll
        for (int e = 0; e < 2; e++) {
            int idx = tid + e * 256;
            int row = idx >> 3, c8 = (idx & 7) << 3;
            uint4 kk = *(const uint4*)(Kg + (size_t)(j0 + row) * QD + c8);
            *(uint4*)&Ks[row][c8 >> 1] = kk;
            uint4 vv = *(const uint4*)(Vg + (size_t)(j0 + row) * QD + c8);
            const hf16* vp = (const hf16*)&vv;
#pragma unroll
            for (int j = 0; j < 8; j++)
                ((hf16*)&Vs[c8 + j][0])[row] = vp[j];
        }
        __syncthreads();

        float accs[8][4];
#pragma unroll
        for (int nt = 0; nt < 8; nt++)
#pragma unroll
            for (int i = 0; i < 4; i++) accs[nt][i] = 0.f;
#pragma unroll
        for (int kc = 0; kc < 4; kc++) {
            const int w = kc * 8;
#pragma unroll
            for (int nt = 0; nt < 8; nt++) {
                uint32_t bb[2];
                bb[0] = Ks[nt * 8 + gid][w + tig];
                bb[1] = Ks[nt * 8 + gid][w + tig + 4];
                mma16h(accs[nt], qf[kc], bb);
            }
        }

        float mx_lo = -1e30f, mx_hi = -1e30f;
#pragma unroll
        for (int nt = 0; nt < 8; nt++) {
            mx_lo = fmaxf(mx_lo, fmaxf(accs[nt][0], accs[nt][1]));
            mx_hi = fmaxf(mx_hi, fmaxf(accs[nt][2], accs[nt][3]));
        }
        mx_lo = fmaxf(mx_lo, __shfl_xor_sync(~0u, mx_lo, 1));
        mx_lo = fmaxf(mx_lo, __shfl_xor_sync(~0u, mx_lo, 2));
        mx_hi = fmaxf(mx_hi, __shfl_xor_sync(~0u, mx_hi, 1));
        mx_hi = fmaxf(mx_hi, __shfl_xor_sync(~0u, mx_hi, 2));
        float mn_lo = fmaxf(m_lo, mx_lo), mn_hi = fmaxf(m_hi, mx_hi);
        float al_lo = __expf(m_lo - mn_lo), al_hi = __expf(m_hi - mn_hi);
        m_lo = mn_lo; m_hi = mn_hi;

        float sum_lo = 0.f, sum_hi = 0.f;
#pragma unroll
        for (int nt = 0; nt < 8; nt++) {
            accs[nt][0] = __expf(accs[nt][0] - m_lo);
            accs[nt][1] = __expf(accs[nt][1] - m_lo);
            accs[nt][2] = __expf(accs[nt][2] - m_hi);
            accs[nt][3] = __expf(accs[nt][3] - m_hi);
            sum_lo += accs[nt][0] + accs[nt][1];
            sum_hi += accs[nt][2] + accs[nt][3];
        }
        sum_lo += __shfl_xor_sync(~0u, sum_lo, 1);
        sum_lo += __shfl_xor_sync(~0u, sum_lo, 2);
        sum_hi += __shfl_xor_sync(~0u, sum_hi, 1);
        sum_hi += __shfl_xor_sync(~0u, sum_hi, 2);
        l_lo = l_lo * al_lo + sum_lo;
        l_hi = l_hi * al_hi + sum_hi;

#pragma unroll
        for (int nt = 0; nt < 8; nt++) {
            acco[nt][0] *= al_lo; acco[nt][1] *= al_lo;
            acco[nt][2] *= al_hi; acco[nt][3] *= al_hi;
        }

#pragma unroll
        for (int s = 0; s < 4; s++) {
            uint32_t a[4];
            a[0] = packhf(accs[2*s][0],     accs[2*s][1]);
            a[1] = packhf(accs[2*s][2],     accs[2*s][3]);
            a[2] = packhf(accs[2*s + 1][0], accs[2*s + 1][1]);
            a[3] = packhf(accs[2*s + 1][2], accs[2*s + 1][3]);
#pragma unroll
            for (int nt = 0; nt < 8; nt++) {
                uint32_t bb[2];
                bb[0] = Vs[nt * 8 + gid][s * 8 + tig];
                bb[1] = Vs[nt * 8 + gid][s * 8 + tig + 4];
                mma16h(acco[nt], a, bb);
            }
        }
    }

    const float inv_lo = 1.0f / l_lo, inv_hi = 1.0f / l_hi;
#pragma unroll
    for (int nt = 0; nt < 8; nt++) {
        int c = nt * 8 + (tig << 1);
        size_t r0 = (size_t)(i0 + mb + gid) * DDIM + c;
        size_t r1 = (size_t)(i0 + mb + gid + 8) * DDIM + c;
        *(__half2*)(Oh + r0) = __floats2half2_rn(acco[nt][0] * inv_lo,
                                                 acco[nt][1] * inv_lo);
        *(__half2*)(Oh + r1) = __floats2half2_rn(acco[nt][2] * inv_hi,
                                                 acco[nt][3] * inv_hi);
    }
}

// ---------------- add + LayerNorm (+ optional fp16 plane output) -------------
__global__ __launch_bounds__(256)
void add_ln(const float* __restrict__ x, const float* __restrict__ y,
            const float* __restrict__ g, const float* __restrict__ be,
            float* __restrict__ out, hf16* __restrict__ hi) {
    __shared__ float sm[8];
    __shared__ float bc;
    const int tid = threadIdx.x;
    const size_t ro = (size_t)blockIdx.x * DDIM;
    float4 a = reinterpret_cast<const float4*>(x + ro)[tid];
    float4 b = reinterpret_cast<const float4*>(y + ro)[tid];
    a.x += b.x; a.y += b.y; a.z += b.z; a.w += b.w;

    float s = a.x + a.y + a.z + a.w;
#pragma unroll
    for (int o = 16; o; o >>= 1) s += __shfl_xor_sync(~0u, s, o);
    if ((tid & 31) == 0) sm[tid >> 5] = s;
    __syncthreads();
    if (tid < 32) {
        float t = (tid < 8) ? sm[tid] : 0.f;
#pragma unroll
        for (int o = 4; o; o >>= 1) t += __shfl_xor_sync(~0u, t, o);
        if (tid == 0) bc = t;
    }
    __syncthreads();
    const float mu = bc * (1.0f / DDIM);
    a.x -= mu; a.y -= mu; a.z -= mu; a.w -= mu;
    float qv = a.x*a.x + a.y*a.y + a.z*a.z + a.w*a.w;
    __syncthreads();
#pragma unroll
    for (int o = 16; o; o >>= 1) qv += __shfl_xor_sync(~0u, qv, o);
    if ((tid & 31) == 0) sm[tid >> 5] = qv;
    __syncthreads();
    if (tid < 32) {
        float t = (tid < 8) ? sm[tid] : 0.f;
#pragma unroll
        for (int o = 4; o; o >>= 1) t += __shfl_xor_sync(~0u, t, o);
        if (tid == 0) bc = t;
    }
    __syncthreads();
    const float rs = rsqrtf(bc * (1.0f / DDIM) + 1e-5f);
    float4 gv = reinterpret_cast<const float4*>(g)[tid];
    float4 bv = reinterpret_cast<const float4*>(be)[tid];
    float4 o;
    o.x = a.x * rs * gv.x + bv.x;
    o.y = a.y * rs * gv.y + bv.y;
    o.z = a.z * rs * gv.z + bv.z;
    o.w = a.w * rs * gv.w + bv.w;
    reinterpret_cast<float4*>(out + ro)[tid] = o;
    if (hi) {
        size_t i4 = ro + tid * 4;
        *(__half2*)(hi + i4)     = __floats2half2_rn(o.x, o.y);
        *(__half2*)(hi + i4 + 2) = __floats2half2_rn(o.z, o.w);
    }
}

// ---------------- launch ------------------------------------------------------
extern "C" void kernel_launch(void* const* d_in, const int* in_sizes, int n_in,
                              void* d_out, int out_size) {
    const int*   tokens = (const int*)  d_in[0];
    const float* emb    = (const float*)d_in[1];
    const float* Wq = (const float*)d_in[2],  *bq = (const float*)d_in[3];
    const float* Wk = (const float*)d_in[4],  *bk = (const float*)d_in[5];
    const float* Wv = (const float*)d_in[6],  *bv = (const float*)d_in[7];
    const float* Wo = (const float*)d_in[8],  *bo = (const float*)d_in[9];
    const float* W1 = (const float*)d_in[10], *b1 = (const float*)d_in[11];
    const float* W2 = (const float*)d_in[12], *b2 = (const float*)d_in[13];
    const float* gamma = (const float*)d_in[14], *beta = (const float*)d_in[15];
    float* out = (float*)d_out;

    float *x, *t, *bqkv;
    cudaGetSymbolAddress((void**)&x,    g_x);
    cudaGetSymbolAddress((void**)&t,    g_t);
    cudaGetSymbolAddress((void**)&bqkv, g_bqkv);
    hf16 *qkv, *wqkvh, *woh, *w1h, *w2h, *ah, *hh;
    cudaGetSymbolAddress((void**)&qkv,   g_qkv);
    cudaGetSymbolAddress((void**)&wqkvh, g_wqkvh);
    cudaGetSymbolAddress((void**)&woh, g_woh);
    cudaGetSymbolAddress((void**)&w1h, g_w1h);
    cudaGetSymbolAddress((void**)&w2h, g_w2h);
    cudaGetSymbolAddress((void**)&ah,  g_ah);
    cudaGetSymbolAddress((void**)&hh,  g_hh);

    cudaFuncSetAttribute(gemm_hf1<false, true, true>,
                         cudaFuncAttributeMaxDynamicSharedMemorySize, G1_SMEM);
    cudaFuncSetAttribute(gemm_hf1<false, false, false>,
                         cudaFuncAttributeMaxDynamicSharedMemorySize, G1_SMEM);
    cudaFuncSetAttribute(gemm_hf1<true, true, false>,
                         cudaFuncAttributeMaxDynamicSharedMemorySize, G1_SMEM);

    embed_pe<<<BSR * DDIM / 256, 256>>>(tokens, emb);

    // weight conversion (hi only)
    const size_t DD = (size_t)DDIM * DDIM, DF = (size_t)DDIM * FFD;
    conv_w_t<<<dim3(DDIM / 32, DDIM / 32, LLAY), 256>>>(Wq, wqkvh,          DDIM, DDIM, 3 * DD);
    conv_w_t<<<dim3(DDIM / 32, DDIM / 32, LLAY), 256>>>(Wk, wqkvh + DD,     DDIM, DDIM, 3 * DD);
    conv_w_t<<<dim3(DDIM / 32, DDIM / 32, LLAY), 256>>>(Wv, wqkvh + 2 * DD, DDIM, DDIM, 3 * DD);
    conv_w_t<<<dim3(DDIM / 32, DDIM / 32, LLAY), 256>>>(Wo, woh, DDIM, DDIM, DD);
    conv_w_t<<<dim3(FFD  / 32, DDIM / 32, LLAY), 256>>>(W1, w1h, DDIM, FFD, DF);
    conv_w_t<<<dim3(DDIM / 32, FFD  / 32, LLAY), 256>>>(W2, w2h, FFD, DDIM, DF);
    pack_bias<<<dim3(QD / 256, LLAY), 256>>>(bq, bk, bv);

    const dim3 gqkv(QD  / 128, BSR / 128);  // 24 x 16
    const dim3 gp(DDIM / 128, BSR / 128);
    const dim3 gf(FFD  / 128, BSR / 128);

    for (int l = 0; l < LLAY; l++) {
        size_t od = (size_t)l * DD, of = (size_t)l * DF;
        const float* lbo = bo + (size_t)l * DDIM;
        const float* lb1 = b1 + (size_t)l * FFD;
        const float* lb2 = b2 + (size_t)l * DDIM;
        const float* lg  = gamma + (size_t)l * DDIM;
        const float* lbe = beta  + (size_t)l * DDIM;

        gemm_hf1<false, true, true><<<gqkv, 256, G1_SMEM>>>(
            ah, wqkvh + (size_t)l * 3 * DD, bqkv + (size_t)l * QD,
            nullptr, qkv, BSR, QD, DDIM);

        flash_attn<<<dim3(SS / 128, BB * HH), 256>>>(qkv);

        gemm_hf1<false, false, false><<<gp, 256, G1_SMEM>>>(
            ah, woh + od, lbo, t, nullptr, BSR, DDIM, DDIM);
        add_ln<<<BSR, 256>>>(x, t, lg, lbe, x, ah);

        gemm_hf1<true, true, false><<<gf, 256, G1_SMEM>>>(
            ah, w1h + of, lb1, nullptr, hh, BSR, FFD, DDIM);
        gemm_hf1<false, false, false><<<gp, 256, G1_SMEM>>>(
            hh, w2h + of, lb2, t, nullptr, BSR, DDIM, FFD);

        float* xo = (l == LLAY - 1) ? out : x;
        hf16* nh = (l == LLAY - 1) ? nullptr : ah;
        add_ln<<<BSR, 256>>>(x, t, lg, lbe, xo, nh);
    }
}

// round 15
// speedup vs baseline: 5.0919x; 1.0821x over previous
#include <cuda_runtime.h>
#include <cuda_bf16.h>
#include <cuda_fp16.h>
#include <math.h>
#include <stdint.h>

// Problem constants
#define BB   2
#define SS   1024
#define DDIM 1024
#define HH   16
#define LLAY 4
#define FFD  2048
#define DKH  64
#define BSR  (BB*SS)   // 2048 rows
#define QD   (3*DDIM)  // fused QKV width

typedef __half hf16;

// ---------------- scratch (static device globals; no allocs allowed) ----------
__device__ float g_x  [BSR*DDIM];
__device__ float g_t  [BSR*DDIM];
__device__ __align__(256) hf16 g_qkv[BSR*QD];   // fp16, Q pre-scaled by 1/8

// fp16 weights (hi only, 1-pass), transposed to [N][K]
__device__ __align__(256) hf16 g_wqkvh[LLAY*3*DDIM*DDIM];
__device__ __align__(256) hf16 g_woh[LLAY*DDIM*DDIM];
__device__ __align__(256) hf16 g_w1h[LLAY*DDIM*FFD];
__device__ __align__(256) hf16 g_w2h[LLAY*FFD*DDIM];
__device__ float g_bqkv[LLAY*QD];
// single fp16 activation planes
__device__ __align__(256) hf16 g_ah[BSR*DDIM];
__device__ __align__(256) hf16 g_hh[BSR*FFD];

// ---------------- helpers -----------------------------------------------------
__device__ __forceinline__ void mma16h(float* c, const uint32_t* a, const uint32_t* b) {
    asm volatile(
        "mma.sync.aligned.m16n8k16.row.col.f32.f16.f16.f32 "
        "{%0,%1,%2,%3}, {%4,%5,%6,%7}, {%8,%9}, {%0,%1,%2,%3};"
        : "+f"(c[0]), "+f"(c[1]), "+f"(c[2]), "+f"(c[3])
        : "r"(a[0]), "r"(a[1]), "r"(a[2]), "r"(a[3]), "r"(b[0]), "r"(b[1]));
}
__device__ __forceinline__ void ldsm4(uint32_t& r0, uint32_t& r1, uint32_t& r2,
                                      uint32_t& r3, uint32_t addr) {
    asm volatile("ldmatrix.sync.aligned.m8n8.x4.shared.b16 {%0,%1,%2,%3}, [%4];"
                 : "=r"(r0), "=r"(r1), "=r"(r2), "=r"(r3) : "r"(addr));
}
__device__ __forceinline__ void cp16(uint32_t* s, const void* g) {
    uint32_t sa = (uint32_t)__cvta_generic_to_shared(s);
    asm volatile("cp.async.cg.shared.global [%0], [%1], 16;" :: "r"(sa), "l"(g));
}
#define CP_COMMIT() asm volatile("cp.async.commit_group;")
#define CP_WAIT1()  asm volatile("cp.async.wait_group 1;" ::: "memory")

__device__ __forceinline__ uint32_t packhf(float a, float b) {
    __half2 p = __floats2half2_rn(a, b);
    return *(uint32_t*)&p;
}

// ---------------- embedding + pe (buggy-faithful) + fp16 plane ---------------
__global__ void embed_pe(const int* __restrict__ tok, const float* __restrict__ emb) {
    int idx = blockIdx.x * 256 + threadIdx.x;
    int d  = idx & (DDIM - 1);
    int bs = idx >> 10;
    int b  = bs >> 10;
    int t  = tok[bs];
    int i2 = (d >> 1) << 1;
    float div = expf(-(float)i2 * (9.210340371976184f / (float)DDIM));
    float ang = (float)b * div;
    float pe  = (d & 1) ? cosf(ang) : sinf(ang);
    float v = emb[(size_t)t * DDIM + d] + pe;
    g_x[idx]  = v;
    g_ah[idx] = __float2half_rn(v);
}

// ---------------- weight transpose + fp16 convert, all layers (z) -------------
__global__ __launch_bounds__(256)
void conv_w_t(const float* __restrict__ W0, hf16* __restrict__ th0,
              int K, int N, size_t ostride) {
    const size_t li = (size_t)blockIdx.z * K * N;
    const float* W = W0 + li;
    hf16* th = th0 + (size_t)blockIdx.z * ostride;
    __shared__ float tile[32][33];
    const int n0 = blockIdx.x * 32, k0 = blockIdx.y * 32;
    const int tx = threadIdx.x & 31, ty = threadIdx.x >> 5;
#pragma unroll
    for (int i = 0; i < 32; i += 8)
        tile[ty + i][tx] = W[(size_t)(k0 + ty + i) * N + n0 + tx];
    __syncthreads();
#pragma unroll
    for (int i = 0; i < 32; i += 8) {
        int n = n0 + ty + i, k = k0 + tx;
        th[(size_t)n * K + k] = __float2half_rn(tile[tx][ty + i]);
    }
}

// ---------------- pack QKV biases ---------------------------------------------
__global__ void pack_bias(const float* __restrict__ bq, const float* __restrict__ bk,
                          const float* __restrict__ bv) {
    int l = blockIdx.y;
    int i = blockIdx.x * 256 + threadIdx.x;
    float v = (i < DDIM) ? bq[l * DDIM + i]
            : (i < 2 * DDIM) ? bk[l * DDIM + i - DDIM]
            : bv[l * DDIM + i - 2 * DDIM];
    g_bqkv[l * QD + i] = v;
}

// ---------------- fp16 1-pass GEMM, 3-stage ring, templated BM ---------------
// C = A[M,K] @ B[N,K]^T + bias.  BM = MT*32, BN=128, BK=32, 256 thr, 8 warps.
// stage layout: A rows [0,BM) then B rows [BM,BM+128), 20 words per row.
#define G1_SMEM_MT(MT) (3 * ((MT * 32 + 128) * 20) * 4)

template<int MT>
__device__ __forceinline__ void g1_copy_stage(
    uint32_t* sm, const hf16* __restrict__ Ah, const hf16* __restrict__ Bh,
    int m0, int n0, int K, int k0, int s, int tid) {
    constexpr int BM  = MT * 32;
    constexpr int STW = (BM + 128) * 20;
    constexpr int PER = (BM + 128) * 4 / 256;
#pragma unroll
    for (int e = 0; e < PER; e++) {
        int c = tid + e * 256;
        int row = c >> 2, cw = (c & 3) << 2;
        int kk  = k0 + ((c & 3) << 3);
        int so = s * STW + row * 20 + cw;
        if (row < BM)
            cp16(sm + so, Ah + (size_t)(m0 + row) * K + kk);
        else
            cp16(sm + so, Bh + (size_t)(n0 + row - BM) * K + kk);
    }
}

template<int MT, bool RELU, bool PLANES, bool QSCALE>
__global__ __launch_bounds__(256, 3)
void gemm_hf1(const hf16* __restrict__ Ah, const hf16* __restrict__ Bh,
              const float* __restrict__ bias, float* __restrict__ C,
              hf16* __restrict__ Chf, int M, int N, int K) {
    constexpr int BM  = MT * 32;
    constexpr int STW = (BM + 128) * 20;
    extern __shared__ uint32_t sm[];
    const int tid  = threadIdx.x;
    const int wid  = tid >> 5, lane = tid & 31;
    const int gid  = lane >> 2, tig = lane & 3;
    const int wm   = wid >> 2, wn = wid & 3;
    const int m0   = blockIdx.y * BM, n0 = blockIdx.x * 128;
    const uint32_t sbase = (uint32_t)__cvta_generic_to_shared(sm);

    const int lr  = lane & 7;
    const int lg1 = (lane >> 3) & 1;
    const int lg2 = (lane >> 4) & 1;
    int rowA[MT], rowB[2];
#pragma unroll
    for (int mt = 0; mt < MT; mt++)
        rowA[mt] = wm * (MT * 16) + mt * 16 + lg1 * 8 + lr;
#pragma unroll
    for (int np = 0; np < 2; np++) rowB[np] = wn * 32 + np * 16 + lg2 * 8 + lr;
    const int kA = lg2 * 4, kB = lg1 * 4;

    float acc[MT][4][4];
#pragma unroll
    for (int mt = 0; mt < MT; mt++)
#pragma unroll
        for (int nt = 0; nt < 4; nt++)
#pragma unroll
            for (int i = 0; i < 4; i++) acc[mt][nt][i] = 0.f;

    g1_copy_stage<MT>(sm, Ah, Bh, m0, n0, K, 0, 0, tid);
    CP_COMMIT();
    g1_copy_stage<MT>(sm, Ah, Bh, m0, n0, K, 32, 1, tid);
    CP_COMMIT();

    int s = 0;
    for (int k0 = 0; k0 < K; k0 += 32) {
        CP_WAIT1();
        __syncthreads();
        if (k0 + 64 < K) {
            int s2 = s + 2; if (s2 >= 3) s2 -= 3;
            g1_copy_stage<MT>(sm, Ah, Bh, m0, n0, K, k0 + 64, s2, tid);
        }
        CP_COMMIT();

        const uint32_t aA = sbase + (s * STW) * 4;
        const uint32_t aB = sbase + (s * STW + BM * 20) * 4;
#pragma unroll
        for (int sb = 0; sb < 2; sb++) {
            const int kb = sb * 8;
            uint32_t a4[MT][4], b4[4][2];
#pragma unroll
            for (int mt = 0; mt < MT; mt++) {
                uint32_t off = (uint32_t)(rowA[mt] * 20 + kb + kA) * 4;
                ldsm4(a4[mt][0], a4[mt][1], a4[mt][2], a4[mt][3], aA + off);
            }
#pragma unroll
            for (int np = 0; np < 2; np++) {
                uint32_t off = (uint32_t)(rowB[np] * 20 + kb + kB) * 4;
                ldsm4(b4[2*np][0], b4[2*np][1], b4[2*np+1][0], b4[2*np+1][1],
                      aB + off);
            }
#pragma unroll
            for (int mt = 0; mt < MT; mt++)
#pragma unroll
                for (int nt = 0; nt < 4; nt++)
                    mma16h(acc[mt][nt], a4[mt], b4[nt]);
        }
        __syncthreads();
        if (++s == 3) s = 0;
    }

#pragma unroll
    for (int mt = 0; mt < MT; mt++) {
        int r0 = m0 + wm * (MT * 16) + mt * 16 + gid;
#pragma unroll
        for (int nt = 0; nt < 4; nt++) {
            int c = n0 + wn * 32 + nt * 8 + (tig << 1);
            float b0 = bias[c], b1 = bias[c + 1];
            float2 o0 = make_float2(acc[mt][nt][0] + b0, acc[mt][nt][1] + b1);
            float2 o1 = make_float2(acc[mt][nt][2] + b0, acc[mt][nt][3] + b1);
            if (RELU) {
                o0.x = fmaxf(o0.x, 0.f); o0.y = fmaxf(o0.y, 0.f);
                o1.x = fmaxf(o1.x, 0.f); o1.y = fmaxf(o1.y, 0.f);
            }
            if (QSCALE) {
                float sc = (c < DDIM) ? 0.125f : 1.0f;
                o0.x *= sc; o0.y *= sc; o1.x *= sc; o1.y *= sc;
            }
            if (PLANES) {
                *(__half2*)(Chf + (size_t)r0 * N + c) =
                    __floats2half2_rn(o0.x, o0.y);
                *(__half2*)(Chf + (size_t)(r0 + 8) * N + c) =
                    __floats2half2_rn(o1.x, o1.y);
            } else {
                *(float2*)(C + (size_t)r0 * N + c)       = o0;
                *(float2*)(C + (size_t)(r0 + 8) * N + c) = o1;
            }
        }
    }
}

// ---------------- fused flash attention (fp16 qkv input) ----------------------
__global__ __launch_bounds__(256, 2)
void flash_attn(const hf16* __restrict__ qkv) {
    __shared__ uint32_t Ks[64][36];
    __shared__ uint32_t Vs[64][36];   // [dim][key-pair]

    const int z = blockIdx.y, b = z >> 4, h = z & 15;
    const int i0 = blockIdx.x * 128;
    const hf16* Qg = qkv + (size_t)b * SS * QD + h * DKH;
    const hf16* Kg = Qg + DDIM;
    const hf16* Vg = Qg + 2 * DDIM;
    hf16* Oh = g_ah + (size_t)b * SS * DDIM + h * DKH;

    const int tid = threadIdx.x;
    const int wid = tid >> 5, lane = tid & 31;
    const int gid = lane >> 2, tig = lane & 3;
    const int mb  = wid * 16;

    uint32_t qf[4][4];
    {
        const size_t rA = (size_t)(i0 + mb + gid) * QD;
        const size_t rB = (size_t)(i0 + mb + gid + 8) * QD;
#pragma unroll
        for (int c = 0; c < 4; c++) {
            int col = c * 16 + (tig << 1);
            qf[c][0] = *(const uint32_t*)(Qg + rA + col);
            qf[c][1] = *(const uint32_t*)(Qg + rB + col);
            qf[c][2] = *(const uint32_t*)(Qg + rA + col + 8);
            qf[c][3] = *(const uint32_t*)(Qg + rB + col + 8);
        }
    }

    float acco[8][4];
#pragma unroll
    for (int nt = 0; nt < 8; nt++)
#pragma unroll
        for (int i = 0; i < 4; i++) acco[nt][i] = 0.f;
    float m_lo = -1e30f, m_hi = -1e30f, l_lo = 0.f, l_hi = 0.f;

    for (int j0 = 0; j0 < SS; j0 += 64) {
        __syncthreads();
#pragma unroll
        for (int e = 0; e < 2; e++) {
            int idx = tid + e * 256;
            int row = idx >> 3, c8 = (idx & 7) << 3;
            uint4 kk = *(const uint4*)(Kg + (size_t)(j0 + row) * QD + c8);
            *(uint4*)&Ks[row][c8 >> 1] = kk;
            uint4 vv = *(const uint4*)(Vg + (size_t)(j0 + row) * QD + c8);
            const hf16* vp = (const hf16*)&vv;
#pragma unroll
            for (int j = 0; j < 8; j++)
                ((hf16*)&Vs[c8 + j][0])[row] = vp[j];
        }
        __syncthreads();

        float accs[8][4];
#pragma unroll
        for (int nt = 0; nt < 8; nt++)
#pragma unroll
            for (int i = 0; i < 4; i++) accs[nt][i] = 0.f;
#pragma unroll
        for (int kc = 0; kc < 4; kc++) {
            const int w = kc * 8;
#pragma unroll
            for (int nt = 0; nt < 8; nt++) {
                uint32_t bb[2];
                bb[0] = Ks[nt * 8 + gid][w + tig];
                bb[1] = Ks[nt * 8 + gid][w + tig + 4];
                mma16h(accs[nt], qf[kc], bb);
            }
        }

        float mx_lo = -1e30f, mx_hi = -1e30f;
#pragma unroll
        for (int nt = 0; nt < 8; nt++) {
            mx_lo = fmaxf(mx_lo, fmaxf(accs[nt][0], accs[nt][1]));
            mx_hi = fmaxf(mx_hi, fmaxf(accs[nt][2], accs[nt][3]));
        }
        mx_lo = fmaxf(mx_lo, __shfl_xor_sync(~0u, mx_lo, 1));
        mx_lo = fmaxf(mx_lo, __shfl_xor_sync(~0u, mx_lo, 2));
        mx_hi = fmaxf(mx_hi, __shfl_xor_sync(~0u, mx_hi, 1));
        mx_hi = fmaxf(mx_hi, __shfl_xor_sync(~0u, mx_hi, 2));
        float mn_lo = fmaxf(m_lo, mx_lo), mn_hi = fmaxf(m_hi, mx_hi);
        float al_lo = __expf(m_lo - mn_lo), al_hi = __expf(m_hi - mn_hi);
        m_lo = mn_lo; m_hi = mn_hi;

        float sum_lo = 0.f, sum_hi = 0.f;
#pragma unroll
        for (int nt = 0; nt < 8; nt++) {
            accs[nt][0] = __expf(accs[nt][0] - m_lo);
            accs[nt][1] = __expf(accs[nt][1] - m_lo);
            accs[nt][2] = __expf(accs[nt][2] - m_hi);
            accs[nt][3] = __expf(accs[nt][3] - m_hi);
            sum_lo += accs[nt][0] + accs[nt][1];
            sum_hi += accs[nt][2] + accs[nt][3];
        }
        sum_lo += __shfl_xor_sync(~0u, sum_lo, 1);
        sum_lo += __shfl_xor_sync(~0u, sum_lo, 2);
        sum_hi += __shfl_xor_sync(~0u, sum_hi, 1);
        sum_hi += __shfl_xor_sync(~0u, sum_hi, 2);
        l_lo = l_lo * al_lo + sum_lo;
        l_hi = l_hi * al_hi + sum_hi;

#pragma unroll
        for (int nt = 0; nt < 8; nt++) {
            acco[nt][0] *= al_lo; acco[nt][1] *= al_lo;
            acco[nt][2] *= al_hi; acco[nt][3] *= al_hi;
        }

#pragma unroll
        for (int s = 0; s < 4; s++) {
            uint32_t a[4];
            a[0] = packhf(accs[2*s][0],     accs[2*s][1]);
            a[1] = packhf(accs[2*s][2],     accs[2*s][3]);
            a[2] = packhf(accs[2*s + 1][0], accs[2*s + 1][1]);
            a[3] = packhf(accs[2*s + 1][2], accs[2*s + 1][3]);
#pragma unroll
            for (int nt = 0; nt < 8; nt++) {
                uint32_t bb[2];
                bb[0] = Vs[nt * 8 + gid][s * 8 + tig];
                bb[1] = Vs[nt * 8 + gid][s * 8 + tig + 4];
                mma16h(acco[nt], a, bb);
            }
        }
    }

    const float inv_lo = 1.0f / l_lo, inv_hi = 1.0f / l_hi;
#pragma unroll
    for (int nt = 0; nt < 8; nt++) {
        int c = nt * 8 + (tig << 1);
        size_t r0 = (size_t)(i0 + mb + gid) * DDIM + c;
        size_t r1 = (size_t)(i0 + mb + gid + 8) * DDIM + c;
        *(__half2*)(Oh + r0) = __floats2half2_rn(acco[nt][0] * inv_lo,
                                                 acco[nt][1] * inv_lo);
        *(__half2*)(Oh + r1) = __floats2half2_rn(acco[nt][2] * inv_hi,
                                                 acco[nt][3] * inv_hi);
    }
}

// ---------------- add + LayerNorm (+ optional fp16 plane output) -------------
__global__ __launch_bounds__(256)
void add_ln(const float* __restrict__ x, const float* __restrict__ y,
            const float* __restrict__ g, const float* __restrict__ be,
            float* __restrict__ out, hf16* __restrict__ hi) {
    __shared__ float sm[8];
    __shared__ float bc;
    const int tid = threadIdx.x;
    const size_t ro = (size_t)blockIdx.x * DDIM;
    float4 a = reinterpret_cast<const float4*>(x + ro)[tid];
    float4 b = reinterpret_cast<const float4*>(y + ro)[tid];
    a.x += b.x; a.y += b.y; a.z += b.z; a.w += b.w;

    float s = a.x + a.y + a.z + a.w;
#pragma unroll
    for (int o = 16; o; o >>= 1) s += __shfl_xor_sync(~0u, s, o);
    if ((tid & 31) == 0) sm[tid >> 5] = s;
    __syncthreads();
    if (tid < 32) {
        float t = (tid < 8) ? sm[tid] : 0.f;
#pragma unroll
        for (int o = 4; o; o >>= 1) t += __shfl_xor_sync(~0u, t, o);
        if (tid == 0) bc = t;
    }
    __syncthreads();
    const float mu = bc * (1.0f / DDIM);
    a.x -= mu; a.y -= mu; a.z -= mu; a.w -= mu;
    float qv = a.x*a.x + a.y*a.y + a.z*a.z + a.w*a.w;
    __syncthreads();
#pragma unroll
    for (int o = 16; o; o >>= 1) qv += __shfl_xor_sync(~0u, qv, o);
    if ((tid & 31) == 0) sm[tid >> 5] = qv;
    __syncthreads();
    if (tid < 32) {
        float t = (tid < 8) ? sm[tid] : 0.f;
#pragma unroll
        for (int o = 4; o; o >>= 1) t += __shfl_xor_sync(~0u, t, o);
        if (tid == 0) bc = t;
    }
    __syncthreads();
    const float rs = rsqrtf(bc * (1.0f / DDIM) + 1e-5f);
    float4 gv = reinterpret_cast<const float4*>(g)[tid];
    float4 bv = reinterpret_cast<const float4*>(be)[tid];
    float4 o;
    o.x = a.x * rs * gv.x + bv.x;
    o.y = a.y * rs * gv.y + bv.y;
    o.z = a.z * rs * gv.z + bv.z;
    o.w = a.w * rs * gv.w + bv.w;
    reinterpret_cast<float4*>(out + ro)[tid] = o;
    if (hi) {
        size_t i4 = ro + tid * 4;
        *(__half2*)(hi + i4)     = __floats2half2_rn(o.x, o.y);
        *(__half2*)(hi + i4 + 2) = __floats2half2_rn(o.z, o.w);
    }
}

// ---------------- launch ------------------------------------------------------
extern "C" void kernel_launch(void* const* d_in, const int* in_sizes, int n_in,
                              void* d_out, int out_size) {
    const int*   tokens = (const int*)  d_in[0];
    const float* emb    = (const float*)d_in[1];
    const float* Wq = (const float*)d_in[2],  *bq = (const float*)d_in[3];
    const float* Wk = (const float*)d_in[4],  *bk = (const float*)d_in[5];
    const float* Wv = (const float*)d_in[6],  *bv = (const float*)d_in[7];
    const float* Wo = (const float*)d_in[8],  *bo = (const float*)d_in[9];
    const float* W1 = (const float*)d_in[10], *b1 = (const float*)d_in[11];
    const float* W2 = (const float*)d_in[12], *b2 = (const float*)d_in[13];
    const float* gamma = (const float*)d_in[14], *beta = (const float*)d_in[15];
    float* out = (float*)d_out;

    float *x, *t, *bqkv;
    cudaGetSymbolAddress((void**)&x,    g_x);
    cudaGetSymbolAddress((void**)&t,    g_t);
    cudaGetSymbolAddress((void**)&bqkv, g_bqkv);
    hf16 *qkv, *wqkvh, *woh, *w1h, *w2h, *ah, *hh;
    cudaGetSymbolAddress((void**)&qkv,   g_qkv);
    cudaGetSymbolAddress((void**)&wqkvh, g_wqkvh);
    cudaGetSymbolAddress((void**)&woh, g_woh);
    cudaGetSymbolAddress((void**)&w1h, g_w1h);
    cudaGetSymbolAddress((void**)&w2h, g_w2h);
    cudaGetSymbolAddress((void**)&ah,  g_ah);
    cudaGetSymbolAddress((void**)&hh,  g_hh);

    cudaFuncSetAttribute(gemm_hf1<4, false, true, true>,
                         cudaFuncAttributeMaxDynamicSharedMemorySize, G1_SMEM_MT(4));
    cudaFuncSetAttribute(gemm_hf1<4, true, true, false>,
                         cudaFuncAttributeMaxDynamicSharedMemorySize, G1_SMEM_MT(4));
    cudaFuncSetAttribute(gemm_hf1<2, false, false, false>,
                         cudaFuncAttributeMaxDynamicSharedMemorySize, G1_SMEM_MT(2));

    embed_pe<<<BSR * DDIM / 256, 256>>>(tokens, emb);

    // weight conversion (hi only)
    const size_t DD = (size_t)DDIM * DDIM, DF = (size_t)DDIM * FFD;
    conv_w_t<<<dim3(DDIM / 32, DDIM / 32, LLAY), 256>>>(Wq, wqkvh,          DDIM, DDIM, 3 * DD);
    conv_w_t<<<dim3(DDIM / 32, DDIM / 32, LLAY), 256>>>(Wk, wqkvh + DD,     DDIM, DDIM, 3 * DD);
    conv_w_t<<<dim3(DDIM / 32, DDIM / 32, LLAY), 256>>>(Wv, wqkvh + 2 * DD, DDIM, DDIM, 3 * DD);
    conv_w_t<<<dim3(DDIM / 32, DDIM / 32, LLAY), 256>>>(Wo, woh, DDIM, DDIM, DD);
    conv_w_t<<<dim3(FFD  / 32, DDIM / 32, LLAY), 256>>>(W1, w1h, DDIM, FFD, DF);
    conv_w_t<<<dim3(DDIM / 32, FFD  / 32, LLAY), 256>>>(W2, w2h, FFD, DDIM, DF);
    pack_bias<<<dim3(QD / 256, LLAY), 256>>>(bq, bk, bv);

    const dim3 gqkv(QD  / 128, BSR / 128);  // 24 x 16
    const dim3 gp64(DDIM / 128, BSR / 64);  // 8 x 32 = 256 CTAs (BM=64)
    const dim3 gf(FFD  / 128, BSR / 128);   // 16 x 16

    for (int l = 0; l < LLAY; l++) {
        size_t od = (size_t)l * DD, of = (size_t)l * DF;
        const float* lbo = bo + (size_t)l * DDIM;
        const float* lb1 = b1 + (size_t)l * FFD;
        const float* lb2 = b2 + (size_t)l * DDIM;
        const float* lg  = gamma + (size_t)l * DDIM;
        const float* lbe = beta  + (size_t)l * DDIM;

        gemm_hf1<4, false, true, true><<<gqkv, 256, G1_SMEM_MT(4)>>>(
            ah, wqkvh + (size_t)l * 3 * DD, bqkv + (size_t)l * QD,
            nullptr, qkv, BSR, QD, DDIM);

        flash_attn<<<dim3(SS / 128, BB * HH), 256>>>(qkv);

        gemm_hf1<2, false, false, false><<<gp64, 256, G1_SMEM_MT(2)>>>(
            ah, woh + od, lbo, t, nullptr, BSR, DDIM, DDIM);
        add_ln<<<BSR, 256>>>(x, t, lg, lbe, x, ah);

        gemm_hf1<4, true, true, false><<<gf, 256, G1_SMEM_MT(4)>>>(
            ah, w1h + of, lb1, nullptr, hh, BSR, FFD, DDIM);
        gemm_hf1<2, false, false, false><<<gp64, 256, G1_SMEM_MT(2)>>>(
            hh, w2h + of, lb2, t, nullptr, BSR, DDIM, FFD);

        float* xo = (l == LLAY - 1) ? out : x;
        hf16* nh = (l == LLAY - 1) ? nullptr : ah;
        add_ln<<<BSR, 256>>>(x, t, lg, lbe, xo, nh);
    }
}

// round 16
// speedup vs baseline: 5.2249x; 1.0261x over previous
#include <cuda_runtime.h>
#include <cuda_bf16.h>
#include <cuda_fp16.h>
#include <math.h>
#include <stdint.h>

// Problem constants
#define BB   2
#define SS   1024
#define DDIM 1024
#define HH   16
#define LLAY 4
#define FFD  2048
#define DKH  64
#define BSR  (BB*SS)   // 2048 rows
#define QD   (3*DDIM)  // fused QKV width

typedef __half hf16;

// ---------------- scratch (static device globals; no allocs allowed) ----------
__device__ float g_x  [BSR*DDIM];
__device__ float g_t  [BSR*DDIM];
__device__ __align__(256) hf16 g_qkv[BSR*QD];   // fp16, Q pre-scaled by 1/8

// fp16 weights (hi only, 1-pass), transposed to [N][K]
__device__ __align__(256) hf16 g_wqkvh[LLAY*3*DDIM*DDIM];
__device__ __align__(256) hf16 g_woh[LLAY*DDIM*DDIM];
__device__ __align__(256) hf16 g_w1h[LLAY*DDIM*FFD];
__device__ __align__(256) hf16 g_w2h[LLAY*FFD*DDIM];
__device__ float g_bqkv[LLAY*QD];
// single fp16 activation planes
__device__ __align__(256) hf16 g_ah[BSR*DDIM];
__device__ __align__(256) hf16 g_hh[BSR*FFD];

// ---------------- helpers -----------------------------------------------------
__device__ __forceinline__ void mma16h(float* c, const uint32_t* a, const uint32_t* b) {
    asm volatile(
        "mma.sync.aligned.m16n8k16.row.col.f32.f16.f16.f32 "
        "{%0,%1,%2,%3}, {%4,%5,%6,%7}, {%8,%9}, {%0,%1,%2,%3};"
        : "+f"(c[0]), "+f"(c[1]), "+f"(c[2]), "+f"(c[3])
        : "r"(a[0]), "r"(a[1]), "r"(a[2]), "r"(a[3]), "r"(b[0]), "r"(b[1]));
}
__device__ __forceinline__ void ldsm4(uint32_t& r0, uint32_t& r1, uint32_t& r2,
                                      uint32_t& r3, uint32_t addr) {
    asm volatile("ldmatrix.sync.aligned.m8n8.x4.shared.b16 {%0,%1,%2,%3}, [%4];"
                 : "=r"(r0), "=r"(r1), "=r"(r2), "=r"(r3) : "r"(addr));
}
__device__ __forceinline__ void cp16(uint32_t* s, const void* g) {
    uint32_t sa = (uint32_t)__cvta_generic_to_shared(s);
    asm volatile("cp.async.cg.shared.global [%0], [%1], 16;" :: "r"(sa), "l"(g));
}
#define CP_COMMIT() asm volatile("cp.async.commit_group;")
#define CP_WAIT1()  asm volatile("cp.async.wait_group 1;" ::: "memory")

__device__ __forceinline__ uint32_t packhf(float a, float b) {
    __half2 p = __floats2half2_rn(a, b);
    return *(uint32_t*)&p;
}

// ---------------- embedding + pe (buggy-faithful) + fp16 plane ---------------
__global__ void embed_pe(const int* __restrict__ tok, const float* __restrict__ emb) {
    int idx = blockIdx.x * 256 + threadIdx.x;
    int d  = idx & (DDIM - 1);
    int bs = idx >> 10;
    int b  = bs >> 10;
    int t  = tok[bs];
    int i2 = (d >> 1) << 1;
    float div = expf(-(float)i2 * (9.210340371976184f / (float)DDIM));
    float ang = (float)b * div;
    float pe  = (d & 1) ? cosf(ang) : sinf(ang);
    float v = emb[(size_t)t * DDIM + d] + pe;
    g_x[idx]  = v;
    g_ah[idx] = __float2half_rn(v);
}

// ---------------- weight transpose + fp16 convert (fast, half2 stores) -------
// tile 64(k) x 32(n); output th[n][k] with 4-byte coalesced stores.
__global__ __launch_bounds__(256)
void conv_w_t(const float* __restrict__ W0, hf16* __restrict__ th0,
              int K, int N, size_t ostride) {
    const size_t li = (size_t)blockIdx.z * K * N;
    const float* W = W0 + li;
    hf16* th = th0 + (size_t)blockIdx.z * ostride;
    __shared__ float tile[64][33];
    const int n0 = blockIdx.x * 32, k0 = blockIdx.y * 64;
    const int tx = threadIdx.x & 31, ty = threadIdx.x >> 5;
    // read: 64 k-rows x 32 n-cols, coalesced along n
#pragma unroll
    for (int i = 0; i < 64; i += 8)
        tile[ty + i][tx] = W[(size_t)(k0 + ty + i) * N + n0 + tx];
    __syncthreads();
    // write: per warp, one n-row, 32 half2 along k = 128B coalesced
#pragma unroll
    for (int i = 0; i < 32; i += 8) {
        int n = n0 + ty + i;
        __half2 h = __floats2half2_rn(tile[2 * tx][ty + i],
                                      tile[2 * tx + 1][ty + i]);
        *(__half2*)(th + (size_t)n * K + k0 + 2 * tx) = h;
    }
}

// ---------------- pack QKV biases ---------------------------------------------
__global__ void pack_bias(const float* __restrict__ bq, const float* __restrict__ bk,
                          const float* __restrict__ bv) {
    int l = blockIdx.y;
    int i = blockIdx.x * 256 + threadIdx.x;
    float v = (i < DDIM) ? bq[l * DDIM + i]
            : (i < 2 * DDIM) ? bk[l * DDIM + i - DDIM]
            : bv[l * DDIM + i - 2 * DDIM];
    g_bqkv[l * QD + i] = v;
}

// ---------------- fp16 1-pass GEMM, 3-stage ring, templated BM ---------------
// C = A[M,K] @ B[N,K]^T + bias.  BM = MT*32, BN=128, BK=32, 256 thr, 8 warps.
#define G1_SMEM_MT(MT) (3 * ((MT * 32 + 128) * 20) * 4)

template<int MT>
__device__ __forceinline__ void g1_copy_stage(
    uint32_t* sm, const hf16* __restrict__ Ah, const hf16* __restrict__ Bh,
    int m0, int n0, int K, int k0, int s, int tid) {
    constexpr int BM  = MT * 32;
    constexpr int STW = (BM + 128) * 20;
    constexpr int PER = (BM + 128) * 4 / 256;
#pragma unroll
    for (int e = 0; e < PER; e++) {
        int c = tid + e * 256;
        int row = c >> 2, cw = (c & 3) << 2;
        int kk  = k0 + ((c & 3) << 3);
        int so = s * STW + row * 20 + cw;
        if (row < BM)
            cp16(sm + so, Ah + (size_t)(m0 + row) * K + kk);
        else
            cp16(sm + so, Bh + (size_t)(n0 + row - BM) * K + kk);
    }
}

template<int MT, bool RELU, bool PLANES, bool QSCALE>
__global__ __launch_bounds__(256, 3)
void gemm_hf1(const hf16* __restrict__ Ah, const hf16* __restrict__ Bh,
              const float* __restrict__ bias, float* __restrict__ C,
              hf16* __restrict__ Chf, int M, int N, int K) {
    constexpr int BM  = MT * 32;
    constexpr int STW = (BM + 128) * 20;
    extern __shared__ uint32_t sm[];
    const int tid  = threadIdx.x;
    const int wid  = tid >> 5, lane = tid & 31;
    const int gid  = lane >> 2, tig = lane & 3;
    const int wm   = wid >> 2, wn = wid & 3;
    const int m0   = blockIdx.y * BM, n0 = blockIdx.x * 128;
    const uint32_t sbase = (uint32_t)__cvta_generic_to_shared(sm);

    const int lr  = lane & 7;
    const int lg1 = (lane >> 3) & 1;
    const int lg2 = (lane >> 4) & 1;
    int rowA[MT], rowB[2];
#pragma unroll
    for (int mt = 0; mt < MT; mt++)
        rowA[mt] = wm * (MT * 16) + mt * 16 + lg1 * 8 + lr;
#pragma unroll
    for (int np = 0; np < 2; np++) rowB[np] = wn * 32 + np * 16 + lg2 * 8 + lr;
    const int kA = lg2 * 4, kB = lg1 * 4;

    float acc[MT][4][4];
#pragma unroll
    for (int mt = 0; mt < MT; mt++)
#pragma unroll
        for (int nt = 0; nt < 4; nt++)
#pragma unroll
            for (int i = 0; i < 4; i++) acc[mt][nt][i] = 0.f;

    g1_copy_stage<MT>(sm, Ah, Bh, m0, n0, K, 0, 0, tid);
    CP_COMMIT();
    g1_copy_stage<MT>(sm, Ah, Bh, m0, n0, K, 32, 1, tid);
    CP_COMMIT();

    int s = 0;
    for (int k0 = 0; k0 < K; k0 += 32) {
        CP_WAIT1();
        __syncthreads();
        if (k0 + 64 < K) {
            int s2 = s + 2; if (s2 >= 3) s2 -= 3;
            g1_copy_stage<MT>(sm, Ah, Bh, m0, n0, K, k0 + 64, s2, tid);
        }
        CP_COMMIT();

        const uint32_t aA = sbase + (s * STW) * 4;
        const uint32_t aB = sbase + (s * STW + BM * 20) * 4;
#pragma unroll
        for (int sb = 0; sb < 2; sb++) {
            const int kb = sb * 8;
            uint32_t a4[MT][4], b4[4][2];
#pragma unroll
            for (int mt = 0; mt < MT; mt++) {
                uint32_t off = (uint32_t)(rowA[mt] * 20 + kb + kA) * 4;
                ldsm4(a4[mt][0], a4[mt][1], a4[mt][2], a4[mt][3], aA + off);
            }
#pragma unroll
            for (int np = 0; np < 2; np++) {
                uint32_t off = (uint32_t)(rowB[np] * 20 + kb + kB) * 4;
                ldsm4(b4[2*np][0], b4[2*np][1], b4[2*np+1][0], b4[2*np+1][1],
                      aB + off);
            }
#pragma unroll
            for (int mt = 0; mt < MT; mt++)
#pragma unroll
                for (int nt = 0; nt < 4; nt++)
                    mma16h(acc[mt][nt], a4[mt], b4[nt]);
        }
        __syncthreads();
        if (++s == 3) s = 0;
    }

#pragma unroll
    for (int mt = 0; mt < MT; mt++) {
        int r0 = m0 + wm * (MT * 16) + mt * 16 + gid;
#pragma unroll
        for (int nt = 0; nt < 4; nt++) {
            int c = n0 + wn * 32 + nt * 8 + (tig << 1);
            float b0 = bias[c], b1 = bias[c + 1];
            float2 o0 = make_float2(acc[mt][nt][0] + b0, acc[mt][nt][1] + b1);
            float2 o1 = make_float2(acc[mt][nt][2] + b0, acc[mt][nt][3] + b1);
            if (RELU) {
                o0.x = fmaxf(o0.x, 0.f); o0.y = fmaxf(o0.y, 0.f);
                o1.x = fmaxf(o1.x, 0.f); o1.y = fmaxf(o1.y, 0.f);
            }
            if (QSCALE) {
                float sc = (c < DDIM) ? 0.125f : 1.0f;
                o0.x *= sc; o0.y *= sc; o1.x *= sc; o1.y *= sc;
            }
            if (PLANES) {
                *(__half2*)(Chf + (size_t)r0 * N + c) =
                    __floats2half2_rn(o0.x, o0.y);
                *(__half2*)(Chf + (size_t)(r0 + 8) * N + c) =
                    __floats2half2_rn(o1.x, o1.y);
            } else {
                *(float2*)(C + (size_t)r0 * N + c)       = o0;
                *(float2*)(C + (size_t)(r0 + 8) * N + c) = o1;
            }
        }
    }
}

// ---------------- fused flash attention (fp16 qkv input) ----------------------
__global__ __launch_bounds__(256, 2)
void flash_attn(const hf16* __restrict__ qkv) {
    __shared__ uint32_t Ks[64][36];
    __shared__ uint32_t Vs[64][36];   // [dim][key-pair]

    const int z = blockIdx.y, b = z >> 4, h = z & 15;
    const int i0 = blockIdx.x * 128;
    const hf16* Qg = qkv + (size_t)b * SS * QD + h * DKH;
    const hf16* Kg = Qg + DDIM;
    const hf16* Vg = Qg + 2 * DDIM;
    hf16* Oh = g_ah + (size_t)b * SS * DDIM + h * DKH;

    const int tid = threadIdx.x;
    const int wid = tid >> 5, lane = tid & 31;
    const int gid = lane >> 2, tig = lane & 3;
    const int mb  = wid * 16;

    uint32_t qf[4][4];
    {
        const size_t rA = (size_t)(i0 + mb + gid) * QD;
        const size_t rB = (size_t)(i0 + mb + gid + 8) * QD;
#pragma unroll
        for (int c = 0; c < 4; c++) {
            int col = c * 16 + (tig << 1);
            qf[c][0] = *(const uint32_t*)(Qg + rA + col);
            qf[c][1] = *(const uint32_t*)(Qg + rB + col);
            qf[c][2] = *(const uint32_t*)(Qg + rA + col + 8);
            qf[c][3] = *(const uint32_t*)(Qg + rB + col + 8);
        }
    }

    float acco[8][4];
#pragma unroll
    for (int nt = 0; nt < 8; nt++)
#pragma unroll
        for (int i = 0; i < 4; i++) acco[nt][i] = 0.f;
    float m_lo = -1e30f, m_hi = -1e30f, l_lo = 0.f, l_hi = 0.f;

    for (int j0 = 0; j0 < SS; j0 += 64) {
        __syncthreads();
#pragma unroll
        for (int e = 0; e < 2; e++) {
            int idx = tid + e * 256;
            int row = idx >> 3, c8 = (idx & 7) << 3;
            uint4 kk = *(const uint4*)(Kg + (size_t)(j0 + row) * QD + c8);
            *(uint4*)&Ks[row][c8 >> 1] = kk;
            uint4 vv = *(const uint4*)(Vg + (size_t)(j0 + row) * QD + c8);
            const hf16* vp = (const hf16*)&vv;
#pragma unroll
            for (int j = 0; j < 8; j++)
                ((hf16*)&Vs[c8 + j][0])[row] = vp[j];
        }
        __syncthreads();

        float accs[8][4];
#pragma unroll
        for (int nt = 0; nt < 8; nt++)
#pragma unroll
            for (int i = 0; i < 4; i++) accs[nt][i] = 0.f;
#pragma unroll
        for (int kc = 0; kc < 4; kc++) {
            const int w = kc * 8;
#pragma unroll
            for (int nt = 0; nt < 8; nt++) {
                uint32_t bb[2];
                bb[0] = Ks[nt * 8 + gid][w + tig];
                bb[1] = Ks[nt * 8 + gid][w + tig + 4];
                mma16h(accs[nt], qf[kc], bb);
            }
        }

        float mx_lo = -1e30f, mx_hi = -1e30f;
#pragma unroll
        for (int nt = 0; nt < 8; nt++) {
            mx_lo = fmaxf(mx_lo, fmaxf(accs[nt][0], accs[nt][1]));
            mx_hi = fmaxf(mx_hi, fmaxf(accs[nt][2], accs[nt][3]));
        }
        mx_lo = fmaxf(mx_lo, __shfl_xor_sync(~0u, mx_lo, 1));
        mx_lo = fmaxf(mx_lo, __shfl_xor_sync(~0u, mx_lo, 2));
        mx_hi = fmaxf(mx_hi, __shfl_xor_sync(~0u, mx_hi, 1));
        mx_hi = fmaxf(mx_hi, __shfl_xor_sync(~0u, mx_hi, 2));
        float mn_lo = fmaxf(m_lo, mx_lo), mn_hi = fmaxf(m_hi, mx_hi);
        float al_lo = __expf(m_lo - mn_lo), al_hi = __expf(m_hi - mn_hi);
        m_lo = mn_lo; m_hi = mn_hi;

        float sum_lo = 0.f, sum_hi = 0.f;
#pragma unroll
        for (int nt = 0; nt < 8; nt++) {
            accs[nt][0] = __expf(accs[nt][0] - m_lo);
            accs[nt][1] = __expf(accs[nt][1] - m_lo);
            accs[nt][2] = __expf(accs[nt][2] - m_hi);
            accs[nt][3] = __expf(accs[nt][3] - m_hi);
            sum_lo += accs[nt][0] + accs[nt][1];
            sum_hi += accs[nt][2] + accs[nt][3];
        }
        sum_lo += __shfl_xor_sync(~0u, sum_lo, 1);
        sum_lo += __shfl_xor_sync(~0u, sum_lo, 2);
        sum_hi += __shfl_xor_sync(~0u, sum_hi, 1);
        sum_hi += __shfl_xor_sync(~0u, sum_hi, 2);
        l_lo = l_lo * al_lo + sum_lo;
        l_hi = l_hi * al_hi + sum_hi;

#pragma unroll
        for (int nt = 0; nt < 8; nt++) {
            acco[nt][0] *= al_lo; acco[nt][1] *= al_lo;
            acco[nt][2] *= al_hi; acco[nt][3] *= al_hi;
        }

#pragma unroll
        for (int s = 0; s < 4; s++) {
            uint32_t a[4];
            a[0] = packhf(accs[2*s][0],     accs[2*s][1]);
            a[1] = packhf(accs[2*s][2],     accs[2*s][3]);
            a[2] = packhf(accs[2*s + 1][0], accs[2*s + 1][1]);
            a[3] = packhf(accs[2*s + 1][2], accs[2*s + 1][3]);
#pragma unroll
            for (int nt = 0; nt < 8; nt++) {
                uint32_t bb[2];
                bb[0] = Vs[nt * 8 + gid][s * 8 + tig];
                bb[1] = Vs[nt * 8 + gid][s * 8 + tig + 4];
                mma16h(acco[nt], a, bb);
            }
        }
    }

    const float inv_lo = 1.0f / l_lo, inv_hi = 1.0f / l_hi;
#pragma unroll
    for (int nt = 0; nt < 8; nt++) {
        int c = nt * 8 + (tig << 1);
        size_t r0 = (size_t)(i0 + mb + gid) * DDIM + c;
        size_t r1 = (size_t)(i0 + mb + gid + 8) * DDIM + c;
        *(__half2*)(Oh + r0) = __floats2half2_rn(acco[nt][0] * inv_lo,
                                                 acco[nt][1] * inv_lo);
        *(__half2*)(Oh + r1) = __floats2half2_rn(acco[nt][2] * inv_hi,
                                                 acco[nt][3] * inv_hi);
    }
}

// ---------------- add + LayerNorm (+ optional fp16 plane output) -------------
__global__ __launch_bounds__(256)
void add_ln(const float* __restrict__ x, const float* __restrict__ y,
            const float* __restrict__ g, const float* __restrict__ be,
            float* __restrict__ out, hf16* __restrict__ hi) {
    __shared__ float sm[8];
    __shared__ float bc;
    const int tid = threadIdx.x;
    const size_t ro = (size_t)blockIdx.x * DDIM;
    float4 a = reinterpret_cast<const float4*>(x + ro)[tid];
    float4 b = reinterpret_cast<const float4*>(y + ro)[tid];
    a.x += b.x; a.y += b.y; a.z += b.z; a.w += b.w;

    float s = a.x + a.y + a.z + a.w;
#pragma unroll
    for (int o = 16; o; o >>= 1) s += __shfl_xor_sync(~0u, s, o);
    if ((tid & 31) == 0) sm[tid >> 5] = s;
    __syncthreads();
    if (tid < 32) {
        float t = (tid < 8) ? sm[tid] : 0.f;
#pragma unroll
        for (int o = 4; o; o >>= 1) t += __shfl_xor_sync(~0u, t, o);
        if (tid == 0) bc = t;
    }
    __syncthreads();
    const float mu = bc * (1.0f / DDIM);
    a.x -= mu; a.y -= mu; a.z -= mu; a.w -= mu;
    float qv = a.x*a.x + a.y*a.y + a.z*a.z + a.w*a.w;
    __syncthreads();
#pragma unroll
    for (int o = 16; o; o >>= 1) qv += __shfl_xor_sync(~0u, qv, o);
    if ((tid & 31) == 0) sm[tid >> 5] = qv;
    __syncthreads();
    if (tid < 32) {
        float t = (tid < 8) ? sm[tid] : 0.f;
#pragma unroll
        for (int o = 4; o; o >>= 1) t += __shfl_xor_sync(~0u, t, o);
        if (tid == 0) bc = t;
    }
    __syncthreads();
    const float rs = rsqrtf(bc * (1.0f / DDIM) + 1e-5f);
    float4 gv = reinterpret_cast<const float4*>(g)[tid];
    float4 bv = reinterpret_cast<const float4*>(be)[tid];
    float4 o;
    o.x = a.x * rs * gv.x + bv.x;
    o.y = a.y * rs * gv.y + bv.y;
    o.z = a.z * rs * gv.z + bv.z;
    o.w = a.w * rs * gv.w + bv.w;
    reinterpret_cast<float4*>(out + ro)[tid] = o;
    if (hi) {
        size_t i4 = ro + tid * 4;
        *(__half2*)(hi + i4)     = __floats2half2_rn(o.x, o.y);
        *(__half2*)(hi + i4 + 2) = __floats2half2_rn(o.z, o.w);
    }
}

// ---------------- launch ------------------------------------------------------
extern "C" void kernel_launch(void* const* d_in, const int* in_sizes, int n_in,
                              void* d_out, int out_size) {
    const int*   tokens = (const int*)  d_in[0];
    const float* emb    = (const float*)d_in[1];
    const float* Wq = (const float*)d_in[2],  *bq = (const float*)d_in[3];
    const float* Wk = (const float*)d_in[4],  *bk = (const float*)d_in[5];
    const float* Wv = (const float*)d_in[6],  *bv = (const float*)d_in[7];
    const float* Wo = (const float*)d_in[8],  *bo = (const float*)d_in[9];
    const float* W1 = (const float*)d_in[10], *b1 = (const float*)d_in[11];
    const float* W2 = (const float*)d_in[12], *b2 = (const float*)d_in[13];
    const float* gamma = (const float*)d_in[14], *beta = (const float*)d_in[15];
    float* out = (float*)d_out;

    float *x, *t, *bqkv;
    cudaGetSymbolAddress((void**)&x,    g_x);
    cudaGetSymbolAddress((void**)&t,    g_t);
    cudaGetSymbolAddress((void**)&bqkv, g_bqkv);
    hf16 *qkv, *wqkvh, *woh, *w1h, *w2h, *ah, *hh;
    cudaGetSymbolAddress((void**)&qkv,   g_qkv);
    cudaGetSymbolAddress((void**)&wqkvh, g_wqkvh);
    cudaGetSymbolAddress((void**)&woh, g_woh);
    cudaGetSymbolAddress((void**)&w1h, g_w1h);
    cudaGetSymbolAddress((void**)&w2h, g_w2h);
    cudaGetSymbolAddress((void**)&ah,  g_ah);
    cudaGetSymbolAddress((void**)&hh,  g_hh);

    cudaFuncSetAttribute(gemm_hf1<4, false, true, true>,
                         cudaFuncAttributeMaxDynamicSharedMemorySize, G1_SMEM_MT(4));
    cudaFuncSetAttribute(gemm_hf1<2, true, true, false>,
                         cudaFuncAttributeMaxDynamicSharedMemorySize, G1_SMEM_MT(2));
    cudaFuncSetAttribute(gemm_hf1<2, false, false, false>,
                         cudaFuncAttributeMaxDynamicSharedMemorySize, G1_SMEM_MT(2));

    embed_pe<<<BSR * DDIM / 256, 256>>>(tokens, emb);

    // weight conversion (hi only, fast transpose)
    const size_t DD = (size_t)DDIM * DDIM, DF = (size_t)DDIM * FFD;
    conv_w_t<<<dim3(DDIM / 32, DDIM / 64, LLAY), 256>>>(Wq, wqkvh,          DDIM, DDIM, 3 * DD);
    conv_w_t<<<dim3(DDIM / 32, DDIM / 64, LLAY), 256>>>(Wk, wqkvh + DD,     DDIM, DDIM, 3 * DD);
    conv_w_t<<<dim3(DDIM / 32, DDIM / 64, LLAY), 256>>>(Wv, wqkvh + 2 * DD, DDIM, DDIM, 3 * DD);
    conv_w_t<<<dim3(DDIM / 32, DDIM / 64, LLAY), 256>>>(Wo, woh, DDIM, DDIM, DD);
    conv_w_t<<<dim3(FFD  / 32, DDIM / 64, LLAY), 256>>>(W1, w1h, DDIM, FFD, DF);
    conv_w_t<<<dim3(DDIM / 32, FFD  / 64, LLAY), 256>>>(W2, w2h, FFD, DDIM, DF);
    pack_bias<<<dim3(QD / 256, LLAY), 256>>>(bq, bk, bv);

    const dim3 gqkv(QD  / 128, BSR / 128);  // 24 x 16 = 384 CTAs (MT=4)
    const dim3 gp64(DDIM / 128, BSR / 64);  // 8 x 32 = 256 CTAs (MT=2)
    const dim3 gf64(FFD  / 128, BSR / 64);  // 16 x 32 = 512 CTAs (MT=2)

    for (int l = 0; l < LLAY; l++) {
        size_t od = (size_t)l * DD, of = (size_t)l * DF;
        const float* lbo = bo + (size_t)l * DDIM;
        const float* lb1 = b1 + (size_t)l * FFD;
        const float* lb2 = b2 + (size_t)l * DDIM;
        const float* lg  = gamma + (size_t)l * DDIM;
        const float* lbe = beta  + (size_t)l * DDIM;

        gemm_hf1<4, false, true, true><<<gqkv, 256, G1_SMEM_MT(4)>>>(
            ah, wqkvh + (size_t)l * 3 * DD, bqkv + (size_t)l * QD,
            nullptr, qkv, BSR, QD, DDIM);

        flash_attn<<<dim3(SS / 128, BB * HH), 256>>>(qkv);

        gemm_hf1<2, false, false, false><<<gp64, 256, G1_SMEM_MT(2)>>>(
            ah, woh + od, lbo, t, nullptr, BSR, DDIM, DDIM);
        add_ln<<<BSR, 256>>>(x, t, lg, lbe, x, ah);

        gemm_hf1<2, true, true, false><<<gf64, 256, G1_SMEM_MT(2)>>>(
            ah, w1h + of, lb1, nullptr, hh, BSR, FFD, DDIM);
        gemm_hf1<2, false, false, false><<<gp64, 256, G1_SMEM_MT(2)>>>(
            hh, w2h + of, lb2, t, nullptr, BSR, DDIM, FFD);

        float* xo = (l == LLAY - 1) ? out : x;
        hf16* nh = (l == LLAY - 1) ? nullptr : ah;
        add_ln<<<BSR, 256>>>(x, t, lg, lbe, xo, nh);
    }
}

// round 17
// speedup vs baseline: 5.4448x; 1.0421x over previous
#include <cuda_runtime.h>
#include <cuda_bf16.h>
#include <cuda_fp16.h>
#include <math.h>
#include <stdint.h>

// Problem constants
#define BB   2
#define SS   1024
#define DDIM 1024
#define HH   16
#define LLAY 4
#define FFD  2048
#define DKH  64
#define BSR  (BB*SS)   // 2048 rows
#define QD   (3*DDIM)  // fused QKV width

typedef __half hf16;

// ---------------- scratch (static device globals; no allocs allowed) ----------
__device__ float g_x  [BSR*DDIM];
__device__ float g_t  [BSR*DDIM];
__device__ __align__(256) hf16 g_qkv[BSR*QD];   // fp16, Q pre-scaled by 1/8

// fp16 weights (hi only), NATURAL [K][N] layout (no transpose)
__device__ __align__(256) hf16 g_wqkvh[LLAY*DDIM*QD];        // [K][3N] packed
__device__ __align__(256) hf16 g_woh[LLAY*DDIM*DDIM];
__device__ __align__(256) hf16 g_w1h[LLAY*DDIM*FFD];
__device__ __align__(256) hf16 g_w2h[LLAY*FFD*DDIM];
__device__ float g_bqkv[LLAY*QD];
// single fp16 activation planes
__device__ __align__(256) hf16 g_ah[BSR*DDIM];
__device__ __align__(256) hf16 g_hh[BSR*FFD];

// ---------------- helpers -----------------------------------------------------
__device__ __forceinline__ void mma16h(float* c, const uint32_t* a, const uint32_t* b) {
    asm volatile(
        "mma.sync.aligned.m16n8k16.row.col.f32.f16.f16.f32 "
        "{%0,%1,%2,%3}, {%4,%5,%6,%7}, {%8,%9}, {%0,%1,%2,%3};"
        : "+f"(c[0]), "+f"(c[1]), "+f"(c[2]), "+f"(c[3])
        : "r"(a[0]), "r"(a[1]), "r"(a[2]), "r"(a[3]), "r"(b[0]), "r"(b[1]));
}
__device__ __forceinline__ void ldsm4(uint32_t& r0, uint32_t& r1, uint32_t& r2,
                                      uint32_t& r3, uint32_t addr) {
    asm volatile("ldmatrix.sync.aligned.m8n8.x4.shared.b16 {%0,%1,%2,%3}, [%4];"
                 : "=r"(r0), "=r"(r1), "=r"(r2), "=r"(r3) : "r"(addr));
}
__device__ __forceinline__ void ldsm4t(uint32_t& r0, uint32_t& r1, uint32_t& r2,
                                       uint32_t& r3, uint32_t addr) {
    asm volatile("ldmatrix.sync.aligned.m8n8.x4.trans.shared.b16 {%0,%1,%2,%3}, [%4];"
                 : "=r"(r0), "=r"(r1), "=r"(r2), "=r"(r3) : "r"(addr));
}
__device__ __forceinline__ void cp16(uint32_t* s, const void* g) {
    uint32_t sa = (uint32_t)__cvta_generic_to_shared(s);
    asm volatile("cp.async.cg.shared.global [%0], [%1], 16;" :: "r"(sa), "l"(g));
}
#define CP_COMMIT() asm volatile("cp.async.commit_group;")
#define CP_WAIT1()  asm volatile("cp.async.wait_group 1;" ::: "memory")

__device__ __forceinline__ uint32_t packhf(float a, float b) {
    __half2 p = __floats2half2_rn(a, b);
    return *(uint32_t*)&p;
}

// ---------------- embedding + pe (buggy-faithful) + fp16 plane ---------------
__global__ void embed_pe(const int* __restrict__ tok, const float* __restrict__ emb) {
    int idx = blockIdx.x * 256 + threadIdx.x;
    int d  = idx & (DDIM - 1);
    int bs = idx >> 10;
    int b  = bs >> 10;
    int t  = tok[bs];
    int i2 = (d >> 1) << 1;
    float div = expf(-(float)i2 * (9.210340371976184f / (float)DDIM));
    float ang = (float)b * div;
    float pe  = (d & 1) ? cosf(ang) : sinf(ang);
    float v = emb[(size_t)t * DDIM + d] + pe;
    g_x[idx]  = v;
    g_ah[idx] = __float2half_rn(v);
}

// ---------------- weight fp16 convert (flat, no transpose) --------------------
// in: W[z][K][N] fp32; out: out + z*ostride + k*oldb + ooff + n (fp16)
__global__ __launch_bounds__(256)
void conv_w(const float* __restrict__ W, hf16* __restrict__ out,
            int N, int oldb, int ooff, size_t istride, size_t ostride) {
    const float* Wl = W + (size_t)blockIdx.z * istride;
    hf16* ol = out + (size_t)blockIdx.z * ostride;
    size_t i4 = ((size_t)blockIdx.x * 256 + threadIdx.x) * 4;
    float4 v = *(const float4*)(Wl + i4);
    size_t k = i4 / N, n = i4 - k * N;
    hf16* p = ol + k * oldb + ooff + n;
    *(__half2*)(p)     = __floats2half2_rn(v.x, v.y);
    *(__half2*)(p + 2) = __floats2half2_rn(v.z, v.w);
}

// ---------------- pack QKV biases ---------------------------------------------
__global__ void pack_bias(const float* __restrict__ bq, const float* __restrict__ bk,
                          const float* __restrict__ bv) {
    int l = blockIdx.y;
    int i = blockIdx.x * 256 + threadIdx.x;
    float v = (i < DDIM) ? bq[l * DDIM + i]
            : (i < 2 * DDIM) ? bk[l * DDIM + i - DDIM]
            : bv[l * DDIM + i - 2 * DDIM];
    g_bqkv[l * QD + i] = v;
}

// ---------------- fp16 1-pass GEMM, 3-stage ring, B via ldmatrix.trans -------
// C = A[M,K] @ B[K,N] + bias.  BM = MT*32, BN=128, BK=32, 256 thr, 8 warps.
// stage: A rows [0,BM) x 20 words; B k-rows [0,32) x 68 words ([k][n] fp16).
#define G1_STW(MT)     (MT * 32 * 20 + 32 * 68)
#define G1_SMEM_MT(MT) (3 * G1_STW(MT) * 4)

template<int MT>
__device__ __forceinline__ void g1_copy_stage(
    uint32_t* sm, const hf16* __restrict__ Ah, const hf16* __restrict__ Bh,
    int m0, int n0, int K, int ldb, int k0, int s, int tid) {
    constexpr int BM  = MT * 32;
    constexpr int STW = G1_STW(MT);
    constexpr int ACP = BM * 4;
    constexpr int PER = (ACP + 512) / 256;
#pragma unroll
    for (int e = 0; e < PER; e++) {
        int c = tid + e * 256;
        if (c < ACP) {
            int row = c >> 2, cw = (c & 3) << 2;
            int kk  = k0 + ((c & 3) << 3);
            cp16(sm + s * STW + row * 20 + cw, Ah + (size_t)(m0 + row) * K + kk);
        } else {
            int c2 = c - ACP;
            int kr = c2 >> 4, ch = c2 & 15;
            cp16(sm + s * STW + BM * 20 + kr * 68 + ch * 4,
                 Bh + (size_t)(k0 + kr) * ldb + n0 + ch * 8);
        }
    }
}

template<int MT, bool RELU, bool PLANES, bool QSCALE>
__global__ __launch_bounds__(256, 3)
void gemm_hf1(const hf16* __restrict__ Ah, const hf16* __restrict__ Bh,
              const float* __restrict__ bias, float* __restrict__ C,
              hf16* __restrict__ Chf, int M, int N, int K, int ldb) {
    constexpr int BM  = MT * 32;
    constexpr int STW = G1_STW(MT);
    extern __shared__ uint32_t sm[];
    const int tid  = threadIdx.x;
    const int wid  = tid >> 5, lane = tid & 31;
    const int gid  = lane >> 2, tig = lane & 3;
    const int wm   = wid >> 2, wn = wid & 3;
    const int m0   = blockIdx.y * BM, n0 = blockIdx.x * 128;
    const uint32_t sbase = (uint32_t)__cvta_generic_to_shared(sm);

    const int lr  = lane & 7;
    const int lg1 = (lane >> 3) & 1;
    const int lg2 = (lane >> 4) & 1;
    int rowA[MT];
#pragma unroll
    for (int mt = 0; mt < MT; mt++)
        rowA[mt] = wm * (MT * 16) + mt * 16 + lg1 * 8 + lr;
    const int kA = lg2 * 4;
    // B trans addressing: group (lane>>3): bit0 = k-half, bit1 = n-block
    const int rB = ((lane >> 3) & 1) * 8 + lr;         // k row within 16
    const int nB = ((lane >> 4) & 1) * 8 + wn * 32;    // n offset (+np*16)

    float acc[MT][4][4];
#pragma unroll
    for (int mt = 0; mt < MT; mt++)
#pragma unroll
        for (int nt = 0; nt < 4; nt++)
#pragma unroll
            for (int i = 0; i < 4; i++) acc[mt][nt][i] = 0.f;

    g1_copy_stage<MT>(sm, Ah, Bh, m0, n0, K, ldb, 0, 0, tid);
    CP_COMMIT();
    g1_copy_stage<MT>(sm, Ah, Bh, m0, n0, K, ldb, 32, 1, tid);
    CP_COMMIT();

    int s = 0;
    for (int k0 = 0; k0 < K; k0 += 32) {
        CP_WAIT1();
        __syncthreads();
        if (k0 + 64 < K) {
            int s2 = s + 2; if (s2 >= 3) s2 -= 3;
            g1_copy_stage<MT>(sm, Ah, Bh, m0, n0, K, ldb, k0 + 64, s2, tid);
        }
        CP_COMMIT();

        const uint32_t aA = sbase + (s * STW) * 4;
        const uint32_t aB = sbase + (s * STW + BM * 20) * 4;
#pragma unroll
        for (int sb = 0; sb < 2; sb++) {
            const int kb = sb * 8;       // word offset for A
            const int kh = sb * 16;      // half offset for B k rows
            uint32_t a4[MT][4], b4[4][2];
#pragma unroll
            for (int mt = 0; mt < MT; mt++) {
                uint32_t off = (uint32_t)(rowA[mt] * 20 + kb + kA) * 4;
                ldsm4(a4[mt][0], a4[mt][1], a4[mt][2], a4[mt][3], aA + off);
            }
#pragma unroll
            for (int np = 0; np < 2; np++) {
                uint32_t addr = aB + (uint32_t)(kh + rB) * 272
                                   + (uint32_t)(nB + np * 16) * 2;
                ldsm4t(b4[2*np][0], b4[2*np][1], b4[2*np+1][0], b4[2*np+1][1],
                       addr);
            }
#pragma unroll
            for (int mt = 0; mt < MT; mt++)
#pragma unroll
                for (int nt = 0; nt < 4; nt++)
                    mma16h(acc[mt][nt], a4[mt], b4[nt]);
        }
        __syncthreads();
        if (++s == 3) s = 0;
    }

#pragma unroll
    for (int mt = 0; mt < MT; mt++) {
        int r0 = m0 + wm * (MT * 16) + mt * 16 + gid;
#pragma unroll
        for (int nt = 0; nt < 4; nt++) {
            int c = n0 + wn * 32 + nt * 8 + (tig << 1);
            float b0 = bias[c], b1 = bias[c + 1];
            float2 o0 = make_float2(acc[mt][nt][0] + b0, acc[mt][nt][1] + b1);
            float2 o1 = make_float2(acc[mt][nt][2] + b0, acc[mt][nt][3] + b1);
            if (RELU) {
                o0.x = fmaxf(o0.x, 0.f); o0.y = fmaxf(o0.y, 0.f);
                o1.x = fmaxf(o1.x, 0.f); o1.y = fmaxf(o1.y, 0.f);
            }
            if (QSCALE) {
                float sc = (c < DDIM) ? 0.125f : 1.0f;
                o0.x *= sc; o0.y *= sc; o1.x *= sc; o1.y *= sc;
            }
            if (PLANES) {
                *(__half2*)(Chf + (size_t)r0 * N + c) =
                    __floats2half2_rn(o0.x, o0.y);
                *(__half2*)(Chf + (size_t)(r0 + 8) * N + c) =
                    __floats2half2_rn(o1.x, o1.y);
            } else {
                *(float2*)(C + (size_t)r0 * N + c)       = o0;
                *(float2*)(C + (size_t)(r0 + 8) * N + c) = o1;
            }
        }
    }
}

// ---------------- fused flash attention (fp16 qkv input) ----------------------
__global__ __launch_bounds__(256, 2)
void flash_attn(const hf16* __restrict__ qkv) {
    __shared__ uint32_t Ks[64][36];
    __shared__ uint32_t Vs[64][36];   // [dim][key-pair]

    const int z = blockIdx.y, b = z >> 4, h = z & 15;
    const int i0 = blockIdx.x * 128;
    const hf16* Qg = qkv + (size_t)b * SS * QD + h * DKH;
    const hf16* Kg = Qg + DDIM;
    const hf16* Vg = Qg + 2 * DDIM;
    hf16* Oh = g_ah + (size_t)b * SS * DDIM + h * DKH;

    const int tid = threadIdx.x;
    const int wid = tid >> 5, lane = tid & 31;
    const int gid = lane >> 2, tig = lane & 3;
    const int mb  = wid * 16;

    uint32_t qf[4][4];
    {
        const size_t rA = (size_t)(i0 + mb + gid) * QD;
        const size_t rB = (size_t)(i0 + mb + gid + 8) * QD;
#pragma unroll
        for (int c = 0; c < 4; c++) {
            int col = c * 16 + (tig << 1);
            qf[c][0] = *(const uint32_t*)(Qg + rA + col);
            qf[c][1] = *(const uint32_t*)(Qg + rB + col);
            qf[c][2] = *(const uint32_t*)(Qg + rA + col + 8);
            qf[c][3] = *(const uint32_t*)(Qg + rB + col + 8);
        }
    }

    float acco[8][4];
#pragma unroll
    for (int nt = 0; nt < 8; nt++)
#pragma unroll
        for (int i = 0; i < 4; i++) acco[nt][i] = 0.f;
    float m_lo = -1e30f, m_hi = -1e30f, l_lo = 0.f, l_hi = 0.f;

    for (int j0 = 0; j0 < SS; j0 += 64) {
        __syncthreads();
#pragma unroll
        for (int e = 0; e < 2; e++) {
            int idx = tid + e * 256;
            int row = idx >> 3, c8 = (idx & 7) << 3;
            uint4 kk = *(const uint4*)(Kg + (size_t)(j0 + row) * QD + c8);
            *(uint4*)&Ks[row][c8 >> 1] = kk;
            uint4 vv = *(const uint4*)(Vg + (size_t)(j0 + row) * QD + c8);
            const hf16* vp = (const hf16*)&vv;
#pragma unroll
            for (int j = 0; j < 8; j++)
                ((hf16*)&Vs[c8 + j][0])[row] = vp[j];
        }
        __syncthreads();

        float accs[8][4];
#pragma unroll
        for (int nt = 0; nt < 8; nt++)
#pragma unroll
            for (int i = 0; i < 4; i++) accs[nt][i] = 0.f;
#pragma unroll
        for (int kc = 0; kc < 4; kc++) {
            const int w = kc * 8;
#pragma unroll
            for (int nt = 0; nt < 8; nt++) {
                uint32_t bb[2];
                bb[0] = Ks[nt * 8 + gid][w + tig];
                bb[1] = Ks[nt * 8 + gid][w + tig + 4];
                mma16h(accs[nt], qf[kc], bb);
            }
        }

        float mx_lo = -1e30f, mx_hi = -1e30f;
#pragma unroll
        for (int nt = 0; nt < 8; nt++) {
            mx_lo = fmaxf(mx_lo, fmaxf(accs[nt][0], accs[nt][1]));
            mx_hi = fmaxf(mx_hi, fmaxf(accs[nt][2], accs[nt][3]));
        }
        mx_lo = fmaxf(mx_lo, __shfl_xor_sync(~0u, mx_lo, 1));
        mx_lo = fmaxf(mx_lo, __shfl_xor_sync(~0u, mx_lo, 2));
        mx_hi = fmaxf(mx_hi, __shfl_xor_sync(~0u, mx_hi, 1));
        mx_hi = fmaxf(mx_hi, __shfl_xor_sync(~0u, mx_hi, 2));
        float mn_lo = fmaxf(m_lo, mx_lo), mn_hi = fmaxf(m_hi, mx_hi);
        float al_lo = __expf(m_lo - mn_lo), al_hi = __expf(m_hi - mn_hi);
        m_lo = mn_lo; m_hi = mn_hi;

        float sum_lo = 0.f, sum_hi = 0.f;
#pragma unroll
        for (int nt = 0; nt < 8; nt++) {
            accs[nt][0] = __expf(accs[nt][0] - m_lo);
            accs[nt][1] = __expf(accs[nt][1] - m_lo);
            accs[nt][2] = __expf(accs[nt][2] - m_hi);
            accs[nt][3] = __expf(accs[nt][3] - m_hi);
            sum_lo += accs[nt][0] + accs[nt][1];
            sum_hi += accs[nt][2] + accs[nt][3];
        }
        sum_lo += __shfl_xor_sync(~0u, sum_lo, 1);
        sum_lo += __shfl_xor_sync(~0u, sum_lo, 2);
        sum_hi += __shfl_xor_sync(~0u, sum_hi, 1);
        sum_hi += __shfl_xor_sync(~0u, sum_hi, 2);
        l_lo = l_lo * al_lo + sum_lo;
        l_hi = l_hi * al_hi + sum_hi;

#pragma unroll
        for (int nt = 0; nt < 8; nt++) {
            acco[nt][0] *= al_lo; acco[nt][1] *= al_lo;
            acco[nt][2] *= al_hi; acco[nt][3] *= al_hi;
        }

#pragma unroll
        for (int s = 0; s < 4; s++) {
            uint32_t a[4];
            a[0] = packhf(accs[2*s][0],     accs[2*s][1]);
            a[1] = packhf(accs[2*s][2],     accs[2*s][3]);
            a[2] = packhf(accs[2*s + 1][0], accs[2*s + 1][1]);
            a[3] = packhf(accs[2*s + 1][2], accs[2*s + 1][3]);
#pragma unroll
            for (int nt = 0; nt < 8; nt++) {
                uint32_t bb[2];
                bb[0] = Vs[nt * 8 + gid][s * 8 + tig];
                bb[1] = Vs[nt * 8 + gid][s * 8 + tig + 4];
                mma16h(acco[nt], a, bb);
            }
        }
    }

    const float inv_lo = 1.0f / l_lo, inv_hi = 1.0f / l_hi;
#pragma unroll
    for (int nt = 0; nt < 8; nt++) {
        int c = nt * 8 + (tig << 1);
        size_t r0 = (size_t)(i0 + mb + gid) * DDIM + c;
        size_t r1 = (size_t)(i0 + mb + gid + 8) * DDIM + c;
        *(__half2*)(Oh + r0) = __floats2half2_rn(acco[nt][0] * inv_lo,
                                                 acco[nt][1] * inv_lo);
        *(__half2*)(Oh + r1) = __floats2half2_rn(acco[nt][2] * inv_hi,
                                                 acco[nt][3] * inv_hi);
    }
}

// ---------------- add + LayerNorm (+ optional fp16 plane output) -------------
__global__ __launch_bounds__(256)
void add_ln(const float* __restrict__ x, const float* __restrict__ y,
            const float* __restrict__ g, const float* __restrict__ be,
            float* __restrict__ out, hf16* __restrict__ hi) {
    __shared__ float sm[8];
    __shared__ float bc;
    const int tid = threadIdx.x;
    const size_t ro = (size_t)blockIdx.x * DDIM;
    float4 a = reinterpret_cast<const float4*>(x + ro)[tid];
    float4 b = reinterpret_cast<const float4*>(y + ro)[tid];
    a.x += b.x; a.y += b.y; a.z += b.z; a.w += b.w;

    float s = a.x + a.y + a.z + a.w;
#pragma unroll
    for (int o = 16; o; o >>= 1) s += __shfl_xor_sync(~0u, s, o);
    if ((tid & 31) == 0) sm[tid >> 5] = s;
    __syncthreads();
    if (tid < 32) {
        float t = (tid < 8) ? sm[tid] : 0.f;
#pragma unroll
        for (int o = 4; o; o >>= 1) t += __shfl_xor_sync(~0u, t, o);
        if (tid == 0) bc = t;
    }
    __syncthreads();
    const float mu = bc * (1.0f / DDIM);
    a.x -= mu; a.y -= mu; a.z -= mu; a.w -= mu;
    float qv = a.x*a.x + a.y*a.y + a.z*a.z + a.w*a.w;
    __syncthreads();
#pragma unroll
    for (int o = 16; o; o >>= 1) qv += __shfl_xor_sync(~0u, qv, o);
    if ((tid & 31) == 0) sm[tid >> 5] = qv;
    __syncthreads();
    if (tid < 32) {
        float t = (tid < 8) ? sm[tid] : 0.f;
#pragma unroll
        for (int o = 4; o; o >>= 1) t += __shfl_xor_sync(~0u, t, o);
        if (tid == 0) bc = t;
    }
    __syncthreads();
    const float rs = rsqrtf(bc * (1.0f / DDIM) + 1e-5f);
    float4 gv = reinterpret_cast<const float4*>(g)[tid];
    float4 bv = reinterpret_cast<const float4*>(be)[tid];
    float4 o;
    o.x = a.x * rs * gv.x + bv.x;
    o.y = a.y * rs * gv.y + bv.y;
    o.z = a.z * rs * gv.z + bv.z;
    o.w = a.w * rs * gv.w + bv.w;
    reinterpret_cast<float4*>(out + ro)[tid] = o;
    if (hi) {
        size_t i4 = ro + tid * 4;
        *(__half2*)(hi + i4)     = __floats2half2_rn(o.x, o.y);
        *(__half2*)(hi + i4 + 2) = __floats2half2_rn(o.z, o.w);
    }
}

// ---------------- launch ------------------------------------------------------
extern "C" void kernel_launch(void* const* d_in, const int* in_sizes, int n_in,
                              void* d_out, int out_size) {
    const int*   tokens = (const int*)  d_in[0];
    const float* emb    = (const float*)d_in[1];
    const float* Wq = (const float*)d_in[2],  *bq = (const float*)d_in[3];
    const float* Wk = (const float*)d_in[4],  *bk = (const float*)d_in[5];
    const float* Wv = (const float*)d_in[6],  *bv = (const float*)d_in[7];
    const float* Wo = (const float*)d_in[8],  *bo = (const float*)d_in[9];
    const float* W1 = (const float*)d_in[10], *b1 = (const float*)d_in[11];
    const float* W2 = (const float*)d_in[12], *b2 = (const float*)d_in[13];
    const float* gamma = (const float*)d_in[14], *beta = (const float*)d_in[15];
    float* out = (float*)d_out;

    float *x, *t, *bqkv;
    cudaGetSymbolAddress((void**)&x,    g_x);
    cudaGetSymbolAddress((void**)&t,    g_t);
    cudaGetSymbolAddress((void**)&bqkv, g_bqkv);
    hf16 *qkv, *wqkvh, *woh, *w1h, *w2h, *ah, *hh;
    cudaGetSymbolAddress((void**)&qkv,   g_qkv);
    cudaGetSymbolAddress((void**)&wqkvh, g_wqkvh);
    cudaGetSymbolAddress((void**)&woh, g_woh);
    cudaGetSymbolAddress((void**)&w1h, g_w1h);
    cudaGetSymbolAddress((void**)&w2h, g_w2h);
    cudaGetSymbolAddress((void**)&ah,  g_ah);
    cudaGetSymbolAddress((void**)&hh,  g_hh);

    cudaFuncSetAttribute(gemm_hf1<4, false, true, true>,
                         cudaFuncAttributeMaxDynamicSharedMemorySize, G1_SMEM_MT(4));
    cudaFuncSetAttribute(gemm_hf1<2, true, true, false>,
                         cudaFuncAttributeMaxDynamicSharedMemorySize, G1_SMEM_MT(2));
    cudaFuncSetAttribute(gemm_hf1<2, false, false, false>,
                         cudaFuncAttributeMaxDynamicSharedMemorySize, G1_SMEM_MT(2));

    embed_pe<<<BSR * DDIM / 256, 256>>>(tokens, emb);

    // weight conversion: flat fp32->fp16 (QKV packed into [K][3N] columns)
    const size_t DD = (size_t)DDIM * DDIM, DF = (size_t)DDIM * FFD;
    const int nDD = (int)(DD / 1024), nDF = (int)(DF / 1024);
    conv_w<<<dim3(nDD, 1, LLAY), 256>>>(Wq, wqkvh, DDIM, QD, 0,        DD, 3 * DD);
    conv_w<<<dim3(nDD, 1, LLAY), 256>>>(Wk, wqkvh, DDIM, QD, DDIM,     DD, 3 * DD);
    conv_w<<<dim3(nDD, 1, LLAY), 256>>>(Wv, wqkvh, DDIM, QD, 2 * DDIM, DD, 3 * DD);
    conv_w<<<dim3(nDD, 1, LLAY), 256>>>(Wo, woh, DDIM, DDIM, 0, DD, DD);
    conv_w<<<dim3(nDF, 1, LLAY), 256>>>(W1, w1h, FFD,  FFD,  0, DF, DF);
    conv_w<<<dim3(nDF, 1, LLAY), 256>>>(W2, w2h, DDIM, DDIM, 0, DF, DF);
    pack_bias<<<dim3(QD / 256, LLAY), 256>>>(bq, bk, bv);

    const dim3 gqkv(QD  / 128, BSR / 128);  // 24 x 16 = 384 CTAs (MT=4)
    const dim3 gp64(DDIM / 128, BSR / 64);  // 8 x 32 = 256 CTAs (MT=2)
    const dim3 gf64(FFD  / 128, BSR / 64);  // 16 x 32 = 512 CTAs (MT=2)

    for (int l = 0; l < LLAY; l++) {
        size_t od = (size_t)l * DD, of = (size_t)l * DF;
        const float* lbo = bo + (size_t)l * DDIM;
        const float* lb1 = b1 + (size_t)l * FFD;
        const float* lb2 = b2 + (size_t)l * DDIM;
        const float* lg  = gamma + (size_t)l * DDIM;
        const float* lbe = beta  + (size_t)l * DDIM;

        gemm_hf1<4, false, true, true><<<gqkv, 256, G1_SMEM_MT(4)>>>(
            ah, wqkvh + (size_t)l * 3 * DD, bqkv + (size_t)l * QD,
            nullptr, qkv, BSR, QD, DDIM, QD);

        flash_attn<<<dim3(SS / 128, BB * HH), 256>>>(qkv);

        gemm_hf1<2, false, false, false><<<gp64, 256, G1_SMEM_MT(2)>>>(
            ah, woh + od, lbo, t, nullptr, BSR, DDIM, DDIM, DDIM);
        add_ln<<<BSR, 256>>>(x, t, lg, lbe, x, ah);

        gemm_hf1<2, true, true, false><<<gf64, 256, G1_SMEM_MT(2)>>>(
            ah, w1h + of, lb1, nullptr, hh, BSR, FFD, DDIM, FFD);
        gemm_hf1<2, false, false, false><<<gp64, 256, G1_SMEM_MT(2)>>>(
            hh, w2h + of, lb2, t, nullptr, BSR, DDIM, FFD, DDIM);

        float* xo = (l == LLAY - 1) ? out : x;
        hf16* nh = (l == LLAY - 1) ? nullptr : ah;
        add_ln<<<BSR, 256>>>(x, t, lg, lbe, xo, nh);
    }
}